// round 7
// baseline (speedup 1.0000x reference)
#include <cuda_runtime.h>
#include <math.h>

typedef unsigned long long u64;

#define TPB 256
#define PW 260     // pitch of transposed W tile; PW%32==4 -> conflict-free STS.128

#define OUT_GATE_BASE 33554432UL   // B*M*D

// y scratch: [B,M,D] fp32 = 128MB
__device__ float g_y[32768u * 4u * 256u];

// ---------- packed fp32 helpers (Blackwell f32x2) ----------
static __device__ __forceinline__ u64 ffma2(u64 a, u64 b, u64 c) {
    u64 d;
    asm("fma.rn.f32x2 %0, %1, %2, %3;" : "=l"(d) : "l"(a), "l"(b), "l"(c));
    return d;
}
static __device__ __forceinline__ u64 dup2(float a) {
    u64 d;
    asm("mov.b64 %0, {%1, %1};" : "=l"(d) : "f"(a));
    return d;
}
static __device__ __forceinline__ float2 unpk(u64 p) {
    float2 r;
    asm("mov.b64 {%0, %1}, %2;" : "=f"(r.x), "=f"(r.y) : "l"(p));
    return r;
}
static __device__ __forceinline__ float comp4(const float4& v, int dd) {
    return dd == 0 ? v.x : dd == 1 ? v.y : dd == 2 ? v.z : v.w;
}

// ---------- W tile prefetch, d-major: idx -> (c4 = idx>>5, d = idx&31) ----------
template<int NIT>
struct Wreg { float f[NIT][4]; };

template<int NIT>
static __device__ __forceinline__ void ldgW(const float* __restrict__ W, int ldw, int k0,
                                            Wreg<NIT>& r, int tid) {
#pragma unroll
    for (int k = 0; k < NIT; ++k) {
        const int idx = tid + k * TPB;
        const int d = idx & 31, c4 = idx >> 5;
#pragma unroll
        for (int i = 0; i < 4; ++i)
            r.f[k][i] = W[(size_t)(c4 * 4 + i) * ldw + k0 + d];
    }
}

// STS.128 to sWT[d*PW + c4*4] — conflict-free (PW%32==4)
template<int NIT>
static __device__ __forceinline__ void stsW(float* sWT, const Wreg<NIT>& r, int tid) {
#pragma unroll
    for (int k = 0; k < NIT; ++k) {
        const int idx = tid + k * TPB;
        const int d = idx & 31, c4 = idx >> 5;
        *reinterpret_cast<float4*>(sWT + d * PW + c4 * 4) =
            make_float4(r.f[k][0], r.f[k][1], r.f[k][2], r.f[k][3]);
    }
}

// ---------- mma: 64 rows x 256 cols, 256 threads, 8x8 thread tiles ----------
static __device__ __forceinline__ void mma64b(const float* __restrict__ aRow, int lda,
                                              const float* __restrict__ sWT,
                                              u64 acc[8][4], int colg) {
#pragma unroll
    for (int d4 = 0; d4 < 8; ++d4) {
        float4 a4[8];
#pragma unroll
        for (int i = 0; i < 8; ++i)
            a4[i] = *reinterpret_cast<const float4*>(aRow + i * lda + (d4 << 2));
#pragma unroll
        for (int dd = 0; dd < 4; ++dd) {
            const int d = (d4 << 2) + dd;
            const ulonglong2 w0 = *reinterpret_cast<const ulonglong2*>(sWT + d * PW + (colg << 2));
            const ulonglong2 w1 = *reinterpret_cast<const ulonglong2*>(sWT + d * PW + 128 + (colg << 2));
#pragma unroll
            for (int i = 0; i < 8; ++i) {
                const u64 ad = dup2(comp4(a4[i], dd));
                acc[i][0] = ffma2(ad, w0.x, acc[i][0]);
                acc[i][1] = ffma2(ad, w0.y, acc[i][1]);
                acc[i][2] = ffma2(ad, w1.x, acc[i][2]);
                acc[i][3] = ffma2(ad, w1.y, acc[i][3]);
            }
        }
    }
}

// ---------- mma: 16 rows x 256 cols ----------
static __device__ __forceinline__ void mma16b(const float* __restrict__ aRow, int lda,
                                              const float* __restrict__ sWT,
                                              u64 acc[2][4], int colg) {
#pragma unroll
    for (int d4 = 0; d4 < 8; ++d4) {
        float4 a4[2];
        a4[0] = *reinterpret_cast<const float4*>(aRow + (d4 << 2));
        a4[1] = *reinterpret_cast<const float4*>(aRow + lda + (d4 << 2));
#pragma unroll
        for (int dd = 0; dd < 4; ++dd) {
            const int d = (d4 << 2) + dd;
            const ulonglong2 w0 = *reinterpret_cast<const ulonglong2*>(sWT + d * PW + (colg << 2));
            const ulonglong2 w1 = *reinterpret_cast<const ulonglong2*>(sWT + d * PW + 128 + (colg << 2));
#pragma unroll
            for (int i = 0; i < 2; ++i) {
                const u64 ad = dup2(comp4(a4[i], dd));
                acc[i][0] = ffma2(ad, w0.x, acc[i][0]);
                acc[i][1] = ffma2(ad, w0.y, acc[i][1]);
                acc[i][2] = ffma2(ad, w1.x, acc[i][2]);
                acc[i][3] = ffma2(ad, w1.y, acc[i][3]);
            }
        }
    }
}

// ---------- mma: 16 rows x 64 cols (gate1) ----------
static __device__ __forceinline__ void mmagb(const float* __restrict__ aRow, int lda,
                                             const float* __restrict__ sWT,
                                             u64 gacc[2], int colg) {
#pragma unroll
    for (int d4 = 0; d4 < 8; ++d4) {
        const float4 a0 = *reinterpret_cast<const float4*>(aRow + (d4 << 2));
        const float4 a1 = *reinterpret_cast<const float4*>(aRow + lda + (d4 << 2));
#pragma unroll
        for (int dd = 0; dd < 4; ++dd) {
            const u64 w = *reinterpret_cast<const u64*>(sWT + ((d4 << 2) + dd) * PW + colg * 2);
            gacc[0] = ffma2(dup2(comp4(a0, dd)), w, gacc[0]);
            gacc[1] = ffma2(dup2(comp4(a1, dd)), w, gacc[1]);
        }
    }
}

// =====================================================================
// Kernel 1: KV proj + attention + Wo + gate + LayerNorm -> g_y, gate->out
// grid (2048, 4), 16 batch elements per block, 256 threads
// sAO overlaid on dead sX rows (r%4 == (m+1)&3); sGH on (m+2)&3.
// =====================================================================
#define SM1_X    0        // 64*256 = 16384
#define SM1_WT0  16384    // 8320
#define SM1_WT1  24704    // 8320
#define SM1_Q    33024    // 16*256 = 4096 (Q, then Oh)
#define SM1_KV   37120    // 64*256 = 16384 (K, then V)
#define SM1_P    53504    // 512
#define SM1_GATE 54016    // 16
#define SM1_FLOATS 54032
#define SM1_BYTES  (SM1_FLOATS * 4)

__global__ __launch_bounds__(TPB, 1)
void gcma_part1(const float* __restrict__ x,
                const float* __restrict__ Wq, const float* __restrict__ bq,
                const float* __restrict__ Wk, const float* __restrict__ bk,
                const float* __restrict__ Wv, const float* __restrict__ bv,
                const float* __restrict__ Wo, const float* __restrict__ bo,
                const float* __restrict__ g1w, const float* __restrict__ g1b,
                const float* __restrict__ g2w, const float* __restrict__ g2b,
                const float* __restrict__ lng, const float* __restrict__ lnb,
                float* __restrict__ out)
{
    extern __shared__ float sm[];
    float* sX    = sm + SM1_X;
    float* sWT0  = sm + SM1_WT0;
    float* sWT1  = sm + SM1_WT1;
    float* sQ    = sm + SM1_Q;
    float* sKV   = sm + SM1_KV;
    float* sP    = sm + SM1_P;
    float* sGate = sm + SM1_GATE;

    const int tid = threadIdx.x;
    const int m   = blockIdx.y;
    const int b0  = blockIdx.x * 16;
    const long g0 = (long)b0 * 4;

    const int warp = tid >> 5;    // 0..7
    const int colg = tid & 31;
    const int offAO = (m + 1) & 3;   // dead-row modality slot for attn_out
    const int offGH = (m + 2) & 3;   // dead-row modality slot for gate hidden

    float* const bufs[2] = {sWT0, sWT1};

    // ---- stage X block [64 rows][256] row-major ----
    {
        const float* Xblk = x + (size_t)g0 * 256;
        for (int idx = tid; idx < 4096; idx += TPB) {
            const int r = idx >> 6, q = idx & 63;
            *reinterpret_cast<float4*>(sX + r * 256 + q * 4) =
                *reinterpret_cast<const float4*>(Xblk + r * 256 + q * 4);
        }
    }

    // ---- Q: [16 x 256], scaled ----
    {
        const float* W    = Wq + (size_t)m * 65536;
        const float* bias = bq + m * 256;
        Wreg<8> wr;
        ldgW<8>(W, 256, 0, wr, tid);
        stsW<8>(sWT0, wr, tid);
        ldgW<8>(W, 256, 32, wr, tid);
        __syncthreads();
        u64 acc[2][4];
#pragma unroll
        for (int i = 0; i < 2; ++i)
#pragma unroll
            for (int j = 0; j < 4; ++j) acc[i][j] = 0ULL;
        const float* aRow = sX + m * 256 + warp * 2 * 1024;
        for (int dt = 0; dt < 8; ++dt) {
            mma16b(aRow + dt * 32, 1024, bufs[dt & 1], acc, colg);
            if (dt < 7) {
                stsW<8>(bufs[(dt + 1) & 1], wr, tid);
                if (dt < 6) ldgW<8>(W, 256, (dt + 2) * 32, wr, tid);
                __syncthreads();
            }
        }
        float bl0[4], bl1[4];
#pragma unroll
        for (int j = 0; j < 4; ++j) { bl0[j] = bias[colg * 4 + j]; bl1[j] = bias[128 + colg * 4 + j]; }
#pragma unroll
        for (int i = 0; i < 2; ++i) {
            const int r = warp * 2 + i;
            const float2 pa = unpk(acc[i][0]), pb = unpk(acc[i][1]);
            const float2 pc = unpk(acc[i][2]), pd = unpk(acc[i][3]);
            const float s = 0.17677669529663687f;
            *reinterpret_cast<float4*>(sQ + r * 256 + colg * 4) =
                make_float4((pa.x + bl0[0]) * s, (pa.y + bl0[1]) * s,
                            (pb.x + bl0[2]) * s, (pb.y + bl0[3]) * s);
            *reinterpret_cast<float4*>(sQ + r * 256 + 128 + colg * 4) =
                make_float4((pc.x + bl1[0]) * s, (pc.y + bl1[1]) * s,
                            (pd.x + bl1[2]) * s, (pd.y + bl1[3]) * s);
        }
    }
    __syncthreads();

    // ---- K: [64 x 256] -> sKV ----
    {
        const float* W    = Wk + (size_t)m * 65536;
        const float* bias = bk + m * 256;
        Wreg<8> wr;
        ldgW<8>(W, 256, 0, wr, tid);
        stsW<8>(sWT0, wr, tid);
        ldgW<8>(W, 256, 32, wr, tid);
        __syncthreads();
        u64 acc[8][4];
#pragma unroll
        for (int i = 0; i < 8; ++i)
#pragma unroll
            for (int j = 0; j < 4; ++j) acc[i][j] = 0ULL;
        const float* aRow = sX + warp * 8 * 256;
        for (int dt = 0; dt < 8; ++dt) {
            mma64b(aRow + dt * 32, 256, bufs[dt & 1], acc, colg);
            if (dt < 7) {
                stsW<8>(bufs[(dt + 1) & 1], wr, tid);
                if (dt < 6) ldgW<8>(W, 256, (dt + 2) * 32, wr, tid);
                __syncthreads();
            }
        }
        float bl0[4], bl1[4];
#pragma unroll
        for (int j = 0; j < 4; ++j) { bl0[j] = bias[colg * 4 + j]; bl1[j] = bias[128 + colg * 4 + j]; }
#pragma unroll
        for (int i = 0; i < 8; ++i) {
            const int r = warp * 8 + i;
            const float2 pa = unpk(acc[i][0]), pb = unpk(acc[i][1]);
            const float2 pc = unpk(acc[i][2]), pd = unpk(acc[i][3]);
            *reinterpret_cast<float4*>(sKV + r * 256 + colg * 4) =
                make_float4(pa.x + bl0[0], pa.y + bl0[1], pb.x + bl0[2], pb.y + bl0[3]);
            *reinterpret_cast<float4*>(sKV + r * 256 + 128 + colg * 4) =
                make_float4(pc.x + bl1[0], pc.y + bl1[1], pd.x + bl1[2], pd.y + bl1[3]);
        }
    }
    __syncthreads();

    // ---- scores + softmax -> probs sP ----
    if (tid < 128) {
        const int bl = tid >> 3, h = tid & 7;
        const float* qp = sQ + bl * 256 + h * 32;
        float q[32];
#pragma unroll
        for (int i = 0; i < 32; ++i) q[i] = qp[i];
        float s[4];
#pragma unroll
        for (int n = 0; n < 4; ++n) {
            const float* kp = sKV + (bl * 4 + n) * 256 + h * 32;
            float dot = 0.f;
#pragma unroll
            for (int i = 0; i < 32; ++i) dot = fmaf(q[i], kp[i], dot);
            s[n] = dot;
        }
        const float mx = fmaxf(fmaxf(s[0], s[1]), fmaxf(s[2], s[3]));
        float e[4], se = 0.f;
#pragma unroll
        for (int n = 0; n < 4; ++n) { e[n] = expf(s[n] - mx); se += e[n]; }
        const float inv = 1.f / se;
#pragma unroll
        for (int n = 0; n < 4; ++n) sP[tid * 4 + n] = e[n] * inv;
    }

    // ---- V: [64 x 256] -> sKV (first barrier of this GEMM orders scores) ----
    {
        const float* W    = Wv + (size_t)m * 65536;
        const float* bias = bv + m * 256;
        Wreg<8> wr;
        ldgW<8>(W, 256, 0, wr, tid);
        stsW<8>(sWT0, wr, tid);
        ldgW<8>(W, 256, 32, wr, tid);
        __syncthreads();
        u64 acc[8][4];
#pragma unroll
        for (int i = 0; i < 8; ++i)
#pragma unroll
            for (int j = 0; j < 4; ++j) acc[i][j] = 0ULL;
        const float* aRow = sX + warp * 8 * 256;
        for (int dt = 0; dt < 8; ++dt) {
            mma64b(aRow + dt * 32, 256, bufs[dt & 1], acc, colg);
            if (dt < 7) {
                stsW<8>(bufs[(dt + 1) & 1], wr, tid);
                if (dt < 6) ldgW<8>(W, 256, (dt + 2) * 32, wr, tid);
                __syncthreads();
            }
        }
        __syncthreads();   // all scores reads of K (and all mma) done before overwrite
        float bl0[4], bl1[4];
#pragma unroll
        for (int j = 0; j < 4; ++j) { bl0[j] = bias[colg * 4 + j]; bl1[j] = bias[128 + colg * 4 + j]; }
#pragma unroll
        for (int i = 0; i < 8; ++i) {
            const int r = warp * 8 + i;
            const float2 pa = unpk(acc[i][0]), pb = unpk(acc[i][1]);
            const float2 pc = unpk(acc[i][2]), pd = unpk(acc[i][3]);
            *reinterpret_cast<float4*>(sKV + r * 256 + colg * 4) =
                make_float4(pa.x + bl0[0], pa.y + bl0[1], pb.x + bl0[2], pb.y + bl0[3]);
            *reinterpret_cast<float4*>(sKV + r * 256 + 128 + colg * 4) =
                make_float4(pc.x + bl1[0], pc.y + bl1[1], pd.x + bl1[2], pd.y + bl1[3]);
        }
    }
    __syncthreads();

    // ---- Oh = P @ V -> sQ (overwrites Q) ----
    if (tid < 128) {
        const int bl = tid >> 3, h = tid & 7;
        float o[32];
#pragma unroll
        for (int i = 0; i < 32; ++i) o[i] = 0.f;
#pragma unroll
        for (int n = 0; n < 4; ++n) {
            const float p = sP[tid * 4 + n];
            const float* vp = sKV + (bl * 4 + n) * 256 + h * 32;
#pragma unroll
            for (int i = 0; i < 32; ++i) o[i] = fmaf(p, vp[i], o[i]);
        }
        float* op = sQ + bl * 256 + h * 32;
#pragma unroll
        for (int i = 0; i < 32; ++i) op[i] = o[i];
    }

    // ---- Wo: attn_out [16 x 256] -> sAO overlay (first bar orders Oh) ----
    {
        const float* W    = Wo + (size_t)m * 65536;
        const float* bias = bo + m * 256;
        Wreg<8> wr;
        ldgW<8>(W, 256, 0, wr, tid);
        stsW<8>(sWT0, wr, tid);
        ldgW<8>(W, 256, 32, wr, tid);
        __syncthreads();
        u64 acc[2][4];
#pragma unroll
        for (int i = 0; i < 2; ++i)
#pragma unroll
            for (int j = 0; j < 4; ++j) acc[i][j] = 0ULL;
        const float* aRow = sQ + warp * 2 * 256;
        for (int dt = 0; dt < 8; ++dt) {
            mma16b(aRow + dt * 32, 256, bufs[dt & 1], acc, colg);
            if (dt < 7) {
                stsW<8>(bufs[(dt + 1) & 1], wr, tid);
                if (dt < 6) ldgW<8>(W, 256, (dt + 2) * 32, wr, tid);
                __syncthreads();
            }
        }
        float bl0[4], bl1[4];
#pragma unroll
        for (int j = 0; j < 4; ++j) { bl0[j] = bias[colg * 4 + j]; bl1[j] = bias[128 + colg * 4 + j]; }
#pragma unroll
        for (int i = 0; i < 2; ++i) {
            float* aoR = sX + (size_t)((warp * 2 + i) * 4 + offAO) * 256;
            const float2 pa = unpk(acc[i][0]), pb = unpk(acc[i][1]);
            const float2 pc = unpk(acc[i][2]), pd = unpk(acc[i][3]);
            *reinterpret_cast<float4*>(aoR + colg * 4) =
                make_float4(pa.x + bl0[0], pa.y + bl0[1], pb.x + bl0[2], pb.y + bl0[3]);
            *reinterpret_cast<float4*>(aoR + 128 + colg * 4) =
                make_float4(pc.x + bl1[0], pc.y + bl1[1], pd.x + bl1[2], pd.y + bl1[3]);
        }
    }

    // ---- gate layer 1: tanh([x_m ; AO] @ g1w^T) [16 x 64] -> sGH overlay ----
    {
        const float* W = g1w + (size_t)m * 32768;   // [64][512]
        Wreg<2> wr;
        ldgW<2>(W, 512, 0, wr, tid);
        stsW<2>(sWT0, wr, tid);
        ldgW<2>(W, 512, 32, wr, tid);
        __syncthreads();
        u64 gacc[2] = {0ULL, 0ULL};
        const float* aX  = sX + (size_t)(warp * 8 + m) * 256;
        const float* aAO = sX + (size_t)(warp * 8 + offAO) * 256;
        for (int dt = 0; dt < 16; ++dt) {
            const float* a = (dt < 8) ? (aX + dt * 32) : (aAO + (dt - 8) * 32);
            mmagb(a, 1024, bufs[dt & 1], gacc, colg);
            if (dt < 15) {
                stsW<2>(bufs[(dt + 1) & 1], wr, tid);
                if (dt < 14) ldgW<2>(W, 512, (dt + 2) * 32, wr, tid);
                __syncthreads();
            }
        }
        const float gb0 = g1b[m * 64 + colg * 2];
        const float gb1 = g1b[m * 64 + colg * 2 + 1];
#pragma unroll
        for (int i = 0; i < 2; ++i) {
            const int r = warp * 2 + i;
            float* g = sX + (size_t)((r >> 2) * 4 + offGH) * 256 + (r & 3) * 64;
            const float2 p = unpk(gacc[i]);
            g[colg * 2]     = tanhf(p.x + gb0);
            g[colg * 2 + 1] = tanhf(p.y + gb1);
        }
    }
    __syncthreads();

    // ---- gate layer 2 + sigmoid ----
    if (tid < 16) {
        const float* g2 = g2w + m * 64;
        const float* g  = sX + (size_t)((tid >> 2) * 4 + offGH) * 256 + (tid & 3) * 64;
        float dot = g2b[m];
#pragma unroll 8
        for (int j = 0; j < 64; ++j) dot = fmaf(g[j], g2[j], dot);
        const float gate = 1.f / (1.f + expf(-dot));
        sGate[tid] = gate;
        out[OUT_GATE_BASE + (size_t)(b0 + tid) * 4 + m] = gate;
    }
    __syncthreads();

    // ---- residual + LayerNorm -> g_y ----
    {
        const int lane = tid & 31;
        for (int bl = warp; bl < 16; bl += 8) {
            const float* xr  = sX + (size_t)(bl * 4 + m) * 256;
            const float* aor = sX + (size_t)(bl * 4 + offAO) * 256;
            const float gate = sGate[bl];
            float r[8];
            float sum = 0.f;
#pragma unroll
            for (int k = 0; k < 8; ++k) {
                const int d = k * 32 + lane;
                r[k] = xr[d] + gate * aor[d];
                sum += r[k];
            }
#pragma unroll
            for (int o = 16; o; o >>= 1) sum += __shfl_xor_sync(0xffffffffu, sum, o);
            const float mu = sum * (1.f / 256.f);
            float var = 0.f;
#pragma unroll
            for (int k = 0; k < 8; ++k) { const float t = r[k] - mu; var = fmaf(t, t, var); }
#pragma unroll
            for (int o = 16; o; o >>= 1) var += __shfl_xor_sync(0xffffffffu, var, o);
            const float rs = rsqrtf(var * (1.f / 256.f) + 1e-5f);
            float* yr = g_y + (size_t)(g0 + bl * 4 + m) * 256;
#pragma unroll
            for (int k = 0; k < 8; ++k) {
                const int d = k * 32 + lane;
                yr[d] = (r[k] - mu) * rs * lng[m * 256 + d] + lnb[m * 256 + d];
            }
        }
    }
}

// =====================================================================
// Kernel 2: FF over y: out = y + f2( gelu(f1(y)) )
// grid (512, 4), 64 batch rows, 256 threads, double-buffered W tiles
// =====================================================================
#define SM2_Y    0          // 16384
#define SM2_HF   16384      // 16384
#define SM2_WT0  32768      // 8320
#define SM2_WT1  41088      // 8320
#define SM2_FLOATS 49408
#define SM2_BYTES  (SM2_FLOATS * 4)

__global__ __launch_bounds__(TPB, 1)
void gcma_part2(const float* __restrict__ f1w, const float* __restrict__ f1b,
                const float* __restrict__ f2w, const float* __restrict__ f2b,
                float* __restrict__ out)
{
    extern __shared__ float sm[];
    float* sY   = sm + SM2_Y;
    float* sHF  = sm + SM2_HF;
    float* sWT0 = sm + SM2_WT0;
    float* sWT1 = sm + SM2_WT1;
    float* const bufs[2] = {sWT0, sWT1};

    const int tid = threadIdx.x;
    const int m   = blockIdx.y;
    const int b0  = blockIdx.x * 64;

    const int warp = tid >> 5;   // 0..7, 8 rows each
    const int colg = tid & 31;   // cols {colg*4..+3, 128+colg*4..+3}

    // load y tile [64 rows][256]
    for (int idx = tid; idx < 4096; idx += TPB) {
        const int r = idx >> 6, q = idx & 63;
        *reinterpret_cast<float4*>(sY + r * 256 + q * 4) =
            *reinterpret_cast<const float4*>(g_y + ((size_t)(b0 + r) * 4 + m) * 256 + q * 4);
    }

    u64 facc[8][4];
#pragma unroll
    for (int i = 0; i < 8; ++i)
#pragma unroll
        for (int j = 0; j < 4; ++j) facc[i][j] = 0ULL;

    const float* aY  = sY  + warp * 8 * 256;
    const float* aHF = sHF + warp * 8 * 256;

    for (int ch = 0; ch < 4; ++ch) {
        // ---- FF1 chunk: hf[:, ch*256 .. +255] ----
        u64 hacc[8][4];
#pragma unroll
        for (int i = 0; i < 8; ++i)
#pragma unroll
            for (int j = 0; j < 4; ++j) hacc[i][j] = 0ULL;
        {
            const float* W1 = f1w + (size_t)m * 262144 + (size_t)ch * 65536;
            Wreg<8> wr;
            ldgW<8>(W1, 256, 0, wr, tid);
            stsW<8>(sWT0, wr, tid);
            ldgW<8>(W1, 256, 32, wr, tid);
            __syncthreads();
            for (int dt = 0; dt < 8; ++dt) {
                mma64b(aY + dt * 32, 256, bufs[dt & 1], hacc, colg);
                if (dt < 7) {
                    stsW<8>(bufs[(dt + 1) & 1], wr, tid);
                    if (dt < 6) ldgW<8>(W1, 256, (dt + 2) * 32, wr, tid);
                    __syncthreads();
                }
            }
        }
        __syncthreads();   // previous FF2 reads of sHF complete before overwrite
        // bias + exact GELU -> sHF
        {
            const float* b1 = f1b + m * 1024 + ch * 256;
            float bl0[4], bl1[4];
#pragma unroll
            for (int j = 0; j < 4; ++j) { bl0[j] = b1[colg * 4 + j]; bl1[j] = b1[128 + colg * 4 + j]; }
#pragma unroll
            for (int i = 0; i < 8; ++i) {
                const int r = warp * 8 + i;
                const float2 pa = unpk(hacc[i][0]), pb = unpk(hacc[i][1]);
                const float2 pc = unpk(hacc[i][2]), pd = unpk(hacc[i][3]);
                float v0[4] = {pa.x + bl0[0], pa.y + bl0[1], pb.x + bl0[2], pb.y + bl0[3]};
                float v1[4] = {pc.x + bl1[0], pc.y + bl1[1], pd.x + bl1[2], pd.y + bl1[3]};
#pragma unroll
                for (int j = 0; j < 4; ++j) {
                    v0[j] = 0.5f * v0[j] * (1.f + erff(v0[j] * 0.7071067811865476f));
                    v1[j] = 0.5f * v1[j] * (1.f + erff(v1[j] * 0.7071067811865476f));
                }
                *reinterpret_cast<float4*>(sHF + r * 256 + colg * 4) =
                    make_float4(v0[0], v0[1], v0[2], v0[3]);
                *reinterpret_cast<float4*>(sHF + r * 256 + 128 + colg * 4) =
                    make_float4(v1[0], v1[1], v1[2], v1[3]);
            }
        }
        // ---- FF2 partial (first bar orders GELU stores) ----
        {
            const float* W2 = f2w + (size_t)m * 262144;
            Wreg<8> wr;
            ldgW<8>(W2, 1024, ch * 256, wr, tid);
            stsW<8>(sWT0, wr, tid);
            ldgW<8>(W2, 1024, ch * 256 + 32, wr, tid);
            __syncthreads();
            for (int dt = 0; dt < 8; ++dt) {
                mma64b(aHF + dt * 32, 256, bufs[dt & 1], facc, colg);
                if (dt < 7) {
                    stsW<8>(bufs[(dt + 1) & 1], wr, tid);
                    if (dt < 6) ldgW<8>(W2, 1024, ch * 256 + (dt + 2) * 32, wr, tid);
                    __syncthreads();
                }
            }
        }
        __syncthreads();
    }

    // ---- epilogue: out = y + ff + f2b ----
    {
        const float* b2 = f2b + m * 256;
        float bl0[4], bl1[4];
#pragma unroll
        for (int j = 0; j < 4; ++j) { bl0[j] = b2[colg * 4 + j]; bl1[j] = b2[128 + colg * 4 + j]; }
#pragma unroll
        for (int i = 0; i < 8; ++i) {
            const int r = warp * 8 + i;
            const float4 y0 = *reinterpret_cast<const float4*>(sY + r * 256 + colg * 4);
            const float4 y1 = *reinterpret_cast<const float4*>(sY + r * 256 + 128 + colg * 4);
            const float2 pa = unpk(facc[i][0]), pb = unpk(facc[i][1]);
            const float2 pc = unpk(facc[i][2]), pd = unpk(facc[i][3]);
            float* op = out + ((size_t)(b0 + r) * 4 + m) * 256;
            *reinterpret_cast<float4*>(op + colg * 4) =
                make_float4(y0.x + pa.x + bl0[0], y0.y + pa.y + bl0[1],
                            y0.z + pb.x + bl0[2], y0.w + pb.y + bl0[3]);
            *reinterpret_cast<float4*>(op + 128 + colg * 4) =
                make_float4(y1.x + pc.x + bl1[0], y1.y + pc.y + bl1[1],
                            y1.z + pd.x + bl1[2], y1.w + pd.y + bl1[3]);
        }
    }
}

extern "C" void kernel_launch(void* const* d_in, const int* in_sizes, int n_in,
                              void* d_out, int out_size) {
    const float* x   = (const float*)d_in[0];
    const float* Wq  = (const float*)d_in[1];
    const float* bq  = (const float*)d_in[2];
    const float* Wk  = (const float*)d_in[3];
    const float* bk  = (const float*)d_in[4];
    const float* Wv  = (const float*)d_in[5];
    const float* bv  = (const float*)d_in[6];
    const float* Wo  = (const float*)d_in[7];
    const float* bo  = (const float*)d_in[8];
    const float* g1w = (const float*)d_in[9];
    const float* g1b = (const float*)d_in[10];
    const float* g2w = (const float*)d_in[11];
    const float* g2b = (const float*)d_in[12];
    const float* lng = (const float*)d_in[13];
    const float* lnb = (const float*)d_in[14];
    const float* f1w = (const float*)d_in[15];
    const float* f1b = (const float*)d_in[16];
    const float* f2w = (const float*)d_in[17];
    const float* f2b = (const float*)d_in[18];
    float* out = (float*)d_out;

    cudaFuncSetAttribute(gcma_part1, cudaFuncAttributeMaxDynamicSharedMemorySize, SM1_BYTES);
    cudaFuncSetAttribute(gcma_part2, cudaFuncAttributeMaxDynamicSharedMemorySize, SM2_BYTES);

    dim3 grid1(32768 / 16, 4, 1);
    gcma_part1<<<grid1, TPB, SM1_BYTES>>>(x, Wq, bq, Wk, bk, Wv, bv, Wo, bo,
                                          g1w, g1b, g2w, g2b, lng, lnb, out);
    dim3 grid2(32768 / 64, 4, 1);
    gcma_part2<<<grid2, TPB, SM2_BYTES>>>(f1w, f1b, f2w, f2b, out);
}

// round 9
// speedup vs baseline: 1.3350x; 1.3350x over previous
#include <cuda_runtime.h>
#include <cuda_bf16.h>
#include <math.h>
#include <stdint.h>

typedef unsigned long long u64;

#define TPB 256
#define PW 260     // pitch of transposed W tile; PW%32==4 -> conflict-free STS.128

#define OUT_GATE_BASE 33554432UL   // B*M*D

// tcgen05 only exists in the arch-specific (sm_103a) compile pass
#if defined(__CUDA_ARCH_FEAT_SM103_ALL) || \
    (defined(__CUDA_ARCH_SPECIFIC__) && (__CUDA_ARCH_SPECIFIC__ == 1030)) || \
    (defined(__CUDA_ARCH_FAMILY_SPECIFIC__) && (__CUDA_ARCH_FAMILY_SPECIFIC__ == 1030))
#define GB_TC 1
#else
#define GB_TC 0
#endif

// y scratch: [B,M,D] fp32 = 128MB
__device__ float g_y[32768u * 4u * 256u];
// pre-split, pre-swizzled bf16 weight tiles: [m][c1][c2][hi 16384 | lo 16384]
__device__ __nv_bfloat16 g_w1t[64u * 32768u];
__device__ __nv_bfloat16 g_w2t[64u * 32768u];
// hf scratch per part2 block: [1024 blocks][128 rows][1024 k] (hi,lo bf16 packed u32)
__device__ unsigned g_hfscr[1024u * 131072u];

// ---------- packed fp32 helpers (Blackwell f32x2) ----------
static __device__ __forceinline__ u64 ffma2(u64 a, u64 b, u64 c) {
    u64 d;
    asm("fma.rn.f32x2 %0, %1, %2, %3;" : "=l"(d) : "l"(a), "l"(b), "l"(c));
    return d;
}
static __device__ __forceinline__ u64 dup2(float a) {
    u64 d;
    asm("mov.b64 %0, {%1, %1};" : "=l"(d) : "f"(a));
    return d;
}
static __device__ __forceinline__ float2 unpk(u64 p) {
    float2 r;
    asm("mov.b64 {%0, %1}, %2;" : "=f"(r.x), "=f"(r.y) : "l"(p));
    return r;
}
static __device__ __forceinline__ float comp4(const float4& v, int dd) {
    return dd == 0 ? v.x : dd == 1 ? v.y : dd == 2 ? v.z : v.w;
}

static __device__ __forceinline__ unsigned pk2(__nv_bfloat16 a, __nv_bfloat16 b) {
    return (unsigned)__bfloat16_as_ushort(a) | ((unsigned)__bfloat16_as_ushort(b) << 16);
}
static __device__ __forceinline__ void bsplit(float v, __nv_bfloat16& h, __nv_bfloat16& l) {
    h = __float2bfloat16(v);
    l = __float2bfloat16(v - __bfloat162float(h));
}
static __device__ __forceinline__ uint32_t swz128(uint32_t b) { return b ^ ((b >> 3) & 0x70); }

// ---------- fp32 W tile prefetch ----------
template<int NIT>
struct Wreg { float f[NIT][4]; };

template<int NIT>
static __device__ __forceinline__ void ldgW(const float* __restrict__ W, int ldw, int k0,
                                            Wreg<NIT>& r, int tid) {
#pragma unroll
    for (int k = 0; k < NIT; ++k) {
        const int idx = tid + k * TPB;
        const int d = idx & 31, c4 = idx >> 5;
#pragma unroll
        for (int i = 0; i < 4; ++i)
            r.f[k][i] = W[(size_t)(c4 * 4 + i) * ldw + k0 + d];
    }
}
template<int NIT>
static __device__ __forceinline__ void stsW(float* sWT, const Wreg<NIT>& r, int tid) {
#pragma unroll
    for (int k = 0; k < NIT; ++k) {
        const int idx = tid + k * TPB;
        const int d = idx & 31, c4 = idx >> 5;
        *reinterpret_cast<float4*>(sWT + d * PW + c4 * 4) =
            make_float4(r.f[k][0], r.f[k][1], r.f[k][2], r.f[k][3]);
    }
}

static __device__ __forceinline__ void mma64b(const float* __restrict__ aRow, int lda,
                                              const float* __restrict__ sWT,
                                              u64 acc[8][4], int colg) {
#pragma unroll
    for (int d4 = 0; d4 < 8; ++d4) {
        float4 a4[8];
#pragma unroll
        for (int i = 0; i < 8; ++i)
            a4[i] = *reinterpret_cast<const float4*>(aRow + i * lda + (d4 << 2));
#pragma unroll
        for (int dd = 0; dd < 4; ++dd) {
            const int d = (d4 << 2) + dd;
            const ulonglong2 w0 = *reinterpret_cast<const ulonglong2*>(sWT + d * PW + (colg << 2));
            const ulonglong2 w1 = *reinterpret_cast<const ulonglong2*>(sWT + d * PW + 128 + (colg << 2));
#pragma unroll
            for (int i = 0; i < 8; ++i) {
                const u64 ad = dup2(comp4(a4[i], dd));
                acc[i][0] = ffma2(ad, w0.x, acc[i][0]);
                acc[i][1] = ffma2(ad, w0.y, acc[i][1]);
                acc[i][2] = ffma2(ad, w1.x, acc[i][2]);
                acc[i][3] = ffma2(ad, w1.y, acc[i][3]);
            }
        }
    }
}
static __device__ __forceinline__ void mma16b(const float* __restrict__ aRow, int lda,
                                              const float* __restrict__ sWT,
                                              u64 acc[2][4], int colg) {
#pragma unroll
    for (int d4 = 0; d4 < 8; ++d4) {
        float4 a4[2];
        a4[0] = *reinterpret_cast<const float4*>(aRow + (d4 << 2));
        a4[1] = *reinterpret_cast<const float4*>(aRow + lda + (d4 << 2));
#pragma unroll
        for (int dd = 0; dd < 4; ++dd) {
            const int d = (d4 << 2) + dd;
            const ulonglong2 w0 = *reinterpret_cast<const ulonglong2*>(sWT + d * PW + (colg << 2));
            const ulonglong2 w1 = *reinterpret_cast<const ulonglong2*>(sWT + d * PW + 128 + (colg << 2));
#pragma unroll
            for (int i = 0; i < 2; ++i) {
                const u64 ad = dup2(comp4(a4[i], dd));
                acc[i][0] = ffma2(ad, w0.x, acc[i][0]);
                acc[i][1] = ffma2(ad, w0.y, acc[i][1]);
                acc[i][2] = ffma2(ad, w1.x, acc[i][2]);
                acc[i][3] = ffma2(ad, w1.y, acc[i][3]);
            }
        }
    }
}
static __device__ __forceinline__ void mmagb(const float* __restrict__ aRow, int lda,
                                             const float* __restrict__ sWT,
                                             u64 gacc[2], int colg) {
#pragma unroll
    for (int d4 = 0; d4 < 8; ++d4) {
        const float4 a0 = *reinterpret_cast<const float4*>(aRow + (d4 << 2));
        const float4 a1 = *reinterpret_cast<const float4*>(aRow + lda + (d4 << 2));
#pragma unroll
        for (int dd = 0; dd < 4; ++dd) {
            const u64 w = *reinterpret_cast<const u64*>(sWT + ((d4 << 2) + dd) * PW + colg * 2);
            gacc[0] = ffma2(dup2(comp4(a0, dd)), w, gacc[0]);
            gacc[1] = ffma2(dup2(comp4(a1, dd)), w, gacc[1]);
        }
    }
}

#if GB_TC
// ---------- tcgen05 helpers (sm_103a pass only) ----------
static __device__ __forceinline__ uint32_t elect_one_pred() {
    uint32_t pred;
    asm volatile(
        "{\n\t.reg .pred p;\n\telect.sync _|p, 0xFFFFFFFF;\n\tselp.b32 %0, 1, 0, p;\n\t}"
        : "=r"(pred));
    return pred;
}
#define TCGEN05_ALLOC(sa, n) \
    asm volatile("tcgen05.alloc.cta_group::1.sync.aligned.shared::cta.b32 [%0], %1;" \
                 :: "r"((uint32_t)(sa)), "r"((uint32_t)(n)) : "memory")
#define TCGEN05_DEALLOC(ta, n) \
    asm volatile("tcgen05.dealloc.cta_group::1.sync.aligned.b32 %0, %1;" :: "r"(ta), "r"((uint32_t)(n)))
#define TCGEN05_COMMIT(mb) \
    asm volatile("tcgen05.commit.cta_group::1.mbarrier::arrive::one.shared::cluster.b64 [%0];" \
                 :: "r"((uint32_t)(mb)) : "memory")
#define TCGEN05_WAIT_LD()  asm volatile("tcgen05.wait::ld.sync.aligned;" ::: "memory")
#define TCGEN05_FENCE_AFTER()  asm volatile("tcgen05.fence::after_thread_sync;" ::: "memory")
#define TCGEN05_FENCE_BEFORE() asm volatile("tcgen05.fence::before_thread_sync;" ::: "memory")
#define MBARRIER_INIT(mb, c) \
    asm volatile("mbarrier.init.shared.b64 [%0], %1;" :: "r"((uint32_t)(mb)), "r"((uint32_t)(c)) : "memory")
#define MBARRIER_WAIT_PARITY(mb, par) do { \
    uint32_t _mb = (uint32_t)(mb), _pa = (uint32_t)(par), _dn; \
    asm volatile("{\n\t.reg .pred p;\n\t" \
        "mbarrier.try_wait.parity.acquire.cta.shared::cta.b64 p, [%1], %2;\n\t" \
        "selp.b32 %0, 1, 0, p;\n\t}" : "=r"(_dn) : "r"(_mb), "r"(_pa) : "memory"); \
    if (!_dn) { \
        asm volatile("{\n\t.reg .pred P1;\n\t" \
            "WL_%=:\n\tmbarrier.try_wait.parity.acquire.cta.shared::cta.b64 P1, [%0], %1, 0x989680;\n\t" \
            "@P1 bra.uni WD_%=;\n\tbra.uni WL_%=;\n\tWD_%=:\n\t}" \
            :: "r"(_mb), "r"(_pa) : "memory"); \
    } \
} while (0)
#define TCGEN05_LD_32X32B_X32(r, ta) \
    asm volatile("tcgen05.ld.sync.aligned.32x32b.x32.b32 " \
        "{%0, %1, %2, %3, %4, %5, %6, %7, %8, %9, %10, %11, %12, %13, %14, %15, " \
        "%16, %17, %18, %19, %20, %21, %22, %23, %24, %25, %26, %27, %28, %29, %30, %31}, [%32];" \
        : "=r"((r)[0]),  "=r"((r)[1]),  "=r"((r)[2]),  "=r"((r)[3]), \
          "=r"((r)[4]),  "=r"((r)[5]),  "=r"((r)[6]),  "=r"((r)[7]), \
          "=r"((r)[8]),  "=r"((r)[9]),  "=r"((r)[10]), "=r"((r)[11]), \
          "=r"((r)[12]), "=r"((r)[13]), "=r"((r)[14]), "=r"((r)[15]), \
          "=r"((r)[16]), "=r"((r)[17]), "=r"((r)[18]), "=r"((r)[19]), \
          "=r"((r)[20]), "=r"((r)[21]), "=r"((r)[22]), "=r"((r)[23]), \
          "=r"((r)[24]), "=r"((r)[25]), "=r"((r)[26]), "=r"((r)[27]), \
          "=r"((r)[28]), "=r"((r)[29]), "=r"((r)[30]), "=r"((r)[31]) \
        : "r"(ta))

static constexpr u64 SMEM_DESC_BASE_SW128 =
    (u64(2) << 61) | (u64(1) << 46) | (u64(64) << 32) | (u64(1) << 16);
#define MAKE_SMEM_DESC(a) (SMEM_DESC_BASE_SW128 | ((u64)((a) >> 4) & 0x3FFF))

// kind::f16 SS cg1 mma; idesc = F32 out | BF16 a/b | N=256 | M=128
static __device__ __forceinline__ void mma_f16_ss(uint32_t d, u64 ad, u64 bd,
                                                  uint32_t idesc, uint32_t en) {
    asm volatile(
        "{\n\t.reg .pred p;\n\tsetp.ne.u32 p, %4, 0;\n\t"
        "tcgen05.mma.cta_group::1.kind::f16 [%0], %1, %2, %3, {%5, %5, %5, %5}, p;\n\t}"
        :: "r"(d), "l"(ad), "l"(bd), "r"(idesc), "r"(en), "r"(0u)
        : "memory");
}
#endif  // GB_TC

static __device__ __forceinline__ uint32_t smem_to_u32(const void* p) {
    uint32_t a;
    asm("{ .reg .u64 t; cvta.to.shared.u64 t, %1; cvt.u32.u64 %0, t; }" : "=r"(a) : "l"(p));
    return a;
}

// =====================================================================
// Kernel 0: pre-split + pre-swizzle FF weights into bf16 tiles
// =====================================================================
__global__ __launch_bounds__(256, 4)
void conv_w_kernel(const float* __restrict__ f1w, const float* __restrict__ f2w)
{
    const unsigned gidx = blockIdx.x * 256 + threadIdx.x;
    const int arr = gidx >> 20;
    const unsigned rem = gidx & 0xFFFFFu;
    const int t = rem >> 14;          // tile 0..63
    const int e = rem & 16383;
    const int n = e >> 6, k = e & 63;
    const int m = t >> 4, c1 = (t >> 2) & 3, c2 = t & 3;
    float w;
    if (arr == 0)
        w = f1w[(size_t)m * 262144 + (size_t)(c1 * 256 + n) * 256 + c2 * 64 + k];
    else
        w = f2w[(size_t)m * 262144 + (size_t)n * 1024 + c1 * 256 + c2 * 64 + k];
    __nv_bfloat16 h, l;
    bsplit(w, h, l);
    const uint32_t byte = (uint32_t)(n >> 3) * 1024 + (n & 7) * 128 + k * 2;
    const uint32_t sw = swz128(byte);
    __nv_bfloat16* dst = (arr == 0 ? g_w1t : g_w2t) + (size_t)t * 32768;
    dst[sw >> 1]           = h;
    dst[16384 + (sw >> 1)] = l;
}

// =====================================================================
// Kernel 1: KV proj + attention + Wo + gate + LayerNorm (fp32, round-6 best)
// =====================================================================
#define SM1_X    0
#define SM1_WT   16384
#define SM1_Q    24704
#define SM1_KV   28800
#define SM1_P    45184
#define SM1_AO   45696
#define SM1_GH   49792
#define SM1_GATE 50816
#define SM1_FLOATS 50832
#define SM1_BYTES  (SM1_FLOATS * 4)

__global__ __launch_bounds__(TPB, 1)
void gcma_part1(const float* __restrict__ x,
                const float* __restrict__ Wq, const float* __restrict__ bq,
                const float* __restrict__ Wk, const float* __restrict__ bk,
                const float* __restrict__ Wv, const float* __restrict__ bv,
                const float* __restrict__ Wo, const float* __restrict__ bo,
                const float* __restrict__ g1w, const float* __restrict__ g1b,
                const float* __restrict__ g2w, const float* __restrict__ g2b,
                const float* __restrict__ lng, const float* __restrict__ lnb,
                float* __restrict__ out)
{
    extern __shared__ float sm[];
    float* sX    = sm + SM1_X;
    float* sWT   = sm + SM1_WT;
    float* sQ    = sm + SM1_Q;
    float* sKV   = sm + SM1_KV;
    float* sP    = sm + SM1_P;
    float* sAO   = sm + SM1_AO;
    float* sGH   = sm + SM1_GH;
    float* sGate = sm + SM1_GATE;

    const int tid = threadIdx.x;
    const int m   = blockIdx.y;
    const int b0  = blockIdx.x * 16;
    const long g0 = (long)b0 * 4;

    const int warp = tid >> 5;
    const int colg = tid & 31;

    {
        const float* Xblk = x + (size_t)g0 * 256;
        for (int idx = tid; idx < 4096; idx += TPB) {
            const int r = idx >> 6, q = idx & 63;
            *reinterpret_cast<float4*>(sX + r * 256 + q * 4) =
                *reinterpret_cast<const float4*>(Xblk + r * 256 + q * 4);
        }
    }

    // ---- Q ----
    {
        const float* W    = Wq + (size_t)m * 65536;
        const float* bias = bq + m * 256;
        Wreg<8> wr;
        ldgW<8>(W, 256, 0, wr, tid);
        u64 acc[2][4];
#pragma unroll
        for (int i = 0; i < 2; ++i)
#pragma unroll
            for (int j = 0; j < 4; ++j) acc[i][j] = 0ULL;
        const float* aRow = sX + m * 256 + warp * 2 * 1024;
        for (int dt = 0; dt < 8; ++dt) {
            __syncthreads();
            stsW<8>(sWT, wr, tid);
            if (dt < 7) ldgW<8>(W, 256, (dt + 1) * 32, wr, tid);
            __syncthreads();
            mma16b(aRow + dt * 32, 1024, sWT, acc, colg);
        }
        float bl0[4], bl1[4];
#pragma unroll
        for (int j = 0; j < 4; ++j) { bl0[j] = bias[colg * 4 + j]; bl1[j] = bias[128 + colg * 4 + j]; }
#pragma unroll
        for (int i = 0; i < 2; ++i) {
            const int r = warp * 2 + i;
            const float2 pa = unpk(acc[i][0]), pb = unpk(acc[i][1]);
            const float2 pc = unpk(acc[i][2]), pd = unpk(acc[i][3]);
            const float s = 0.17677669529663687f;
            *reinterpret_cast<float4*>(sQ + r * 256 + colg * 4) =
                make_float4((pa.x + bl0[0]) * s, (pa.y + bl0[1]) * s,
                            (pb.x + bl0[2]) * s, (pb.y + bl0[3]) * s);
            *reinterpret_cast<float4*>(sQ + r * 256 + 128 + colg * 4) =
                make_float4((pc.x + bl1[0]) * s, (pc.y + bl1[1]) * s,
                            (pd.x + bl1[2]) * s, (pd.y + bl1[3]) * s);
        }
    }

    // ---- K ----
    {
        const float* W    = Wk + (size_t)m * 65536;
        const float* bias = bk + m * 256;
        Wreg<8> wr;
        ldgW<8>(W, 256, 0, wr, tid);
        u64 acc[8][4];
#pragma unroll
        for (int i = 0; i < 8; ++i)
#pragma unroll
            for (int j = 0; j < 4; ++j) acc[i][j] = 0ULL;
        const float* aRow = sX + warp * 8 * 256;
        for (int dt = 0; dt < 8; ++dt) {
            __syncthreads();
            stsW<8>(sWT, wr, tid);
            if (dt < 7) ldgW<8>(W, 256, (dt + 1) * 32, wr, tid);
            __syncthreads();
            mma64b(aRow + dt * 32, 256, sWT, acc, colg);
        }
        float bl0[4], bl1[4];
#pragma unroll
        for (int j = 0; j < 4; ++j) { bl0[j] = bias[colg * 4 + j]; bl1[j] = bias[128 + colg * 4 + j]; }
#pragma unroll
        for (int i = 0; i < 8; ++i) {
            const int r = warp * 8 + i;
            const float2 pa = unpk(acc[i][0]), pb = unpk(acc[i][1]);
            const float2 pc = unpk(acc[i][2]), pd = unpk(acc[i][3]);
            *reinterpret_cast<float4*>(sKV + r * 256 + colg * 4) =
                make_float4(pa.x + bl0[0], pa.y + bl0[1], pb.x + bl0[2], pb.y + bl0[3]);
            *reinterpret_cast<float4*>(sKV + r * 256 + 128 + colg * 4) =
                make_float4(pc.x + bl1[0], pc.y + bl1[1], pd.x + bl1[2], pd.y + bl1[3]);
        }
    }
    __syncthreads();

    // ---- scores + softmax ----
    if (tid < 128) {
        const int bl = tid >> 3, h = tid & 7;
        const float* qp = sQ + bl * 256 + h * 32;
        float q[32];
#pragma unroll
        for (int i = 0; i < 32; ++i) q[i] = qp[i];
        float s[4];
#pragma unroll
        for (int n = 0; n < 4; ++n) {
            const float* kp = sKV + (bl * 4 + n) * 256 + h * 32;
            float dot = 0.f;
#pragma unroll
            for (int i = 0; i < 32; ++i) dot = fmaf(q[i], kp[i], dot);
            s[n] = dot;
        }
        const float mx = fmaxf(fmaxf(s[0], s[1]), fmaxf(s[2], s[3]));
        float e[4], se = 0.f;
#pragma unroll
        for (int n = 0; n < 4; ++n) { e[n] = expf(s[n] - mx); se += e[n]; }
        const float inv = 1.f / se;
#pragma unroll
        for (int n = 0; n < 4; ++n) sP[tid * 4 + n] = e[n] * inv;
    }

    // ---- V ----
    {
        const float* W    = Wv + (size_t)m * 65536;
        const float* bias = bv + m * 256;
        Wreg<8> wr;
        ldgW<8>(W, 256, 0, wr, tid);
        u64 acc[8][4];
#pragma unroll
        for (int i = 0; i < 8; ++i)
#pragma unroll
            for (int j = 0; j < 4; ++j) acc[i][j] = 0ULL;
        const float* aRow = sX + warp * 8 * 256;
        for (int dt = 0; dt < 8; ++dt) {
            __syncthreads();
            stsW<8>(sWT, wr, tid);
            if (dt < 7) ldgW<8>(W, 256, (dt + 1) * 32, wr, tid);
            __syncthreads();
            mma64b(aRow + dt * 32, 256, sWT, acc, colg);
        }
        __syncthreads();
        float bl0[4], bl1[4];
#pragma unroll
        for (int j = 0; j < 4; ++j) { bl0[j] = bias[colg * 4 + j]; bl1[j] = bias[128 + colg * 4 + j]; }
#pragma unroll
        for (int i = 0; i < 8; ++i) {
            const int r = warp * 8 + i;
            const float2 pa = unpk(acc[i][0]), pb = unpk(acc[i][1]);
            const float2 pc = unpk(acc[i][2]), pd = unpk(acc[i][3]);
            *reinterpret_cast<float4*>(sKV + r * 256 + colg * 4) =
                make_float4(pa.x + bl0[0], pa.y + bl0[1], pb.x + bl0[2], pb.y + bl0[3]);
            *reinterpret_cast<float4*>(sKV + r * 256 + 128 + colg * 4) =
                make_float4(pc.x + bl1[0], pc.y + bl1[1], pd.x + bl1[2], pd.y + bl1[3]);
        }
    }
    __syncthreads();

    // ---- Oh = P @ V ----
    if (tid < 128) {
        const int bl = tid >> 3, h = tid & 7;
        float o[32];
#pragma unroll
        for (int i = 0; i < 32; ++i) o[i] = 0.f;
#pragma unroll
        for (int n = 0; n < 4; ++n) {
            const float p = sP[tid * 4 + n];
            const float* vp = sKV + (bl * 4 + n) * 256 + h * 32;
#pragma unroll
            for (int i = 0; i < 32; ++i) o[i] = fmaf(p, vp[i], o[i]);
        }
        float* op = sQ + bl * 256 + h * 32;
#pragma unroll
        for (int i = 0; i < 32; ++i) op[i] = o[i];
    }

    // ---- Wo ----
    {
        const float* W    = Wo + (size_t)m * 65536;
        const float* bias = bo + m * 256;
        Wreg<8> wr;
        ldgW<8>(W, 256, 0, wr, tid);
        u64 acc[2][4];
#pragma unroll
        for (int i = 0; i < 2; ++i)
#pragma unroll
            for (int j = 0; j < 4; ++j) acc[i][j] = 0ULL;
        const float* aRow = sQ + warp * 2 * 256;
        for (int dt = 0; dt < 8; ++dt) {
            __syncthreads();
            stsW<8>(sWT, wr, tid);
            if (dt < 7) ldgW<8>(W, 256, (dt + 1) * 32, wr, tid);
            __syncthreads();
            mma16b(aRow + dt * 32, 256, sWT, acc, colg);
        }
        float bl0[4], bl1[4];
#pragma unroll
        for (int j = 0; j < 4; ++j) { bl0[j] = bias[colg * 4 + j]; bl1[j] = bias[128 + colg * 4 + j]; }
#pragma unroll
        for (int i = 0; i < 2; ++i) {
            const int r = warp * 2 + i;
            const float2 pa = unpk(acc[i][0]), pb = unpk(acc[i][1]);
            const float2 pc = unpk(acc[i][2]), pd = unpk(acc[i][3]);
            *reinterpret_cast<float4*>(sAO + r * 256 + colg * 4) =
                make_float4(pa.x + bl0[0], pa.y + bl0[1], pb.x + bl0[2], pb.y + bl0[3]);
            *reinterpret_cast<float4*>(sAO + r * 256 + 128 + colg * 4) =
                make_float4(pc.x + bl1[0], pc.y + bl1[1], pd.x + bl1[2], pd.y + bl1[3]);
        }
    }

    // ---- gate layer 1 ----
    {
        const float* W = g1w + (size_t)m * 32768;
        Wreg<2> wr;
        ldgW<2>(W, 512, 0, wr, tid);
        u64 gacc[2] = {0ULL, 0ULL};
        for (int dt = 0; dt < 16; ++dt) {
            __syncthreads();
            stsW<2>(sWT, wr, tid);
            if (dt < 15) ldgW<2>(W, 512, (dt + 1) * 32, wr, tid);
            __syncthreads();
            if (dt < 8)
                mmagb(sX + m * 256 + warp * 2 * 1024 + dt * 32, 1024, sWT, gacc, colg);
            else
                mmagb(sAO + warp * 2 * 256 + (dt - 8) * 32, 256, sWT, gacc, colg);
        }
        const float gb0 = g1b[m * 64 + colg * 2];
        const float gb1 = g1b[m * 64 + colg * 2 + 1];
#pragma unroll
        for (int i = 0; i < 2; ++i) {
            const float2 p = unpk(gacc[i]);
            sGH[(warp * 2 + i) * 64 + colg * 2]     = tanhf(p.x + gb0);
            sGH[(warp * 2 + i) * 64 + colg * 2 + 1] = tanhf(p.y + gb1);
        }
    }
    __syncthreads();

    // ---- gate layer 2 ----
    if (tid < 16) {
        const float* g2 = g2w + m * 64;
        float dot = g2b[m];
#pragma unroll 8
        for (int j = 0; j < 64; ++j) dot = fmaf(sGH[tid * 64 + j], g2[j], dot);
        const float gate = 1.f / (1.f + expf(-dot));
        sGate[tid] = gate;
        out[OUT_GATE_BASE + (size_t)(b0 + tid) * 4 + m] = gate;
    }
    __syncthreads();

    // ---- residual + LayerNorm -> g_y ----
    {
        const int lane = tid & 31;
        for (int bl = warp; bl < 16; bl += 8) {
            const float* xr = sX + (bl * 4 + m) * 256;
            const float gate = sGate[bl];
            float r[8];
            float sum = 0.f;
#pragma unroll
            for (int k = 0; k < 8; ++k) {
                const int d = k * 32 + lane;
                r[k] = xr[d] + gate * sAO[bl * 256 + d];
                sum += r[k];
            }
#pragma unroll
            for (int o = 16; o; o >>= 1) sum += __shfl_xor_sync(0xffffffffu, sum, o);
            const float mu = sum * (1.f / 256.f);
            float var = 0.f;
#pragma unroll
            for (int k = 0; k < 8; ++k) { const float t = r[k] - mu; var = fmaf(t, t, var); }
#pragma unroll
            for (int o = 16; o; o >>= 1) var += __shfl_xor_sync(0xffffffffu, var, o);
            const float rs = rsqrtf(var * (1.f / 256.f) + 1e-5f);
            float* yr = g_y + (size_t)(g0 + bl * 4 + m) * 256;
#pragma unroll
            for (int k = 0; k < 8; ++k) {
                const int d = k * 32 + lane;
                yr[d] = (r[k] - mu) * rs * lng[m * 256 + d] + lnb[m * 256 + d];
            }
        }
    }
}

// =====================================================================
// Kernel 2: FF. tcgen05 bf16 2-split on sm_103a; fp32 fallback otherwise.
// grid (256, 4), 128 batch rows per block, 256 threads
// =====================================================================
#define P2_SMEM 197632
#define P2_TM    0
#define P2_MB    8
#define P2_AHI   1024
#define P2_ALO   66560
#define P2_BHI   132096
#define P2_BLO   164864
#define IDESC_BF16_M128_N256 0x8400490u

static __device__ __forceinline__ void loadB(const __nv_bfloat16* base, int m, int c1, int c2,
                                             float4 pf[16], int tid) {
    const float4* src = reinterpret_cast<const float4*>(base + (size_t)((m * 4 + c1) * 4 + c2) * 32768);
#pragma unroll
    for (int i = 0; i < 8; ++i) {
        pf[i]     = src[tid + i * 256];
        pf[8 + i] = src[2048 + tid + i * 256];
    }
}
static __device__ __forceinline__ void stsB(char* sBhi, char* sBlo, const float4 pf[16], int tid) {
#pragma unroll
    for (int i = 0; i < 8; ++i) {
        reinterpret_cast<float4*>(sBhi)[tid + i * 256] = pf[i];
        reinterpret_cast<float4*>(sBlo)[tid + i * 256] = pf[8 + i];
    }
}

__global__ __launch_bounds__(256, 1)
void gcma_part2tc(const float* __restrict__ f1w, const float* __restrict__ f1b,
                  const float* __restrict__ f2w, const float* __restrict__ f2b,
                  float* __restrict__ out)
{
    extern __shared__ char sm2[];
    const int tid  = threadIdx.x;
    const int m    = blockIdx.y;
    const int b0   = blockIdx.x * 128;

#if GB_TC
    const uint32_t sbase = smem_to_u32(sm2);
    const uint32_t TMP  = sbase + P2_TM;
    const uint32_t MBAR = sbase + P2_MB;
    char* sAhi = sm2 + P2_AHI;
    char* sAlo = sm2 + P2_ALO;
    char* sBhi = sm2 + P2_BHI;
    char* sBlo = sm2 + P2_BLO;
    const uint32_t aHiA = sbase + P2_AHI, aLoA = sbase + P2_ALO;
    const uint32_t bHiA = sbase + P2_BHI, bLoA = sbase + P2_BLO;

    const int wid  = tid >> 5, lane = tid & 31;
    unsigned* hfbase = g_hfscr + (size_t)(blockIdx.y * 256 + blockIdx.x) * 131072u;

    if (wid == 0) TCGEN05_ALLOC(TMP, 512);
    if (tid == 0) MBARRIER_INIT(MBAR, 1);
    __syncthreads();
    uint32_t tmem;
    asm volatile("ld.shared.b32 %0, [%1];" : "=r"(tmem) : "r"(TMP));

    // ---- stage y (fp32 -> bf16 split, blocked SW128) ----
    for (int idx = tid; idx < 8192; idx += 256) {
        const int r = idx >> 6, k = (idx & 63) << 2;
        const float4 v = *reinterpret_cast<const float4*>(
            g_y + ((size_t)(b0 + r) * 4 + m) * 256 + k);
        __nv_bfloat16 h0, h1, h2, h3, l0, l1, l2, l3;
        bsplit(v.x, h0, l0); bsplit(v.y, h1, l1);
        bsplit(v.z, h2, l2); bsplit(v.w, h3, l3);
        const uint32_t byte = (uint32_t)((r >> 3) + (k >> 6) * 16) * 1024 + (r & 7) * 128 + (k & 63) * 2;
        const uint32_t sw = swz128(byte);
        *reinterpret_cast<uint2*>(sAhi + sw) = make_uint2(pk2(h0, h1), pk2(h2, h3));
        *reinterpret_cast<uint2*>(sAlo + sw) = make_uint2(pk2(l0, l1), pk2(l2, l3));
    }

    float4 pf[16];
    loadB(g_w1t, m, 0, 0, pf, tid);
    int ph = 0;
    const u64 aH = MAKE_SMEM_DESC(aHiA), aL = MAKE_SMEM_DESC(aLoA);
    const u64 bH = MAKE_SMEM_DESC(bHiA), bL = MAKE_SMEM_DESC(bLoA);

    // ============ FF1: D1 (tmem cols 0..255) ============
    for (int nch = 0; nch < 4; ++nch) {
        for (int kch = 0; kch < 4; ++kch) {
            stsB(sBhi, sBlo, pf, tid);
            __syncthreads();
            if (wid == 0) {
                asm volatile("fence.proxy.async.shared::cta;" ::: "memory");
                TCGEN05_FENCE_AFTER();
                if (elect_one_pred()) {
#pragma unroll
                    for (int j = 0; j < 4; ++j) {
                        const u64 ao = (u64)(kch * 1024 + j * 2), bo = (u64)(j * 2);
                        mma_f16_ss(tmem, aH + ao, bH + bo, IDESC_BF16_M128_N256,
                                   (kch == 0 && j == 0) ? 0u : 1u);
                        mma_f16_ss(tmem, aH + ao, bL + bo, IDESC_BF16_M128_N256, 1u);
                        mma_f16_ss(tmem, aL + ao, bH + bo, IDESC_BF16_M128_N256, 1u);
                    }
                    TCGEN05_COMMIT(MBAR);
                }
            }
            const int nb = nch * 4 + kch + 1;
            if (nb < 16) loadB(g_w1t, m, nb >> 2, nb & 3, pf, tid);
            else         loadB(g_w2t, m, 0, 0, pf, tid);
            MBARRIER_WAIT_PARITY(MBAR, ph & 1);
            ++ph;
            TCGEN05_FENCE_AFTER();
        }
        // ---- epilogue: bias + GELU + split -> hf scratch ----
        {
            const int r  = (wid & 3) * 32 + lane;
            const int cb = (wid >> 2) * 128;
            for (int cc = 0; cc < 4; ++cc) {
                uint32_t dr[32];
                TCGEN05_LD_32X32B_X32(dr, tmem + cb + cc * 32);
                TCGEN05_WAIT_LD();
                TCGEN05_FENCE_BEFORE();
                const int c0 = nch * 256 + cb + cc * 32;
                unsigned* dst = hfbase + (size_t)r * 1024 + c0;
#pragma unroll
                for (int j = 0; j < 32; ++j) {
                    float v = __uint_as_float(dr[j]) + f1b[m * 1024 + c0 + j];
                    v = 0.5f * v * (1.f + erff(v * 0.7071067811865476f));
                    __nv_bfloat16 h, l;
                    bsplit(v, h, l);
                    dst[j] = pk2(h, l);
                }
            }
        }
        __syncthreads();
    }

    // ============ FF2: D2 (tmem cols 256..511) ============
    for (int ch = 0; ch < 4; ++ch) {
        for (int idx = tid; idx < 8192; idx += 256) {
            const int r = idx >> 6, k = (idx & 63) << 2;
            const uint4 u = *reinterpret_cast<const uint4*>(
                hfbase + (size_t)r * 1024 + ch * 256 + k);
            const unsigned uu[4] = {u.x, u.y, u.z, u.w};
            __nv_bfloat16 h[4], l[4];
#pragma unroll
            for (int j = 0; j < 4; ++j) {
                h[j] = __ushort_as_bfloat16((unsigned short)(uu[j] & 0xFFFFu));
                l[j] = __ushort_as_bfloat16((unsigned short)(uu[j] >> 16));
            }
            const uint32_t byte = (uint32_t)((r >> 3) + (k >> 6) * 16) * 1024 + (r & 7) * 128 + (k & 63) * 2;
            const uint32_t sw = swz128(byte);
            *reinterpret_cast<uint2*>(sAhi + sw) = make_uint2(pk2(h[0], h[1]), pk2(h[2], h[3]));
            *reinterpret_cast<uint2*>(sAlo + sw) = make_uint2(pk2(l[0], l[1]), pk2(l[2], l[3]));
        }
        for (int kc = 0; kc < 4; ++kc) {
            stsB(sBhi, sBlo, pf, tid);
            __syncthreads();
            if (wid == 0) {
                asm volatile("fence.proxy.async.shared::cta;" ::: "memory");
                TCGEN05_FENCE_AFTER();
                if (elect_one_pred()) {
#pragma unroll
                    for (int j = 0; j < 4; ++j) {
                        const u64 ao = (u64)(kc * 1024 + j * 2), bo = (u64)(j * 2);
                        mma_f16_ss(tmem + 256, aH + ao, bH + bo, IDESC_BF16_M128_N256,
                                   (ch == 0 && kc == 0 && j == 0) ? 0u : 1u);
                        mma_f16_ss(tmem + 256, aH + ao, bL + bo, IDESC_BF16_M128_N256, 1u);
                        mma_f16_ss(tmem + 256, aL + ao, bH + bo, IDESC_BF16_M128_N256, 1u);
                    }
                    TCGEN05_COMMIT(MBAR);
                }
            }
            const int nb = ch * 4 + kc + 1;
            if (nb < 16) loadB(g_w2t, m, nb >> 2, nb & 3, pf, tid);
            MBARRIER_WAIT_PARITY(MBAR, ph & 1);
            ++ph;
            TCGEN05_FENCE_AFTER();
        }
    }

    // ---- FF2 epilogue: out = y + D2 + f2b ----
    {
        const int r  = (wid & 3) * 32 + lane;
        const int cb = (wid >> 2) * 128;
        for (int cc = 0; cc < 4; ++cc) {
            uint32_t dr[32];
            TCGEN05_LD_32X32B_X32(dr, tmem + 256 + cb + cc * 32);
            TCGEN05_WAIT_LD();
            TCGEN05_FENCE_BEFORE();
            const int c0 = cb + cc * 32;
            const float* yrow = g_y + ((size_t)(b0 + r) * 4 + m) * 256 + c0;
            float* orow = out + ((size_t)(b0 + r) * 4 + m) * 256 + c0;
#pragma unroll
            for (int j = 0; j < 32; ++j)
                orow[j] = yrow[j] + __uint_as_float(dr[j]) + f2b[m * 256 + c0 + j];
        }
    }

    __syncthreads();
    if (tid == 0)
        asm volatile("mbarrier.inval.shared.b64 [%0];" :: "r"(MBAR) : "memory");
    __syncthreads();
    if (wid == 0) TCGEN05_DEALLOC(tmem, 512);

#else  // ------- fp32 fallback (round-6 logic, two 64-row halves) -------
    float* smf = reinterpret_cast<float*>(sm2);
    float* sY  = smf;            // 16384
    float* sHF = smf + 16384;    // 16384
    float* sWT = smf + 32768;    // 8320
    const int warp = tid >> 5;
    const int colg = tid & 31;

    for (int half = 0; half < 2; ++half) {
        const int hb0 = b0 + half * 64;
        __syncthreads();
        for (int idx = tid; idx < 4096; idx += TPB) {
            const int r = idx >> 6, q = idx & 63;
            *reinterpret_cast<float4*>(sY + r * 256 + q * 4) =
                *reinterpret_cast<const float4*>(g_y + ((size_t)(hb0 + r) * 4 + m) * 256 + q * 4);
        }
        u64 facc[8][4];
#pragma unroll
        for (int i = 0; i < 8; ++i)
#pragma unroll
            for (int j = 0; j < 4; ++j) facc[i][j] = 0ULL;
        const float* aY  = sY  + warp * 8 * 256;
        const float* aHF = sHF + warp * 8 * 256;

        for (int ch = 0; ch < 4; ++ch) {
            u64 hacc[8][4];
#pragma unroll
            for (int i = 0; i < 8; ++i)
#pragma unroll
                for (int j = 0; j < 4; ++j) hacc[i][j] = 0ULL;
            {
                const float* W1 = f1w + (size_t)m * 262144 + (size_t)ch * 65536;
                Wreg<8> wr;
                ldgW<8>(W1, 256, 0, wr, tid);
                for (int dt = 0; dt < 8; ++dt) {
                    __syncthreads();
                    stsW<8>(sWT, wr, tid);
                    if (dt < 7) ldgW<8>(W1, 256, (dt + 1) * 32, wr, tid);
                    __syncthreads();
                    mma64b(aY + dt * 32, 256, sWT, hacc, colg);
                }
            }
            __syncthreads();
            {
                const float* b1 = f1b + m * 1024 + ch * 256;
                float bl0[4], bl1[4];
#pragma unroll
                for (int j = 0; j < 4; ++j) { bl0[j] = b1[colg * 4 + j]; bl1[j] = b1[128 + colg * 4 + j]; }
#pragma unroll
                for (int i = 0; i < 8; ++i) {
                    const int r = warp * 8 + i;
                    const float2 pa = unpk(hacc[i][0]), pb = unpk(hacc[i][1]);
                    const float2 pc = unpk(hacc[i][2]), pd = unpk(hacc[i][3]);
                    float v0[4] = {pa.x + bl0[0], pa.y + bl0[1], pb.x + bl0[2], pb.y + bl0[3]};
                    float v1[4] = {pc.x + bl1[0], pc.y + bl1[1], pd.x + bl1[2], pd.y + bl1[3]};
#pragma unroll
                    for (int j = 0; j < 4; ++j) {
                        v0[j] = 0.5f * v0[j] * (1.f + erff(v0[j] * 0.7071067811865476f));
                        v1[j] = 0.5f * v1[j] * (1.f + erff(v1[j] * 0.7071067811865476f));
                    }
                    *reinterpret_cast<float4*>(sHF + r * 256 + colg * 4) =
                        make_float4(v0[0], v0[1], v0[2], v0[3]);
                    *reinterpret_cast<float4*>(sHF + r * 256 + 128 + colg * 4) =
                        make_float4(v1[0], v1[1], v1[2], v1[3]);
                }
            }
            {
                const float* W2 = f2w + (size_t)m * 262144;
                Wreg<8> wr;
                ldgW<8>(W2, 1024, ch * 256, wr, tid);
                for (int dt = 0; dt < 8; ++dt) {
                    __syncthreads();
                    stsW<8>(sWT, wr, tid);
                    if (dt < 7) ldgW<8>(W2, 1024, ch * 256 + (dt + 1) * 32, wr, tid);
                    __syncthreads();
                    mma64b(aHF + dt * 32, 256, sWT, facc, colg);
                }
            }
            __syncthreads();
        }
        {
            const float* b2 = f2b + m * 256;
            float bl0[4], bl1[4];
#pragma unroll
            for (int j = 0; j < 4; ++j) { bl0[j] = b2[colg * 4 + j]; bl1[j] = b2[128 + colg * 4 + j]; }
#pragma unroll
            for (int i = 0; i < 8; ++i) {
                const int r = warp * 8 + i;
                const float4 y0 = *reinterpret_cast<const float4*>(sY + r * 256 + colg * 4);
                const float4 y1 = *reinterpret_cast<const float4*>(sY + r * 256 + 128 + colg * 4);
                const float2 pa = unpk(facc[i][0]), pb = unpk(facc[i][1]);
                const float2 pc = unpk(facc[i][2]), pd = unpk(facc[i][3]);
                float* op = out + ((size_t)(hb0 + r) * 4 + m) * 256;
                *reinterpret_cast<float4*>(op + colg * 4) =
                    make_float4(y0.x + pa.x + bl0[0], y0.y + pa.y + bl0[1],
                                y0.z + pb.x + bl0[2], y0.w + pb.y + bl0[3]);
                *reinterpret_cast<float4*>(op + 128 + colg * 4) =
                    make_float4(y1.x + pc.x + bl1[0], y1.y + pc.y + bl1[1],
                                y1.z + pd.x + bl1[2], y1.w + pd.y + bl1[3]);
            }
        }
    }
#endif
}

extern "C" void kernel_launch(void* const* d_in, const int* in_sizes, int n_in,
                              void* d_out, int out_size) {
    const float* x   = (const float*)d_in[0];
    const float* Wq  = (const float*)d_in[1];
    const float* bq  = (const float*)d_in[2];
    const float* Wk  = (const float*)d_in[3];
    const float* bk  = (const float*)d_in[4];
    const float* Wv  = (const float*)d_in[5];
    const float* bv  = (const float*)d_in[6];
    const float* Wo  = (const float*)d_in[7];
    const float* bo  = (const float*)d_in[8];
    const float* g1w = (const float*)d_in[9];
    const float* g1b = (const float*)d_in[10];
    const float* g2w = (const float*)d_in[11];
    const float* g2b = (const float*)d_in[12];
    const float* lng = (const float*)d_in[13];
    const float* lnb = (const float*)d_in[14];
    const float* f1w = (const float*)d_in[15];
    const float* f1b = (const float*)d_in[16];
    const float* f2w = (const float*)d_in[17];
    const float* f2b = (const float*)d_in[18];
    float* out = (float*)d_out;

    cudaFuncSetAttribute(gcma_part1, cudaFuncAttributeMaxDynamicSharedMemorySize, SM1_BYTES);
    cudaFuncSetAttribute(gcma_part2tc, cudaFuncAttributeMaxDynamicSharedMemorySize, P2_SMEM);

    conv_w_kernel<<<8192, 256>>>(f1w, f2w);

    dim3 grid1(32768 / 16, 4, 1);
    gcma_part1<<<grid1, TPB, SM1_BYTES>>>(x, Wq, bq, Wk, bk, Wv, bv, Wo, bo,
                                          g1w, g1b, g2w, g2b, lng, lnb, out);
    dim3 grid2(32768 / 128, 4, 1);
    gcma_part2tc<<<grid2, 256, P2_SMEM>>>(f1w, f1b, f2w, f2b, out);
}

// round 10
// speedup vs baseline: 1.4996x; 1.1233x over previous
#include <cuda_runtime.h>
#include <cuda_bf16.h>
#include <math.h>
#include <stdint.h>

typedef unsigned long long u64;

#define TPB 256
#define PW 260     // pitch of transposed W tile; PW%32==4 -> conflict-free STS.128

#define OUT_GATE_BASE 33554432UL   // B*M*D

// tcgen05 only exists in the arch-specific (sm_103a) compile pass
#if defined(__CUDA_ARCH_FEAT_SM103_ALL) || \
    (defined(__CUDA_ARCH_SPECIFIC__) && (__CUDA_ARCH_SPECIFIC__ == 1030)) || \
    (defined(__CUDA_ARCH_FAMILY_SPECIFIC__) && (__CUDA_ARCH_FAMILY_SPECIFIC__ == 1030))
#define GB_TC 1
#else
#define GB_TC 0
#endif

// scratch
__device__ float g_y[32768u * 4u * 256u];                 // 128MB
__device__ float g_k[4u * 131072u * 256u];                // 512MB K[m][row][256]
__device__ float g_v[4u * 131072u * 256u];                // 512MB
__device__ __nv_bfloat16 g_w1t[64u * 32768u];             // FF1 tiles (hi|lo)
__device__ __nv_bfloat16 g_w2t[64u * 32768u];             // FF2 tiles
__device__ __nv_bfloat16 g_wkt[32u * 16384u];             // Wk tiles 128n x 64k (hi|lo)
__device__ __nv_bfloat16 g_wvt[32u * 16384u];             // Wv tiles
__device__ unsigned g_hfscr[1024u * 131072u];             // hf scratch

// ---------- packed fp32 helpers ----------
static __device__ __forceinline__ u64 ffma2(u64 a, u64 b, u64 c) {
    u64 d;
    asm("fma.rn.f32x2 %0, %1, %2, %3;" : "=l"(d) : "l"(a), "l"(b), "l"(c));
    return d;
}
static __device__ __forceinline__ u64 dup2(float a) {
    u64 d;
    asm("mov.b64 %0, {%1, %1};" : "=l"(d) : "f"(a));
    return d;
}
static __device__ __forceinline__ float2 unpk(u64 p) {
    float2 r;
    asm("mov.b64 {%0, %1}, %2;" : "=f"(r.x), "=f"(r.y) : "l"(p));
    return r;
}
static __device__ __forceinline__ float comp4(const float4& v, int dd) {
    return dd == 0 ? v.x : dd == 1 ? v.y : dd == 2 ? v.z : v.w;
}
static __device__ __forceinline__ unsigned pk2(__nv_bfloat16 a, __nv_bfloat16 b) {
    return (unsigned)__bfloat16_as_ushort(a) | ((unsigned)__bfloat16_as_ushort(b) << 16);
}
static __device__ __forceinline__ void bsplit(float v, __nv_bfloat16& h, __nv_bfloat16& l) {
    h = __float2bfloat16(v);
    l = __float2bfloat16(v - __bfloat162float(h));
}
static __device__ __forceinline__ uint32_t swz128(uint32_t b) { return b ^ ((b >> 3) & 0x70); }
static __device__ __forceinline__ uint32_t smem_to_u32(const void* p) {
    uint32_t a;
    asm("{ .reg .u64 t; cvta.to.shared.u64 t, %1; cvt.u32.u64 %0, t; }" : "=r"(a) : "l"(p));
    return a;
}

// ---------- fp32 W tile prefetch ----------
template<int NIT>
struct Wreg { float f[NIT][4]; };

template<int NIT>
static __device__ __forceinline__ void ldgW(const float* __restrict__ W, int ldw, int k0,
                                            Wreg<NIT>& r, int tid) {
#pragma unroll
    for (int k = 0; k < NIT; ++k) {
        const int idx = tid + k * TPB;
        const int d = idx & 31, c4 = idx >> 5;
#pragma unroll
        for (int i = 0; i < 4; ++i)
            r.f[k][i] = W[(size_t)(c4 * 4 + i) * ldw + k0 + d];
    }
}
template<int NIT>
static __device__ __forceinline__ void stsW(float* sWT, const Wreg<NIT>& r, int tid) {
#pragma unroll
    for (int k = 0; k < NIT; ++k) {
        const int idx = tid + k * TPB;
        const int d = idx & 31, c4 = idx >> 5;
        *reinterpret_cast<float4*>(sWT + d * PW + c4 * 4) =
            make_float4(r.f[k][0], r.f[k][1], r.f[k][2], r.f[k][3]);
    }
}
static __device__ __forceinline__ void mma64b(const float* __restrict__ aRow, int lda,
                                              const float* __restrict__ sWT,
                                              u64 acc[8][4], int colg) {
#pragma unroll
    for (int d4 = 0; d4 < 8; ++d4) {
        float4 a4[8];
#pragma unroll
        for (int i = 0; i < 8; ++i)
            a4[i] = *reinterpret_cast<const float4*>(aRow + i * lda + (d4 << 2));
#pragma unroll
        for (int dd = 0; dd < 4; ++dd) {
            const int d = (d4 << 2) + dd;
            const ulonglong2 w0 = *reinterpret_cast<const ulonglong2*>(sWT + d * PW + (colg << 2));
            const ulonglong2 w1 = *reinterpret_cast<const ulonglong2*>(sWT + d * PW + 128 + (colg << 2));
#pragma unroll
            for (int i = 0; i < 8; ++i) {
                const u64 ad = dup2(comp4(a4[i], dd));
                acc[i][0] = ffma2(ad, w0.x, acc[i][0]);
                acc[i][1] = ffma2(ad, w0.y, acc[i][1]);
                acc[i][2] = ffma2(ad, w1.x, acc[i][2]);
                acc[i][3] = ffma2(ad, w1.y, acc[i][3]);
            }
        }
    }
}
static __device__ __forceinline__ void mma16b(const float* __restrict__ aRow, int lda,
                                              const float* __restrict__ sWT,
                                              u64 acc[2][4], int colg) {
#pragma unroll
    for (int d4 = 0; d4 < 8; ++d4) {
        float4 a4[2];
        a4[0] = *reinterpret_cast<const float4*>(aRow + (d4 << 2));
        a4[1] = *reinterpret_cast<const float4*>(aRow + lda + (d4 << 2));
#pragma unroll
        for (int dd = 0; dd < 4; ++dd) {
            const int d = (d4 << 2) + dd;
            const ulonglong2 w0 = *reinterpret_cast<const ulonglong2*>(sWT + d * PW + (colg << 2));
            const ulonglong2 w1 = *reinterpret_cast<const ulonglong2*>(sWT + d * PW + 128 + (colg << 2));
#pragma unroll
            for (int i = 0; i < 2; ++i) {
                const u64 ad = dup2(comp4(a4[i], dd));
                acc[i][0] = ffma2(ad, w0.x, acc[i][0]);
                acc[i][1] = ffma2(ad, w0.y, acc[i][1]);
                acc[i][2] = ffma2(ad, w1.x, acc[i][2]);
                acc[i][3] = ffma2(ad, w1.y, acc[i][3]);
            }
        }
    }
}
static __device__ __forceinline__ void mmagb(const float* __restrict__ aRow, int lda,
                                             const float* __restrict__ sWT,
                                             u64 gacc[2], int colg) {
#pragma unroll
    for (int d4 = 0; d4 < 8; ++d4) {
        const float4 a0 = *reinterpret_cast<const float4*>(aRow + (d4 << 2));
        const float4 a1 = *reinterpret_cast<const float4*>(aRow + lda + (d4 << 2));
#pragma unroll
        for (int dd = 0; dd < 4; ++dd) {
            const u64 w = *reinterpret_cast<const u64*>(sWT + ((d4 << 2) + dd) * PW + colg * 2);
            gacc[0] = ffma2(dup2(comp4(a0, dd)), w, gacc[0]);
            gacc[1] = ffma2(dup2(comp4(a1, dd)), w, gacc[1]);
        }
    }
}

#if GB_TC
// ---------- tcgen05 helpers ----------
static __device__ __forceinline__ uint32_t elect_one_pred() {
    uint32_t pred;
    asm volatile(
        "{\n\t.reg .pred p;\n\telect.sync _|p, 0xFFFFFFFF;\n\tselp.b32 %0, 1, 0, p;\n\t}"
        : "=r"(pred));
    return pred;
}
#define TCGEN05_ALLOC(sa, n) \
    asm volatile("tcgen05.alloc.cta_group::1.sync.aligned.shared::cta.b32 [%0], %1;" \
                 :: "r"((uint32_t)(sa)), "r"((uint32_t)(n)) : "memory")
#define TCGEN05_DEALLOC(ta, n) \
    asm volatile("tcgen05.dealloc.cta_group::1.sync.aligned.b32 %0, %1;" :: "r"(ta), "r"((uint32_t)(n)))
#define TCGEN05_COMMIT(mb) \
    asm volatile("tcgen05.commit.cta_group::1.mbarrier::arrive::one.shared::cluster.b64 [%0];" \
                 :: "r"((uint32_t)(mb)) : "memory")
#define TCGEN05_WAIT_LD()  asm volatile("tcgen05.wait::ld.sync.aligned;" ::: "memory")
#define TCGEN05_FENCE_AFTER()  asm volatile("tcgen05.fence::after_thread_sync;" ::: "memory")
#define TCGEN05_FENCE_BEFORE() asm volatile("tcgen05.fence::before_thread_sync;" ::: "memory")
#define MBARRIER_INIT(mb, c) \
    asm volatile("mbarrier.init.shared.b64 [%0], %1;" :: "r"((uint32_t)(mb)), "r"((uint32_t)(c)) : "memory")
#define MBARRIER_WAIT_PARITY(mb, par) do { \
    uint32_t _mb = (uint32_t)(mb), _pa = (uint32_t)(par), _dn; \
    asm volatile("{\n\t.reg .pred p;\n\t" \
        "mbarrier.try_wait.parity.acquire.cta.shared::cta.b64 p, [%1], %2;\n\t" \
        "selp.b32 %0, 1, 0, p;\n\t}" : "=r"(_dn) : "r"(_mb), "r"(_pa) : "memory"); \
    if (!_dn) { \
        asm volatile("{\n\t.reg .pred P1;\n\t" \
            "WL_%=:\n\tmbarrier.try_wait.parity.acquire.cta.shared::cta.b64 P1, [%0], %1, 0x989680;\n\t" \
            "@P1 bra.uni WD_%=;\n\tbra.uni WL_%=;\n\tWD_%=:\n\t}" \
            :: "r"(_mb), "r"(_pa) : "memory"); \
    } \
} while (0)
#define TCGEN05_LD_32X32B_X32(r, ta) \
    asm volatile("tcgen05.ld.sync.aligned.32x32b.x32.b32 " \
        "{%0, %1, %2, %3, %4, %5, %6, %7, %8, %9, %10, %11, %12, %13, %14, %15, " \
        "%16, %17, %18, %19, %20, %21, %22, %23, %24, %25, %26, %27, %28, %29, %30, %31}, [%32];" \
        : "=r"((r)[0]),  "=r"((r)[1]),  "=r"((r)[2]),  "=r"((r)[3]), \
          "=r"((r)[4]),  "=r"((r)[5]),  "=r"((r)[6]),  "=r"((r)[7]), \
          "=r"((r)[8]),  "=r"((r)[9]),  "=r"((r)[10]), "=r"((r)[11]), \
          "=r"((r)[12]), "=r"((r)[13]), "=r"((r)[14]), "=r"((r)[15]), \
          "=r"((r)[16]), "=r"((r)[17]), "=r"((r)[18]), "=r"((r)[19]), \
          "=r"((r)[20]), "=r"((r)[21]), "=r"((r)[22]), "=r"((r)[23]), \
          "=r"((r)[24]), "=r"((r)[25]), "=r"((r)[26]), "=r"((r)[27]), \
          "=r"((r)[28]), "=r"((r)[29]), "=r"((r)[30]), "=r"((r)[31]) \
        : "r"(ta))

static constexpr u64 SMEM_DESC_BASE_SW128 =
    (u64(2) << 61) | (u64(1) << 46) | (u64(64) << 32) | (u64(1) << 16);
#define MAKE_SMEM_DESC(a) (SMEM_DESC_BASE_SW128 | ((u64)((a) >> 4) & 0x3FFF))

static __device__ __forceinline__ void mma_f16_ss(uint32_t d, u64 ad, u64 bd,
                                                  uint32_t idesc, uint32_t en) {
    asm volatile(
        "{\n\t.reg .pred p;\n\tsetp.ne.u32 p, %4, 0;\n\t"
        "tcgen05.mma.cta_group::1.kind::f16 [%0], %1, %2, %3, {%5, %5, %5, %5}, p;\n\t}"
        :: "r"(d), "l"(ad), "l"(bd), "r"(idesc), "r"(en), "r"(0u)
        : "memory");
}
#endif  // GB_TC

// =====================================================================
// Kernel 0: pre-split + pre-swizzle FF + Wk/Wv weights into bf16 tiles
// =====================================================================
__global__ __launch_bounds__(256, 4)
void conv_w_kernel(const float* __restrict__ f1w, const float* __restrict__ f2w,
                   const float* __restrict__ Wk, const float* __restrict__ Wv)
{
    const unsigned gidx = blockIdx.x * 256 + threadIdx.x;
    if (gidx < 2097152u) {
        const int arr = gidx >> 20;
        const unsigned rem = gidx & 0xFFFFFu;
        const int t = rem >> 14;          // tile 0..63
        const int e = rem & 16383;
        const int n = e >> 6, k = e & 63;
        const int m = t >> 4, c1 = (t >> 2) & 3, c2 = t & 3;
        float w;
        if (arr == 0)
            w = f1w[(size_t)m * 262144 + (size_t)(c1 * 256 + n) * 256 + c2 * 64 + k];
        else
            w = f2w[(size_t)m * 262144 + (size_t)n * 1024 + c1 * 256 + c2 * 64 + k];
        __nv_bfloat16 h, l;
        bsplit(w, h, l);
        const uint32_t byte = (uint32_t)(n >> 3) * 1024 + (n & 7) * 128 + k * 2;
        const uint32_t sw = swz128(byte);
        __nv_bfloat16* dst = (arr == 0 ? g_w1t : g_w2t) + (size_t)t * 32768;
        dst[sw >> 1]           = h;
        dst[16384 + (sw >> 1)] = l;
    } else {
        const unsigned idx2 = gidx - 2097152u;   // < 524288
        const int arr2 = idx2 >> 18;             // 0: Wk, 1: Wv
        const unsigned rem = idx2 & 0x3FFFFu;
        const int t = rem >> 13;                 // tile 0..31
        const int e = rem & 8191;
        const int n = e >> 6, k = e & 63;
        const int m = t >> 3, nch = (t >> 2) & 1, kch = t & 3;
        const float* W = (arr2 == 0 ? Wk : Wv);
        const float w = W[(size_t)m * 65536 + (size_t)(nch * 128 + n) * 256 + kch * 64 + k];
        __nv_bfloat16 h, l;
        bsplit(w, h, l);
        const uint32_t byte = (uint32_t)(n >> 3) * 1024 + (n & 7) * 128 + k * 2;
        const uint32_t sw = swz128(byte);
        __nv_bfloat16* dst = (arr2 == 0 ? g_wkt : g_wvt) + (size_t)t * 16384;
        dst[sw >> 1]          = h;
        dst[8192 + (sw >> 1)] = l;
    }
}

// =====================================================================
// Kernel A: K,V projections via tcgen05 (M=128 row tiles, all 8 (kv,m) jobs)
// grid (1024), 256 threads
// =====================================================================
#define KV_SMEM 197632
#define KV_MB0  16
#define KV_MB1  24
#define KV_AHI  1024
#define KV_ALO  66560
#define KV_B0H  132096
#define KV_B0L  148480
#define KV_B1H  164864
#define KV_B1L  181248
#define IDESC_BF16_M128_N128 0x8200490u
#define IDESC_BF16_M128_N256 0x8400490u

__global__ __launch_bounds__(256, 1)
void gcma_kv(const float* __restrict__ x,
             const float* __restrict__ bk, const float* __restrict__ bv)
{
    extern __shared__ char smA[];
    const int tid = threadIdx.x;
    const int r0  = blockIdx.x * 128;

#if GB_TC
    const uint32_t sbase = smem_to_u32(smA);
    const int wid = tid >> 5, lane = tid & 31;
    char* sAhi = smA + KV_AHI;
    char* sAlo = smA + KV_ALO;

    if (wid == 0) TCGEN05_ALLOC(sbase + 0, 512);
    if (tid == 0) { MBARRIER_INIT(sbase + KV_MB0, 1); MBARRIER_INIT(sbase + KV_MB1, 1); }
    __syncthreads();
    uint32_t tmem;
    asm volatile("ld.shared.b32 %0, [%1];" : "=r"(tmem) : "r"(sbase + 0));

    // stage A: x rows r0..r0+127, split+swizzle
    for (int idx = tid; idx < 8192; idx += 256) {
        const int r = idx >> 6, k = (idx & 63) << 2;
        const float4 v = *reinterpret_cast<const float4*>(x + (size_t)(r0 + r) * 256 + k);
        __nv_bfloat16 h0, h1, h2, h3, l0, l1, l2, l3;
        bsplit(v.x, h0, l0); bsplit(v.y, h1, l1);
        bsplit(v.z, h2, l2); bsplit(v.w, h3, l3);
        const uint32_t byte = (uint32_t)((r >> 3) + (k >> 6) * 16) * 1024 + (r & 7) * 128 + (k & 63) * 2;
        const uint32_t sw = swz128(byte);
        *reinterpret_cast<uint2*>(sAhi + sw) = make_uint2(pk2(h0, h1), pk2(h2, h3));
        *reinterpret_cast<uint2*>(sAlo + sw) = make_uint2(pk2(l0, l1), pk2(l2, l3));
    }

    const u64 aH = MAKE_SMEM_DESC(sbase + KV_AHI), aL = MAKE_SMEM_DESC(sbase + KV_ALO);
    const u64 b0H = MAKE_SMEM_DESC(sbase + KV_B0H), b0L = MAKE_SMEM_DESC(sbase + KV_B0L);
    const u64 b1H = MAKE_SMEM_DESC(sbase + KV_B1H), b1L = MAKE_SMEM_DESC(sbase + KV_B1L);

    int w0 = 0, w1 = 0, pend0 = 0, pend1 = 0;

    for (int job = 0; job < 8; ++job) {
        const int kv = job >> 2, m = job & 3;
        const int half = job & 1;
        const __nv_bfloat16* wbase = kv ? g_wvt : g_wkt;
        for (int c = 0; c < 8; ++c) {
            const int nch = c >> 2, kch = c & 3;
            const int buf = c & 1;
            if (buf == 0) { if (pend0) { MBARRIER_WAIT_PARITY(sbase + KV_MB0, w0 & 1); ++w0; pend0 = 0; } }
            else          { if (pend1) { MBARRIER_WAIT_PARITY(sbase + KV_MB1, w1 & 1); ++w1; pend1 = 0; } }
            // stage B tile (16KB hi + 16KB lo)
            {
                const float4* s4 = reinterpret_cast<const float4*>(
                    wbase + (size_t)(((m * 2 + nch) * 4 + kch)) * 16384);
                float4* dh = reinterpret_cast<float4*>(smA + (buf ? KV_B1H : KV_B0H));
                float4* dl = reinterpret_cast<float4*>(smA + (buf ? KV_B1L : KV_B0L));
#pragma unroll
                for (int i = 0; i < 4; ++i) {
                    dh[tid + i * 256] = s4[tid + i * 256];
                    dl[tid + i * 256] = s4[1024 + tid + i * 256];
                }
            }
            __syncthreads();
            if (wid == 0) {
                asm volatile("fence.proxy.async.shared::cta;" ::: "memory");
                TCGEN05_FENCE_AFTER();
                if (elect_one_pred()) {
                    const u64 bH = buf ? b1H : b0H, bL = buf ? b1L : b0L;
                    const uint32_t dcol = tmem + half * 256 + nch * 128;
#pragma unroll
                    for (int j = 0; j < 4; ++j) {
                        const u64 ao = (u64)(kch * 1024 + j * 2), bo = (u64)(j * 2);
                        mma_f16_ss(dcol, aH + ao, bH + bo, IDESC_BF16_M128_N128,
                                   (kch == 0 && j == 0) ? 0u : 1u);
                        mma_f16_ss(dcol, aH + ao, bL + bo, IDESC_BF16_M128_N128, 1u);
                        mma_f16_ss(dcol, aL + ao, bH + bo, IDESC_BF16_M128_N128, 1u);
                    }
                    TCGEN05_COMMIT(sbase + (buf ? KV_MB1 : KV_MB0));
                }
            }
            if (buf == 0) pend0 = 1; else pend1 = 1;
        }
        // drain both buffers
        if (pend0) { MBARRIER_WAIT_PARITY(sbase + KV_MB0, w0 & 1); ++w0; pend0 = 0; }
        if (pend1) { MBARRIER_WAIT_PARITY(sbase + KV_MB1, w1 & 1); ++w1; pend1 = 0; }
        TCGEN05_FENCE_AFTER();
        // epilogue: bias + store to g_k / g_v
        {
            const float* bias = (kv ? bv : bk) + m * 256;
            float* dst = (kv ? g_v : g_k) + ((size_t)m * 131072 + r0) * 256;
            const int rr = (wid & 3) * 32 + lane;
            const int cb = (wid >> 2) * 128;
            for (int cc = 0; cc < 4; ++cc) {
                uint32_t dr[32];
                TCGEN05_LD_32X32B_X32(dr, tmem + half * 256 + cb + cc * 32);
                TCGEN05_WAIT_LD();
                TCGEN05_FENCE_BEFORE();
                const int c0 = cb + cc * 32;
                float* drow = dst + (size_t)rr * 256 + c0;
#pragma unroll
                for (int q = 0; q < 8; ++q) {
                    *reinterpret_cast<float4*>(drow + q * 4) =
                        make_float4(__uint_as_float(dr[q * 4 + 0]) + bias[c0 + q * 4 + 0],
                                    __uint_as_float(dr[q * 4 + 1]) + bias[c0 + q * 4 + 1],
                                    __uint_as_float(dr[q * 4 + 2]) + bias[c0 + q * 4 + 2],
                                    __uint_as_float(dr[q * 4 + 3]) + bias[c0 + q * 4 + 3]);
                }
            }
        }
        __syncthreads();
    }

    if (tid == 0) {
        asm volatile("mbarrier.inval.shared.b64 [%0];" :: "r"(sbase + KV_MB0) : "memory");
        asm volatile("mbarrier.inval.shared.b64 [%0];" :: "r"(sbase + KV_MB1) : "memory");
    }
    __syncthreads();
    if (wid == 0) TCGEN05_DEALLOC(tmem, 512);

#else  // fp32 fallback (correct; only compiled for the non-103a cubin)
    float* sXf = reinterpret_cast<float*>(smA);          // 128x256 = 131072B
    float* sWT = reinterpret_cast<float*>(smA) + 32768;  // 33280B
    const int warp = tid >> 5, colg = tid & 31;
    for (int idx = tid; idx < 8192; idx += 256) {
        const int r = idx >> 6, q = idx & 63;
        *reinterpret_cast<float4*>(sXf + r * 256 + q * 4) =
            *reinterpret_cast<const float4*>(x + (size_t)(r0 + r) * 256 + q * 4);
    }
    for (int job = 0; job < 8; ++job) {
        const int kv = job >> 2, m = job & 3;
        const float* W = (kv ? /*Wv*/ (const float*)0 : (const float*)0);
        // fallback recomputes from bf16 tiles is wrong; instead do direct dot from gmem weights
        (void)W;
        const float* bias = (kv ? bv : bk) + m * 256;
        float* dst = (kv ? g_v : g_k) + ((size_t)m * 131072 + r0) * 256;
        // direct (slow, never executed on sm_103a machines)
        __syncthreads();
        for (int e = tid; e < 128 * 256; e += 256) {
            const int r = e >> 8, n = e & 255;
            // reconstruct W row from split tiles to stay self-contained
            const __nv_bfloat16* wt = (kv ? g_wvt : g_wkt);
            float dot = 0.f;
            for (int k = 0; k < 256; ++k) {
                const int nch = n >> 7, nn = n & 127, kch = k >> 6, kk = k & 63;
                const __nv_bfloat16* tb = wt + (size_t)(((m * 2 + nch) * 4 + kch)) * 16384;
                const uint32_t sw = swz128((uint32_t)(nn >> 3) * 1024 + (nn & 7) * 128 + kk * 2);
                const float wv = __bfloat162float(tb[sw >> 1]) + __bfloat162float(tb[8192 + (sw >> 1)]);
                dot = fmaf(sXf[r * 256 + k], wv, dot);
            }
            dst[(size_t)r * 256 + n] = dot + bias[n];
        }
        (void)sWT; (void)warp; (void)colg;
    }
#endif
}

// =====================================================================
// Kernel 1: Q + attention (K,V from scratch) + Wo + gate + LayerNorm
// =====================================================================
#define SM1_X    0
#define SM1_WT   16384
#define SM1_Q    24704
#define SM1_KV   28800
#define SM1_P    45184
#define SM1_AO   45696
#define SM1_GH   49792
#define SM1_GATE 50816
#define SM1_FLOATS 50832
#define SM1_BYTES  (SM1_FLOATS * 4)

__global__ __launch_bounds__(TPB, 1)
void gcma_part1(const float* __restrict__ x,
                const float* __restrict__ Wq, const float* __restrict__ bq,
                const float* __restrict__ Wo, const float* __restrict__ bo,
                const float* __restrict__ g1w, const float* __restrict__ g1b,
                const float* __restrict__ g2w, const float* __restrict__ g2b,
                const float* __restrict__ lng, const float* __restrict__ lnb,
                float* __restrict__ out)
{
    extern __shared__ float sm[];
    float* sX    = sm + SM1_X;
    float* sWT   = sm + SM1_WT;
    float* sQ    = sm + SM1_Q;
    float* sKV   = sm + SM1_KV;
    float* sP    = sm + SM1_P;
    float* sAO   = sm + SM1_AO;
    float* sGH   = sm + SM1_GH;
    float* sGate = sm + SM1_GATE;

    const int tid = threadIdx.x;
    const int m   = blockIdx.y;
    const int b0  = blockIdx.x * 16;
    const long g0 = (long)b0 * 4;

    const int warp = tid >> 5;
    const int colg = tid & 31;

    {
        const float* Xblk = x + (size_t)g0 * 256;
        for (int idx = tid; idx < 4096; idx += TPB) {
            const int r = idx >> 6, q = idx & 63;
            *reinterpret_cast<float4*>(sX + r * 256 + q * 4) =
                *reinterpret_cast<const float4*>(Xblk + r * 256 + q * 4);
        }
    }

    // ---- Q (fp32) ----
    {
        const float* W    = Wq + (size_t)m * 65536;
        const float* bias = bq + m * 256;
        Wreg<8> wr;
        ldgW<8>(W, 256, 0, wr, tid);
        u64 acc[2][4];
#pragma unroll
        for (int i = 0; i < 2; ++i)
#pragma unroll
            for (int j = 0; j < 4; ++j) acc[i][j] = 0ULL;
        const float* aRow = sX + m * 256 + warp * 2 * 1024;
        for (int dt = 0; dt < 8; ++dt) {
            __syncthreads();
            stsW<8>(sWT, wr, tid);
            if (dt < 7) ldgW<8>(W, 256, (dt + 1) * 32, wr, tid);
            __syncthreads();
            mma16b(aRow + dt * 32, 1024, sWT, acc, colg);
        }
        float bl0[4], bl1[4];
#pragma unroll
        for (int j = 0; j < 4; ++j) { bl0[j] = bias[colg * 4 + j]; bl1[j] = bias[128 + colg * 4 + j]; }
#pragma unroll
        for (int i = 0; i < 2; ++i) {
            const int r = warp * 2 + i;
            const float2 pa = unpk(acc[i][0]), pb = unpk(acc[i][1]);
            const float2 pc = unpk(acc[i][2]), pd = unpk(acc[i][3]);
            const float s = 0.17677669529663687f;
            *reinterpret_cast<float4*>(sQ + r * 256 + colg * 4) =
                make_float4((pa.x + bl0[0]) * s, (pa.y + bl0[1]) * s,
                            (pb.x + bl0[2]) * s, (pb.y + bl0[3]) * s);
            *reinterpret_cast<float4*>(sQ + r * 256 + 128 + colg * 4) =
                make_float4((pc.x + bl1[0]) * s, (pc.y + bl1[1]) * s,
                            (pd.x + bl1[2]) * s, (pd.y + bl1[3]) * s);
        }
    }

    // ---- load K tile ----
    {
        const float* src = g_k + ((size_t)m * 131072 + g0) * 256;
        for (int idx = tid; idx < 4096; idx += TPB) {
            const int r = idx >> 6, q = idx & 63;
            *reinterpret_cast<float4*>(sKV + r * 256 + q * 4) =
                *reinterpret_cast<const float4*>(src + r * 256 + q * 4);
        }
    }
    __syncthreads();

    // ---- scores + softmax ----
    if (tid < 128) {
        const int bl = tid >> 3, h = tid & 7;
        const float* qp = sQ + bl * 256 + h * 32;
        float q[32];
#pragma unroll
        for (int i = 0; i < 32; ++i) q[i] = qp[i];
        float s[4];
#pragma unroll
        for (int n = 0; n < 4; ++n) {
            const float* kp = sKV + (bl * 4 + n) * 256 + h * 32;
            float dot = 0.f;
#pragma unroll
            for (int i = 0; i < 32; ++i) dot = fmaf(q[i], kp[i], dot);
            s[n] = dot;
        }
        const float mx = fmaxf(fmaxf(s[0], s[1]), fmaxf(s[2], s[3]));
        float e[4], se = 0.f;
#pragma unroll
        for (int n = 0; n < 4; ++n) { e[n] = expf(s[n] - mx); se += e[n]; }
        const float inv = 1.f / se;
#pragma unroll
        for (int n = 0; n < 4; ++n) sP[tid * 4 + n] = e[n] * inv;
    }
    __syncthreads();

    // ---- load V tile (overwrite sKV) ----
    {
        const float* src = g_v + ((size_t)m * 131072 + g0) * 256;
        for (int idx = tid; idx < 4096; idx += TPB) {
            const int r = idx >> 6, q = idx & 63;
            *reinterpret_cast<float4*>(sKV + r * 256 + q * 4) =
                *reinterpret_cast<const float4*>(src + r * 256 + q * 4);
        }
    }
    __syncthreads();

    // ---- Oh = P @ V -> sQ ----
    if (tid < 128) {
        const int bl = tid >> 3, h = tid & 7;
        float o[32];
#pragma unroll
        for (int i = 0; i < 32; ++i) o[i] = 0.f;
#pragma unroll
        for (int n = 0; n < 4; ++n) {
            const float p = sP[tid * 4 + n];
            const float* vp = sKV + (bl * 4 + n) * 256 + h * 32;
#pragma unroll
            for (int i = 0; i < 32; ++i) o[i] = fmaf(p, vp[i], o[i]);
        }
        float* op = sQ + bl * 256 + h * 32;
#pragma unroll
        for (int i = 0; i < 32; ++i) op[i] = o[i];
    }

    // ---- Wo (fp32) ----
    {
        const float* W    = Wo + (size_t)m * 65536;
        const float* bias = bo + m * 256;
        Wreg<8> wr;
        ldgW<8>(W, 256, 0, wr, tid);
        u64 acc[2][4];
#pragma unroll
        for (int i = 0; i < 2; ++i)
#pragma unroll
            for (int j = 0; j < 4; ++j) acc[i][j] = 0ULL;
        const float* aRow = sQ + warp * 2 * 256;
        for (int dt = 0; dt < 8; ++dt) {
            __syncthreads();
            stsW<8>(sWT, wr, tid);
            if (dt < 7) ldgW<8>(W, 256, (dt + 1) * 32, wr, tid);
            __syncthreads();
            mma16b(aRow + dt * 32, 256, sWT, acc, colg);
        }
        float bl0[4], bl1[4];
#pragma unroll
        for (int j = 0; j < 4; ++j) { bl0[j] = bias[colg * 4 + j]; bl1[j] = bias[128 + colg * 4 + j]; }
#pragma unroll
        for (int i = 0; i < 2; ++i) {
            const int r = warp * 2 + i;
            const float2 pa = unpk(acc[i][0]), pb = unpk(acc[i][1]);
            const float2 pc = unpk(acc[i][2]), pd = unpk(acc[i][3]);
            *reinterpret_cast<float4*>(sAO + r * 256 + colg * 4) =
                make_float4(pa.x + bl0[0], pa.y + bl0[1], pb.x + bl0[2], pb.y + bl0[3]);
            *reinterpret_cast<float4*>(sAO + r * 256 + 128 + colg * 4) =
                make_float4(pc.x + bl1[0], pc.y + bl1[1], pd.x + bl1[2], pd.y + bl1[3]);
        }
    }

    // ---- gate layer 1 ----
    {
        const float* W = g1w + (size_t)m * 32768;
        Wreg<2> wr;
        ldgW<2>(W, 512, 0, wr, tid);
        u64 gacc[2] = {0ULL, 0ULL};
        for (int dt = 0; dt < 16; ++dt) {
            __syncthreads();
            stsW<2>(sWT, wr, tid);
            if (dt < 15) ldgW<2>(W, 512, (dt + 1) * 32, wr, tid);
            __syncthreads();
            if (dt < 8)
                mmagb(sX + m * 256 + warp * 2 * 1024 + dt * 32, 1024, sWT, gacc, colg);
            else
                mmagb(sAO + warp * 2 * 256 + (dt - 8) * 32, 256, sWT, gacc, colg);
        }
        const float gb0 = g1b[m * 64 + colg * 2];
        const float gb1 = g1b[m * 64 + colg * 2 + 1];
#pragma unroll
        for (int i = 0; i < 2; ++i) {
            const float2 p = unpk(gacc[i]);
            sGH[(warp * 2 + i) * 64 + colg * 2]     = tanhf(p.x + gb0);
            sGH[(warp * 2 + i) * 64 + colg * 2 + 1] = tanhf(p.y + gb1);
        }
    }
    __syncthreads();

    // ---- gate layer 2 ----
    if (tid < 16) {
        const float* g2 = g2w + m * 64;
        float dot = g2b[m];
#pragma unroll 8
        for (int j = 0; j < 64; ++j) dot = fmaf(sGH[tid * 64 + j], g2[j], dot);
        const float gate = 1.f / (1.f + expf(-dot));
        sGate[tid] = gate;
        out[OUT_GATE_BASE + (size_t)(b0 + tid) * 4 + m] = gate;
    }
    __syncthreads();

    // ---- residual + LayerNorm -> g_y ----
    {
        const int lane = tid & 31;
        for (int bl = warp; bl < 16; bl += 8) {
            const float* xr = sX + (bl * 4 + m) * 256;
            const float gate = sGate[bl];
            float r[8];
            float sum = 0.f;
#pragma unroll
            for (int k = 0; k < 8; ++k) {
                const int d = k * 32 + lane;
                r[k] = xr[d] + gate * sAO[bl * 256 + d];
                sum += r[k];
            }
#pragma unroll
            for (int o = 16; o; o >>= 1) sum += __shfl_xor_sync(0xffffffffu, sum, o);
            const float mu = sum * (1.f / 256.f);
            float var = 0.f;
#pragma unroll
            for (int k = 0; k < 8; ++k) { const float t = r[k] - mu; var = fmaf(t, t, var); }
#pragma unroll
            for (int o = 16; o; o >>= 1) var += __shfl_xor_sync(0xffffffffu, var, o);
            const float rs = rsqrtf(var * (1.f / 256.f) + 1e-5f);
            float* yr = g_y + (size_t)(g0 + bl * 4 + m) * 256;
#pragma unroll
            for (int k = 0; k < 8; ++k) {
                const int d = k * 32 + lane;
                yr[d] = (r[k] - mu) * rs * lng[m * 256 + d] + lnb[m * 256 + d];
            }
        }
    }
}

// =====================================================================
// Kernel 2: FF (unchanged from R9)
// =====================================================================
#define P2_SMEM 197632
#define P2_TM    0
#define P2_MB    8
#define P2_AHI   1024
#define P2_ALO   66560
#define P2_BHI   132096
#define P2_BLO   164864

static __device__ __forceinline__ void loadB(const __nv_bfloat16* base, int m, int c1, int c2,
                                             float4 pf[16], int tid) {
    const float4* src = reinterpret_cast<const float4*>(base + (size_t)((m * 4 + c1) * 4 + c2) * 32768);
#pragma unroll
    for (int i = 0; i < 8; ++i) {
        pf[i]     = src[tid + i * 256];
        pf[8 + i] = src[2048 + tid + i * 256];
    }
}
static __device__ __forceinline__ void stsB(char* sBhi, char* sBlo, const float4 pf[16], int tid) {
#pragma unroll
    for (int i = 0; i < 8; ++i) {
        reinterpret_cast<float4*>(sBhi)[tid + i * 256] = pf[i];
        reinterpret_cast<float4*>(sBlo)[tid + i * 256] = pf[8 + i];
    }
}

__global__ __launch_bounds__(256, 1)
void gcma_part2tc(const float* __restrict__ f1w, const float* __restrict__ f1b,
                  const float* __restrict__ f2w, const float* __restrict__ f2b,
                  float* __restrict__ out)
{
    extern __shared__ char sm2[];
    const int tid  = threadIdx.x;
    const int m    = blockIdx.y;
    const int b0   = blockIdx.x * 128;

#if GB_TC
    const uint32_t sbase = smem_to_u32(sm2);
    const uint32_t TMP  = sbase + P2_TM;
    const uint32_t MBAR = sbase + P2_MB;
    char* sAhi = sm2 + P2_AHI;
    char* sAlo = sm2 + P2_ALO;
    char* sBhi = sm2 + P2_BHI;
    char* sBlo = sm2 + P2_BLO;
    const uint32_t aHiA = sbase + P2_AHI, aLoA = sbase + P2_ALO;
    const uint32_t bHiA = sbase + P2_BHI, bLoA = sbase + P2_BLO;

    const int wid  = tid >> 5, lane = tid & 31;
    unsigned* hfbase = g_hfscr + (size_t)(blockIdx.y * 256 + blockIdx.x) * 131072u;

    if (wid == 0) TCGEN05_ALLOC(TMP, 512);
    if (tid == 0) MBARRIER_INIT(MBAR, 1);
    __syncthreads();
    uint32_t tmem;
    asm volatile("ld.shared.b32 %0, [%1];" : "=r"(tmem) : "r"(TMP));

    for (int idx = tid; idx < 8192; idx += 256) {
        const int r = idx >> 6, k = (idx & 63) << 2;
        const float4 v = *reinterpret_cast<const float4*>(
            g_y + ((size_t)(b0 + r) * 4 + m) * 256 + k);
        __nv_bfloat16 h0, h1, h2, h3, l0, l1, l2, l3;
        bsplit(v.x, h0, l0); bsplit(v.y, h1, l1);
        bsplit(v.z, h2, l2); bsplit(v.w, h3, l3);
        const uint32_t byte = (uint32_t)((r >> 3) + (k >> 6) * 16) * 1024 + (r & 7) * 128 + (k & 63) * 2;
        const uint32_t sw = swz128(byte);
        *reinterpret_cast<uint2*>(sAhi + sw) = make_uint2(pk2(h0, h1), pk2(h2, h3));
        *reinterpret_cast<uint2*>(sAlo + sw) = make_uint2(pk2(l0, l1), pk2(l2, l3));
    }

    float4 pf[16];
    loadB(g_w1t, m, 0, 0, pf, tid);
    int ph = 0;
    const u64 aH = MAKE_SMEM_DESC(aHiA), aL = MAKE_SMEM_DESC(aLoA);
    const u64 bH = MAKE_SMEM_DESC(bHiA), bL = MAKE_SMEM_DESC(bLoA);

    for (int nch = 0; nch < 4; ++nch) {
        for (int kch = 0; kch < 4; ++kch) {
            stsB(sBhi, sBlo, pf, tid);
            __syncthreads();
            if (wid == 0) {
                asm volatile("fence.proxy.async.shared::cta;" ::: "memory");
                TCGEN05_FENCE_AFTER();
                if (elect_one_pred()) {
#pragma unroll
                    for (int j = 0; j < 4; ++j) {
                        const u64 ao = (u64)(kch * 1024 + j * 2), bo = (u64)(j * 2);
                        mma_f16_ss(tmem, aH + ao, bH + bo, IDESC_BF16_M128_N256,
                                   (kch == 0 && j == 0) ? 0u : 1u);
                        mma_f16_ss(tmem, aH + ao, bL + bo, IDESC_BF16_M128_N256, 1u);
                        mma_f16_ss(tmem, aL + ao, bH + bo, IDESC_BF16_M128_N256, 1u);
                    }
                    TCGEN05_COMMIT(MBAR);
                }
            }
            const int nb = nch * 4 + kch + 1;
            if (nb < 16) loadB(g_w1t, m, nb >> 2, nb & 3, pf, tid);
            else         loadB(g_w2t, m, 0, 0, pf, tid);
            MBARRIER_WAIT_PARITY(MBAR, ph & 1);
            ++ph;
            TCGEN05_FENCE_AFTER();
        }
        {
            const int r  = (wid & 3) * 32 + lane;
            const int cb = (wid >> 2) * 128;
            for (int cc = 0; cc < 4; ++cc) {
                uint32_t dr[32];
                TCGEN05_LD_32X32B_X32(dr, tmem + cb + cc * 32);
                TCGEN05_WAIT_LD();
                TCGEN05_FENCE_BEFORE();
                const int c0 = nch * 256 + cb + cc * 32;
                unsigned* dst = hfbase + (size_t)r * 1024 + c0;
#pragma unroll
                for (int j = 0; j < 32; ++j) {
                    float v = __uint_as_float(dr[j]) + f1b[m * 1024 + c0 + j];
                    v = 0.5f * v * (1.f + erff(v * 0.7071067811865476f));
                    __nv_bfloat16 h, l;
                    bsplit(v, h, l);
                    dst[j] = pk2(h, l);
                }
            }
        }
        __syncthreads();
    }

    for (int ch = 0; ch < 4; ++ch) {
        for (int idx = tid; idx < 8192; idx += 256) {
            const int r = idx >> 6, k = (idx & 63) << 2;
            const uint4 u = *reinterpret_cast<const uint4*>(
                hfbase + (size_t)r * 1024 + ch * 256 + k);
            const unsigned uu[4] = {u.x, u.y, u.z, u.w};
            __nv_bfloat16 h[4], l[4];
#pragma unroll
            for (int j = 0; j < 4; ++j) {
                h[j] = __ushort_as_bfloat16((unsigned short)(uu[j] & 0xFFFFu));
                l[j] = __ushort_as_bfloat16((unsigned short)(uu[j] >> 16));
            }
            const uint32_t byte = (uint32_t)((r >> 3) + (k >> 6) * 16) * 1024 + (r & 7) * 128 + (k & 63) * 2;
            const uint32_t sw = swz128(byte);
            *reinterpret_cast<uint2*>(sAhi + sw) = make_uint2(pk2(h[0], h[1]), pk2(h[2], h[3]));
            *reinterpret_cast<uint2*>(sAlo + sw) = make_uint2(pk2(l[0], l[1]), pk2(l[2], l[3]));
        }
        for (int kc = 0; kc < 4; ++kc) {
            stsB(sBhi, sBlo, pf, tid);
            __syncthreads();
            if (wid == 0) {
                asm volatile("fence.proxy.async.shared::cta;" ::: "memory");
                TCGEN05_FENCE_AFTER();
                if (elect_one_pred()) {
#pragma unroll
                    for (int j = 0; j < 4; ++j) {
                        const u64 ao = (u64)(kc * 1024 + j * 2), bo = (u64)(j * 2);
                        mma_f16_ss(tmem + 256, aH + ao, bH + bo, IDESC_BF16_M128_N256,
                                   (ch == 0 && kc == 0 && j == 0) ? 0u : 1u);
                        mma_f16_ss(tmem + 256, aH + ao, bL + bo, IDESC_BF16_M128_N256, 1u);
                        mma_f16_ss(tmem + 256, aL + ao, bH + bo, IDESC_BF16_M128_N256, 1u);
                    }
                    TCGEN05_COMMIT(MBAR);
                }
            }
            const int nb = ch * 4 + kc + 1;
            if (nb < 16) loadB(g_w2t, m, nb >> 2, nb & 3, pf, tid);
            MBARRIER_WAIT_PARITY(MBAR, ph & 1);
            ++ph;
            TCGEN05_FENCE_AFTER();
        }
    }

    {
        const int r  = (wid & 3) * 32 + lane;
        const int cb = (wid >> 2) * 128;
        for (int cc = 0; cc < 4; ++cc) {
            uint32_t dr[32];
            TCGEN05_LD_32X32B_X32(dr, tmem + 256 + cb + cc * 32);
            TCGEN05_WAIT_LD();
            TCGEN05_FENCE_BEFORE();
            const int c0 = cb + cc * 32;
            const float* yrow = g_y + ((size_t)(b0 + r) * 4 + m) * 256 + c0;
            float* orow = out + ((size_t)(b0 + r) * 4 + m) * 256 + c0;
#pragma unroll
            for (int j = 0; j < 32; ++j)
                orow[j] = yrow[j] + __uint_as_float(dr[j]) + f2b[m * 256 + c0 + j];
        }
    }

    __syncthreads();
    if (tid == 0)
        asm volatile("mbarrier.inval.shared.b64 [%0];" :: "r"(MBAR) : "memory");
    __syncthreads();
    if (wid == 0) TCGEN05_DEALLOC(tmem, 512);

#else  // fp32 fallback (round-6 logic, two 64-row halves)
    float* smf = reinterpret_cast<float*>(sm2);
    float* sY  = smf;
    float* sHF = smf + 16384;
    float* sWT = smf + 32768;
    const int warp = tid >> 5;
    const int colg = tid & 31;

    for (int half = 0; half < 2; ++half) {
        const int hb0 = b0 + half * 64;
        __syncthreads();
        for (int idx = tid; idx < 4096; idx += TPB) {
            const int r = idx >> 6, q = idx & 63;
            *reinterpret_cast<float4*>(sY + r * 256 + q * 4) =
                *reinterpret_cast<const float4*>(g_y + ((size_t)(hb0 + r) * 4 + m) * 256 + q * 4);
        }
        u64 facc[8][4];
#pragma unroll
        for (int i = 0; i < 8; ++i)
#pragma unroll
            for (int j = 0; j < 4; ++j) facc[i][j] = 0ULL;
        const float* aY  = sY  + warp * 8 * 256;
        const float* aHF = sHF + warp * 8 * 256;

        for (int ch = 0; ch < 4; ++ch) {
            u64 hacc[8][4];
#pragma unroll
            for (int i = 0; i < 8; ++i)
#pragma unroll
                for (int j = 0; j < 4; ++j) hacc[i][j] = 0ULL;
            {
                const float* W1 = f1w + (size_t)m * 262144 + (size_t)ch * 65536;
                Wreg<8> wr;
                ldgW<8>(W1, 256, 0, wr, tid);
                for (int dt = 0; dt < 8; ++dt) {
                    __syncthreads();
                    stsW<8>(sWT, wr, tid);
                    if (dt < 7) ldgW<8>(W1, 256, (dt + 1) * 32, wr, tid);
                    __syncthreads();
                    mma64b(aY + dt * 32, 256, sWT, hacc, colg);
                }
            }
            __syncthreads();
            {
                const float* b1 = f1b + m * 1024 + ch * 256;
                float bl0[4], bl1[4];
#pragma unroll
                for (int j = 0; j < 4; ++j) { bl0[j] = b1[colg * 4 + j]; bl1[j] = b1[128 + colg * 4 + j]; }
#pragma unroll
                for (int i = 0; i < 8; ++i) {
                    const int r = warp * 8 + i;
                    const float2 pa = unpk(hacc[i][0]), pb = unpk(hacc[i][1]);
                    const float2 pc = unpk(hacc[i][2]), pd = unpk(hacc[i][3]);
                    float v0[4] = {pa.x + bl0[0], pa.y + bl0[1], pb.x + bl0[2], pb.y + bl0[3]};
                    float v1[4] = {pc.x + bl1[0], pc.y + bl1[1], pd.x + bl1[2], pd.y + bl1[3]};
#pragma unroll
                    for (int j = 0; j < 4; ++j) {
                        v0[j] = 0.5f * v0[j] * (1.f + erff(v0[j] * 0.7071067811865476f));
                        v1[j] = 0.5f * v1[j] * (1.f + erff(v1[j] * 0.7071067811865476f));
                    }
                    *reinterpret_cast<float4*>(sHF + r * 256 + colg * 4) =
                        make_float4(v0[0], v0[1], v0[2], v0[3]);
                    *reinterpret_cast<float4*>(sHF + r * 256 + 128 + colg * 4) =
                        make_float4(v1[0], v1[1], v1[2], v1[3]);
                }
            }
            {
                const float* W2 = f2w + (size_t)m * 262144;
                Wreg<8> wr;
                ldgW<8>(W2, 1024, ch * 256, wr, tid);
                for (int dt = 0; dt < 8; ++dt) {
                    __syncthreads();
                    stsW<8>(sWT, wr, tid);
                    if (dt < 7) ldgW<8>(W2, 1024, ch * 256 + (dt + 1) * 32, wr, tid);
                    __syncthreads();
                    mma64b(aHF + dt * 32, 256, sWT, facc, colg);
                }
            }
            __syncthreads();
        }
        {
            const float* b2 = f2b + m * 256;
            float bl0[4], bl1[4];
#pragma unroll
            for (int j = 0; j < 4; ++j) { bl0[j] = b2[colg * 4 + j]; bl1[j] = b2[128 + colg * 4 + j]; }
#pragma unroll
            for (int i = 0; i < 8; ++i) {
                const int r = warp * 8 + i;
                const float4 y0 = *reinterpret_cast<const float4*>(sY + r * 256 + colg * 4);
                const float4 y1 = *reinterpret_cast<const float4*>(sY + r * 256 + 128 + colg * 4);
                const float2 pa = unpk(facc[i][0]), pb = unpk(facc[i][1]);
                const float2 pc = unpk(facc[i][2]), pd = unpk(facc[i][3]);
                float* op = out + ((size_t)(hb0 + r) * 4 + m) * 256;
                *reinterpret_cast<float4*>(op + colg * 4) =
                    make_float4(y0.x + pa.x + bl0[0], y0.y + pa.y + bl0[1],
                                y0.z + pb.x + bl0[2], y0.w + pb.y + bl0[3]);
                *reinterpret_cast<float4*>(op + 128 + colg * 4) =
                    make_float4(y1.x + pc.x + bl1[0], y1.y + pc.y + bl1[1],
                                y1.z + pd.x + bl1[2], y1.w + pd.y + bl1[3]);
            }
        }
    }
#endif
}

extern "C" void kernel_launch(void* const* d_in, const int* in_sizes, int n_in,
                              void* d_out, int out_size) {
    const float* x   = (const float*)d_in[0];
    const float* Wq  = (const float*)d_in[1];
    const float* bq  = (const float*)d_in[2];
    const float* Wk  = (const float*)d_in[3];
    const float* bk  = (const float*)d_in[4];
    const float* Wv  = (const float*)d_in[5];
    const float* bv  = (const float*)d_in[6];
    const float* Wo  = (const float*)d_in[7];
    const float* bo  = (const float*)d_in[8];
    const float* g1w = (const float*)d_in[9];
    const float* g1b = (const float*)d_in[10];
    const float* g2w = (const float*)d_in[11];
    const float* g2b = (const float*)d_in[12];
    const float* lng = (const float*)d_in[13];
    const float* lnb = (const float*)d_in[14];
    const float* f1w = (const float*)d_in[15];
    const float* f1b = (const float*)d_in[16];
    const float* f2w = (const float*)d_in[17];
    const float* f2b = (const float*)d_in[18];
    float* out = (float*)d_out;

    cudaFuncSetAttribute(gcma_kv, cudaFuncAttributeMaxDynamicSharedMemorySize, KV_SMEM);
    cudaFuncSetAttribute(gcma_part1, cudaFuncAttributeMaxDynamicSharedMemorySize, SM1_BYTES);
    cudaFuncSetAttribute(gcma_part2tc, cudaFuncAttributeMaxDynamicSharedMemorySize, P2_SMEM);

    conv_w_kernel<<<10240, 256>>>(f1w, f2w, Wk, Wv);
    gcma_kv<<<1024, 256, KV_SMEM>>>(x, bk, bv);

    dim3 grid1(32768 / 16, 4, 1);
    gcma_part1<<<grid1, TPB, SM1_BYTES>>>(x, Wq, bq, Wo, bo,
                                          g1w, g1b, g2w, g2b, lng, lnb, out);
    dim3 grid2(32768 / 128, 4, 1);
    gcma_part2tc<<<grid2, 256, P2_SMEM>>>(f1w, f1b, f2w, f2b, out);
}

// round 11
// speedup vs baseline: 2.2335x; 1.4894x over previous
#include <cuda_runtime.h>
#include <cuda_bf16.h>
#include <math.h>
#include <stdint.h>

typedef unsigned long long u64;

#define TPB 256
#define PW 260

#define OUT_GATE_BASE 33554432UL   // B*M*D

#if defined(__CUDA_ARCH_FEAT_SM103_ALL) || \
    (defined(__CUDA_ARCH_SPECIFIC__) && (__CUDA_ARCH_SPECIFIC__ == 1030)) || \
    (defined(__CUDA_ARCH_FAMILY_SPECIFIC__) && (__CUDA_ARCH_FAMILY_SPECIFIC__ == 1030))
#define GB_TC 1
#else
#define GB_TC 0
#endif

// scratch
__device__ float g_y [32768u * 4u * 256u];                // 128MB
__device__ float g_k [4u * 131072u * 256u];               // 512MB  K[m][xrow][256]
__device__ float g_v [4u * 131072u * 256u];               // 512MB
__device__ float g_q [4u * 32768u * 256u];                // 128MB  Q[m][b][256] (scaled)
__device__ float g_oh[4u * 32768u * 256u];                // 128MB  Oh[m][b][256]
__device__ float g_ao[4u * 32768u * 256u];                // 128MB  attn_out[m][b][256]
__device__ __nv_bfloat16 g_w1t[64u * 32768u];             // FF1 tiles (hi|lo)
__device__ __nv_bfloat16 g_w2t[64u * 32768u];             // FF2 tiles
__device__ __nv_bfloat16 g_wkt[32u * 16384u];             // Wk tiles 128n x 64k
__device__ __nv_bfloat16 g_wvt[32u * 16384u];             // Wv tiles
__device__ __nv_bfloat16 g_wqt[16u * 32768u];             // Wq tiles 256n x 64k (scaled)
__device__ __nv_bfloat16 g_wot[16u * 32768u];             // Wo tiles 256n x 64k
__device__ unsigned g_hfscr[1024u * 131072u];             // hf scratch

// ---------- helpers ----------
static __device__ __forceinline__ u64 ffma2(u64 a, u64 b, u64 c) {
    u64 d;
    asm("fma.rn.f32x2 %0, %1, %2, %3;" : "=l"(d) : "l"(a), "l"(b), "l"(c));
    return d;
}
static __device__ __forceinline__ u64 dup2(float a) {
    u64 d;
    asm("mov.b64 %0, {%1, %1};" : "=l"(d) : "f"(a));
    return d;
}
static __device__ __forceinline__ float2 unpk(u64 p) {
    float2 r;
    asm("mov.b64 {%0, %1}, %2;" : "=f"(r.x), "=f"(r.y) : "l"(p));
    return r;
}
static __device__ __forceinline__ float comp4(const float4& v, int dd) {
    return dd == 0 ? v.x : dd == 1 ? v.y : dd == 2 ? v.z : v.w;
}
static __device__ __forceinline__ unsigned pk2(__nv_bfloat16 a, __nv_bfloat16 b) {
    return (unsigned)__bfloat16_as_ushort(a) | ((unsigned)__bfloat16_as_ushort(b) << 16);
}
static __device__ __forceinline__ void bsplit(float v, __nv_bfloat16& h, __nv_bfloat16& l) {
    h = __float2bfloat16(v);
    l = __float2bfloat16(v - __bfloat162float(h));
}
static __device__ __forceinline__ uint32_t swz128(uint32_t b) { return b ^ ((b >> 3) & 0x70); }
static __device__ __forceinline__ uint32_t smem_to_u32(const void* p) {
    uint32_t a;
    asm("{ .reg .u64 t; cvta.to.shared.u64 t, %1; cvt.u32.u64 %0, t; }" : "=r"(a) : "l"(p));
    return a;
}

// ---------- fp32 W staging (tail + fallbacks) ----------
template<int NIT>
struct Wreg { float f[NIT][4]; };

template<int NIT>
static __device__ __forceinline__ void ldgW(const float* __restrict__ W, int ldw, int k0,
                                            Wreg<NIT>& r, int tid) {
#pragma unroll
    for (int k = 0; k < NIT; ++k) {
        const int idx = tid + k * TPB;
        const int d = idx & 31, c4 = idx >> 5;
#pragma unroll
        for (int i = 0; i < 4; ++i)
            r.f[k][i] = W[(size_t)(c4 * 4 + i) * ldw + k0 + d];
    }
}
template<int NIT>
static __device__ __forceinline__ void stsW(float* sWT, const Wreg<NIT>& r, int tid) {
#pragma unroll
    for (int k = 0; k < NIT; ++k) {
        const int idx = tid + k * TPB;
        const int d = idx & 31, c4 = idx >> 5;
        *reinterpret_cast<float4*>(sWT + d * PW + c4 * 4) =
            make_float4(r.f[k][0], r.f[k][1], r.f[k][2], r.f[k][3]);
    }
}
static __device__ __forceinline__ void mma64b(const float* __restrict__ aRow, int lda,
                                              const float* __restrict__ sWT,
                                              u64 acc[8][4], int colg) {
#pragma unroll
    for (int d4 = 0; d4 < 8; ++d4) {
        float4 a4[8];
#pragma unroll
        for (int i = 0; i < 8; ++i)
            a4[i] = *reinterpret_cast<const float4*>(aRow + i * lda + (d4 << 2));
#pragma unroll
        for (int dd = 0; dd < 4; ++dd) {
            const int d = (d4 << 2) + dd;
            const ulonglong2 w0 = *reinterpret_cast<const ulonglong2*>(sWT + d * PW + (colg << 2));
            const ulonglong2 w1 = *reinterpret_cast<const ulonglong2*>(sWT + d * PW + 128 + (colg << 2));
#pragma unroll
            for (int i = 0; i < 8; ++i) {
                const u64 ad = dup2(comp4(a4[i], dd));
                acc[i][0] = ffma2(ad, w0.x, acc[i][0]);
                acc[i][1] = ffma2(ad, w0.y, acc[i][1]);
                acc[i][2] = ffma2(ad, w1.x, acc[i][2]);
                acc[i][3] = ffma2(ad, w1.y, acc[i][3]);
            }
        }
    }
}
static __device__ __forceinline__ void mmagb(const float* __restrict__ aRow, int lda,
                                             const float* __restrict__ sWT,
                                             u64 gacc[2], int colg) {
#pragma unroll
    for (int d4 = 0; d4 < 8; ++d4) {
        const float4 a0 = *reinterpret_cast<const float4*>(aRow + (d4 << 2));
        const float4 a1 = *reinterpret_cast<const float4*>(aRow + lda + (d4 << 2));
#pragma unroll
        for (int dd = 0; dd < 4; ++dd) {
            const u64 w = *reinterpret_cast<const u64*>(sWT + ((d4 << 2) + dd) * PW + colg * 2);
            gacc[0] = ffma2(dup2(comp4(a0, dd)), w, gacc[0]);
            gacc[1] = ffma2(dup2(comp4(a1, dd)), w, gacc[1]);
        }
    }
}

#if GB_TC
// ---------- tcgen05 ----------
static __device__ __forceinline__ uint32_t elect_one_pred() {
    uint32_t pred;
    asm volatile(
        "{\n\t.reg .pred p;\n\telect.sync _|p, 0xFFFFFFFF;\n\tselp.b32 %0, 1, 0, p;\n\t}"
        : "=r"(pred));
    return pred;
}
#define TCGEN05_ALLOC(sa, n) \
    asm volatile("tcgen05.alloc.cta_group::1.sync.aligned.shared::cta.b32 [%0], %1;" \
                 :: "r"((uint32_t)(sa)), "r"((uint32_t)(n)) : "memory")
#define TCGEN05_DEALLOC(ta, n) \
    asm volatile("tcgen05.dealloc.cta_group::1.sync.aligned.b32 %0, %1;" :: "r"(ta), "r"((uint32_t)(n)))
#define TCGEN05_COMMIT(mb) \
    asm volatile("tcgen05.commit.cta_group::1.mbarrier::arrive::one.shared::cluster.b64 [%0];" \
                 :: "r"((uint32_t)(mb)) : "memory")
#define TCGEN05_WAIT_LD()  asm volatile("tcgen05.wait::ld.sync.aligned;" ::: "memory")
#define TCGEN05_FENCE_AFTER()  asm volatile("tcgen05.fence::after_thread_sync;" ::: "memory")
#define TCGEN05_FENCE_BEFORE() asm volatile("tcgen05.fence::before_thread_sync;" ::: "memory")
#define MBARRIER_INIT(mb, c) \
    asm volatile("mbarrier.init.shared.b64 [%0], %1;" :: "r"((uint32_t)(mb)), "r"((uint32_t)(c)) : "memory")
#define MBARRIER_WAIT_PARITY(mb, par) do { \
    uint32_t _mb = (uint32_t)(mb), _pa = (uint32_t)(par), _dn; \
    asm volatile("{\n\t.reg .pred p;\n\t" \
        "mbarrier.try_wait.parity.acquire.cta.shared::cta.b64 p, [%1], %2;\n\t" \
        "selp.b32 %0, 1, 0, p;\n\t}" : "=r"(_dn) : "r"(_mb), "r"(_pa) : "memory"); \
    if (!_dn) { \
        asm volatile("{\n\t.reg .pred P1;\n\t" \
            "WL_%=:\n\tmbarrier.try_wait.parity.acquire.cta.shared::cta.b64 P1, [%0], %1, 0x989680;\n\t" \
            "@P1 bra.uni WD_%=;\n\tbra.uni WL_%=;\n\tWD_%=:\n\t}" \
            :: "r"(_mb), "r"(_pa) : "memory"); \
    } \
} while (0)
#define TCGEN05_LD_32X32B_X32(r, ta) \
    asm volatile("tcgen05.ld.sync.aligned.32x32b.x32.b32 " \
        "{%0, %1, %2, %3, %4, %5, %6, %7, %8, %9, %10, %11, %12, %13, %14, %15, " \
        "%16, %17, %18, %19, %20, %21, %22, %23, %24, %25, %26, %27, %28, %29, %30, %31}, [%32];" \
        : "=r"((r)[0]),  "=r"((r)[1]),  "=r"((r)[2]),  "=r"((r)[3]), \
          "=r"((r)[4]),  "=r"((r)[5]),  "=r"((r)[6]),  "=r"((r)[7]), \
          "=r"((r)[8]),  "=r"((r)[9]),  "=r"((r)[10]), "=r"((r)[11]), \
          "=r"((r)[12]), "=r"((r)[13]), "=r"((r)[14]), "=r"((r)[15]), \
          "=r"((r)[16]), "=r"((r)[17]), "=r"((r)[18]), "=r"((r)[19]), \
          "=r"((r)[20]), "=r"((r)[21]), "=r"((r)[22]), "=r"((r)[23]), \
          "=r"((r)[24]), "=r"((r)[25]), "=r"((r)[26]), "=r"((r)[27]), \
          "=r"((r)[28]), "=r"((r)[29]), "=r"((r)[30]), "=r"((r)[31]) \
        : "r"(ta))

static constexpr u64 SMEM_DESC_BASE_SW128 =
    (u64(2) << 61) | (u64(1) << 46) | (u64(64) << 32) | (u64(1) << 16);
#define MAKE_SMEM_DESC(a) (SMEM_DESC_BASE_SW128 | ((u64)((a) >> 4) & 0x3FFF))

static __device__ __forceinline__ void mma_f16_ss(uint32_t d, u64 ad, u64 bd,
                                                  uint32_t idesc, uint32_t en) {
    asm volatile(
        "{\n\t.reg .pred p;\n\tsetp.ne.u32 p, %4, 0;\n\t"
        "tcgen05.mma.cta_group::1.kind::f16 [%0], %1, %2, %3, {%5, %5, %5, %5}, p;\n\t}"
        :: "r"(d), "l"(ad), "l"(bd), "r"(idesc), "r"(en), "r"(0u)
        : "memory");
}
#endif  // GB_TC

#define IDESC_BF16_M128_N128 0x8200490u
#define IDESC_BF16_M128_N256 0x8400490u

// =====================================================================
// Kernel 0: pre-split + pre-swizzle weights (f1,f2,Wk,Wv,Wq,Wo)
// grid 12288 x 256
// =====================================================================
__global__ __launch_bounds__(256, 4)
void conv_w_kernel(const float* __restrict__ f1w, const float* __restrict__ f2w,
                   const float* __restrict__ Wk, const float* __restrict__ Wv,
                   const float* __restrict__ Wq, const float* __restrict__ Wo)
{
    const unsigned gidx = blockIdx.x * 256 + threadIdx.x;
    if (gidx < 2097152u) {
        const int arr = gidx >> 20;
        const unsigned rem = gidx & 0xFFFFFu;
        const int t = rem >> 14;
        const int e = rem & 16383;
        const int n = e >> 6, k = e & 63;
        const int m = t >> 4, c1 = (t >> 2) & 3, c2 = t & 3;
        float w;
        if (arr == 0)
            w = f1w[(size_t)m * 262144 + (size_t)(c1 * 256 + n) * 256 + c2 * 64 + k];
        else
            w = f2w[(size_t)m * 262144 + (size_t)n * 1024 + c1 * 256 + c2 * 64 + k];
        __nv_bfloat16 h, l;
        bsplit(w, h, l);
        const uint32_t sw = swz128((uint32_t)(n >> 3) * 1024 + (n & 7) * 128 + k * 2);
        __nv_bfloat16* dst = (arr == 0 ? g_w1t : g_w2t) + (size_t)t * 32768;
        dst[sw >> 1]           = h;
        dst[16384 + (sw >> 1)] = l;
    } else if (gidx < 2621440u) {
        const unsigned idx2 = gidx - 2097152u;
        const int arr2 = idx2 >> 18;
        const unsigned rem = idx2 & 0x3FFFFu;
        const int t = rem >> 13;
        const int e = rem & 8191;
        const int n = e >> 6, k = e & 63;
        const int m = t >> 3, nch = (t >> 2) & 1, kch = t & 3;
        const float* W = (arr2 == 0 ? Wk : Wv);
        const float w = W[(size_t)m * 65536 + (size_t)(nch * 128 + n) * 256 + kch * 64 + k];
        __nv_bfloat16 h, l;
        bsplit(w, h, l);
        const uint32_t sw = swz128((uint32_t)(n >> 3) * 1024 + (n & 7) * 128 + k * 2);
        __nv_bfloat16* dst = (arr2 == 0 ? g_wkt : g_wvt) + (size_t)t * 16384;
        dst[sw >> 1]          = h;
        dst[8192 + (sw >> 1)] = l;
    } else {
        const unsigned idx3 = gidx - 2621440u;    // < 524288
        const int arr3 = idx3 >> 18;              // 0: Wq, 1: Wo
        const unsigned rem = idx3 & 0x3FFFFu;
        const int t = rem >> 14;                  // m*4+kch
        const int e = rem & 16383;
        const int n = e >> 6, k = e & 63;         // n in 0..255
        const int m = t >> 2, kch = t & 3;
        const float* W = (arr3 == 0 ? Wq : Wo);
        float w = W[(size_t)m * 65536 + (size_t)n * 256 + kch * 64 + k];
        if (arr3 == 0) w *= 0.17677669529663687f;
        __nv_bfloat16 h, l;
        bsplit(w, h, l);
        const uint32_t sw = swz128((uint32_t)(n >> 3) * 1024 + (n & 7) * 128 + k * 2);
        __nv_bfloat16* dst = (arr3 == 0 ? g_wqt : g_wot) + (size_t)t * 32768;
        dst[sw >> 1]           = h;
        dst[16384 + (sw >> 1)] = l;
    }
}

// =====================================================================
// Kernel A: K,V projections (tcgen05), grid 1024
// =====================================================================
#define KV_SMEM 197632
#define KV_MB0  16
#define KV_MB1  24
#define KV_AHI  1024
#define KV_ALO  66560
#define KV_B0H  132096
#define KV_B0L  148480
#define KV_B1H  164864
#define KV_B1L  181248

__global__ __launch_bounds__(256, 1)
void gcma_kv(const float* __restrict__ x,
             const float* __restrict__ bk, const float* __restrict__ bv)
{
    extern __shared__ char smA[];
    const int tid = threadIdx.x;
    const int r0  = blockIdx.x * 128;

#if GB_TC
    const uint32_t sbase = smem_to_u32(smA);
    const int wid = tid >> 5, lane = tid & 31;
    char* sAhi = smA + KV_AHI;
    char* sAlo = smA + KV_ALO;

    if (wid == 0) TCGEN05_ALLOC(sbase + 0, 512);
    if (tid == 0) { MBARRIER_INIT(sbase + KV_MB0, 1); MBARRIER_INIT(sbase + KV_MB1, 1); }
    __syncthreads();
    uint32_t tmem;
    asm volatile("ld.shared.b32 %0, [%1];" : "=r"(tmem) : "r"(sbase + 0));

    for (int idx = tid; idx < 8192; idx += 256) {
        const int r = idx >> 6, k = (idx & 63) << 2;
        const float4 v = *reinterpret_cast<const float4*>(x + (size_t)(r0 + r) * 256 + k);
        __nv_bfloat16 h0, h1, h2, h3, l0, l1, l2, l3;
        bsplit(v.x, h0, l0); bsplit(v.y, h1, l1);
        bsplit(v.z, h2, l2); bsplit(v.w, h3, l3);
        const uint32_t sw = swz128((uint32_t)((r >> 3) + (k >> 6) * 16) * 1024 + (r & 7) * 128 + (k & 63) * 2);
        *reinterpret_cast<uint2*>(sAhi + sw) = make_uint2(pk2(h0, h1), pk2(h2, h3));
        *reinterpret_cast<uint2*>(sAlo + sw) = make_uint2(pk2(l0, l1), pk2(l2, l3));
    }

    const u64 aH = MAKE_SMEM_DESC(sbase + KV_AHI), aL = MAKE_SMEM_DESC(sbase + KV_ALO);
    const u64 b0H = MAKE_SMEM_DESC(sbase + KV_B0H), b0L = MAKE_SMEM_DESC(sbase + KV_B0L);
    const u64 b1H = MAKE_SMEM_DESC(sbase + KV_B1H), b1L = MAKE_SMEM_DESC(sbase + KV_B1L);

    int w0 = 0, w1 = 0, pend0 = 0, pend1 = 0;

    for (int job = 0; job < 8; ++job) {
        const int kv = job >> 2, m = job & 3;
        const int half = job & 1;
        const __nv_bfloat16* wbase = kv ? g_wvt : g_wkt;
        for (int c = 0; c < 8; ++c) {
            const int nch = c >> 2, kch = c & 3;
            const int buf = c & 1;
            if (buf == 0) { if (pend0) { MBARRIER_WAIT_PARITY(sbase + KV_MB0, w0 & 1); ++w0; pend0 = 0; } }
            else          { if (pend1) { MBARRIER_WAIT_PARITY(sbase + KV_MB1, w1 & 1); ++w1; pend1 = 0; } }
            {
                const float4* s4 = reinterpret_cast<const float4*>(
                    wbase + (size_t)(((m * 2 + nch) * 4 + kch)) * 16384);
                float4* dh = reinterpret_cast<float4*>(smA + (buf ? KV_B1H : KV_B0H));
                float4* dl = reinterpret_cast<float4*>(smA + (buf ? KV_B1L : KV_B0L));
#pragma unroll
                for (int i = 0; i < 4; ++i) {
                    dh[tid + i * 256] = s4[tid + i * 256];
                    dl[tid + i * 256] = s4[1024 + tid + i * 256];
                }
            }
            __syncthreads();
            if (wid == 0) {
                asm volatile("fence.proxy.async.shared::cta;" ::: "memory");
                TCGEN05_FENCE_AFTER();
                if (elect_one_pred()) {
                    const u64 bH = buf ? b1H : b0H, bL = buf ? b1L : b0L;
                    const uint32_t dcol = tmem + half * 256 + nch * 128;
#pragma unroll
                    for (int j = 0; j < 4; ++j) {
                        const u64 ao = (u64)(kch * 1024 + j * 2), bo = (u64)(j * 2);
                        mma_f16_ss(dcol, aH + ao, bH + bo, IDESC_BF16_M128_N128,
                                   (kch == 0 && j == 0) ? 0u : 1u);
                        mma_f16_ss(dcol, aH + ao, bL + bo, IDESC_BF16_M128_N128, 1u);
                        mma_f16_ss(dcol, aL + ao, bH + bo, IDESC_BF16_M128_N128, 1u);
                    }
                    TCGEN05_COMMIT(sbase + (buf ? KV_MB1 : KV_MB0));
                }
            }
            if (buf == 0) pend0 = 1; else pend1 = 1;
        }
        if (pend0) { MBARRIER_WAIT_PARITY(sbase + KV_MB0, w0 & 1); ++w0; pend0 = 0; }
        if (pend1) { MBARRIER_WAIT_PARITY(sbase + KV_MB1, w1 & 1); ++w1; pend1 = 0; }
        TCGEN05_FENCE_AFTER();
        {
            const float* bias = (kv ? bv : bk) + m * 256;
            float* dst = (kv ? g_v : g_k) + ((size_t)m * 131072 + r0) * 256;
            const int rr = (wid & 3) * 32 + lane;
            const int cb = (wid >> 2) * 128;
            for (int cc = 0; cc < 4; ++cc) {
                uint32_t dr[32];
                TCGEN05_LD_32X32B_X32(dr, tmem + half * 256 + cb + cc * 32);
                TCGEN05_WAIT_LD();
                TCGEN05_FENCE_BEFORE();
                const int c0 = cb + cc * 32;
                float* drow = dst + (size_t)rr * 256 + c0;
#pragma unroll
                for (int q = 0; q < 8; ++q) {
                    *reinterpret_cast<float4*>(drow + q * 4) =
                        make_float4(__uint_as_float(dr[q * 4 + 0]) + bias[c0 + q * 4 + 0],
                                    __uint_as_float(dr[q * 4 + 1]) + bias[c0 + q * 4 + 1],
                                    __uint_as_float(dr[q * 4 + 2]) + bias[c0 + q * 4 + 2],
                                    __uint_as_float(dr[q * 4 + 3]) + bias[c0 + q * 4 + 3]);
                }
            }
        }
        __syncthreads();
    }

    if (tid == 0) {
        asm volatile("mbarrier.inval.shared.b64 [%0];" :: "r"(sbase + KV_MB0) : "memory");
        asm volatile("mbarrier.inval.shared.b64 [%0];" :: "r"(sbase + KV_MB1) : "memory");
    }
    __syncthreads();
    if (wid == 0) TCGEN05_DEALLOC(tmem, 512);

#else
    float* sXf = reinterpret_cast<float*>(smA);
    for (int idx = tid; idx < 8192; idx += 256) {
        const int r = idx >> 6, q = idx & 63;
        *reinterpret_cast<float4*>(sXf + r * 256 + q * 4) =
            *reinterpret_cast<const float4*>(x + (size_t)(r0 + r) * 256 + q * 4);
    }
    __syncthreads();
    for (int job = 0; job < 8; ++job) {
        const int kv = job >> 2, m = job & 3;
        const float* bias = (kv ? bv : bk) + m * 256;
        float* dst = (kv ? g_v : g_k) + ((size_t)m * 131072 + r0) * 256;
        for (int e = tid; e < 128 * 256; e += 256) {
            const int r = e >> 8, n = e & 255;
            const __nv_bfloat16* wt = (kv ? g_wvt : g_wkt);
            float dot = 0.f;
            for (int k = 0; k < 256; ++k) {
                const int nch = n >> 7, nn = n & 127, kch = k >> 6, kk = k & 63;
                const __nv_bfloat16* tb = wt + (size_t)(((m * 2 + nch) * 4 + kch)) * 16384;
                const uint32_t sw = swz128((uint32_t)(nn >> 3) * 1024 + (nn & 7) * 128 + kk * 2);
                const float wv = __bfloat162float(tb[sw >> 1]) + __bfloat162float(tb[8192 + (sw >> 1)]);
                dot = fmaf(sXf[r * 256 + k], wv, dot);
            }
            dst[(size_t)r * 256 + n] = dot + bias[n];
        }
    }
#endif
}

// =====================================================================
// Kernel B/D: Q or Wo projection (tcgen05, N=256), grid (256,4)
// which=0: Q = gather(x)·(s·Wq)^T + s·bq -> g_q
// which=1: AO = g_oh·Wo^T + bo -> g_ao
// =====================================================================
#define QO_SMEM 197632
#define QO_MB   8
#define QO_AHI  1024
#define QO_ALO  66560
#define QO_BH   132096
#define QO_BL   164864

__global__ __launch_bounds__(256, 1)
void gcma_qo(const float* __restrict__ x,
             const float* __restrict__ bq, const float* __restrict__ bo,
             int which)
{
    extern __shared__ char smQ[];
    const int tid = threadIdx.x;
    const int m   = blockIdx.y;
    const int b0  = blockIdx.x * 128;

    const __nv_bfloat16* wt = which ? g_wot : g_wqt;
    const float* bias = which ? (bo + m * 256) : (bq + m * 256);
    const float bscale = which ? 1.f : 0.17677669529663687f;
    float* dst = (which ? g_ao : g_q) + ((size_t)m * 32768 + b0) * 256;

#if GB_TC
    const uint32_t sbase = smem_to_u32(smQ);
    const int wid = tid >> 5, lane = tid & 31;
    char* sAhi = smQ + QO_AHI;
    char* sAlo = smQ + QO_ALO;

    if (wid == 0) TCGEN05_ALLOC(sbase + 0, 512);
    if (tid == 0) MBARRIER_INIT(sbase + QO_MB, 1);
    __syncthreads();
    uint32_t tmem;
    asm volatile("ld.shared.b32 %0, [%1];" : "=r"(tmem) : "r"(sbase + 0));

    // stage A (gather for Q, contiguous for O)
    for (int idx = tid; idx < 8192; idx += 256) {
        const int r = idx >> 6, k = (idx & 63) << 2;
        const float* src = which
            ? g_oh + ((size_t)m * 32768 + b0 + r) * 256 + k
            : x + ((size_t)(b0 + r) * 4 + m) * 256 + k;
        const float4 v = *reinterpret_cast<const float4*>(src);
        __nv_bfloat16 h0, h1, h2, h3, l0, l1, l2, l3;
        bsplit(v.x, h0, l0); bsplit(v.y, h1, l1);
        bsplit(v.z, h2, l2); bsplit(v.w, h3, l3);
        const uint32_t sw = swz128((uint32_t)((r >> 3) + (k >> 6) * 16) * 1024 + (r & 7) * 128 + (k & 63) * 2);
        *reinterpret_cast<uint2*>(sAhi + sw) = make_uint2(pk2(h0, h1), pk2(h2, h3));
        *reinterpret_cast<uint2*>(sAlo + sw) = make_uint2(pk2(l0, l1), pk2(l2, l3));
    }

    const u64 aH = MAKE_SMEM_DESC(sbase + QO_AHI), aL = MAKE_SMEM_DESC(sbase + QO_ALO);
    const u64 bH = MAKE_SMEM_DESC(sbase + QO_BH),  bL = MAKE_SMEM_DESC(sbase + QO_BL);

    int ph = 0;
    for (int kch = 0; kch < 4; ++kch) {
        // stage B tile (32KB hi + 32KB lo), single-buffered
        {
            const float4* s4 = reinterpret_cast<const float4*>(wt + (size_t)(m * 4 + kch) * 32768);
            float4* dh = reinterpret_cast<float4*>(smQ + QO_BH);
            float4* dl = reinterpret_cast<float4*>(smQ + QO_BL);
#pragma unroll
            for (int i = 0; i < 8; ++i) {
                dh[tid + i * 256] = s4[tid + i * 256];
                dl[tid + i * 256] = s4[2048 + tid + i * 256];
            }
        }
        __syncthreads();
        if (wid == 0) {
            asm volatile("fence.proxy.async.shared::cta;" ::: "memory");
            TCGEN05_FENCE_AFTER();
            if (elect_one_pred()) {
#pragma unroll
                for (int j = 0; j < 4; ++j) {
                    const u64 ao = (u64)(kch * 1024 + j * 2), bo2 = (u64)(j * 2);
                    mma_f16_ss(tmem, aH + ao, bH + bo2, IDESC_BF16_M128_N256,
                               (kch == 0 && j == 0) ? 0u : 1u);
                    mma_f16_ss(tmem, aH + ao, bL + bo2, IDESC_BF16_M128_N256, 1u);
                    mma_f16_ss(tmem, aL + ao, bH + bo2, IDESC_BF16_M128_N256, 1u);
                }
                TCGEN05_COMMIT(sbase + QO_MB);
            }
        }
        MBARRIER_WAIT_PARITY(sbase + QO_MB, ph & 1);
        ++ph;
        TCGEN05_FENCE_AFTER();
    }

    // epilogue: bias + store
    {
        const int rr = (wid & 3) * 32 + lane;
        const int cb = (wid >> 2) * 128;
        for (int cc = 0; cc < 4; ++cc) {
            uint32_t dr[32];
            TCGEN05_LD_32X32B_X32(dr, tmem + cb + cc * 32);
            TCGEN05_WAIT_LD();
            TCGEN05_FENCE_BEFORE();
            const int c0 = cb + cc * 32;
            float* drow = dst + (size_t)rr * 256 + c0;
#pragma unroll
            for (int q = 0; q < 8; ++q) {
                *reinterpret_cast<float4*>(drow + q * 4) =
                    make_float4(__uint_as_float(dr[q * 4 + 0]) + bias[c0 + q * 4 + 0] * bscale,
                                __uint_as_float(dr[q * 4 + 1]) + bias[c0 + q * 4 + 1] * bscale,
                                __uint_as_float(dr[q * 4 + 2]) + bias[c0 + q * 4 + 2] * bscale,
                                __uint_as_float(dr[q * 4 + 3]) + bias[c0 + q * 4 + 3] * bscale);
            }
        }
    }

    __syncthreads();
    if (tid == 0)
        asm volatile("mbarrier.inval.shared.b64 [%0];" :: "r"(sbase + QO_MB) : "memory");
    __syncthreads();
    if (wid == 0) TCGEN05_DEALLOC(tmem, 512);

#else
    // fp32 fallback (slow; only for the non-103a cubin)
    for (int e = tid; e < 128 * 256; e += 256) {
        const int r = e >> 8, n = e & 255;
        float dot = 0.f;
        for (int k = 0; k < 256; ++k) {
            const int kch = k >> 6, kk = k & 63;
            const __nv_bfloat16* tb = wt + (size_t)(m * 4 + kch) * 32768;
            const uint32_t sw = swz128((uint32_t)(n >> 3) * 1024 + (n & 7) * 128 + kk * 2);
            const float wv = __bfloat162float(tb[sw >> 1]) + __bfloat162float(tb[16384 + (sw >> 1)]);
            const float a = which
                ? g_oh[((size_t)m * 32768 + b0 + r) * 256 + k]
                : x[((size_t)(b0 + r) * 4 + m) * 256 + k];
            dot = fmaf(a, wv, dot);
        }
        dst[(size_t)r * 256 + n] = dot + bias[n] * bscale;
    }
#endif
}

// =====================================================================
// Kernel C: attention (fp32, memory-shaped), grid (2048,4)
// =====================================================================
#define AT_Q    0
#define AT_KV   4096
#define AT_P    20480
#define AT_FLOATS 20992
#define AT_BYTES  (AT_FLOATS * 4)

__global__ __launch_bounds__(256, 1)
void gcma_attn()
{
    extern __shared__ float smT[];
    float* sQ  = smT + AT_Q;
    float* sKV = smT + AT_KV;
    float* sP  = smT + AT_P;

    const int tid = threadIdx.x;
    const int m   = blockIdx.y;
    const int b0  = blockIdx.x * 16;
    const long g0 = (long)b0 * 4;

    for (int idx = tid; idx < 1024; idx += 256) {
        const int r = idx >> 6, q = idx & 63;
        *reinterpret_cast<float4*>(sQ + r * 256 + q * 4) =
            *reinterpret_cast<const float4*>(g_q + ((size_t)m * 32768 + b0 + r) * 256 + q * 4);
    }
    for (int idx = tid; idx < 4096; idx += 256) {
        const int r = idx >> 6, q = idx & 63;
        *reinterpret_cast<float4*>(sKV + r * 256 + q * 4) =
            *reinterpret_cast<const float4*>(g_k + ((size_t)m * 131072 + g0 + r) * 256 + q * 4);
    }
    __syncthreads();

    if (tid < 128) {
        const int bl = tid >> 3, h = tid & 7;
        const float* qp = sQ + bl * 256 + h * 32;
        float q[32];
#pragma unroll
        for (int i = 0; i < 32; ++i) q[i] = qp[i];
        float s[4];
#pragma unroll
        for (int n = 0; n < 4; ++n) {
            const float* kp = sKV + (bl * 4 + n) * 256 + h * 32;
            float dot = 0.f;
#pragma unroll
            for (int i = 0; i < 32; ++i) dot = fmaf(q[i], kp[i], dot);
            s[n] = dot;
        }
        const float mx = fmaxf(fmaxf(s[0], s[1]), fmaxf(s[2], s[3]));
        float e[4], se = 0.f;
#pragma unroll
        for (int n = 0; n < 4; ++n) { e[n] = expf(s[n] - mx); se += e[n]; }
        const float inv = 1.f / se;
#pragma unroll
        for (int n = 0; n < 4; ++n) sP[tid * 4 + n] = e[n] * inv;
    }
    __syncthreads();

    for (int idx = tid; idx < 4096; idx += 256) {
        const int r = idx >> 6, q = idx & 63;
        *reinterpret_cast<float4*>(sKV + r * 256 + q * 4) =
            *reinterpret_cast<const float4*>(g_v + ((size_t)m * 131072 + g0 + r) * 256 + q * 4);
    }
    __syncthreads();

    if (tid < 128) {
        const int bl = tid >> 3, h = tid & 7;
        float o[32];
#pragma unroll
        for (int i = 0; i < 32; ++i) o[i] = 0.f;
#pragma unroll
        for (int n = 0; n < 4; ++n) {
            const float p = sP[tid * 4 + n];
            const float* vp = sKV + (bl * 4 + n) * 256 + h * 32;
#pragma unroll
            for (int i = 0; i < 32; ++i) o[i] = fmaf(p, vp[i], o[i]);
        }
        float* op = g_oh + ((size_t)m * 32768 + b0 + bl) * 256 + h * 32;
#pragma unroll
        for (int q = 0; q < 8; ++q)
            *reinterpret_cast<float4*>(op + q * 4) =
                make_float4(o[q * 4], o[q * 4 + 1], o[q * 4 + 2], o[q * 4 + 3]);
    }
}

// =====================================================================
// Kernel E: gate MLP + LayerNorm, grid (2048,4)
// =====================================================================
#define TL_XM   0
#define TL_AO   4096
#define TL_WT   8192
#define TL_GH   16512
#define TL_GATE 17536
#define TL_FLOATS 17552
#define TL_BYTES  (TL_FLOATS * 4)

__global__ __launch_bounds__(256, 1)
void gcma_tail(const float* __restrict__ x,
               const float* __restrict__ g1w, const float* __restrict__ g1b,
               const float* __restrict__ g2w, const float* __restrict__ g2b,
               const float* __restrict__ lng, const float* __restrict__ lnb,
               float* __restrict__ out)
{
    extern __shared__ float smL[];
    float* sXm   = smL + TL_XM;
    float* sAO   = smL + TL_AO;
    float* sWT   = smL + TL_WT;
    float* sGH   = smL + TL_GH;
    float* sGate = smL + TL_GATE;

    const int tid = threadIdx.x;
    const int m   = blockIdx.y;
    const int b0  = blockIdx.x * 16;
    const long g0 = (long)b0 * 4;

    const int warp = tid >> 5;
    const int colg = tid & 31;

    for (int idx = tid; idx < 1024; idx += 256) {
        const int r = idx >> 6, q = idx & 63;
        *reinterpret_cast<float4*>(sXm + r * 256 + q * 4) =
            *reinterpret_cast<const float4*>(x + ((size_t)(b0 + r) * 4 + m) * 256 + q * 4);
        *reinterpret_cast<float4*>(sAO + r * 256 + q * 4) =
            *reinterpret_cast<const float4*>(g_ao + ((size_t)m * 32768 + b0 + r) * 256 + q * 4);
    }

    // gate layer 1
    {
        const float* W = g1w + (size_t)m * 32768;
        Wreg<2> wr;
        ldgW<2>(W, 512, 0, wr, tid);
        u64 gacc[2] = {0ULL, 0ULL};
        for (int dt = 0; dt < 16; ++dt) {
            __syncthreads();
            stsW<2>(sWT, wr, tid);
            if (dt < 15) ldgW<2>(W, 512, (dt + 1) * 32, wr, tid);
            __syncthreads();
            if (dt < 8)
                mmagb(sXm + warp * 2 * 256 + dt * 32, 256, sWT, gacc, colg);
            else
                mmagb(sAO + warp * 2 * 256 + (dt - 8) * 32, 256, sWT, gacc, colg);
        }
        const float gb0 = g1b[m * 64 + colg * 2];
        const float gb1 = g1b[m * 64 + colg * 2 + 1];
#pragma unroll
        for (int i = 0; i < 2; ++i) {
            const float2 p = unpk(gacc[i]);
            sGH[(warp * 2 + i) * 64 + colg * 2]     = tanhf(p.x + gb0);
            sGH[(warp * 2 + i) * 64 + colg * 2 + 1] = tanhf(p.y + gb1);
        }
    }
    __syncthreads();

    // gate layer 2
    if (tid < 16) {
        const float* g2 = g2w + m * 64;
        float dot = g2b[m];
#pragma unroll 8
        for (int j = 0; j < 64; ++j) dot = fmaf(sGH[tid * 64 + j], g2[j], dot);
        const float gate = 1.f / (1.f + expf(-dot));
        sGate[tid] = gate;
        out[OUT_GATE_BASE + (size_t)(b0 + tid) * 4 + m] = gate;
    }
    __syncthreads();

    // residual + LayerNorm -> g_y
    {
        const int lane = tid & 31;
        for (int bl = warp; bl < 16; bl += 8) {
            const float* xr  = sXm + bl * 256;
            const float* aor = sAO + bl * 256;
            const float gate = sGate[bl];
            float r[8];
            float sum = 0.f;
#pragma unroll
            for (int k = 0; k < 8; ++k) {
                const int d = k * 32 + lane;
                r[k] = xr[d] + gate * aor[d];
                sum += r[k];
            }
#pragma unroll
            for (int o = 16; o; o >>= 1) sum += __shfl_xor_sync(0xffffffffu, sum, o);
            const float mu = sum * (1.f / 256.f);
            float var = 0.f;
#pragma unroll
            for (int k = 0; k < 8; ++k) { const float t = r[k] - mu; var = fmaf(t, t, var); }
#pragma unroll
            for (int o = 16; o; o >>= 1) var += __shfl_xor_sync(0xffffffffu, var, o);
            const float rs = rsqrtf(var * (1.f / 256.f) + 1e-5f);
            float* yr = g_y + (size_t)(g0 + bl * 4 + m) * 256;
#pragma unroll
            for (int k = 0; k < 8; ++k) {
                const int d = k * 32 + lane;
                yr[d] = (r[k] - mu) * rs * lng[m * 256 + d] + lnb[m * 256 + d];
            }
        }
    }
}

// =====================================================================
// Kernel F: FF (tcgen05, unchanged from R10)
// =====================================================================
#define P2_SMEM 197632
#define P2_TM    0
#define P2_MB    8
#define P2_AHI   1024
#define P2_ALO   66560
#define P2_BHI   132096
#define P2_BLO   164864

static __device__ __forceinline__ void loadB(const __nv_bfloat16* base, int m, int c1, int c2,
                                             float4 pf[16], int tid) {
    const float4* src = reinterpret_cast<const float4*>(base + (size_t)((m * 4 + c1) * 4 + c2) * 32768);
#pragma unroll
    for (int i = 0; i < 8; ++i) {
        pf[i]     = src[tid + i * 256];
        pf[8 + i] = src[2048 + tid + i * 256];
    }
}
static __device__ __forceinline__ void stsB(char* sBhi, char* sBlo, const float4 pf[16], int tid) {
#pragma unroll
    for (int i = 0; i < 8; ++i) {
        reinterpret_cast<float4*>(sBhi)[tid + i * 256] = pf[i];
        reinterpret_cast<float4*>(sBlo)[tid + i * 256] = pf[8 + i];
    }
}

__global__ __launch_bounds__(256, 1)
void gcma_part2tc(const float* __restrict__ f1w, const float* __restrict__ f1b,
                  const float* __restrict__ f2w, const float* __restrict__ f2b,
                  float* __restrict__ out)
{
    extern __shared__ char sm2[];
    const int tid  = threadIdx.x;
    const int m    = blockIdx.y;
    const int b0   = blockIdx.x * 128;

#if GB_TC
    const uint32_t sbase = smem_to_u32(sm2);
    const uint32_t TMP  = sbase + P2_TM;
    const uint32_t MBAR = sbase + P2_MB;
    char* sAhi = sm2 + P2_AHI;
    char* sAlo = sm2 + P2_ALO;
    char* sBhi = sm2 + P2_BHI;
    char* sBlo = sm2 + P2_BLO;
    const uint32_t aHiA = sbase + P2_AHI, aLoA = sbase + P2_ALO;
    const uint32_t bHiA = sbase + P2_BHI, bLoA = sbase + P2_BLO;

    const int wid  = tid >> 5, lane = tid & 31;
    unsigned* hfbase = g_hfscr + (size_t)(blockIdx.y * 256 + blockIdx.x) * 131072u;

    if (wid == 0) TCGEN05_ALLOC(TMP, 512);
    if (tid == 0) MBARRIER_INIT(MBAR, 1);
    __syncthreads();
    uint32_t tmem;
    asm volatile("ld.shared.b32 %0, [%1];" : "=r"(tmem) : "r"(TMP));

    for (int idx = tid; idx < 8192; idx += 256) {
        const int r = idx >> 6, k = (idx & 63) << 2;
        const float4 v = *reinterpret_cast<const float4*>(
            g_y + ((size_t)(b0 + r) * 4 + m) * 256 + k);
        __nv_bfloat16 h0, h1, h2, h3, l0, l1, l2, l3;
        bsplit(v.x, h0, l0); bsplit(v.y, h1, l1);
        bsplit(v.z, h2, l2); bsplit(v.w, h3, l3);
        const uint32_t sw = swz128((uint32_t)((r >> 3) + (k >> 6) * 16) * 1024 + (r & 7) * 128 + (k & 63) * 2);
        *reinterpret_cast<uint2*>(sAhi + sw) = make_uint2(pk2(h0, h1), pk2(h2, h3));
        *reinterpret_cast<uint2*>(sAlo + sw) = make_uint2(pk2(l0, l1), pk2(l2, l3));
    }

    float4 pf[16];
    loadB(g_w1t, m, 0, 0, pf, tid);
    int ph = 0;
    const u64 aH = MAKE_SMEM_DESC(aHiA), aL = MAKE_SMEM_DESC(aLoA);
    const u64 bH = MAKE_SMEM_DESC(bHiA), bL = MAKE_SMEM_DESC(bLoA);

    for (int nch = 0; nch < 4; ++nch) {
        for (int kch = 0; kch < 4; ++kch) {
            stsB(sBhi, sBlo, pf, tid);
            __syncthreads();
            if (wid == 0) {
                asm volatile("fence.proxy.async.shared::cta;" ::: "memory");
                TCGEN05_FENCE_AFTER();
                if (elect_one_pred()) {
#pragma unroll
                    for (int j = 0; j < 4; ++j) {
                        const u64 ao = (u64)(kch * 1024 + j * 2), bo = (u64)(j * 2);
                        mma_f16_ss(tmem, aH + ao, bH + bo, IDESC_BF16_M128_N256,
                                   (kch == 0 && j == 0) ? 0u : 1u);
                        mma_f16_ss(tmem, aH + ao, bL + bo, IDESC_BF16_M128_N256, 1u);
                        mma_f16_ss(tmem, aL + ao, bH + bo, IDESC_BF16_M128_N256, 1u);
                    }
                    TCGEN05_COMMIT(MBAR);
                }
            }
            const int nb = nch * 4 + kch + 1;
            if (nb < 16) loadB(g_w1t, m, nb >> 2, nb & 3, pf, tid);
            else         loadB(g_w2t, m, 0, 0, pf, tid);
            MBARRIER_WAIT_PARITY(MBAR, ph & 1);
            ++ph;
            TCGEN05_FENCE_AFTER();
        }
        {
            const int r  = (wid & 3) * 32 + lane;
            const int cb = (wid >> 2) * 128;
            for (int cc = 0; cc < 4; ++cc) {
                uint32_t dr[32];
                TCGEN05_LD_32X32B_X32(dr, tmem + cb + cc * 32);
                TCGEN05_WAIT_LD();
                TCGEN05_FENCE_BEFORE();
                const int c0 = nch * 256 + cb + cc * 32;
                unsigned* dst = hfbase + (size_t)r * 1024 + c0;
#pragma unroll
                for (int j = 0; j < 32; ++j) {
                    float v = __uint_as_float(dr[j]) + f1b[m * 1024 + c0 + j];
                    v = 0.5f * v * (1.f + erff(v * 0.7071067811865476f));
                    __nv_bfloat16 h, l;
                    bsplit(v, h, l);
                    dst[j] = pk2(h, l);
                }
            }
        }
        __syncthreads();
    }

    for (int ch = 0; ch < 4; ++ch) {
        for (int idx = tid; idx < 8192; idx += 256) {
            const int r = idx >> 6, k = (idx & 63) << 2;
            const uint4 u = *reinterpret_cast<const uint4*>(
                hfbase + (size_t)r * 1024 + ch * 256 + k);
            const unsigned uu[4] = {u.x, u.y, u.z, u.w};
            __nv_bfloat16 h[4], l[4];
#pragma unroll
            for (int j = 0; j < 4; ++j) {
                h[j] = __ushort_as_bfloat16((unsigned short)(uu[j] & 0xFFFFu));
                l[j] = __ushort_as_bfloat16((unsigned short)(uu[j] >> 16));
            }
            const uint32_t sw = swz128((uint32_t)((r >> 3) + (k >> 6) * 16) * 1024 + (r & 7) * 128 + (k & 63) * 2);
            *reinterpret_cast<uint2*>(sAhi + sw) = make_uint2(pk2(h[0], h[1]), pk2(h[2], h[3]));
            *reinterpret_cast<uint2*>(sAlo + sw) = make_uint2(pk2(l[0], l[1]), pk2(l[2], l[3]));
        }
        for (int kc = 0; kc < 4; ++kc) {
            stsB(sBhi, sBlo, pf, tid);
            __syncthreads();
            if (wid == 0) {
                asm volatile("fence.proxy.async.shared::cta;" ::: "memory");
                TCGEN05_FENCE_AFTER();
                if (elect_one_pred()) {
#pragma unroll
                    for (int j = 0; j < 4; ++j) {
                        const u64 ao = (u64)(kc * 1024 + j * 2), bo = (u64)(j * 2);
                        mma_f16_ss(tmem + 256, aH + ao, bH + bo, IDESC_BF16_M128_N256,
                                   (ch == 0 && kc == 0 && j == 0) ? 0u : 1u);
                        mma_f16_ss(tmem + 256, aH + ao, bL + bo, IDESC_BF16_M128_N256, 1u);
                        mma_f16_ss(tmem + 256, aL + ao, bH + bo, IDESC_BF16_M128_N256, 1u);
                    }
                    TCGEN05_COMMIT(MBAR);
                }
            }
            const int nb = ch * 4 + kc + 1;
            if (nb < 16) loadB(g_w2t, m, nb >> 2, nb & 3, pf, tid);
            MBARRIER_WAIT_PARITY(MBAR, ph & 1);
            ++ph;
            TCGEN05_FENCE_AFTER();
        }
    }

    {
        const int r  = (wid & 3) * 32 + lane;
        const int cb = (wid >> 2) * 128;
        for (int cc = 0; cc < 4; ++cc) {
            uint32_t dr[32];
            TCGEN05_LD_32X32B_X32(dr, tmem + 256 + cb + cc * 32);
            TCGEN05_WAIT_LD();
            TCGEN05_FENCE_BEFORE();
            const int c0 = cb + cc * 32;
            const float* yrow = g_y + ((size_t)(b0 + r) * 4 + m) * 256 + c0;
            float* orow = out + ((size_t)(b0 + r) * 4 + m) * 256 + c0;
#pragma unroll
            for (int j = 0; j < 32; ++j)
                orow[j] = yrow[j] + __uint_as_float(dr[j]) + f2b[m * 256 + c0 + j];
        }
    }

    __syncthreads();
    if (tid == 0)
        asm volatile("mbarrier.inval.shared.b64 [%0];" :: "r"(MBAR) : "memory");
    __syncthreads();
    if (wid == 0) TCGEN05_DEALLOC(tmem, 512);

#else
    float* smf = reinterpret_cast<float*>(sm2);
    float* sY  = smf;
    float* sHF = smf + 16384;
    float* sWT = smf + 32768;
    const int warp = tid >> 5;
    const int colg = tid & 31;

    for (int half = 0; half < 2; ++half) {
        const int hb0 = b0 + half * 64;
        __syncthreads();
        for (int idx = tid; idx < 4096; idx += TPB) {
            const int r = idx >> 6, q = idx & 63;
            *reinterpret_cast<float4*>(sY + r * 256 + q * 4) =
                *reinterpret_cast<const float4*>(g_y + ((size_t)(hb0 + r) * 4 + m) * 256 + q * 4);
        }
        u64 facc[8][4];
#pragma unroll
        for (int i = 0; i < 8; ++i)
#pragma unroll
            for (int j = 0; j < 4; ++j) facc[i][j] = 0ULL;
        const float* aY  = sY  + warp * 8 * 256;
        const float* aHF = sHF + warp * 8 * 256;

        for (int ch = 0; ch < 4; ++ch) {
            u64 hacc[8][4];
#pragma unroll
            for (int i = 0; i < 8; ++i)
#pragma unroll
                for (int j = 0; j < 4; ++j) hacc[i][j] = 0ULL;
            {
                const float* W1 = f1w + (size_t)m * 262144 + (size_t)ch * 65536;
                Wreg<8> wr;
                ldgW<8>(W1, 256, 0, wr, tid);
                for (int dt = 0; dt < 8; ++dt) {
                    __syncthreads();
                    stsW<8>(sWT, wr, tid);
                    if (dt < 7) ldgW<8>(W1, 256, (dt + 1) * 32, wr, tid);
                    __syncthreads();
                    mma64b(aY + dt * 32, 256, sWT, hacc, colg);
                }
            }
            __syncthreads();
            {
                const float* b1 = f1b + m * 1024 + ch * 256;
                float bl0[4], bl1[4];
#pragma unroll
                for (int j = 0; j < 4; ++j) { bl0[j] = b1[colg * 4 + j]; bl1[j] = b1[128 + colg * 4 + j]; }
#pragma unroll
                for (int i = 0; i < 8; ++i) {
                    const int r = warp * 8 + i;
                    const float2 pa = unpk(hacc[i][0]), pb = unpk(hacc[i][1]);
                    const float2 pc = unpk(hacc[i][2]), pd = unpk(hacc[i][3]);
                    float v0[4] = {pa.x + bl0[0], pa.y + bl0[1], pb.x + bl0[2], pb.y + bl0[3]};
                    float v1[4] = {pc.x + bl1[0], pc.y + bl1[1], pd.x + bl1[2], pd.y + bl1[3]};
#pragma unroll
                    for (int j = 0; j < 4; ++j) {
                        v0[j] = 0.5f * v0[j] * (1.f + erff(v0[j] * 0.7071067811865476f));
                        v1[j] = 0.5f * v1[j] * (1.f + erff(v1[j] * 0.7071067811865476f));
                    }
                    *reinterpret_cast<float4*>(sHF + r * 256 + colg * 4) =
                        make_float4(v0[0], v0[1], v0[2], v0[3]);
                    *reinterpret_cast<float4*>(sHF + r * 256 + 128 + colg * 4) =
                        make_float4(v1[0], v1[1], v1[2], v1[3]);
                }
            }
            {
                const float* W2 = f2w + (size_t)m * 262144;
                Wreg<8> wr;
                ldgW<8>(W2, 1024, ch * 256, wr, tid);
                for (int dt = 0; dt < 8; ++dt) {
                    __syncthreads();
                    stsW<8>(sWT, wr, tid);
                    if (dt < 7) ldgW<8>(W2, 1024, ch * 256 + (dt + 1) * 32, wr, tid);
                    __syncthreads();
                    mma64b(aHF + dt * 32, 256, sWT, facc, colg);
                }
            }
            __syncthreads();
        }
        {
            const float* b2 = f2b + m * 256;
            float bl0[4], bl1[4];
#pragma unroll
            for (int j = 0; j < 4; ++j) { bl0[j] = b2[colg * 4 + j]; bl1[j] = b2[128 + colg * 4 + j]; }
#pragma unroll
            for (int i = 0; i < 8; ++i) {
                const int r = warp * 8 + i;
                const float4 y0 = *reinterpret_cast<const float4*>(sY + r * 256 + colg * 4);
                const float4 y1 = *reinterpret_cast<const float4*>(sY + r * 256 + 128 + colg * 4);
                const float2 pa = unpk(facc[i][0]), pb = unpk(facc[i][1]);
                const float2 pc = unpk(facc[i][2]), pd = unpk(facc[i][3]);
                float* op = out + ((size_t)(hb0 + r) * 4 + m) * 256;
                *reinterpret_cast<float4*>(op + colg * 4) =
                    make_float4(y0.x + pa.x + bl0[0], y0.y + pa.y + bl0[1],
                                y0.z + pb.x + bl0[2], y0.w + pb.y + bl0[3]);
                *reinterpret_cast<float4*>(op + 128 + colg * 4) =
                    make_float4(y1.x + pc.x + bl1[0], y1.y + pc.y + bl1[1],
                                y1.z + pd.x + bl1[2], y1.w + pd.y + bl1[3]);
            }
        }
    }
#endif
}

extern "C" void kernel_launch(void* const* d_in, const int* in_sizes, int n_in,
                              void* d_out, int out_size) {
    const float* x   = (const float*)d_in[0];
    const float* Wq  = (const float*)d_in[1];
    const float* bq  = (const float*)d_in[2];
    const float* Wk  = (const float*)d_in[3];
    const float* bk  = (const float*)d_in[4];
    const float* Wv  = (const float*)d_in[5];
    const float* bv  = (const float*)d_in[6];
    const float* Wo  = (const float*)d_in[7];
    const float* bo  = (const float*)d_in[8];
    const float* g1w = (const float*)d_in[9];
    const float* g1b = (const float*)d_in[10];
    const float* g2w = (const float*)d_in[11];
    const float* g2b = (const float*)d_in[12];
    const float* lng = (const float*)d_in[13];
    const float* lnb = (const float*)d_in[14];
    const float* f1w = (const float*)d_in[15];
    const float* f1b = (const float*)d_in[16];
    const float* f2w = (const float*)d_in[17];
    const float* f2b = (const float*)d_in[18];
    float* out = (float*)d_out;

    cudaFuncSetAttribute(gcma_kv, cudaFuncAttributeMaxDynamicSharedMemorySize, KV_SMEM);
    cudaFuncSetAttribute(gcma_qo, cudaFuncAttributeMaxDynamicSharedMemorySize, QO_SMEM);
    cudaFuncSetAttribute(gcma_attn, cudaFuncAttributeMaxDynamicSharedMemorySize, AT_BYTES);
    cudaFuncSetAttribute(gcma_tail, cudaFuncAttributeMaxDynamicSharedMemorySize, TL_BYTES);
    cudaFuncSetAttribute(gcma_part2tc, cudaFuncAttributeMaxDynamicSharedMemorySize, P2_SMEM);

    conv_w_kernel<<<12288, 256>>>(f1w, f2w, Wk, Wv, Wq, Wo);
    gcma_kv<<<1024, 256, KV_SMEM>>>(x, bk, bv);
    gcma_qo<<<dim3(256, 4), 256, QO_SMEM>>>(x, bq, bo, 0);
    gcma_attn<<<dim3(2048, 4), 256, AT_BYTES>>>();
    gcma_qo<<<dim3(256, 4), 256, QO_SMEM>>>(x, bq, bo, 1);
    gcma_tail<<<dim3(2048, 4), 256, TL_BYTES>>>(x, g1w, g1b, g2w, g2b, lng, lnb, out);
    gcma_part2tc<<<dim3(256, 4), 256, P2_SMEM>>>(f1w, f1b, f2w, f2b, out);
}

// round 12
// speedup vs baseline: 2.5940x; 1.1614x over previous
#include <cuda_runtime.h>
#include <cuda_bf16.h>
#include <math.h>
#include <stdint.h>

typedef unsigned long long u64;

#define TPB 256
#define PW 260

#define OUT_GATE_BASE 33554432UL   // B*M*D

#if defined(__CUDA_ARCH_FEAT_SM103_ALL) || \
    (defined(__CUDA_ARCH_SPECIFIC__) && (__CUDA_ARCH_SPECIFIC__ == 1030)) || \
    (defined(__CUDA_ARCH_FAMILY_SPECIFIC__) && (__CUDA_ARCH_FAMILY_SPECIFIC__ == 1030))
#define GB_TC 1
#else
#define GB_TC 0
#endif

// scratch
__device__ float g_y [32768u * 4u * 256u];                // 128MB
__device__ float g_k [4u * 131072u * 256u];               // 512MB  K[m][xrow][256]
__device__ float g_v [4u * 131072u * 256u];               // 512MB
__device__ float g_q [4u * 32768u * 256u];                // 128MB  Q[m][b][256] (scaled)
__device__ float g_oh[4u * 32768u * 256u];                // 128MB  Oh[m][b][256]
__device__ float g_ao[4u * 32768u * 256u];                // 128MB  attn_out[m][b][256]
__device__ __nv_bfloat16 g_w1t[64u * 32768u];             // FF1 tiles (hi|lo)
__device__ __nv_bfloat16 g_w2t[64u * 32768u];             // FF2 tiles
__device__ __nv_bfloat16 g_wkt[32u * 16384u];             // Wk tiles 128n x 64k
__device__ __nv_bfloat16 g_wvt[32u * 16384u];             // Wv tiles
__device__ __nv_bfloat16 g_wqt[16u * 32768u];             // Wq tiles 256n x 64k (scaled)
__device__ __nv_bfloat16 g_wot[16u * 32768u];             // Wo tiles 256n x 64k
__device__ unsigned g_hfscr[1024u * 131072u];             // hf scratch

// ---------- helpers ----------
static __device__ __forceinline__ u64 ffma2(u64 a, u64 b, u64 c) {
    u64 d;
    asm("fma.rn.f32x2 %0, %1, %2, %3;" : "=l"(d) : "l"(a), "l"(b), "l"(c));
    return d;
}
static __device__ __forceinline__ u64 dup2(float a) {
    u64 d;
    asm("mov.b64 %0, {%1, %1};" : "=l"(d) : "f"(a));
    return d;
}
static __device__ __forceinline__ float2 unpk(u64 p) {
    float2 r;
    asm("mov.b64 {%0, %1}, %2;" : "=f"(r.x), "=f"(r.y) : "l"(p));
    return r;
}
static __device__ __forceinline__ float comp4(const float4& v, int dd) {
    return dd == 0 ? v.x : dd == 1 ? v.y : dd == 2 ? v.z : v.w;
}
static __device__ __forceinline__ unsigned pk2(__nv_bfloat16 a, __nv_bfloat16 b) {
    return (unsigned)__bfloat16_as_ushort(a) | ((unsigned)__bfloat16_as_ushort(b) << 16);
}
static __device__ __forceinline__ void bsplit(float v, __nv_bfloat16& h, __nv_bfloat16& l) {
    h = __float2bfloat16(v);
    l = __float2bfloat16(v - __bfloat162float(h));
}
static __device__ __forceinline__ uint32_t swz128(uint32_t b) { return b ^ ((b >> 3) & 0x70); }
static __device__ __forceinline__ uint32_t smem_to_u32(const void* p) {
    uint32_t a;
    asm("{ .reg .u64 t; cvta.to.shared.u64 t, %1; cvt.u32.u64 %0, t; }" : "=r"(a) : "l"(p));
    return a;
}

// ---------- fp32 W staging (tail + fallbacks) ----------
template<int NIT>
struct Wreg { float f[NIT][4]; };

template<int NIT>
static __device__ __forceinline__ void ldgW(const float* __restrict__ W, int ldw, int k0,
                                            Wreg<NIT>& r, int tid) {
#pragma unroll
    for (int k = 0; k < NIT; ++k) {
        const int idx = tid + k * TPB;
        const int d = idx & 31, c4 = idx >> 5;
#pragma unroll
        for (int i = 0; i < 4; ++i)
            r.f[k][i] = W[(size_t)(c4 * 4 + i) * ldw + k0 + d];
    }
}
template<int NIT>
static __device__ __forceinline__ void stsW(float* sWT, const Wreg<NIT>& r, int tid) {
#pragma unroll
    for (int k = 0; k < NIT; ++k) {
        const int idx = tid + k * TPB;
        const int d = idx & 31, c4 = idx >> 5;
        *reinterpret_cast<float4*>(sWT + d * PW + c4 * 4) =
            make_float4(r.f[k][0], r.f[k][1], r.f[k][2], r.f[k][3]);
    }
}
static __device__ __forceinline__ void mma64b(const float* __restrict__ aRow, int lda,
                                              const float* __restrict__ sWT,
                                              u64 acc[8][4], int colg) {
#pragma unroll
    for (int d4 = 0; d4 < 8; ++d4) {
        float4 a4[8];
#pragma unroll
        for (int i = 0; i < 8; ++i)
            a4[i] = *reinterpret_cast<const float4*>(aRow + i * lda + (d4 << 2));
#pragma unroll
        for (int dd = 0; dd < 4; ++dd) {
            const int d = (d4 << 2) + dd;
            const ulonglong2 w0 = *reinterpret_cast<const ulonglong2*>(sWT + d * PW + (colg << 2));
            const ulonglong2 w1 = *reinterpret_cast<const ulonglong2*>(sWT + d * PW + 128 + (colg << 2));
#pragma unroll
            for (int i = 0; i < 8; ++i) {
                const u64 ad = dup2(comp4(a4[i], dd));
                acc[i][0] = ffma2(ad, w0.x, acc[i][0]);
                acc[i][1] = ffma2(ad, w0.y, acc[i][1]);
                acc[i][2] = ffma2(ad, w1.x, acc[i][2]);
                acc[i][3] = ffma2(ad, w1.y, acc[i][3]);
            }
        }
    }
}
static __device__ __forceinline__ void mmagb(const float* __restrict__ aRow, int lda,
                                             const float* __restrict__ sWT,
                                             u64 gacc[2], int colg) {
#pragma unroll
    for (int d4 = 0; d4 < 8; ++d4) {
        const float4 a0 = *reinterpret_cast<const float4*>(aRow + (d4 << 2));
        const float4 a1 = *reinterpret_cast<const float4*>(aRow + lda + (d4 << 2));
#pragma unroll
        for (int dd = 0; dd < 4; ++dd) {
            const u64 w = *reinterpret_cast<const u64*>(sWT + ((d4 << 2) + dd) * PW + colg * 2);
            gacc[0] = ffma2(dup2(comp4(a0, dd)), w, gacc[0]);
            gacc[1] = ffma2(dup2(comp4(a1, dd)), w, gacc[1]);
        }
    }
}

#if GB_TC
// ---------- tcgen05 ----------
static __device__ __forceinline__ uint32_t elect_one_pred() {
    uint32_t pred;
    asm volatile(
        "{\n\t.reg .pred p;\n\telect.sync _|p, 0xFFFFFFFF;\n\tselp.b32 %0, 1, 0, p;\n\t}"
        : "=r"(pred));
    return pred;
}
#define TCGEN05_ALLOC(sa, n) \
    asm volatile("tcgen05.alloc.cta_group::1.sync.aligned.shared::cta.b32 [%0], %1;" \
                 :: "r"((uint32_t)(sa)), "r"((uint32_t)(n)) : "memory")
#define TCGEN05_DEALLOC(ta, n) \
    asm volatile("tcgen05.dealloc.cta_group::1.sync.aligned.b32 %0, %1;" :: "r"(ta), "r"((uint32_t)(n)))
#define TCGEN05_COMMIT(mb) \
    asm volatile("tcgen05.commit.cta_group::1.mbarrier::arrive::one.shared::cluster.b64 [%0];" \
                 :: "r"((uint32_t)(mb)) : "memory")
#define TCGEN05_WAIT_LD()  asm volatile("tcgen05.wait::ld.sync.aligned;" ::: "memory")
#define TCGEN05_FENCE_AFTER()  asm volatile("tcgen05.fence::after_thread_sync;" ::: "memory")
#define TCGEN05_FENCE_BEFORE() asm volatile("tcgen05.fence::before_thread_sync;" ::: "memory")
#define MBARRIER_INIT(mb, c) \
    asm volatile("mbarrier.init.shared.b64 [%0], %1;" :: "r"((uint32_t)(mb)), "r"((uint32_t)(c)) : "memory")
#define MBARRIER_WAIT_PARITY(mb, par) do { \
    uint32_t _mb = (uint32_t)(mb), _pa = (uint32_t)(par), _dn; \
    asm volatile("{\n\t.reg .pred p;\n\t" \
        "mbarrier.try_wait.parity.acquire.cta.shared::cta.b64 p, [%1], %2;\n\t" \
        "selp.b32 %0, 1, 0, p;\n\t}" : "=r"(_dn) : "r"(_mb), "r"(_pa) : "memory"); \
    if (!_dn) { \
        asm volatile("{\n\t.reg .pred P1;\n\t" \
            "WL_%=:\n\tmbarrier.try_wait.parity.acquire.cta.shared::cta.b64 P1, [%0], %1, 0x989680;\n\t" \
            "@P1 bra.uni WD_%=;\n\tbra.uni WL_%=;\n\tWD_%=:\n\t}" \
            :: "r"(_mb), "r"(_pa) : "memory"); \
    } \
} while (0)
#define TCGEN05_LD_32X32B_X32(r, ta) \
    asm volatile("tcgen05.ld.sync.aligned.32x32b.x32.b32 " \
        "{%0, %1, %2, %3, %4, %5, %6, %7, %8, %9, %10, %11, %12, %13, %14, %15, " \
        "%16, %17, %18, %19, %20, %21, %22, %23, %24, %25, %26, %27, %28, %29, %30, %31}, [%32];" \
        : "=r"((r)[0]),  "=r"((r)[1]),  "=r"((r)[2]),  "=r"((r)[3]), \
          "=r"((r)[4]),  "=r"((r)[5]),  "=r"((r)[6]),  "=r"((r)[7]), \
          "=r"((r)[8]),  "=r"((r)[9]),  "=r"((r)[10]), "=r"((r)[11]), \
          "=r"((r)[12]), "=r"((r)[13]), "=r"((r)[14]), "=r"((r)[15]), \
          "=r"((r)[16]), "=r"((r)[17]), "=r"((r)[18]), "=r"((r)[19]), \
          "=r"((r)[20]), "=r"((r)[21]), "=r"((r)[22]), "=r"((r)[23]), \
          "=r"((r)[24]), "=r"((r)[25]), "=r"((r)[26]), "=r"((r)[27]), \
          "=r"((r)[28]), "=r"((r)[29]), "=r"((r)[30]), "=r"((r)[31]) \
        : "r"(ta))

static constexpr u64 SMEM_DESC_BASE_SW128 =
    (u64(2) << 61) | (u64(1) << 46) | (u64(64) << 32) | (u64(1) << 16);
#define MAKE_SMEM_DESC(a) (SMEM_DESC_BASE_SW128 | ((u64)((a) >> 4) & 0x3FFF))

static __device__ __forceinline__ void mma_f16_ss(uint32_t d, u64 ad, u64 bd,
                                                  uint32_t idesc, uint32_t en) {
    asm volatile(
        "{\n\t.reg .pred p;\n\tsetp.ne.u32 p, %4, 0;\n\t"
        "tcgen05.mma.cta_group::1.kind::f16 [%0], %1, %2, %3, {%5, %5, %5, %5}, p;\n\t}"
        :: "r"(d), "l"(ad), "l"(bd), "r"(idesc), "r"(en), "r"(0u)
        : "memory");
}
#endif  // GB_TC

#define IDESC_BF16_M128_N128 0x8200490u
#define IDESC_BF16_M128_N256 0x8400490u

// =====================================================================
// Kernel 0: pre-split + pre-swizzle weights (f1,f2,Wk,Wv,Wq,Wo)
// =====================================================================
__global__ __launch_bounds__(256, 4)
void conv_w_kernel(const float* __restrict__ f1w, const float* __restrict__ f2w,
                   const float* __restrict__ Wk, const float* __restrict__ Wv,
                   const float* __restrict__ Wq, const float* __restrict__ Wo)
{
    const unsigned gidx = blockIdx.x * 256 + threadIdx.x;
    if (gidx < 2097152u) {
        const int arr = gidx >> 20;
        const unsigned rem = gidx & 0xFFFFFu;
        const int t = rem >> 14;
        const int e = rem & 16383;
        const int n = e >> 6, k = e & 63;
        const int m = t >> 4, c1 = (t >> 2) & 3, c2 = t & 3;
        float w;
        if (arr == 0)
            w = f1w[(size_t)m * 262144 + (size_t)(c1 * 256 + n) * 256 + c2 * 64 + k];
        else
            w = f2w[(size_t)m * 262144 + (size_t)n * 1024 + c1 * 256 + c2 * 64 + k];
        __nv_bfloat16 h, l;
        bsplit(w, h, l);
        const uint32_t sw = swz128((uint32_t)(n >> 3) * 1024 + (n & 7) * 128 + k * 2);
        __nv_bfloat16* dst = (arr == 0 ? g_w1t : g_w2t) + (size_t)t * 32768;
        dst[sw >> 1]           = h;
        dst[16384 + (sw >> 1)] = l;
    } else if (gidx < 2621440u) {
        const unsigned idx2 = gidx - 2097152u;
        const int arr2 = idx2 >> 18;
        const unsigned rem = idx2 & 0x3FFFFu;
        const int t = rem >> 13;
        const int e = rem & 8191;
        const int n = e >> 6, k = e & 63;
        const int m = t >> 3, nch = (t >> 2) & 1, kch = t & 3;
        const float* W = (arr2 == 0 ? Wk : Wv);
        const float w = W[(size_t)m * 65536 + (size_t)(nch * 128 + n) * 256 + kch * 64 + k];
        __nv_bfloat16 h, l;
        bsplit(w, h, l);
        const uint32_t sw = swz128((uint32_t)(n >> 3) * 1024 + (n & 7) * 128 + k * 2);
        __nv_bfloat16* dst = (arr2 == 0 ? g_wkt : g_wvt) + (size_t)t * 16384;
        dst[sw >> 1]          = h;
        dst[8192 + (sw >> 1)] = l;
    } else {
        const unsigned idx3 = gidx - 2621440u;
        const int arr3 = idx3 >> 18;
        const unsigned rem = idx3 & 0x3FFFFu;
        const int t = rem >> 14;
        const int e = rem & 16383;
        const int n = e >> 6, k = e & 63;
        const int m = t >> 2, kch = t & 3;
        const float* W = (arr3 == 0 ? Wq : Wo);
        float w = W[(size_t)m * 65536 + (size_t)n * 256 + kch * 64 + k];
        if (arr3 == 0) w *= 0.17677669529663687f;
        __nv_bfloat16 h, l;
        bsplit(w, h, l);
        const uint32_t sw = swz128((uint32_t)(n >> 3) * 1024 + (n & 7) * 128 + k * 2);
        __nv_bfloat16* dst = (arr3 == 0 ? g_wqt : g_wot) + (size_t)t * 32768;
        dst[sw >> 1]           = h;
        dst[16384 + (sw >> 1)] = l;
    }
}

// =====================================================================
// Kernel A: K,V projections (tcgen05), grid 1024
// =====================================================================
#define KV_SMEM 197632
#define KV_MB0  16
#define KV_MB1  24
#define KV_AHI  1024
#define KV_ALO  66560
#define KV_B0H  132096
#define KV_B0L  148480
#define KV_B1H  164864
#define KV_B1L  181248

__global__ __launch_bounds__(256, 1)
void gcma_kv(const float* __restrict__ x,
             const float* __restrict__ bk, const float* __restrict__ bv)
{
    extern __shared__ char smA[];
    const int tid = threadIdx.x;
    const int r0  = blockIdx.x * 128;

#if GB_TC
    const uint32_t sbase = smem_to_u32(smA);
    const int wid = tid >> 5, lane = tid & 31;
    char* sAhi = smA + KV_AHI;
    char* sAlo = smA + KV_ALO;

    if (wid == 0) TCGEN05_ALLOC(sbase + 0, 512);
    if (tid == 0) { MBARRIER_INIT(sbase + KV_MB0, 1); MBARRIER_INIT(sbase + KV_MB1, 1); }
    __syncthreads();
    uint32_t tmem;
    asm volatile("ld.shared.b32 %0, [%1];" : "=r"(tmem) : "r"(sbase + 0));

    for (int idx = tid; idx < 8192; idx += 256) {
        const int r = idx >> 6, k = (idx & 63) << 2;
        const float4 v = *reinterpret_cast<const float4*>(x + (size_t)(r0 + r) * 256 + k);
        __nv_bfloat16 h0, h1, h2, h3, l0, l1, l2, l3;
        bsplit(v.x, h0, l0); bsplit(v.y, h1, l1);
        bsplit(v.z, h2, l2); bsplit(v.w, h3, l3);
        const uint32_t sw = swz128((uint32_t)((r >> 3) + (k >> 6) * 16) * 1024 + (r & 7) * 128 + (k & 63) * 2);
        *reinterpret_cast<uint2*>(sAhi + sw) = make_uint2(pk2(h0, h1), pk2(h2, h3));
        *reinterpret_cast<uint2*>(sAlo + sw) = make_uint2(pk2(l0, l1), pk2(l2, l3));
    }

    const u64 aH = MAKE_SMEM_DESC(sbase + KV_AHI), aL = MAKE_SMEM_DESC(sbase + KV_ALO);
    const u64 b0H = MAKE_SMEM_DESC(sbase + KV_B0H), b0L = MAKE_SMEM_DESC(sbase + KV_B0L);
    const u64 b1H = MAKE_SMEM_DESC(sbase + KV_B1H), b1L = MAKE_SMEM_DESC(sbase + KV_B1L);

    int w0 = 0, w1 = 0, pend0 = 0, pend1 = 0;

    for (int job = 0; job < 8; ++job) {
        const int kv = job >> 2, m = job & 3;
        const int half = job & 1;
        const __nv_bfloat16* wbase = kv ? g_wvt : g_wkt;
        for (int c = 0; c < 8; ++c) {
            const int nch = c >> 2, kch = c & 3;
            const int buf = c & 1;
            if (buf == 0) { if (pend0) { MBARRIER_WAIT_PARITY(sbase + KV_MB0, w0 & 1); ++w0; pend0 = 0; } }
            else          { if (pend1) { MBARRIER_WAIT_PARITY(sbase + KV_MB1, w1 & 1); ++w1; pend1 = 0; } }
            {
                const float4* s4 = reinterpret_cast<const float4*>(
                    wbase + (size_t)(((m * 2 + nch) * 4 + kch)) * 16384);
                float4* dh = reinterpret_cast<float4*>(smA + (buf ? KV_B1H : KV_B0H));
                float4* dl = reinterpret_cast<float4*>(smA + (buf ? KV_B1L : KV_B0L));
#pragma unroll
                for (int i = 0; i < 4; ++i) {
                    dh[tid + i * 256] = s4[tid + i * 256];
                    dl[tid + i * 256] = s4[1024 + tid + i * 256];
                }
            }
            __syncthreads();
            if (wid == 0) {
                asm volatile("fence.proxy.async.shared::cta;" ::: "memory");
                TCGEN05_FENCE_AFTER();
                if (elect_one_pred()) {
                    const u64 bH = buf ? b1H : b0H, bL = buf ? b1L : b0L;
                    const uint32_t dcol = tmem + half * 256 + nch * 128;
#pragma unroll
                    for (int j = 0; j < 4; ++j) {
                        const u64 ao = (u64)(kch * 1024 + j * 2), bo = (u64)(j * 2);
                        mma_f16_ss(dcol, aH + ao, bH + bo, IDESC_BF16_M128_N128,
                                   (kch == 0 && j == 0) ? 0u : 1u);
                        mma_f16_ss(dcol, aH + ao, bL + bo, IDESC_BF16_M128_N128, 1u);
                        mma_f16_ss(dcol, aL + ao, bH + bo, IDESC_BF16_M128_N128, 1u);
                    }
                    TCGEN05_COMMIT(sbase + (buf ? KV_MB1 : KV_MB0));
                }
            }
            if (buf == 0) pend0 = 1; else pend1 = 1;
        }
        if (pend0) { MBARRIER_WAIT_PARITY(sbase + KV_MB0, w0 & 1); ++w0; pend0 = 0; }
        if (pend1) { MBARRIER_WAIT_PARITY(sbase + KV_MB1, w1 & 1); ++w1; pend1 = 0; }
        TCGEN05_FENCE_AFTER();
        {
            const float* bias = (kv ? bv : bk) + m * 256;
            float* dst = (kv ? g_v : g_k) + ((size_t)m * 131072 + r0) * 256;
            const int rr = (wid & 3) * 32 + lane;
            const int cb = (wid >> 2) * 128;
            for (int cc = 0; cc < 4; ++cc) {
                uint32_t dr[32];
                TCGEN05_LD_32X32B_X32(dr, tmem + half * 256 + cb + cc * 32);
                TCGEN05_WAIT_LD();
                TCGEN05_FENCE_BEFORE();
                const int c0 = cb + cc * 32;
                float* drow = dst + (size_t)rr * 256 + c0;
#pragma unroll
                for (int q = 0; q < 8; ++q) {
                    *reinterpret_cast<float4*>(drow + q * 4) =
                        make_float4(__uint_as_float(dr[q * 4 + 0]) + bias[c0 + q * 4 + 0],
                                    __uint_as_float(dr[q * 4 + 1]) + bias[c0 + q * 4 + 1],
                                    __uint_as_float(dr[q * 4 + 2]) + bias[c0 + q * 4 + 2],
                                    __uint_as_float(dr[q * 4 + 3]) + bias[c0 + q * 4 + 3]);
                }
            }
        }
        __syncthreads();
    }

    if (tid == 0) {
        asm volatile("mbarrier.inval.shared.b64 [%0];" :: "r"(sbase + KV_MB0) : "memory");
        asm volatile("mbarrier.inval.shared.b64 [%0];" :: "r"(sbase + KV_MB1) : "memory");
    }
    __syncthreads();
    if (wid == 0) TCGEN05_DEALLOC(tmem, 512);

#else
    float* sXf = reinterpret_cast<float*>(smA);
    for (int idx = tid; idx < 8192; idx += 256) {
        const int r = idx >> 6, q = idx & 63;
        *reinterpret_cast<float4*>(sXf + r * 256 + q * 4) =
            *reinterpret_cast<const float4*>(x + (size_t)(r0 + r) * 256 + q * 4);
    }
    __syncthreads();
    for (int job = 0; job < 8; ++job) {
        const int kv = job >> 2, m = job & 3;
        const float* bias = (kv ? bv : bk) + m * 256;
        float* dst = (kv ? g_v : g_k) + ((size_t)m * 131072 + r0) * 256;
        for (int e = tid; e < 128 * 256; e += 256) {
            const int r = e >> 8, n = e & 255;
            const __nv_bfloat16* wt = (kv ? g_wvt : g_wkt);
            float dot = 0.f;
            for (int k = 0; k < 256; ++k) {
                const int nch = n >> 7, nn = n & 127, kch = k >> 6, kk = k & 63;
                const __nv_bfloat16* tb = wt + (size_t)(((m * 2 + nch) * 4 + kch)) * 16384;
                const uint32_t sw = swz128((uint32_t)(nn >> 3) * 1024 + (nn & 7) * 128 + kk * 2);
                const float wv = __bfloat162float(tb[sw >> 1]) + __bfloat162float(tb[8192 + (sw >> 1)]);
                dot = fmaf(sXf[r * 256 + k], wv, dot);
            }
            dst[(size_t)r * 256 + n] = dot + bias[n];
        }
    }
#endif
}

// =====================================================================
// Kernel B/D: Q or Wo projection (tcgen05, N=256), grid (256,4)
// =====================================================================
#define QO_SMEM 197632
#define QO_MB   8
#define QO_AHI  1024
#define QO_ALO  66560
#define QO_BH   132096
#define QO_BL   164864

__global__ __launch_bounds__(256, 1)
void gcma_qo(const float* __restrict__ x,
             const float* __restrict__ bq, const float* __restrict__ bo,
             int which)
{
    extern __shared__ char smQ[];
    const int tid = threadIdx.x;
    const int m   = blockIdx.y;
    const int b0  = blockIdx.x * 128;

    const __nv_bfloat16* wt = which ? g_wot : g_wqt;
    const float* bias = which ? (bo + m * 256) : (bq + m * 256);
    const float bscale = which ? 1.f : 0.17677669529663687f;
    float* dst = (which ? g_ao : g_q) + ((size_t)m * 32768 + b0) * 256;

#if GB_TC
    const uint32_t sbase = smem_to_u32(smQ);
    const int wid = tid >> 5, lane = tid & 31;
    char* sAhi = smQ + QO_AHI;
    char* sAlo = smQ + QO_ALO;

    if (wid == 0) TCGEN05_ALLOC(sbase + 0, 512);
    if (tid == 0) MBARRIER_INIT(sbase + QO_MB, 1);
    __syncthreads();
    uint32_t tmem;
    asm volatile("ld.shared.b32 %0, [%1];" : "=r"(tmem) : "r"(sbase + 0));

    for (int idx = tid; idx < 8192; idx += 256) {
        const int r = idx >> 6, k = (idx & 63) << 2;
        const float* src = which
            ? g_oh + ((size_t)m * 32768 + b0 + r) * 256 + k
            : x + ((size_t)(b0 + r) * 4 + m) * 256 + k;
        const float4 v = *reinterpret_cast<const float4*>(src);
        __nv_bfloat16 h0, h1, h2, h3, l0, l1, l2, l3;
        bsplit(v.x, h0, l0); bsplit(v.y, h1, l1);
        bsplit(v.z, h2, l2); bsplit(v.w, h3, l3);
        const uint32_t sw = swz128((uint32_t)((r >> 3) + (k >> 6) * 16) * 1024 + (r & 7) * 128 + (k & 63) * 2);
        *reinterpret_cast<uint2*>(sAhi + sw) = make_uint2(pk2(h0, h1), pk2(h2, h3));
        *reinterpret_cast<uint2*>(sAlo + sw) = make_uint2(pk2(l0, l1), pk2(l2, l3));
    }

    const u64 aH = MAKE_SMEM_DESC(sbase + QO_AHI), aL = MAKE_SMEM_DESC(sbase + QO_ALO);
    const u64 bH = MAKE_SMEM_DESC(sbase + QO_BH),  bL = MAKE_SMEM_DESC(sbase + QO_BL);

    int ph = 0;
    for (int kch = 0; kch < 4; ++kch) {
        {
            const float4* s4 = reinterpret_cast<const float4*>(wt + (size_t)(m * 4 + kch) * 32768);
            float4* dh = reinterpret_cast<float4*>(smQ + QO_BH);
            float4* dl = reinterpret_cast<float4*>(smQ + QO_BL);
#pragma unroll
            for (int i = 0; i < 8; ++i) {
                dh[tid + i * 256] = s4[tid + i * 256];
                dl[tid + i * 256] = s4[2048 + tid + i * 256];
            }
        }
        __syncthreads();
        if (wid == 0) {
            asm volatile("fence.proxy.async.shared::cta;" ::: "memory");
            TCGEN05_FENCE_AFTER();
            if (elect_one_pred()) {
#pragma unroll
                for (int j = 0; j < 4; ++j) {
                    const u64 ao = (u64)(kch * 1024 + j * 2), bo2 = (u64)(j * 2);
                    mma_f16_ss(tmem, aH + ao, bH + bo2, IDESC_BF16_M128_N256,
                               (kch == 0 && j == 0) ? 0u : 1u);
                    mma_f16_ss(tmem, aH + ao, bL + bo2, IDESC_BF16_M128_N256, 1u);
                    mma_f16_ss(tmem, aL + ao, bH + bo2, IDESC_BF16_M128_N256, 1u);
                }
                TCGEN05_COMMIT(sbase + QO_MB);
            }
        }
        MBARRIER_WAIT_PARITY(sbase + QO_MB, ph & 1);
        ++ph;
        TCGEN05_FENCE_AFTER();
    }

    {
        const int rr = (wid & 3) * 32 + lane;
        const int cb = (wid >> 2) * 128;
        for (int cc = 0; cc < 4; ++cc) {
            uint32_t dr[32];
            TCGEN05_LD_32X32B_X32(dr, tmem + cb + cc * 32);
            TCGEN05_WAIT_LD();
            TCGEN05_FENCE_BEFORE();
            const int c0 = cb + cc * 32;
            float* drow = dst + (size_t)rr * 256 + c0;
#pragma unroll
            for (int q = 0; q < 8; ++q) {
                *reinterpret_cast<float4*>(drow + q * 4) =
                    make_float4(__uint_as_float(dr[q * 4 + 0]) + bias[c0 + q * 4 + 0] * bscale,
                                __uint_as_float(dr[q * 4 + 1]) + bias[c0 + q * 4 + 1] * bscale,
                                __uint_as_float(dr[q * 4 + 2]) + bias[c0 + q * 4 + 2] * bscale,
                                __uint_as_float(dr[q * 4 + 3]) + bias[c0 + q * 4 + 3] * bscale);
            }
        }
    }

    __syncthreads();
    if (tid == 0)
        asm volatile("mbarrier.inval.shared.b64 [%0];" :: "r"(sbase + QO_MB) : "memory");
    __syncthreads();
    if (wid == 0) TCGEN05_DEALLOC(tmem, 512);

#else
    for (int e = tid; e < 128 * 256; e += 256) {
        const int r = e >> 8, n = e & 255;
        float dot = 0.f;
        for (int k = 0; k < 256; ++k) {
            const int kch = k >> 6, kk = k & 63;
            const __nv_bfloat16* tb = wt + (size_t)(m * 4 + kch) * 32768;
            const uint32_t sw = swz128((uint32_t)(n >> 3) * 1024 + (n & 7) * 128 + kk * 2);
            const float wv = __bfloat162float(tb[sw >> 1]) + __bfloat162float(tb[16384 + (sw >> 1)]);
            const float a = which
                ? g_oh[((size_t)m * 32768 + b0 + r) * 256 + k]
                : x[((size_t)(b0 + r) * 4 + m) * 256 + k];
            dot = fmaf(a, wv, dot);
        }
        dst[(size_t)r * 256 + n] = dot + bias[n] * bscale;
    }
#endif
}

// =====================================================================
// Kernel C: attention — warp-per-(b,m), pure registers, streaming
// grid 16384 x 256 (8 warps/block, warp w -> b = w>>2, m = w&3)
// =====================================================================
__global__ __launch_bounds__(256)
void gcma_attn()
{
    const int gw   = blockIdx.x * 8 + (threadIdx.x >> 5);   // 0..131071
    const int lane = threadIdx.x & 31;
    const int b    = gw >> 2, m = gw & 3;

    const size_t qoff  = ((size_t)m * 32768 + b) * 256 + lane * 8;
    const size_t kvoff = ((size_t)m * 131072 + (size_t)b * 4) * 256 + lane * 8;

    // load q (8 floats)
    const float4 q0 = *reinterpret_cast<const float4*>(g_q + qoff);
    const float4 q1 = *reinterpret_cast<const float4*>(g_q + qoff + 4);
    // load K rows (4 x 8 floats) — independent, batched for MLP
    float4 k0[4], k1[4];
#pragma unroll
    for (int n = 0; n < 4; ++n) {
        k0[n] = *reinterpret_cast<const float4*>(g_k + kvoff + (size_t)n * 256);
        k1[n] = *reinterpret_cast<const float4*>(g_k + kvoff + (size_t)n * 256 + 4);
    }
    // load V rows early (independent of softmax)
    float4 v0[4], v1[4];
#pragma unroll
    for (int n = 0; n < 4; ++n) {
        v0[n] = *reinterpret_cast<const float4*>(g_v + kvoff + (size_t)n * 256);
        v1[n] = *reinterpret_cast<const float4*>(g_v + kvoff + (size_t)n * 256 + 4);
    }

    // scores: dot over this lane's 8 dims, then quad-reduce (head = lane>>2)
    float s[4];
#pragma unroll
    for (int n = 0; n < 4; ++n) {
        float d = q0.x * k0[n].x + q0.y * k0[n].y + q0.z * k0[n].z + q0.w * k0[n].w
                + q1.x * k1[n].x + q1.y * k1[n].y + q1.z * k1[n].z + q1.w * k1[n].w;
        d += __shfl_xor_sync(0xffffffffu, d, 1);
        d += __shfl_xor_sync(0xffffffffu, d, 2);
        s[n] = d;
    }
    const float mx = fmaxf(fmaxf(s[0], s[1]), fmaxf(s[2], s[3]));
    float e[4], se = 0.f;
#pragma unroll
    for (int n = 0; n < 4; ++n) { e[n] = expf(s[n] - mx); se += e[n]; }
    const float inv = 1.f / se;

    // Oh = sum p_n * v_n (this lane's 8 dims)
    float4 o0 = make_float4(0.f, 0.f, 0.f, 0.f);
    float4 o1 = make_float4(0.f, 0.f, 0.f, 0.f);
#pragma unroll
    for (int n = 0; n < 4; ++n) {
        const float p = e[n] * inv;
        o0.x = fmaf(p, v0[n].x, o0.x); o0.y = fmaf(p, v0[n].y, o0.y);
        o0.z = fmaf(p, v0[n].z, o0.z); o0.w = fmaf(p, v0[n].w, o0.w);
        o1.x = fmaf(p, v1[n].x, o1.x); o1.y = fmaf(p, v1[n].y, o1.y);
        o1.z = fmaf(p, v1[n].z, o1.z); o1.w = fmaf(p, v1[n].w, o1.w);
    }
    float* op = g_oh + qoff;
    *reinterpret_cast<float4*>(op)     = o0;
    *reinterpret_cast<float4*>(op + 4) = o1;
}

// =====================================================================
// Kernel E: gate MLP + LayerNorm, grid (2048,4)
// =====================================================================
#define TL_XM   0
#define TL_AO   4096
#define TL_WT   8192
#define TL_GH   16512
#define TL_GATE 17536
#define TL_FLOATS 17552
#define TL_BYTES  (TL_FLOATS * 4)

__global__ __launch_bounds__(256, 1)
void gcma_tail(const float* __restrict__ x,
               const float* __restrict__ g1w, const float* __restrict__ g1b,
               const float* __restrict__ g2w, const float* __restrict__ g2b,
               const float* __restrict__ lng, const float* __restrict__ lnb,
               float* __restrict__ out)
{
    extern __shared__ float smL[];
    float* sXm   = smL + TL_XM;
    float* sAO   = smL + TL_AO;
    float* sWT   = smL + TL_WT;
    float* sGH   = smL + TL_GH;
    float* sGate = smL + TL_GATE;

    const int tid = threadIdx.x;
    const int m   = blockIdx.y;
    const int b0  = blockIdx.x * 16;
    const long g0 = (long)b0 * 4;

    const int warp = tid >> 5;
    const int colg = tid & 31;

    for (int idx = tid; idx < 1024; idx += 256) {
        const int r = idx >> 6, q = idx & 63;
        *reinterpret_cast<float4*>(sXm + r * 256 + q * 4) =
            *reinterpret_cast<const float4*>(x + ((size_t)(b0 + r) * 4 + m) * 256 + q * 4);
        *reinterpret_cast<float4*>(sAO + r * 256 + q * 4) =
            *reinterpret_cast<const float4*>(g_ao + ((size_t)m * 32768 + b0 + r) * 256 + q * 4);
    }

    {
        const float* W = g1w + (size_t)m * 32768;
        Wreg<2> wr;
        ldgW<2>(W, 512, 0, wr, tid);
        u64 gacc[2] = {0ULL, 0ULL};
        for (int dt = 0; dt < 16; ++dt) {
            __syncthreads();
            stsW<2>(sWT, wr, tid);
            if (dt < 15) ldgW<2>(W, 512, (dt + 1) * 32, wr, tid);
            __syncthreads();
            if (dt < 8)
                mmagb(sXm + warp * 2 * 256 + dt * 32, 256, sWT, gacc, colg);
            else
                mmagb(sAO + warp * 2 * 256 + (dt - 8) * 32, 256, sWT, gacc, colg);
        }
        const float gb0 = g1b[m * 64 + colg * 2];
        const float gb1 = g1b[m * 64 + colg * 2 + 1];
#pragma unroll
        for (int i = 0; i < 2; ++i) {
            const float2 p = unpk(gacc[i]);
            sGH[(warp * 2 + i) * 64 + colg * 2]     = tanhf(p.x + gb0);
            sGH[(warp * 2 + i) * 64 + colg * 2 + 1] = tanhf(p.y + gb1);
        }
    }
    __syncthreads();

    if (tid < 16) {
        const float* g2 = g2w + m * 64;
        float dot = g2b[m];
#pragma unroll 8
        for (int j = 0; j < 64; ++j) dot = fmaf(sGH[tid * 64 + j], g2[j], dot);
        const float gate = 1.f / (1.f + expf(-dot));
        sGate[tid] = gate;
        out[OUT_GATE_BASE + (size_t)(b0 + tid) * 4 + m] = gate;
    }
    __syncthreads();

    {
        const int lane = tid & 31;
        for (int bl = warp; bl < 16; bl += 8) {
            const float* xr  = sXm + bl * 256;
            const float* aor = sAO + bl * 256;
            const float gate = sGate[bl];
            float r[8];
            float sum = 0.f;
#pragma unroll
            for (int k = 0; k < 8; ++k) {
                const int d = k * 32 + lane;
                r[k] = xr[d] + gate * aor[d];
                sum += r[k];
            }
#pragma unroll
            for (int o = 16; o; o >>= 1) sum += __shfl_xor_sync(0xffffffffu, sum, o);
            const float mu = sum * (1.f / 256.f);
            float var = 0.f;
#pragma unroll
            for (int k = 0; k < 8; ++k) { const float t = r[k] - mu; var = fmaf(t, t, var); }
#pragma unroll
            for (int o = 16; o; o >>= 1) var += __shfl_xor_sync(0xffffffffu, var, o);
            const float rs = rsqrtf(var * (1.f / 256.f) + 1e-5f);
            float* yr = g_y + (size_t)(g0 + bl * 4 + m) * 256;
#pragma unroll
            for (int k = 0; k < 8; ++k) {
                const int d = k * 32 + lane;
                yr[d] = (r[k] - mu) * rs * lng[m * 256 + d] + lnb[m * 256 + d];
            }
        }
    }
}

// =====================================================================
// Kernel F: FF (tcgen05)
// =====================================================================
#define P2_SMEM 197632
#define P2_TM    0
#define P2_MB    8
#define P2_AHI   1024
#define P2_ALO   66560
#define P2_BHI   132096
#define P2_BLO   164864

static __device__ __forceinline__ void loadB(const __nv_bfloat16* base, int m, int c1, int c2,
                                             float4 pf[16], int tid) {
    const float4* src = reinterpret_cast<const float4*>(base + (size_t)((m * 4 + c1) * 4 + c2) * 32768);
#pragma unroll
    for (int i = 0; i < 8; ++i) {
        pf[i]     = src[tid + i * 256];
        pf[8 + i] = src[2048 + tid + i * 256];
    }
}
static __device__ __forceinline__ void stsB(char* sBhi, char* sBlo, const float4 pf[16], int tid) {
#pragma unroll
    for (int i = 0; i < 8; ++i) {
        reinterpret_cast<float4*>(sBhi)[tid + i * 256] = pf[i];
        reinterpret_cast<float4*>(sBlo)[tid + i * 256] = pf[8 + i];
    }
}

__global__ __launch_bounds__(256, 1)
void gcma_part2tc(const float* __restrict__ f1w, const float* __restrict__ f1b,
                  const float* __restrict__ f2w, const float* __restrict__ f2b,
                  float* __restrict__ out)
{
    extern __shared__ char sm2[];
    const int tid  = threadIdx.x;
    const int m    = blockIdx.y;
    const int b0   = blockIdx.x * 128;

#if GB_TC
    const uint32_t sbase = smem_to_u32(sm2);
    const uint32_t TMP  = sbase + P2_TM;
    const uint32_t MBAR = sbase + P2_MB;
    char* sAhi = sm2 + P2_AHI;
    char* sAlo = sm2 + P2_ALO;
    char* sBhi = sm2 + P2_BHI;
    char* sBlo = sm2 + P2_BLO;
    const uint32_t aHiA = sbase + P2_AHI, aLoA = sbase + P2_ALO;
    const uint32_t bHiA = sbase + P2_BHI, bLoA = sbase + P2_BLO;

    const int wid  = tid >> 5, lane = tid & 31;
    unsigned* hfbase = g_hfscr + (size_t)(blockIdx.y * 256 + blockIdx.x) * 131072u;

    if (wid == 0) TCGEN05_ALLOC(TMP, 512);
    if (tid == 0) MBARRIER_INIT(MBAR, 1);
    __syncthreads();
    uint32_t tmem;
    asm volatile("ld.shared.b32 %0, [%1];" : "=r"(tmem) : "r"(TMP));

    for (int idx = tid; idx < 8192; idx += 256) {
        const int r = idx >> 6, k = (idx & 63) << 2;
        const float4 v = *reinterpret_cast<const float4*>(
            g_y + ((size_t)(b0 + r) * 4 + m) * 256 + k);
        __nv_bfloat16 h0, h1, h2, h3, l0, l1, l2, l3;
        bsplit(v.x, h0, l0); bsplit(v.y, h1, l1);
        bsplit(v.z, h2, l2); bsplit(v.w, h3, l3);
        const uint32_t sw = swz128((uint32_t)((r >> 3) + (k >> 6) * 16) * 1024 + (r & 7) * 128 + (k & 63) * 2);
        *reinterpret_cast<uint2*>(sAhi + sw) = make_uint2(pk2(h0, h1), pk2(h2, h3));
        *reinterpret_cast<uint2*>(sAlo + sw) = make_uint2(pk2(l0, l1), pk2(l2, l3));
    }

    float4 pf[16];
    loadB(g_w1t, m, 0, 0, pf, tid);
    int ph = 0;
    const u64 aH = MAKE_SMEM_DESC(aHiA), aL = MAKE_SMEM_DESC(aLoA);
    const u64 bH = MAKE_SMEM_DESC(bHiA), bL = MAKE_SMEM_DESC(bLoA);

    for (int nch = 0; nch < 4; ++nch) {
        for (int kch = 0; kch < 4; ++kch) {
            stsB(sBhi, sBlo, pf, tid);
            __syncthreads();
            if (wid == 0) {
                asm volatile("fence.proxy.async.shared::cta;" ::: "memory");
                TCGEN05_FENCE_AFTER();
                if (elect_one_pred()) {
#pragma unroll
                    for (int j = 0; j < 4; ++j) {
                        const u64 ao = (u64)(kch * 1024 + j * 2), bo = (u64)(j * 2);
                        mma_f16_ss(tmem, aH + ao, bH + bo, IDESC_BF16_M128_N256,
                                   (kch == 0 && j == 0) ? 0u : 1u);
                        mma_f16_ss(tmem, aH + ao, bL + bo, IDESC_BF16_M128_N256, 1u);
                        mma_f16_ss(tmem, aL + ao, bH + bo, IDESC_BF16_M128_N256, 1u);
                    }
                    TCGEN05_COMMIT(MBAR);
                }
            }
            const int nb = nch * 4 + kch + 1;
            if (nb < 16) loadB(g_w1t, m, nb >> 2, nb & 3, pf, tid);
            else         loadB(g_w2t, m, 0, 0, pf, tid);
            MBARRIER_WAIT_PARITY(MBAR, ph & 1);
            ++ph;
            TCGEN05_FENCE_AFTER();
        }
        {
            const int r  = (wid & 3) * 32 + lane;
            const int cb = (wid >> 2) * 128;
            for (int cc = 0; cc < 4; ++cc) {
                uint32_t dr[32];
                TCGEN05_LD_32X32B_X32(dr, tmem + cb + cc * 32);
                TCGEN05_WAIT_LD();
                TCGEN05_FENCE_BEFORE();
                const int c0 = nch * 256 + cb + cc * 32;
                unsigned* dst = hfbase + (size_t)r * 1024 + c0;
#pragma unroll
                for (int j = 0; j < 32; ++j) {
                    float v = __uint_as_float(dr[j]) + f1b[m * 1024 + c0 + j];
                    v = 0.5f * v * (1.f + erff(v * 0.7071067811865476f));
                    __nv_bfloat16 h, l;
                    bsplit(v, h, l);
                    dst[j] = pk2(h, l);
                }
            }
        }
        __syncthreads();
    }

    for (int ch = 0; ch < 4; ++ch) {
        for (int idx = tid; idx < 8192; idx += 256) {
            const int r = idx >> 6, k = (idx & 63) << 2;
            const uint4 u = *reinterpret_cast<const uint4*>(
                hfbase + (size_t)r * 1024 + ch * 256 + k);
            const unsigned uu[4] = {u.x, u.y, u.z, u.w};
            __nv_bfloat16 h[4], l[4];
#pragma unroll
            for (int j = 0; j < 4; ++j) {
                h[j] = __ushort_as_bfloat16((unsigned short)(uu[j] & 0xFFFFu));
                l[j] = __ushort_as_bfloat16((unsigned short)(uu[j] >> 16));
            }
            const uint32_t sw = swz128((uint32_t)((r >> 3) + (k >> 6) * 16) * 1024 + (r & 7) * 128 + (k & 63) * 2);
            *reinterpret_cast<uint2*>(sAhi + sw) = make_uint2(pk2(h[0], h[1]), pk2(h[2], h[3]));
            *reinterpret_cast<uint2*>(sAlo + sw) = make_uint2(pk2(l[0], l[1]), pk2(l[2], l[3]));
        }
        for (int kc = 0; kc < 4; ++kc) {
            stsB(sBhi, sBlo, pf, tid);
            __syncthreads();
            if (wid == 0) {
                asm volatile("fence.proxy.async.shared::cta;" ::: "memory");
                TCGEN05_FENCE_AFTER();
                if (elect_one_pred()) {
#pragma unroll
                    for (int j = 0; j < 4; ++j) {
                        const u64 ao = (u64)(kc * 1024 + j * 2), bo = (u64)(j * 2);
                        mma_f16_ss(tmem + 256, aH + ao, bH + bo, IDESC_BF16_M128_N256,
                                   (ch == 0 && kc == 0 && j == 0) ? 0u : 1u);
                        mma_f16_ss(tmem + 256, aH + ao, bL + bo, IDESC_BF16_M128_N256, 1u);
                        mma_f16_ss(tmem + 256, aL + ao, bH + bo, IDESC_BF16_M128_N256, 1u);
                    }
                    TCGEN05_COMMIT(MBAR);
                }
            }
            const int nb = ch * 4 + kc + 1;
            if (nb < 16) loadB(g_w2t, m, nb >> 2, nb & 3, pf, tid);
            MBARRIER_WAIT_PARITY(MBAR, ph & 1);
            ++ph;
            TCGEN05_FENCE_AFTER();
        }
    }

    {
        const int r  = (wid & 3) * 32 + lane;
        const int cb = (wid >> 2) * 128;
        for (int cc = 0; cc < 4; ++cc) {
            uint32_t dr[32];
            TCGEN05_LD_32X32B_X32(dr, tmem + 256 + cb + cc * 32);
            TCGEN05_WAIT_LD();
            TCGEN05_FENCE_BEFORE();
            const int c0 = cb + cc * 32;
            const float* yrow = g_y + ((size_t)(b0 + r) * 4 + m) * 256 + c0;
            float* orow = out + ((size_t)(b0 + r) * 4 + m) * 256 + c0;
#pragma unroll
            for (int j = 0; j < 32; ++j)
                orow[j] = yrow[j] + __uint_as_float(dr[j]) + f2b[m * 256 + c0 + j];
        }
    }

    __syncthreads();
    if (tid == 0)
        asm volatile("mbarrier.inval.shared.b64 [%0];" :: "r"(MBAR) : "memory");
    __syncthreads();
    if (wid == 0) TCGEN05_DEALLOC(tmem, 512);

#else
    float* smf = reinterpret_cast<float*>(sm2);
    float* sY  = smf;
    float* sHF = smf + 16384;
    float* sWT = smf + 32768;
    const int warp = tid >> 5;
    const int colg = tid & 31;

    for (int half = 0; half < 2; ++half) {
        const int hb0 = b0 + half * 64;
        __syncthreads();
        for (int idx = tid; idx < 4096; idx += TPB) {
            const int r = idx >> 6, q = idx & 63;
            *reinterpret_cast<float4*>(sY + r * 256 + q * 4) =
                *reinterpret_cast<const float4*>(g_y + ((size_t)(hb0 + r) * 4 + m) * 256 + q * 4);
        }
        u64 facc[8][4];
#pragma unroll
        for (int i = 0; i < 8; ++i)
#pragma unroll
            for (int j = 0; j < 4; ++j) facc[i][j] = 0ULL;
        const float* aY  = sY  + warp * 8 * 256;
        const float* aHF = sHF + warp * 8 * 256;

        for (int ch = 0; ch < 4; ++ch) {
            u64 hacc[8][4];
#pragma unroll
            for (int i = 0; i < 8; ++i)
#pragma unroll
                for (int j = 0; j < 4; ++j) hacc[i][j] = 0ULL;
            {
                const float* W1 = f1w + (size_t)m * 262144 + (size_t)ch * 65536;
                Wreg<8> wr;
                ldgW<8>(W1, 256, 0, wr, tid);
                for (int dt = 0; dt < 8; ++dt) {
                    __syncthreads();
                    stsW<8>(sWT, wr, tid);
                    if (dt < 7) ldgW<8>(W1, 256, (dt + 1) * 32, wr, tid);
                    __syncthreads();
                    mma64b(aY + dt * 32, 256, sWT, hacc, colg);
                }
            }
            __syncthreads();
            {
                const float* b1 = f1b + m * 1024 + ch * 256;
                float bl0[4], bl1[4];
#pragma unroll
                for (int j = 0; j < 4; ++j) { bl0[j] = b1[colg * 4 + j]; bl1[j] = b1[128 + colg * 4 + j]; }
#pragma unroll
                for (int i = 0; i < 8; ++i) {
                    const int r = warp * 8 + i;
                    const float2 pa = unpk(hacc[i][0]), pb = unpk(hacc[i][1]);
                    const float2 pc = unpk(hacc[i][2]), pd = unpk(hacc[i][3]);
                    float v0[4] = {pa.x + bl0[0], pa.y + bl0[1], pb.x + bl0[2], pb.y + bl0[3]};
                    float v1[4] = {pc.x + bl1[0], pc.y + bl1[1], pd.x + bl1[2], pd.y + bl1[3]};
#pragma unroll
                    for (int j = 0; j < 4; ++j) {
                        v0[j] = 0.5f * v0[j] * (1.f + erff(v0[j] * 0.7071067811865476f));
                        v1[j] = 0.5f * v1[j] * (1.f + erff(v1[j] * 0.7071067811865476f));
                    }
                    *reinterpret_cast<float4*>(sHF + r * 256 + colg * 4) =
                        make_float4(v0[0], v0[1], v0[2], v0[3]);
                    *reinterpret_cast<float4*>(sHF + r * 256 + 128 + colg * 4) =
                        make_float4(v1[0], v1[1], v1[2], v1[3]);
                }
            }
            {
                const float* W2 = f2w + (size_t)m * 262144;
                Wreg<8> wr;
                ldgW<8>(W2, 1024, ch * 256, wr, tid);
                for (int dt = 0; dt < 8; ++dt) {
                    __syncthreads();
                    stsW<8>(sWT, wr, tid);
                    if (dt < 7) ldgW<8>(W2, 1024, ch * 256 + (dt + 1) * 32, wr, tid);
                    __syncthreads();
                    mma64b(aHF + dt * 32, 256, sWT, facc, colg);
                }
            }
            __syncthreads();
        }
        {
            const float* b2 = f2b + m * 256;
            float bl0[4], bl1[4];
#pragma unroll
            for (int j = 0; j < 4; ++j) { bl0[j] = b2[colg * 4 + j]; bl1[j] = b2[128 + colg * 4 + j]; }
#pragma unroll
            for (int i = 0; i < 8; ++i) {
                const int r = warp * 8 + i;
                const float4 y0 = *reinterpret_cast<const float4*>(sY + r * 256 + colg * 4);
                const float4 y1 = *reinterpret_cast<const float4*>(sY + r * 256 + 128 + colg * 4);
                const float2 pa = unpk(facc[i][0]), pb = unpk(facc[i][1]);
                const float2 pc = unpk(facc[i][2]), pd = unpk(facc[i][3]);
                float* op = out + ((size_t)(hb0 + r) * 4 + m) * 256;
                *reinterpret_cast<float4*>(op + colg * 4) =
                    make_float4(y0.x + pa.x + bl0[0], y0.y + pa.y + bl0[1],
                                y0.z + pb.x + bl0[2], y0.w + pb.y + bl0[3]);
                *reinterpret_cast<float4*>(op + 128 + colg * 4) =
                    make_float4(y1.x + pc.x + bl1[0], y1.y + pc.y + bl1[1],
                                y1.z + pd.x + bl1[2], y1.w + pd.y + bl1[3]);
            }
        }
    }
#endif
}

extern "C" void kernel_launch(void* const* d_in, const int* in_sizes, int n_in,
                              void* d_out, int out_size) {
    const float* x   = (const float*)d_in[0];
    const float* Wq  = (const float*)d_in[1];
    const float* bq  = (const float*)d_in[2];
    const float* Wk  = (const float*)d_in[3];
    const float* bk  = (const float*)d_in[4];
    const float* Wv  = (const float*)d_in[5];
    const float* bv  = (const float*)d_in[6];
    const float* Wo  = (const float*)d_in[7];
    const float* bo  = (const float*)d_in[8];
    const float* g1w = (const float*)d_in[9];
    const float* g1b = (const float*)d_in[10];
    const float* g2w = (const float*)d_in[11];
    const float* g2b = (const float*)d_in[12];
    const float* lng = (const float*)d_in[13];
    const float* lnb = (const float*)d_in[14];
    const float* f1w = (const float*)d_in[15];
    const float* f1b = (const float*)d_in[16];
    const float* f2w = (const float*)d_in[17];
    const float* f2b = (const float*)d_in[18];
    float* out = (float*)d_out;

    cudaFuncSetAttribute(gcma_kv, cudaFuncAttributeMaxDynamicSharedMemorySize, KV_SMEM);
    cudaFuncSetAttribute(gcma_qo, cudaFuncAttributeMaxDynamicSharedMemorySize, QO_SMEM);
    cudaFuncSetAttribute(gcma_tail, cudaFuncAttributeMaxDynamicSharedMemorySize, TL_BYTES);
    cudaFuncSetAttribute(gcma_part2tc, cudaFuncAttributeMaxDynamicSharedMemorySize, P2_SMEM);

    conv_w_kernel<<<12288, 256>>>(f1w, f2w, Wk, Wv, Wq, Wo);
    gcma_kv<<<1024, 256, KV_SMEM>>>(x, bk, bv);
    gcma_qo<<<dim3(256, 4), 256, QO_SMEM>>>(x, bq, bo, 0);
    gcma_attn<<<16384, 256>>>();
    gcma_qo<<<dim3(256, 4), 256, QO_SMEM>>>(x, bq, bo, 1);
    gcma_tail<<<dim3(2048, 4), 256, TL_BYTES>>>(x, g1w, g1b, g2w, g2b, lng, lnb, out);
    gcma_part2tc<<<dim3(256, 4), 256, P2_SMEM>>>(f1w, f1b, f2w, f2b, out);
}

// round 13
// speedup vs baseline: 2.9220x; 1.1264x over previous
#include <cuda_runtime.h>
#include <cuda_bf16.h>
#include <math.h>
#include <stdint.h>

typedef unsigned long long u64;

#define TPB 256
#define PW 260

#define OUT_GATE_BASE 33554432UL   // B*M*D

#if defined(__CUDA_ARCH_FEAT_SM103_ALL) || \
    (defined(__CUDA_ARCH_SPECIFIC__) && (__CUDA_ARCH_SPECIFIC__ == 1030)) || \
    (defined(__CUDA_ARCH_FAMILY_SPECIFIC__) && (__CUDA_ARCH_FAMILY_SPECIFIC__ == 1030))
#define GB_TC 1
#else
#define GB_TC 0
#endif

// scratch
__device__ float g_y [32768u * 4u * 256u];                // 128MB
__device__ float g_q [4u * 32768u * 256u];                // 128MB  Q[m][b][256] (scaled, +bias)
__device__ float g_oh[4u * 32768u * 256u];                // 128MB  Oh[m][b][256]
__device__ float g_ao[4u * 32768u * 256u];                // 128MB  attn_out[m][b][256]
__device__ __nv_bfloat16 g_w1t[64u * 32768u];             // FF1 tiles (hi|lo)
__device__ __nv_bfloat16 g_w2t[64u * 32768u];             // FF2 tiles
__device__ __nv_bfloat16 g_wkt[32u * 16384u];             // Wk tiles 128n x 64k (hi|lo)
__device__ __nv_bfloat16 g_wvt[32u * 16384u];             // Wv tiles
__device__ __nv_bfloat16 g_wqt[16u * 32768u];             // Wq tiles 256n x 64k (scaled)
__device__ __nv_bfloat16 g_wot[16u * 32768u];             // Wo tiles 256n x 64k
__device__ unsigned g_hfscr[1024u * 131072u];             // hf scratch

// ---------- helpers ----------
static __device__ __forceinline__ u64 ffma2(u64 a, u64 b, u64 c) {
    u64 d;
    asm("fma.rn.f32x2 %0, %1, %2, %3;" : "=l"(d) : "l"(a), "l"(b), "l"(c));
    return d;
}
static __device__ __forceinline__ u64 dup2(float a) {
    u64 d;
    asm("mov.b64 %0, {%1, %1};" : "=l"(d) : "f"(a));
    return d;
}
static __device__ __forceinline__ float2 unpk(u64 p) {
    float2 r;
    asm("mov.b64 {%0, %1}, %2;" : "=f"(r.x), "=f"(r.y) : "l"(p));
    return r;
}
static __device__ __forceinline__ float comp4(const float4& v, int dd) {
    return dd == 0 ? v.x : dd == 1 ? v.y : dd == 2 ? v.z : v.w;
}
static __device__ __forceinline__ unsigned pk2(__nv_bfloat16 a, __nv_bfloat16 b) {
    return (unsigned)__bfloat16_as_ushort(a) | ((unsigned)__bfloat16_as_ushort(b) << 16);
}
static __device__ __forceinline__ void bsplit(float v, __nv_bfloat16& h, __nv_bfloat16& l) {
    h = __float2bfloat16(v);
    l = __float2bfloat16(v - __bfloat162float(h));
}
static __device__ __forceinline__ uint32_t swz128(uint32_t b) { return b ^ ((b >> 3) & 0x70); }
static __device__ __forceinline__ uint32_t smem_to_u32(const void* p) {
    uint32_t a;
    asm("{ .reg .u64 t; cvta.to.shared.u64 t, %1; cvt.u32.u64 %0, t; }" : "=r"(a) : "l"(p));
    return a;
}

// ---------- fp32 W staging (tail + fallbacks) ----------
template<int NIT>
struct Wreg { float f[NIT][4]; };

template<int NIT>
static __device__ __forceinline__ void ldgW(const float* __restrict__ W, int ldw, int k0,
                                            Wreg<NIT>& r, int tid) {
#pragma unroll
    for (int k = 0; k < NIT; ++k) {
        const int idx = tid + k * TPB;
        const int d = idx & 31, c4 = idx >> 5;
#pragma unroll
        for (int i = 0; i < 4; ++i)
            r.f[k][i] = W[(size_t)(c4 * 4 + i) * ldw + k0 + d];
    }
}
template<int NIT>
static __device__ __forceinline__ void stsW(float* sWT, const Wreg<NIT>& r, int tid) {
#pragma unroll
    for (int k = 0; k < NIT; ++k) {
        const int idx = tid + k * TPB;
        const int d = idx & 31, c4 = idx >> 5;
        *reinterpret_cast<float4*>(sWT + d * PW + c4 * 4) =
            make_float4(r.f[k][0], r.f[k][1], r.f[k][2], r.f[k][3]);
    }
}
static __device__ __forceinline__ void mma64b(const float* __restrict__ aRow, int lda,
                                              const float* __restrict__ sWT,
                                              u64 acc[8][4], int colg) {
#pragma unroll
    for (int d4 = 0; d4 < 8; ++d4) {
        float4 a4[8];
#pragma unroll
        for (int i = 0; i < 8; ++i)
            a4[i] = *reinterpret_cast<const float4*>(aRow + i * lda + (d4 << 2));
#pragma unroll
        for (int dd = 0; dd < 4; ++dd) {
            const int d = (d4 << 2) + dd;
            const ulonglong2 w0 = *reinterpret_cast<const ulonglong2*>(sWT + d * PW + (colg << 2));
            const ulonglong2 w1 = *reinterpret_cast<const ulonglong2*>(sWT + d * PW + 128 + (colg << 2));
#pragma unroll
            for (int i = 0; i < 8; ++i) {
                const u64 ad = dup2(comp4(a4[i], dd));
                acc[i][0] = ffma2(ad, w0.x, acc[i][0]);
                acc[i][1] = ffma2(ad, w0.y, acc[i][1]);
                acc[i][2] = ffma2(ad, w1.x, acc[i][2]);
                acc[i][3] = ffma2(ad, w1.y, acc[i][3]);
            }
        }
    }
}
static __device__ __forceinline__ void mmagb(const float* __restrict__ aRow, int lda,
                                             const float* __restrict__ sWT,
                                             u64 gacc[2], int colg) {
#pragma unroll
    for (int d4 = 0; d4 < 8; ++d4) {
        const float4 a0 = *reinterpret_cast<const float4*>(aRow + (d4 << 2));
        const float4 a1 = *reinterpret_cast<const float4*>(aRow + lda + (d4 << 2));
#pragma unroll
        for (int dd = 0; dd < 4; ++dd) {
            const u64 w = *reinterpret_cast<const u64*>(sWT + ((d4 << 2) + dd) * PW + colg * 2);
            gacc[0] = ffma2(dup2(comp4(a0, dd)), w, gacc[0]);
            gacc[1] = ffma2(dup2(comp4(a1, dd)), w, gacc[1]);
        }
    }
}

// reconstruct a weight element from 128n x 64k split tiles (fallback only)
static __device__ __forceinline__ float wrec128(const __nv_bfloat16* wt, int m, int n, int k) {
    const int nch = n >> 7, nn = n & 127, kch = k >> 6, kk = k & 63;
    const __nv_bfloat16* tb = wt + (size_t)(((m * 2 + nch) * 4 + kch)) * 16384;
    const uint32_t sw = swz128((uint32_t)(nn >> 3) * 1024 + (nn & 7) * 128 + kk * 2);
    return __bfloat162float(tb[sw >> 1]) + __bfloat162float(tb[8192 + (sw >> 1)]);
}

#if GB_TC
// ---------- tcgen05 ----------
static __device__ __forceinline__ uint32_t elect_one_pred() {
    uint32_t pred;
    asm volatile(
        "{\n\t.reg .pred p;\n\telect.sync _|p, 0xFFFFFFFF;\n\tselp.b32 %0, 1, 0, p;\n\t}"
        : "=r"(pred));
    return pred;
}
#define TCGEN05_ALLOC(sa, n) \
    asm volatile("tcgen05.alloc.cta_group::1.sync.aligned.shared::cta.b32 [%0], %1;" \
                 :: "r"((uint32_t)(sa)), "r"((uint32_t)(n)) : "memory")
#define TCGEN05_DEALLOC(ta, n) \
    asm volatile("tcgen05.dealloc.cta_group::1.sync.aligned.b32 %0, %1;" :: "r"(ta), "r"((uint32_t)(n)))
#define TCGEN05_COMMIT(mb) \
    asm volatile("tcgen05.commit.cta_group::1.mbarrier::arrive::one.shared::cluster.b64 [%0];" \
                 :: "r"((uint32_t)(mb)) : "memory")
#define TCGEN05_WAIT_LD()  asm volatile("tcgen05.wait::ld.sync.aligned;" ::: "memory")
#define TCGEN05_FENCE_AFTER()  asm volatile("tcgen05.fence::after_thread_sync;" ::: "memory")
#define TCGEN05_FENCE_BEFORE() asm volatile("tcgen05.fence::before_thread_sync;" ::: "memory")
#define MBARRIER_INIT(mb, c) \
    asm volatile("mbarrier.init.shared.b64 [%0], %1;" :: "r"((uint32_t)(mb)), "r"((uint32_t)(c)) : "memory")
#define MBARRIER_WAIT_PARITY(mb, par) do { \
    uint32_t _mb = (uint32_t)(mb), _pa = (uint32_t)(par), _dn; \
    asm volatile("{\n\t.reg .pred p;\n\t" \
        "mbarrier.try_wait.parity.acquire.cta.shared::cta.b64 p, [%1], %2;\n\t" \
        "selp.b32 %0, 1, 0, p;\n\t}" : "=r"(_dn) : "r"(_mb), "r"(_pa) : "memory"); \
    if (!_dn) { \
        asm volatile("{\n\t.reg .pred P1;\n\t" \
            "WL_%=:\n\tmbarrier.try_wait.parity.acquire.cta.shared::cta.b64 P1, [%0], %1, 0x989680;\n\t" \
            "@P1 bra.uni WD_%=;\n\tbra.uni WL_%=;\n\tWD_%=:\n\t}" \
            :: "r"(_mb), "r"(_pa) : "memory"); \
    } \
} while (0)
#define TCGEN05_LD_32X32B_X32(r, ta) \
    asm volatile("tcgen05.ld.sync.aligned.32x32b.x32.b32 " \
        "{%0, %1, %2, %3, %4, %5, %6, %7, %8, %9, %10, %11, %12, %13, %14, %15, " \
        "%16, %17, %18, %19, %20, %21, %22, %23, %24, %25, %26, %27, %28, %29, %30, %31}, [%32];" \
        : "=r"((r)[0]),  "=r"((r)[1]),  "=r"((r)[2]),  "=r"((r)[3]), \
          "=r"((r)[4]),  "=r"((r)[5]),  "=r"((r)[6]),  "=r"((r)[7]), \
          "=r"((r)[8]),  "=r"((r)[9]),  "=r"((r)[10]), "=r"((r)[11]), \
          "=r"((r)[12]), "=r"((r)[13]), "=r"((r)[14]), "=r"((r)[15]), \
          "=r"((r)[16]), "=r"((r)[17]), "=r"((r)[18]), "=r"((r)[19]), \
          "=r"((r)[20]), "=r"((r)[21]), "=r"((r)[22]), "=r"((r)[23]), \
          "=r"((r)[24]), "=r"((r)[25]), "=r"((r)[26]), "=r"((r)[27]), \
          "=r"((r)[28]), "=r"((r)[29]), "=r"((r)[30]), "=r"((r)[31]) \
        : "r"(ta))

static constexpr u64 SMEM_DESC_BASE_SW128 =
    (u64(2) << 61) | (u64(1) << 46) | (u64(64) << 32) | (u64(1) << 16);
#define MAKE_SMEM_DESC(a) (SMEM_DESC_BASE_SW128 | ((u64)((a) >> 4) & 0x3FFF))

static __device__ __forceinline__ void mma_f16_ss(uint32_t d, u64 ad, u64 bd,
                                                  uint32_t idesc, uint32_t en) {
    asm volatile(
        "{\n\t.reg .pred p;\n\tsetp.ne.u32 p, %4, 0;\n\t"
        "tcgen05.mma.cta_group::1.kind::f16 [%0], %1, %2, %3, {%5, %5, %5, %5}, p;\n\t}"
        :: "r"(d), "l"(ad), "l"(bd), "r"(idesc), "r"(en), "r"(0u)
        : "memory");
}
#endif  // GB_TC

#define IDESC_BF16_M128_N128 0x8200490u
#define IDESC_BF16_M128_N256 0x8400490u

// =====================================================================
// Kernel 0: pre-split + pre-swizzle weights (f1,f2,Wk,Wv,Wq,Wo)
// =====================================================================
__global__ __launch_bounds__(256, 4)
void conv_w_kernel(const float* __restrict__ f1w, const float* __restrict__ f2w,
                   const float* __restrict__ Wk, const float* __restrict__ Wv,
                   const float* __restrict__ Wq, const float* __restrict__ Wo)
{
    const unsigned gidx = blockIdx.x * 256 + threadIdx.x;
    if (gidx < 2097152u) {
        const int arr = gidx >> 20;
        const unsigned rem = gidx & 0xFFFFFu;
        const int t = rem >> 14;
        const int e = rem & 16383;
        const int n = e >> 6, k = e & 63;
        const int m = t >> 4, c1 = (t >> 2) & 3, c2 = t & 3;
        float w;
        if (arr == 0)
            w = f1w[(size_t)m * 262144 + (size_t)(c1 * 256 + n) * 256 + c2 * 64 + k];
        else
            w = f2w[(size_t)m * 262144 + (size_t)n * 1024 + c1 * 256 + c2 * 64 + k];
        __nv_bfloat16 h, l;
        bsplit(w, h, l);
        const uint32_t sw = swz128((uint32_t)(n >> 3) * 1024 + (n & 7) * 128 + k * 2);
        __nv_bfloat16* dst = (arr == 0 ? g_w1t : g_w2t) + (size_t)t * 32768;
        dst[sw >> 1]           = h;
        dst[16384 + (sw >> 1)] = l;
    } else if (gidx < 2621440u) {
        const unsigned idx2 = gidx - 2097152u;
        const int arr2 = idx2 >> 18;
        const unsigned rem = idx2 & 0x3FFFFu;
        const int t = rem >> 13;
        const int e = rem & 8191;
        const int n = e >> 6, k = e & 63;
        const int m = t >> 3, nch = (t >> 2) & 1, kch = t & 3;
        const float* W = (arr2 == 0 ? Wk : Wv);
        const float w = W[(size_t)m * 65536 + (size_t)(nch * 128 + n) * 256 + kch * 64 + k];
        __nv_bfloat16 h, l;
        bsplit(w, h, l);
        const uint32_t sw = swz128((uint32_t)(n >> 3) * 1024 + (n & 7) * 128 + k * 2);
        __nv_bfloat16* dst = (arr2 == 0 ? g_wkt : g_wvt) + (size_t)t * 16384;
        dst[sw >> 1]          = h;
        dst[8192 + (sw >> 1)] = l;
    } else {
        const unsigned idx3 = gidx - 2621440u;
        const int arr3 = idx3 >> 18;
        const unsigned rem = idx3 & 0x3FFFFu;
        const int t = rem >> 14;
        const int e = rem & 16383;
        const int n = e >> 6, k = e & 63;
        const int m = t >> 2, kch = t & 3;
        const float* W = (arr3 == 0 ? Wq : Wo);
        float w = W[(size_t)m * 65536 + (size_t)n * 256 + kch * 64 + k];
        if (arr3 == 0) w *= 0.17677669529663687f;
        __nv_bfloat16 h, l;
        bsplit(w, h, l);
        const uint32_t sw = swz128((uint32_t)(n >> 3) * 1024 + (n & 7) * 128 + k * 2);
        __nv_bfloat16* dst = (arr3 == 0 ? g_wqt : g_wot) + (size_t)t * 32768;
        dst[sw >> 1]           = h;
        dst[16384 + (sw >> 1)] = l;
    }
}

// =====================================================================
// shared smem layout for kvattn/qo: A 128KB + 2 x (16KB hi + 16KB lo) B
// =====================================================================
#define KV_SMEM 197632
#define KV_MB0  16
#define KV_MB1  24
#define KV_AHI  1024
#define KV_ALO  66560
#define KV_B0H  132096
#define KV_B0L  148480
#define KV_B1H  164864
#define KV_B1L  181248

// =====================================================================
// Kernel A: fused K,V projection + attention. grid 1024, 256 threads.
// K -> TMEM cols 0-255, V -> cols 256-511 per modality; attention reads
// TMEM directly and writes Oh only. K/V never touch gmem.
// =====================================================================
__global__ __launch_bounds__(256, 1)
void gcma_kvattn(const float* __restrict__ x,
                 const float* __restrict__ bk, const float* __restrict__ bv)
{
    extern __shared__ char smA[];
    const int tid = threadIdx.x;
    const int r0  = blockIdx.x * 128;

#if GB_TC
    const uint32_t sbase = smem_to_u32(smA);
    const int wid = tid >> 5, lane = tid & 31;
    char* sAhi = smA + KV_AHI;
    char* sAlo = smA + KV_ALO;

    if (wid == 0) TCGEN05_ALLOC(sbase + 0, 512);
    if (tid == 0) { MBARRIER_INIT(sbase + KV_MB0, 1); MBARRIER_INIT(sbase + KV_MB1, 1); }
    __syncthreads();
    uint32_t tmem;
    asm volatile("ld.shared.b32 %0, [%1];" : "=r"(tmem) : "r"(sbase + 0));

    // stage A: x rows r0..r0+127, split+swizzle
    for (int idx = tid; idx < 8192; idx += 256) {
        const int r = idx >> 6, k = (idx & 63) << 2;
        const float4 v = *reinterpret_cast<const float4*>(x + (size_t)(r0 + r) * 256 + k);
        __nv_bfloat16 h0, h1, h2, h3, l0, l1, l2, l3;
        bsplit(v.x, h0, l0); bsplit(v.y, h1, l1);
        bsplit(v.z, h2, l2); bsplit(v.w, h3, l3);
        const uint32_t sw = swz128((uint32_t)((r >> 3) + (k >> 6) * 16) * 1024 + (r & 7) * 128 + (k & 63) * 2);
        *reinterpret_cast<uint2*>(sAhi + sw) = make_uint2(pk2(h0, h1), pk2(h2, h3));
        *reinterpret_cast<uint2*>(sAlo + sw) = make_uint2(pk2(l0, l1), pk2(l2, l3));
    }

    const u64 aH = MAKE_SMEM_DESC(sbase + KV_AHI), aL = MAKE_SMEM_DESC(sbase + KV_ALO);
    const u64 b0H = MAKE_SMEM_DESC(sbase + KV_B0H), b0L = MAKE_SMEM_DESC(sbase + KV_B0L);
    const u64 b1H = MAKE_SMEM_DESC(sbase + KV_B1H), b1L = MAKE_SMEM_DESC(sbase + KV_B1L);

    const int rr = (wid & 3) * 32 + lane;      // row 0..127
    const int cb = (wid >> 2) * 128;           // col half
    const int b  = blockIdx.x * 32 + (rr >> 2);

    int w0 = 0, w1 = 0, pend0 = 0, pend1 = 0;

    for (int m = 0; m < 4; ++m) {
        // ---- 16 MMA chunks: K quadrants (cols 0-255), V quadrants (256-511) ----
        for (int t = 0; t < 16; ++t) {
            const int kv2 = t >> 3, nch = (t >> 2) & 1, kch = t & 3;
            const int buf = t & 1;
            if (buf == 0) { if (pend0) { MBARRIER_WAIT_PARITY(sbase + KV_MB0, w0 & 1); ++w0; pend0 = 0; } }
            else          { if (pend1) { MBARRIER_WAIT_PARITY(sbase + KV_MB1, w1 & 1); ++w1; pend1 = 0; } }
            {
                const float4* s4 = reinterpret_cast<const float4*>(
                    (kv2 ? g_wvt : g_wkt) + (size_t)(((m * 2 + nch) * 4 + kch)) * 16384);
                float4* dh = reinterpret_cast<float4*>(smA + (buf ? KV_B1H : KV_B0H));
                float4* dl = reinterpret_cast<float4*>(smA + (buf ? KV_B1L : KV_B0L));
#pragma unroll
                for (int i = 0; i < 4; ++i) {
                    dh[tid + i * 256] = s4[tid + i * 256];
                    dl[tid + i * 256] = s4[1024 + tid + i * 256];
                }
            }
            __syncthreads();
            if (wid == 0) {
                asm volatile("fence.proxy.async.shared::cta;" ::: "memory");
                TCGEN05_FENCE_AFTER();
                if (elect_one_pred()) {
                    const u64 bH = buf ? b1H : b0H, bL = buf ? b1L : b0L;
                    const uint32_t dcol = tmem + kv2 * 256 + nch * 128;
#pragma unroll
                    for (int j = 0; j < 4; ++j) {
                        const u64 ao = (u64)(kch * 1024 + j * 2), bo = (u64)(j * 2);
                        mma_f16_ss(dcol, aH + ao, bH + bo, IDESC_BF16_M128_N128,
                                   (kch == 0 && j == 0) ? 0u : 1u);
                        mma_f16_ss(dcol, aH + ao, bL + bo, IDESC_BF16_M128_N128, 1u);
                        mma_f16_ss(dcol, aL + ao, bH + bo, IDESC_BF16_M128_N128, 1u);
                    }
                    TCGEN05_COMMIT(sbase + (buf ? KV_MB1 : KV_MB0));
                }
            }
            if (buf == 0) pend0 = 1; else pend1 = 1;
        }
        if (pend0) { MBARRIER_WAIT_PARITY(sbase + KV_MB0, w0 & 1); ++w0; pend0 = 0; }
        if (pend1) { MBARRIER_WAIT_PARITY(sbase + KV_MB1, w1 & 1); ++w1; pend1 = 0; }
        TCGEN05_FENCE_AFTER();

        // ---- attention epilogue from TMEM (per 32-dim head chunk) ----
        for (int cc = 0; cc < 4; ++cc) {
            const int dof = cb + cc * 32;      // head = dof/32, dims dof..dof+31
            uint32_t kr[32];
            TCGEN05_LD_32X32B_X32(kr, tmem + dof);
            TCGEN05_WAIT_LD();
            const float* qrow = g_q + ((size_t)m * 32768 + b) * 256 + dof;
            const float* bkp  = bk + m * 256 + dof;
            float s = 0.f;
#pragma unroll
            for (int j = 0; j < 32; ++j)
                s = fmaf(qrow[j], __uint_as_float(kr[j]) + bkp[j], s);
            // quad softmax (rows b*4+n live in lanes (lane&~3)+n)
            float mx = s;
            mx = fmaxf(mx, __shfl_xor_sync(0xffffffffu, mx, 1));
            mx = fmaxf(mx, __shfl_xor_sync(0xffffffffu, mx, 2));
            float e = expf(s - mx);
            float se = e;
            se += __shfl_xor_sync(0xffffffffu, se, 1);
            se += __shfl_xor_sync(0xffffffffu, se, 2);
            const float p = e / se;

            uint32_t vr[32];
            TCGEN05_LD_32X32B_X32(vr, tmem + 256 + dof);
            TCGEN05_WAIT_LD();
            const float* bvp = bv + m * 256 + dof;
            float t32[32];
#pragma unroll
            for (int j = 0; j < 32; ++j)
                t32[j] = p * (__uint_as_float(vr[j]) + bvp[j]);
#pragma unroll
            for (int j = 0; j < 32; ++j) {
                t32[j] += __shfl_xor_sync(0xffffffffu, t32[j], 1);
                t32[j] += __shfl_xor_sync(0xffffffffu, t32[j], 2);
            }
            // all 4 lanes of the quad hold Oh[b][dof..dof+31]; split the store
            const int qi = lane & 3;
            float* op = g_oh + ((size_t)m * 32768 + b) * 256 + dof + qi * 8;
            *reinterpret_cast<float4*>(op) =
                make_float4(t32[qi * 8 + 0], t32[qi * 8 + 1], t32[qi * 8 + 2], t32[qi * 8 + 3]);
            *reinterpret_cast<float4*>(op + 4) =
                make_float4(t32[qi * 8 + 4], t32[qi * 8 + 5], t32[qi * 8 + 6], t32[qi * 8 + 7]);
        }
        TCGEN05_FENCE_BEFORE();
        __syncthreads();   // all TMEM reads done before next m overwrites
    }

    if (tid == 0) {
        asm volatile("mbarrier.inval.shared.b64 [%0];" :: "r"(sbase + KV_MB0) : "memory");
        asm volatile("mbarrier.inval.shared.b64 [%0];" :: "r"(sbase + KV_MB1) : "memory");
    }
    __syncthreads();
    if (wid == 0) TCGEN05_DEALLOC(tmem, 512);

#else  // fp32 fallback (slow; never runs on sm_103a)
    const int b = blockIdx.x * 32 + (tid >> 3);
    const int h = tid & 7;
    for (int m = 0; m < 4; ++m) {
        const float* q = g_q + ((size_t)m * 32768 + b) * 256 + h * 32;
        float sc[4];
        for (int n = 0; n < 4; ++n) {
            float s = 0.f;
            for (int d = 0; d < 32; ++d) {
                float kd = bk[m * 256 + h * 32 + d];
                for (int k = 0; k < 256; ++k)
                    kd = fmaf(x[(size_t)(b * 4 + n) * 256 + k], wrec128(g_wkt, m, h * 32 + d, k), kd);
                s = fmaf(q[d], kd, s);
            }
            sc[n] = s;
        }
        const float mx = fmaxf(fmaxf(sc[0], sc[1]), fmaxf(sc[2], sc[3]));
        float e[4], se = 0.f;
        for (int n = 0; n < 4; ++n) { e[n] = expf(sc[n] - mx); se += e[n]; }
        for (int d = 0; d < 32; ++d) {
            float o = 0.f;
            for (int n = 0; n < 4; ++n) {
                float vd = bv[m * 256 + h * 32 + d];
                for (int k = 0; k < 256; ++k)
                    vd = fmaf(x[(size_t)(b * 4 + n) * 256 + k], wrec128(g_wvt, m, h * 32 + d, k), vd);
                o = fmaf(e[n] / se, vd, o);
            }
            g_oh[((size_t)m * 32768 + b) * 256 + h * 32 + d] = o;
        }
    }
#endif
}

// =====================================================================
// Kernel B/D: Q or Wo projection (tcgen05, 8 double-buffered N=128 chunks)
// =====================================================================
__global__ __launch_bounds__(256, 1)
void gcma_qo(const float* __restrict__ x,
             const float* __restrict__ bq, const float* __restrict__ bo,
             int which)
{
    extern __shared__ char smQ[];
    const int tid = threadIdx.x;
    const int m   = blockIdx.y;
    const int b0  = blockIdx.x * 128;

    const __nv_bfloat16* wt = which ? g_wot : g_wqt;
    const float* bias = which ? (bo + m * 256) : (bq + m * 256);
    const float bscale = which ? 1.f : 0.17677669529663687f;
    float* dst = (which ? g_ao : g_q) + ((size_t)m * 32768 + b0) * 256;

#if GB_TC
    const uint32_t sbase = smem_to_u32(smQ);
    const int wid = tid >> 5, lane = tid & 31;
    char* sAhi = smQ + KV_AHI;
    char* sAlo = smQ + KV_ALO;

    if (wid == 0) TCGEN05_ALLOC(sbase + 0, 512);
    if (tid == 0) { MBARRIER_INIT(sbase + KV_MB0, 1); MBARRIER_INIT(sbase + KV_MB1, 1); }
    __syncthreads();
    uint32_t tmem;
    asm volatile("ld.shared.b32 %0, [%1];" : "=r"(tmem) : "r"(sbase + 0));

    for (int idx = tid; idx < 8192; idx += 256) {
        const int r = idx >> 6, k = (idx & 63) << 2;
        const float* src = which
            ? g_oh + ((size_t)m * 32768 + b0 + r) * 256 + k
            : x + ((size_t)(b0 + r) * 4 + m) * 256 + k;
        const float4 v = *reinterpret_cast<const float4*>(src);
        __nv_bfloat16 h0, h1, h2, h3, l0, l1, l2, l3;
        bsplit(v.x, h0, l0); bsplit(v.y, h1, l1);
        bsplit(v.z, h2, l2); bsplit(v.w, h3, l3);
        const uint32_t sw = swz128((uint32_t)((r >> 3) + (k >> 6) * 16) * 1024 + (r & 7) * 128 + (k & 63) * 2);
        *reinterpret_cast<uint2*>(sAhi + sw) = make_uint2(pk2(h0, h1), pk2(h2, h3));
        *reinterpret_cast<uint2*>(sAlo + sw) = make_uint2(pk2(l0, l1), pk2(l2, l3));
    }

    const u64 aH = MAKE_SMEM_DESC(sbase + KV_AHI), aL = MAKE_SMEM_DESC(sbase + KV_ALO);
    const u64 b0H = MAKE_SMEM_DESC(sbase + KV_B0H), b0L = MAKE_SMEM_DESC(sbase + KV_B0L);
    const u64 b1H = MAKE_SMEM_DESC(sbase + KV_B1H), b1L = MAKE_SMEM_DESC(sbase + KV_B1L);

    int w0 = 0, w1 = 0, pend0 = 0, pend1 = 0;
    for (int c = 0; c < 8; ++c) {
        const int nch = c >> 2, kch = c & 3;
        const int buf = c & 1;
        if (buf == 0) { if (pend0) { MBARRIER_WAIT_PARITY(sbase + KV_MB0, w0 & 1); ++w0; pend0 = 0; } }
        else          { if (pend1) { MBARRIER_WAIT_PARITY(sbase + KV_MB1, w1 & 1); ++w1; pend1 = 0; } }
        {
            const float4* s4 = reinterpret_cast<const float4*>(wt + (size_t)(m * 4 + kch) * 32768);
            float4* dh = reinterpret_cast<float4*>(smQ + (buf ? KV_B1H : KV_B0H));
            float4* dl = reinterpret_cast<float4*>(smQ + (buf ? KV_B1L : KV_B0L));
#pragma unroll
            for (int i = 0; i < 4; ++i) {
                dh[tid + i * 256] = s4[nch * 1024 + tid + i * 256];
                dl[tid + i * 256] = s4[2048 + nch * 1024 + tid + i * 256];
            }
        }
        __syncthreads();
        if (wid == 0) {
            asm volatile("fence.proxy.async.shared::cta;" ::: "memory");
            TCGEN05_FENCE_AFTER();
            if (elect_one_pred()) {
                const u64 bH = buf ? b1H : b0H, bL = buf ? b1L : b0L;
                const uint32_t dcol = tmem + nch * 128;
#pragma unroll
                for (int j = 0; j < 4; ++j) {
                    const u64 ao = (u64)(kch * 1024 + j * 2), bo2 = (u64)(j * 2);
                    mma_f16_ss(dcol, aH + ao, bH + bo2, IDESC_BF16_M128_N128,
                               (kch == 0 && j == 0) ? 0u : 1u);
                    mma_f16_ss(dcol, aH + ao, bL + bo2, IDESC_BF16_M128_N128, 1u);
                    mma_f16_ss(dcol, aL + ao, bH + bo2, IDESC_BF16_M128_N128, 1u);
                }
                TCGEN05_COMMIT(sbase + (buf ? KV_MB1 : KV_MB0));
            }
        }
        if (buf == 0) pend0 = 1; else pend1 = 1;
    }
    if (pend0) { MBARRIER_WAIT_PARITY(sbase + KV_MB0, w0 & 1); ++w0; pend0 = 0; }
    if (pend1) { MBARRIER_WAIT_PARITY(sbase + KV_MB1, w1 & 1); ++w1; pend1 = 0; }
    TCGEN05_FENCE_AFTER();

    {
        const int rr = (wid & 3) * 32 + lane;
        const int cb = (wid >> 2) * 128;
        for (int cc = 0; cc < 4; ++cc) {
            uint32_t dr[32];
            TCGEN05_LD_32X32B_X32(dr, tmem + cb + cc * 32);
            TCGEN05_WAIT_LD();
            TCGEN05_FENCE_BEFORE();
            const int c0 = cb + cc * 32;
            float* drow = dst + (size_t)rr * 256 + c0;
#pragma unroll
            for (int q = 0; q < 8; ++q) {
                *reinterpret_cast<float4*>(drow + q * 4) =
                    make_float4(__uint_as_float(dr[q * 4 + 0]) + bias[c0 + q * 4 + 0] * bscale,
                                __uint_as_float(dr[q * 4 + 1]) + bias[c0 + q * 4 + 1] * bscale,
                                __uint_as_float(dr[q * 4 + 2]) + bias[c0 + q * 4 + 2] * bscale,
                                __uint_as_float(dr[q * 4 + 3]) + bias[c0 + q * 4 + 3] * bscale);
            }
        }
    }

    __syncthreads();
    if (tid == 0) {
        asm volatile("mbarrier.inval.shared.b64 [%0];" :: "r"(sbase + KV_MB0) : "memory");
        asm volatile("mbarrier.inval.shared.b64 [%0];" :: "r"(sbase + KV_MB1) : "memory");
    }
    __syncthreads();
    if (wid == 0) TCGEN05_DEALLOC(tmem, 512);

#else
    for (int e = tid; e < 128 * 256; e += 256) {
        const int r = e >> 8, n = e & 255;
        float dot = 0.f;
        for (int k = 0; k < 256; ++k) {
            const int kch = k >> 6, kk = k & 63;
            const __nv_bfloat16* tb = wt + (size_t)(m * 4 + kch) * 32768;
            const uint32_t sw = swz128((uint32_t)(n >> 3) * 1024 + (n & 7) * 128 + kk * 2);
            const float wv = __bfloat162float(tb[sw >> 1]) + __bfloat162float(tb[16384 + (sw >> 1)]);
            const float a = which
                ? g_oh[((size_t)m * 32768 + b0 + r) * 256 + k]
                : x[((size_t)(b0 + r) * 4 + m) * 256 + k];
            dot = fmaf(a, wv, dot);
        }
        dst[(size_t)r * 256 + n] = dot + bias[n] * bscale;
    }
#endif
}

// =====================================================================
// Kernel E: gate MLP + LayerNorm, grid (2048,4)
// =====================================================================
#define TL_XM   0
#define TL_AO   4096
#define TL_WT   8192
#define TL_GH   16512
#define TL_GATE 17536
#define TL_FLOATS 17552
#define TL_BYTES  (TL_FLOATS * 4)

__global__ __launch_bounds__(256, 1)
void gcma_tail(const float* __restrict__ x,
               const float* __restrict__ g1w, const float* __restrict__ g1b,
               const float* __restrict__ g2w, const float* __restrict__ g2b,
               const float* __restrict__ lng, const float* __restrict__ lnb,
               float* __restrict__ out)
{
    extern __shared__ float smL[];
    float* sXm   = smL + TL_XM;
    float* sAO   = smL + TL_AO;
    float* sWT   = smL + TL_WT;
    float* sGH   = smL + TL_GH;
    float* sGate = smL + TL_GATE;

    const int tid = threadIdx.x;
    const int m   = blockIdx.y;
    const int b0  = blockIdx.x * 16;
    const long g0 = (long)b0 * 4;

    const int warp = tid >> 5;
    const int colg = tid & 31;

    for (int idx = tid; idx < 1024; idx += 256) {
        const int r = idx >> 6, q = idx & 63;
        *reinterpret_cast<float4*>(sXm + r * 256 + q * 4) =
            *reinterpret_cast<const float4*>(x + ((size_t)(b0 + r) * 4 + m) * 256 + q * 4);
        *reinterpret_cast<float4*>(sAO + r * 256 + q * 4) =
            *reinterpret_cast<const float4*>(g_ao + ((size_t)m * 32768 + b0 + r) * 256 + q * 4);
    }

    {
        const float* W = g1w + (size_t)m * 32768;
        Wreg<2> wr;
        ldgW<2>(W, 512, 0, wr, tid);
        u64 gacc[2] = {0ULL, 0ULL};
        for (int dt = 0; dt < 16; ++dt) {
            __syncthreads();
            stsW<2>(sWT, wr, tid);
            if (dt < 15) ldgW<2>(W, 512, (dt + 1) * 32, wr, tid);
            __syncthreads();
            if (dt < 8)
                mmagb(sXm + warp * 2 * 256 + dt * 32, 256, sWT, gacc, colg);
            else
                mmagb(sAO + warp * 2 * 256 + (dt - 8) * 32, 256, sWT, gacc, colg);
        }
        const float gb0 = g1b[m * 64 + colg * 2];
        const float gb1 = g1b[m * 64 + colg * 2 + 1];
#pragma unroll
        for (int i = 0; i < 2; ++i) {
            const float2 p = unpk(gacc[i]);
            sGH[(warp * 2 + i) * 64 + colg * 2]     = tanhf(p.x + gb0);
            sGH[(warp * 2 + i) * 64 + colg * 2 + 1] = tanhf(p.y + gb1);
        }
    }
    __syncthreads();

    if (tid < 16) {
        const float* g2 = g2w + m * 64;
        float dot = g2b[m];
#pragma unroll 8
        for (int j = 0; j < 64; ++j) dot = fmaf(sGH[tid * 64 + j], g2[j], dot);
        const float gate = 1.f / (1.f + expf(-dot));
        sGate[tid] = gate;
        out[OUT_GATE_BASE + (size_t)(b0 + tid) * 4 + m] = gate;
    }
    __syncthreads();

    {
        const int lane = tid & 31;
        for (int bl = warp; bl < 16; bl += 8) {
            const float* xr  = sXm + bl * 256;
            const float* aor = sAO + bl * 256;
            const float gate = sGate[bl];
            float r[8];
            float sum = 0.f;
#pragma unroll
            for (int k = 0; k < 8; ++k) {
                const int d = k * 32 + lane;
                r[k] = xr[d] + gate * aor[d];
                sum += r[k];
            }
#pragma unroll
            for (int o = 16; o; o >>= 1) sum += __shfl_xor_sync(0xffffffffu, sum, o);
            const float mu = sum * (1.f / 256.f);
            float var = 0.f;
#pragma unroll
            for (int k = 0; k < 8; ++k) { const float t = r[k] - mu; var = fmaf(t, t, var); }
#pragma unroll
            for (int o = 16; o; o >>= 1) var += __shfl_xor_sync(0xffffffffu, var, o);
            const float rs = rsqrtf(var * (1.f / 256.f) + 1e-5f);
            float* yr = g_y + (size_t)(g0 + bl * 4 + m) * 256;
#pragma unroll
            for (int k = 0; k < 8; ++k) {
                const int d = k * 32 + lane;
                yr[d] = (r[k] - mu) * rs * lng[m * 256 + d] + lnb[m * 256 + d];
            }
        }
    }
}

// =====================================================================
// Kernel F: FF (tcgen05)
// =====================================================================
#define P2_SMEM 197632
#define P2_TM    0
#define P2_MB    8
#define P2_AHI   1024
#define P2_ALO   66560
#define P2_BHI   132096
#define P2_BLO   164864

static __device__ __forceinline__ void loadB(const __nv_bfloat16* base, int m, int c1, int c2,
                                             float4 pf[16], int tid) {
    const float4* src = reinterpret_cast<const float4*>(base + (size_t)((m * 4 + c1) * 4 + c2) * 32768);
#pragma unroll
    for (int i = 0; i < 8; ++i) {
        pf[i]     = src[tid + i * 256];
        pf[8 + i] = src[2048 + tid + i * 256];
    }
}
static __device__ __forceinline__ void stsB(char* sBhi, char* sBlo, const float4 pf[16], int tid) {
#pragma unroll
    for (int i = 0; i < 8; ++i) {
        reinterpret_cast<float4*>(sBhi)[tid + i * 256] = pf[i];
        reinterpret_cast<float4*>(sBlo)[tid + i * 256] = pf[8 + i];
    }
}

__global__ __launch_bounds__(256, 1)
void gcma_part2tc(const float* __restrict__ f1w, const float* __restrict__ f1b,
                  const float* __restrict__ f2w, const float* __restrict__ f2b,
                  float* __restrict__ out)
{
    extern __shared__ char sm2[];
    const int tid  = threadIdx.x;
    const int m    = blockIdx.y;
    const int b0   = blockIdx.x * 128;

#if GB_TC
    const uint32_t sbase = smem_to_u32(sm2);
    const uint32_t TMP  = sbase + P2_TM;
    const uint32_t MBAR = sbase + P2_MB;
    char* sAhi = sm2 + P2_AHI;
    char* sAlo = sm2 + P2_ALO;
    char* sBhi = sm2 + P2_BHI;
    char* sBlo = sm2 + P2_BLO;
    const uint32_t aHiA = sbase + P2_AHI, aLoA = sbase + P2_ALO;
    const uint32_t bHiA = sbase + P2_BHI, bLoA = sbase + P2_BLO;

    const int wid  = tid >> 5, lane = tid & 31;
    unsigned* hfbase = g_hfscr + (size_t)(blockIdx.y * 256 + blockIdx.x) * 131072u;

    if (wid == 0) TCGEN05_ALLOC(TMP, 512);
    if (tid == 0) MBARRIER_INIT(MBAR, 1);
    __syncthreads();
    uint32_t tmem;
    asm volatile("ld.shared.b32 %0, [%1];" : "=r"(tmem) : "r"(TMP));

    for (int idx = tid; idx < 8192; idx += 256) {
        const int r = idx >> 6, k = (idx & 63) << 2;
        const float4 v = *reinterpret_cast<const float4*>(
            g_y + ((size_t)(b0 + r) * 4 + m) * 256 + k);
        __nv_bfloat16 h0, h1, h2, h3, l0, l1, l2, l3;
        bsplit(v.x, h0, l0); bsplit(v.y, h1, l1);
        bsplit(v.z, h2, l2); bsplit(v.w, h3, l3);
        const uint32_t sw = swz128((uint32_t)((r >> 3) + (k >> 6) * 16) * 1024 + (r & 7) * 128 + (k & 63) * 2);
        *reinterpret_cast<uint2*>(sAhi + sw) = make_uint2(pk2(h0, h1), pk2(h2, h3));
        *reinterpret_cast<uint2*>(sAlo + sw) = make_uint2(pk2(l0, l1), pk2(l2, l3));
    }

    float4 pf[16];
    loadB(g_w1t, m, 0, 0, pf, tid);
    int ph = 0;
    const u64 aH = MAKE_SMEM_DESC(aHiA), aL = MAKE_SMEM_DESC(aLoA);
    const u64 bH = MAKE_SMEM_DESC(bHiA), bL = MAKE_SMEM_DESC(bLoA);

    for (int nch = 0; nch < 4; ++nch) {
        for (int kch = 0; kch < 4; ++kch) {
            stsB(sBhi, sBlo, pf, tid);
            __syncthreads();
            if (wid == 0) {
                asm volatile("fence.proxy.async.shared::cta;" ::: "memory");
                TCGEN05_FENCE_AFTER();
                if (elect_one_pred()) {
#pragma unroll
                    for (int j = 0; j < 4; ++j) {
                        const u64 ao = (u64)(kch * 1024 + j * 2), bo = (u64)(j * 2);
                        mma_f16_ss(tmem, aH + ao, bH + bo, IDESC_BF16_M128_N256,
                                   (kch == 0 && j == 0) ? 0u : 1u);
                        mma_f16_ss(tmem, aH + ao, bL + bo, IDESC_BF16_M128_N256, 1u);
                        mma_f16_ss(tmem, aL + ao, bH + bo, IDESC_BF16_M128_N256, 1u);
                    }
                    TCGEN05_COMMIT(MBAR);
                }
            }
            const int nb = nch * 4 + kch + 1;
            if (nb < 16) loadB(g_w1t, m, nb >> 2, nb & 3, pf, tid);
            else         loadB(g_w2t, m, 0, 0, pf, tid);
            MBARRIER_WAIT_PARITY(MBAR, ph & 1);
            ++ph;
            TCGEN05_FENCE_AFTER();
        }
        {
            const int r  = (wid & 3) * 32 + lane;
            const int cb = (wid >> 2) * 128;
            for (int cc = 0; cc < 4; ++cc) {
                uint32_t dr[32];
                TCGEN05_LD_32X32B_X32(dr, tmem + cb + cc * 32);
                TCGEN05_WAIT_LD();
                TCGEN05_FENCE_BEFORE();
                const int c0 = nch * 256 + cb + cc * 32;
                unsigned* dst = hfbase + (size_t)r * 1024 + c0;
#pragma unroll
                for (int j = 0; j < 32; ++j) {
                    float v = __uint_as_float(dr[j]) + f1b[m * 1024 + c0 + j];
                    v = 0.5f * v * (1.f + erff(v * 0.7071067811865476f));
                    __nv_bfloat16 h, l;
                    bsplit(v, h, l);
                    dst[j] = pk2(h, l);
                }
            }
        }
        __syncthreads();
    }

    for (int ch = 0; ch < 4; ++ch) {
        for (int idx = tid; idx < 8192; idx += 256) {
            const int r = idx >> 6, k = (idx & 63) << 2;
            const uint4 u = *reinterpret_cast<const uint4*>(
                hfbase + (size_t)r * 1024 + ch * 256 + k);
            const unsigned uu[4] = {u.x, u.y, u.z, u.w};
            __nv_bfloat16 h[4], l[4];
#pragma unroll
            for (int j = 0; j < 4; ++j) {
                h[j] = __ushort_as_bfloat16((unsigned short)(uu[j] & 0xFFFFu));
                l[j] = __ushort_as_bfloat16((unsigned short)(uu[j] >> 16));
            }
            const uint32_t sw = swz128((uint32_t)((r >> 3) + (k >> 6) * 16) * 1024 + (r & 7) * 128 + (k & 63) * 2);
            *reinterpret_cast<uint2*>(sAhi + sw) = make_uint2(pk2(h[0], h[1]), pk2(h[2], h[3]));
            *reinterpret_cast<uint2*>(sAlo + sw) = make_uint2(pk2(l[0], l[1]), pk2(l[2], l[3]));
        }
        for (int kc = 0; kc < 4; ++kc) {
            stsB(sBhi, sBlo, pf, tid);
            __syncthreads();
            if (wid == 0) {
                asm volatile("fence.proxy.async.shared::cta;" ::: "memory");
                TCGEN05_FENCE_AFTER();
                if (elect_one_pred()) {
#pragma unroll
                    for (int j = 0; j < 4; ++j) {
                        const u64 ao = (u64)(kc * 1024 + j * 2), bo = (u64)(j * 2);
                        mma_f16_ss(tmem + 256, aH + ao, bH + bo, IDESC_BF16_M128_N256,
                                   (ch == 0 && kc == 0 && j == 0) ? 0u : 1u);
                        mma_f16_ss(tmem + 256, aH + ao, bL + bo, IDESC_BF16_M128_N256, 1u);
                        mma_f16_ss(tmem + 256, aL + ao, bH + bo, IDESC_BF16_M128_N256, 1u);
                    }
                    TCGEN05_COMMIT(MBAR);
                }
            }
            const int nb = ch * 4 + kc + 1;
            if (nb < 16) loadB(g_w2t, m, nb >> 2, nb & 3, pf, tid);
            MBARRIER_WAIT_PARITY(MBAR, ph & 1);
            ++ph;
            TCGEN05_FENCE_AFTER();
        }
    }

    {
        const int r  = (wid & 3) * 32 + lane;
        const int cb = (wid >> 2) * 128;
        for (int cc = 0; cc < 4; ++cc) {
            uint32_t dr[32];
            TCGEN05_LD_32X32B_X32(dr, tmem + 256 + cb + cc * 32);
            TCGEN05_WAIT_LD();
            TCGEN05_FENCE_BEFORE();
            const int c0 = cb + cc * 32;
            const float* yrow = g_y + ((size_t)(b0 + r) * 4 + m) * 256 + c0;
            float* orow = out + ((size_t)(b0 + r) * 4 + m) * 256 + c0;
#pragma unroll
            for (int j = 0; j < 32; ++j)
                orow[j] = yrow[j] + __uint_as_float(dr[j]) + f2b[m * 256 + c0 + j];
        }
    }

    __syncthreads();
    if (tid == 0)
        asm volatile("mbarrier.inval.shared.b64 [%0];" :: "r"(MBAR) : "memory");
    __syncthreads();
    if (wid == 0) TCGEN05_DEALLOC(tmem, 512);

#else
    float* smf = reinterpret_cast<float*>(sm2);
    float* sY  = smf;
    float* sHF = smf + 16384;
    float* sWT = smf + 32768;
    const int warp = tid >> 5;
    const int colg = tid & 31;

    for (int half = 0; half < 2; ++half) {
        const int hb0 = b0 + half * 64;
        __syncthreads();
        for (int idx = tid; idx < 4096; idx += TPB) {
            const int r = idx >> 6, q = idx & 63;
            *reinterpret_cast<float4*>(sY + r * 256 + q * 4) =
                *reinterpret_cast<const float4*>(g_y + ((size_t)(hb0 + r) * 4 + m) * 256 + q * 4);
        }
        u64 facc[8][4];
#pragma unroll
        for (int i = 0; i < 8; ++i)
#pragma unroll
            for (int j = 0; j < 4; ++j) facc[i][j] = 0ULL;
        const float* aY  = sY  + warp * 8 * 256;
        const float* aHF = sHF + warp * 8 * 256;

        for (int ch = 0; ch < 4; ++ch) {
            u64 hacc[8][4];
#pragma unroll
            for (int i = 0; i < 8; ++i)
#pragma unroll
                for (int j = 0; j < 4; ++j) hacc[i][j] = 0ULL;
            {
                const float* W1 = f1w + (size_t)m * 262144 + (size_t)ch * 65536;
                Wreg<8> wr;
                ldgW<8>(W1, 256, 0, wr, tid);
                for (int dt = 0; dt < 8; ++dt) {
                    __syncthreads();
                    stsW<8>(sWT, wr, tid);
                    if (dt < 7) ldgW<8>(W1, 256, (dt + 1) * 32, wr, tid);
                    __syncthreads();
                    mma64b(aY + dt * 32, 256, sWT, hacc, colg);
                }
            }
            __syncthreads();
            {
                const float* b1 = f1b + m * 1024 + ch * 256;
                float bl0[4], bl1[4];
#pragma unroll
                for (int j = 0; j < 4; ++j) { bl0[j] = b1[colg * 4 + j]; bl1[j] = b1[128 + colg * 4 + j]; }
#pragma unroll
                for (int i = 0; i < 8; ++i) {
                    const int r = warp * 8 + i;
                    const float2 pa = unpk(hacc[i][0]), pb = unpk(hacc[i][1]);
                    const float2 pc = unpk(hacc[i][2]), pd = unpk(hacc[i][3]);
                    float v0[4] = {pa.x + bl0[0], pa.y + bl0[1], pb.x + bl0[2], pb.y + bl0[3]};
                    float v1[4] = {pc.x + bl1[0], pc.y + bl1[1], pd.x + bl1[2], pd.y + bl1[3]};
#pragma unroll
                    for (int j = 0; j < 4; ++j) {
                        v0[j] = 0.5f * v0[j] * (1.f + erff(v0[j] * 0.7071067811865476f));
                        v1[j] = 0.5f * v1[j] * (1.f + erff(v1[j] * 0.7071067811865476f));
                    }
                    *reinterpret_cast<float4*>(sHF + r * 256 + colg * 4) =
                        make_float4(v0[0], v0[1], v0[2], v0[3]);
                    *reinterpret_cast<float4*>(sHF + r * 256 + 128 + colg * 4) =
                        make_float4(v1[0], v1[1], v1[2], v1[3]);
                }
            }
            {
                const float* W2 = f2w + (size_t)m * 262144;
                Wreg<8> wr;
                ldgW<8>(W2, 1024, ch * 256, wr, tid);
                for (int dt = 0; dt < 8; ++dt) {
                    __syncthreads();
                    stsW<8>(sWT, wr, tid);
                    if (dt < 7) ldgW<8>(W2, 1024, ch * 256 + (dt + 1) * 32, wr, tid);
                    __syncthreads();
                    mma64b(aHF + dt * 32, 256, sWT, facc, colg);
                }
            }
            __syncthreads();
        }
        {
            const float* b2 = f2b + m * 256;
            float bl0[4], bl1[4];
#pragma unroll
            for (int j = 0; j < 4; ++j) { bl0[j] = b2[colg * 4 + j]; bl1[j] = b2[128 + colg * 4 + j]; }
#pragma unroll
            for (int i = 0; i < 8; ++i) {
                const int r = warp * 8 + i;
                const float4 y0 = *reinterpret_cast<const float4*>(sY + r * 256 + colg * 4);
                const float4 y1 = *reinterpret_cast<const float4*>(sY + r * 256 + 128 + colg * 4);
                const float2 pa = unpk(facc[i][0]), pb = unpk(facc[i][1]);
                const float2 pc = unpk(facc[i][2]), pd = unpk(facc[i][3]);
                float* op = out + ((size_t)(hb0 + r) * 4 + m) * 256;
                *reinterpret_cast<float4*>(op + colg * 4) =
                    make_float4(y0.x + pa.x + bl0[0], y0.y + pa.y + bl0[1],
                                y0.z + pb.x + bl0[2], y0.w + pb.y + bl0[3]);
                *reinterpret_cast<float4*>(op + 128 + colg * 4) =
                    make_float4(y1.x + pc.x + bl1[0], y1.y + pc.y + bl1[1],
                                y1.z + pd.x + bl1[2], y1.w + pd.y + bl1[3]);
            }
        }
    }
#endif
}

extern "C" void kernel_launch(void* const* d_in, const int* in_sizes, int n_in,
                              void* d_out, int out_size) {
    const float* x   = (const float*)d_in[0];
    const float* Wq  = (const float*)d_in[1];
    const float* bq  = (const float*)d_in[2];
    const float* Wk  = (const float*)d_in[3];
    const float* bk  = (const float*)d_in[4];
    const float* Wv  = (const float*)d_in[5];
    const float* bv  = (const float*)d_in[6];
    const float* Wo  = (const float*)d_in[7];
    const float* bo  = (const float*)d_in[8];
    const float* g1w = (const float*)d_in[9];
    const float* g1b = (const float*)d_in[10];
    const float* g2w = (const float*)d_in[11];
    const float* g2b = (const float*)d_in[12];
    const float* lng = (const float*)d_in[13];
    const float* lnb = (const float*)d_in[14];
    const float* f1w = (const float*)d_in[15];
    const float* f1b = (const float*)d_in[16];
    const float* f2w = (const float*)d_in[17];
    const float* f2b = (const float*)d_in[18];
    float* out = (float*)d_out;

    cudaFuncSetAttribute(gcma_kvattn, cudaFuncAttributeMaxDynamicSharedMemorySize, KV_SMEM);
    cudaFuncSetAttribute(gcma_qo, cudaFuncAttributeMaxDynamicSharedMemorySize, KV_SMEM);
    cudaFuncSetAttribute(gcma_tail, cudaFuncAttributeMaxDynamicSharedMemorySize, TL_BYTES);
    cudaFuncSetAttribute(gcma_part2tc, cudaFuncAttributeMaxDynamicSharedMemorySize, P2_SMEM);

    conv_w_kernel<<<12288, 256>>>(f1w, f2w, Wk, Wv, Wq, Wo);
    gcma_qo<<<dim3(256, 4), 256, KV_SMEM>>>(x, bq, bo, 0);
    gcma_kvattn<<<1024, 256, KV_SMEM>>>(x, bk, bv);
    gcma_qo<<<dim3(256, 4), 256, KV_SMEM>>>(x, bq, bo, 1);
    gcma_tail<<<dim3(2048, 4), 256, TL_BYTES>>>(x, g1w, g1b, g2w, g2b, lng, lnb, out);
    gcma_part2tc<<<dim3(256, 4), 256, P2_SMEM>>>(f1w, f1b, f2w, f2b, out);
}

// round 14
// speedup vs baseline: 3.0068x; 1.0290x over previous
#include <cuda_runtime.h>
#include <cuda_bf16.h>
#include <math.h>
#include <stdint.h>

typedef unsigned long long u64;

#define TPB 256
#define PW 260

#define OUT_GATE_BASE 33554432UL   // B*M*D

#if defined(__CUDA_ARCH_FEAT_SM103_ALL) || \
    (defined(__CUDA_ARCH_SPECIFIC__) && (__CUDA_ARCH_SPECIFIC__ == 1030)) || \
    (defined(__CUDA_ARCH_FAMILY_SPECIFIC__) && (__CUDA_ARCH_FAMILY_SPECIFIC__ == 1030))
#define GB_TC 1
#else
#define GB_TC 0
#endif

// scratch
__device__ float g_y [32768u * 4u * 256u];                // 128MB
__device__ float g_oh[4u * 32768u * 256u];                // 128MB  Oh[m][b][256]
__device__ float g_ao[4u * 32768u * 256u];                // 128MB  attn_out[m][b][256]
__device__ __nv_bfloat16 g_w1t[64u * 32768u];             // FF1 tiles (hi|lo)
__device__ __nv_bfloat16 g_w2t[64u * 32768u];             // FF2 tiles
__device__ __nv_bfloat16 g_wkt[32u * 16384u];             // Wk tiles 128n x 64k (hi|lo)
__device__ __nv_bfloat16 g_wvt[32u * 16384u];             // Wv tiles
__device__ __nv_bfloat16 g_wqt[16u * 32768u];             // Wq tiles 256n x 64k (scaled)
__device__ __nv_bfloat16 g_wot[16u * 32768u];             // Wo tiles 256n x 64k
__device__ unsigned g_hfscr[1024u * 131072u];             // hf scratch

// ---------- helpers ----------
static __device__ __forceinline__ u64 ffma2(u64 a, u64 b, u64 c) {
    u64 d;
    asm("fma.rn.f32x2 %0, %1, %2, %3;" : "=l"(d) : "l"(a), "l"(b), "l"(c));
    return d;
}
static __device__ __forceinline__ u64 dup2(float a) {
    u64 d;
    asm("mov.b64 %0, {%1, %1};" : "=l"(d) : "f"(a));
    return d;
}
static __device__ __forceinline__ float2 unpk(u64 p) {
    float2 r;
    asm("mov.b64 {%0, %1}, %2;" : "=f"(r.x), "=f"(r.y) : "l"(p));
    return r;
}
static __device__ __forceinline__ float comp4(const float4& v, int dd) {
    return dd == 0 ? v.x : dd == 1 ? v.y : dd == 2 ? v.z : v.w;
}
static __device__ __forceinline__ unsigned pk2(__nv_bfloat16 a, __nv_bfloat16 b) {
    return (unsigned)__bfloat16_as_ushort(a) | ((unsigned)__bfloat16_as_ushort(b) << 16);
}
static __device__ __forceinline__ void bsplit(float v, __nv_bfloat16& h, __nv_bfloat16& l) {
    h = __float2bfloat16(v);
    l = __float2bfloat16(v - __bfloat162float(h));
}
static __device__ __forceinline__ uint32_t swz128(uint32_t b) { return b ^ ((b >> 3) & 0x70); }
static __device__ __forceinline__ uint32_t smem_to_u32(const void* p) {
    uint32_t a;
    asm("{ .reg .u64 t; cvta.to.shared.u64 t, %1; cvt.u32.u64 %0, t; }" : "=r"(a) : "l"(p));
    return a;
}

// ---------- fp32 W staging (tail + fallbacks) ----------
template<int NIT>
struct Wreg { float f[NIT][4]; };

template<int NIT>
static __device__ __forceinline__ void ldgW(const float* __restrict__ W, int ldw, int k0,
                                            Wreg<NIT>& r, int tid) {
#pragma unroll
    for (int k = 0; k < NIT; ++k) {
        const int idx = tid + k * TPB;
        const int d = idx & 31, c4 = idx >> 5;
#pragma unroll
        for (int i = 0; i < 4; ++i)
            r.f[k][i] = W[(size_t)(c4 * 4 + i) * ldw + k0 + d];
    }
}
template<int NIT>
static __device__ __forceinline__ void stsW(float* sWT, const Wreg<NIT>& r, int tid) {
#pragma unroll
    for (int k = 0; k < NIT; ++k) {
        const int idx = tid + k * TPB;
        const int d = idx & 31, c4 = idx >> 5;
        *reinterpret_cast<float4*>(sWT + d * PW + c4 * 4) =
            make_float4(r.f[k][0], r.f[k][1], r.f[k][2], r.f[k][3]);
    }
}
static __device__ __forceinline__ void mma64b(const float* __restrict__ aRow, int lda,
                                              const float* __restrict__ sWT,
                                              u64 acc[8][4], int colg) {
#pragma unroll
    for (int d4 = 0; d4 < 8; ++d4) {
        float4 a4[8];
#pragma unroll
        for (int i = 0; i < 8; ++i)
            a4[i] = *reinterpret_cast<const float4*>(aRow + i * lda + (d4 << 2));
#pragma unroll
        for (int dd = 0; dd < 4; ++dd) {
            const int d = (d4 << 2) + dd;
            const ulonglong2 w0 = *reinterpret_cast<const ulonglong2*>(sWT + d * PW + (colg << 2));
            const ulonglong2 w1 = *reinterpret_cast<const ulonglong2*>(sWT + d * PW + 128 + (colg << 2));
#pragma unroll
            for (int i = 0; i < 8; ++i) {
                const u64 ad = dup2(comp4(a4[i], dd));
                acc[i][0] = ffma2(ad, w0.x, acc[i][0]);
                acc[i][1] = ffma2(ad, w0.y, acc[i][1]);
                acc[i][2] = ffma2(ad, w1.x, acc[i][2]);
                acc[i][3] = ffma2(ad, w1.y, acc[i][3]);
            }
        }
    }
}
static __device__ __forceinline__ void mmagb(const float* __restrict__ aRow, int lda,
                                             const float* __restrict__ sWT,
                                             u64 gacc[2], int colg) {
#pragma unroll
    for (int d4 = 0; d4 < 8; ++d4) {
        const float4 a0 = *reinterpret_cast<const float4*>(aRow + (d4 << 2));
        const float4 a1 = *reinterpret_cast<const float4*>(aRow + lda + (d4 << 2));
#pragma unroll
        for (int dd = 0; dd < 4; ++dd) {
            const u64 w = *reinterpret_cast<const u64*>(sWT + ((d4 << 2) + dd) * PW + colg * 2);
            gacc[0] = ffma2(dup2(comp4(a0, dd)), w, gacc[0]);
            gacc[1] = ffma2(dup2(comp4(a1, dd)), w, gacc[1]);
        }
    }
}

// reconstruct a weight element from 128n x 64k split tiles (fallback only)
static __device__ __forceinline__ float wrec128(const __nv_bfloat16* wt, int m, int n, int k) {
    const int nch = n >> 7, nn = n & 127, kch = k >> 6, kk = k & 63;
    const __nv_bfloat16* tb = wt + (size_t)(((m * 2 + nch) * 4 + kch)) * 16384;
    const uint32_t sw = swz128((uint32_t)(nn >> 3) * 1024 + (nn & 7) * 128 + kk * 2);
    return __bfloat162float(tb[sw >> 1]) + __bfloat162float(tb[8192 + (sw >> 1)]);
}
// reconstruct from 256n x 64k split tiles (fallback only)
static __device__ __forceinline__ float wrec256(const __nv_bfloat16* wt, int m, int n, int k) {
    const int kch = k >> 6, kk = k & 63;
    const __nv_bfloat16* tb = wt + (size_t)(m * 4 + kch) * 32768;
    const uint32_t sw = swz128((uint32_t)(n >> 3) * 1024 + (n & 7) * 128 + kk * 2);
    return __bfloat162float(tb[sw >> 1]) + __bfloat162float(tb[16384 + (sw >> 1)]);
}

#if GB_TC
// ---------- tcgen05 ----------
static __device__ __forceinline__ uint32_t elect_one_pred() {
    uint32_t pred;
    asm volatile(
        "{\n\t.reg .pred p;\n\telect.sync _|p, 0xFFFFFFFF;\n\tselp.b32 %0, 1, 0, p;\n\t}"
        : "=r"(pred));
    return pred;
}
#define TCGEN05_ALLOC(sa, n) \
    asm volatile("tcgen05.alloc.cta_group::1.sync.aligned.shared::cta.b32 [%0], %1;" \
                 :: "r"((uint32_t)(sa)), "r"((uint32_t)(n)) : "memory")
#define TCGEN05_DEALLOC(ta, n) \
    asm volatile("tcgen05.dealloc.cta_group::1.sync.aligned.b32 %0, %1;" :: "r"(ta), "r"((uint32_t)(n)))
#define TCGEN05_COMMIT(mb) \
    asm volatile("tcgen05.commit.cta_group::1.mbarrier::arrive::one.shared::cluster.b64 [%0];" \
                 :: "r"((uint32_t)(mb)) : "memory")
#define TCGEN05_WAIT_LD()  asm volatile("tcgen05.wait::ld.sync.aligned;" ::: "memory")
#define TCGEN05_FENCE_AFTER()  asm volatile("tcgen05.fence::after_thread_sync;" ::: "memory")
#define TCGEN05_FENCE_BEFORE() asm volatile("tcgen05.fence::before_thread_sync;" ::: "memory")
#define MBARRIER_INIT(mb, c) \
    asm volatile("mbarrier.init.shared.b64 [%0], %1;" :: "r"((uint32_t)(mb)), "r"((uint32_t)(c)) : "memory")
#define MBARRIER_WAIT_PARITY(mb, par) do { \
    uint32_t _mb = (uint32_t)(mb), _pa = (uint32_t)(par), _dn; \
    asm volatile("{\n\t.reg .pred p;\n\t" \
        "mbarrier.try_wait.parity.acquire.cta.shared::cta.b64 p, [%1], %2;\n\t" \
        "selp.b32 %0, 1, 0, p;\n\t}" : "=r"(_dn) : "r"(_mb), "r"(_pa) : "memory"); \
    if (!_dn) { \
        asm volatile("{\n\t.reg .pred P1;\n\t" \
            "WL_%=:\n\tmbarrier.try_wait.parity.acquire.cta.shared::cta.b64 P1, [%0], %1, 0x989680;\n\t" \
            "@P1 bra.uni WD_%=;\n\tbra.uni WL_%=;\n\tWD_%=:\n\t}" \
            :: "r"(_mb), "r"(_pa) : "memory"); \
    } \
} while (0)
#define TCGEN05_LD_32X32B_X32(r, ta) \
    asm volatile("tcgen05.ld.sync.aligned.32x32b.x32.b32 " \
        "{%0, %1, %2, %3, %4, %5, %6, %7, %8, %9, %10, %11, %12, %13, %14, %15, " \
        "%16, %17, %18, %19, %20, %21, %22, %23, %24, %25, %26, %27, %28, %29, %30, %31}, [%32];" \
        : "=r"((r)[0]),  "=r"((r)[1]),  "=r"((r)[2]),  "=r"((r)[3]), \
          "=r"((r)[4]),  "=r"((r)[5]),  "=r"((r)[6]),  "=r"((r)[7]), \
          "=r"((r)[8]),  "=r"((r)[9]),  "=r"((r)[10]), "=r"((r)[11]), \
          "=r"((r)[12]), "=r"((r)[13]), "=r"((r)[14]), "=r"((r)[15]), \
          "=r"((r)[16]), "=r"((r)[17]), "=r"((r)[18]), "=r"((r)[19]), \
          "=r"((r)[20]), "=r"((r)[21]), "=r"((r)[22]), "=r"((r)[23]), \
          "=r"((r)[24]), "=r"((r)[25]), "=r"((r)[26]), "=r"((r)[27]), \
          "=r"((r)[28]), "=r"((r)[29]), "=r"((r)[30]), "=r"((r)[31]) \
        : "r"(ta))

static constexpr u64 SMEM_DESC_BASE_SW128 =
    (u64(2) << 61) | (u64(1) << 46) | (u64(64) << 32) | (u64(1) << 16);
#define MAKE_SMEM_DESC(a) (SMEM_DESC_BASE_SW128 | ((u64)((a) >> 4) & 0x3FFF))

static __device__ __forceinline__ void mma_f16_ss(uint32_t d, u64 ad, u64 bd,
                                                  uint32_t idesc, uint32_t en) {
    asm volatile(
        "{\n\t.reg .pred p;\n\tsetp.ne.u32 p, %4, 0;\n\t"
        "tcgen05.mma.cta_group::1.kind::f16 [%0], %1, %2, %3, {%5, %5, %5, %5}, p;\n\t}"
        :: "r"(d), "l"(ad), "l"(bd), "r"(idesc), "r"(en), "r"(0u)
        : "memory");
}
#endif  // GB_TC

#define IDESC_BF16_M128_N128 0x8200490u
#define IDESC_BF16_M128_N256 0x8400490u

// =====================================================================
// Kernel 0: pre-split + pre-swizzle weights (f1,f2,Wk,Wv,Wq,Wo)
// =====================================================================
__global__ __launch_bounds__(256, 4)
void conv_w_kernel(const float* __restrict__ f1w, const float* __restrict__ f2w,
                   const float* __restrict__ Wk, const float* __restrict__ Wv,
                   const float* __restrict__ Wq, const float* __restrict__ Wo)
{
    const unsigned gidx = blockIdx.x * 256 + threadIdx.x;
    if (gidx < 2097152u) {
        const int arr = gidx >> 20;
        const unsigned rem = gidx & 0xFFFFFu;
        const int t = rem >> 14;
        const int e = rem & 16383;
        const int n = e >> 6, k = e & 63;
        const int m = t >> 4, c1 = (t >> 2) & 3, c2 = t & 3;
        float w;
        if (arr == 0)
            w = f1w[(size_t)m * 262144 + (size_t)(c1 * 256 + n) * 256 + c2 * 64 + k];
        else
            w = f2w[(size_t)m * 262144 + (size_t)n * 1024 + c1 * 256 + c2 * 64 + k];
        __nv_bfloat16 h, l;
        bsplit(w, h, l);
        const uint32_t sw = swz128((uint32_t)(n >> 3) * 1024 + (n & 7) * 128 + k * 2);
        __nv_bfloat16* dst = (arr == 0 ? g_w1t : g_w2t) + (size_t)t * 32768;
        dst[sw >> 1]           = h;
        dst[16384 + (sw >> 1)] = l;
    } else if (gidx < 2621440u) {
        const unsigned idx2 = gidx - 2097152u;
        const int arr2 = idx2 >> 18;
        const unsigned rem = idx2 & 0x3FFFFu;
        const int t = rem >> 13;
        const int e = rem & 8191;
        const int n = e >> 6, k = e & 63;
        const int m = t >> 3, nch = (t >> 2) & 1, kch = t & 3;
        const float* W = (arr2 == 0 ? Wk : Wv);
        const float w = W[(size_t)m * 65536 + (size_t)(nch * 128 + n) * 256 + kch * 64 + k];
        __nv_bfloat16 h, l;
        bsplit(w, h, l);
        const uint32_t sw = swz128((uint32_t)(n >> 3) * 1024 + (n & 7) * 128 + k * 2);
        __nv_bfloat16* dst = (arr2 == 0 ? g_wkt : g_wvt) + (size_t)t * 16384;
        dst[sw >> 1]          = h;
        dst[8192 + (sw >> 1)] = l;
    } else {
        const unsigned idx3 = gidx - 2621440u;
        const int arr3 = idx3 >> 18;
        const unsigned rem = idx3 & 0x3FFFFu;
        const int t = rem >> 14;
        const int e = rem & 16383;
        const int n = e >> 6, k = e & 63;
        const int m = t >> 2, kch = t & 3;
        const float* W = (arr3 == 0 ? Wq : Wo);
        float w = W[(size_t)m * 65536 + (size_t)n * 256 + kch * 64 + k];
        if (arr3 == 0) w *= 0.17677669529663687f;
        __nv_bfloat16 h, l;
        bsplit(w, h, l);
        const uint32_t sw = swz128((uint32_t)(n >> 3) * 1024 + (n & 7) * 128 + k * 2);
        __nv_bfloat16* dst = (arr3 == 0 ? g_wqt : g_wot) + (size_t)t * 32768;
        dst[sw >> 1]           = h;
        dst[16384 + (sw >> 1)] = l;
    }
}

// =====================================================================
// shared smem layout: A 128KB + 2 x (16KB hi + 16KB lo) B
// =====================================================================
#define KV_SMEM 197632
#define KV_MB0  16
#define KV_MB1  24
#define KV_AHI  1024
#define KV_ALO  66560
#define KV_B0H  132096
#define KV_B0L  148480
#define KV_B1H  164864
#define KV_B1L  181248

// =====================================================================
// Kernel A: fused Q,K,V projection + attention. grid 1024, 256 threads.
// Per m: Q -> TMEM cols 0-255, K -> 256-511 (16 pipelined chunks);
// epi1 computes softmax probs from TMEM; V -> cols 0-255 (overwrite Q);
// epi2 applies probs and writes Oh. Q/K/V never touch gmem.
// =====================================================================
__global__ __launch_bounds__(256, 1)
void gcma_kvattn(const float* __restrict__ x,
                 const float* __restrict__ bq,
                 const float* __restrict__ bk, const float* __restrict__ bv)
{
    extern __shared__ char smA[];
    const int tid = threadIdx.x;
    const int r0  = blockIdx.x * 128;

#if GB_TC
    const uint32_t sbase = smem_to_u32(smA);
    const int wid = tid >> 5, lane = tid & 31;
    char* sAhi = smA + KV_AHI;
    char* sAlo = smA + KV_ALO;

    if (wid == 0) TCGEN05_ALLOC(sbase + 0, 512);
    if (tid == 0) { MBARRIER_INIT(sbase + KV_MB0, 1); MBARRIER_INIT(sbase + KV_MB1, 1); }
    __syncthreads();
    uint32_t tmem;
    asm volatile("ld.shared.b32 %0, [%1];" : "=r"(tmem) : "r"(sbase + 0));

    // stage A: x rows r0..r0+127, split+swizzle
    for (int idx = tid; idx < 8192; idx += 256) {
        const int r = idx >> 6, k = (idx & 63) << 2;
        const float4 v = *reinterpret_cast<const float4*>(x + (size_t)(r0 + r) * 256 + k);
        __nv_bfloat16 h0, h1, h2, h3, l0, l1, l2, l3;
        bsplit(v.x, h0, l0); bsplit(v.y, h1, l1);
        bsplit(v.z, h2, l2); bsplit(v.w, h3, l3);
        const uint32_t sw = swz128((uint32_t)((r >> 3) + (k >> 6) * 16) * 1024 + (r & 7) * 128 + (k & 63) * 2);
        *reinterpret_cast<uint2*>(sAhi + sw) = make_uint2(pk2(h0, h1), pk2(h2, h3));
        *reinterpret_cast<uint2*>(sAlo + sw) = make_uint2(pk2(l0, l1), pk2(l2, l3));
    }

    const u64 aH = MAKE_SMEM_DESC(sbase + KV_AHI), aL = MAKE_SMEM_DESC(sbase + KV_ALO);
    const u64 b0H = MAKE_SMEM_DESC(sbase + KV_B0H), b0L = MAKE_SMEM_DESC(sbase + KV_B0L);
    const u64 b1H = MAKE_SMEM_DESC(sbase + KV_B1H), b1L = MAKE_SMEM_DESC(sbase + KV_B1L);

    const int rr = (wid & 3) * 32 + lane;      // row 0..127
    const int cb = (wid >> 2) * 128;           // col half
    const int b  = blockIdx.x * 32 + (rr >> 2);

    int w0 = 0, w1 = 0, pend0 = 0, pend1 = 0;

    for (int m = 0; m < 4; ++m) {
        // ======== phase 1: Q (cols 0-255) + K (cols 256-511), 16 chunks ========
        for (int t = 0; t < 16; ++t) {
            const int isK = t >> 3, nch = (t >> 2) & 1, kch = t & 3;
            const int buf = t & 1;
            if (buf == 0) { if (pend0) { MBARRIER_WAIT_PARITY(sbase + KV_MB0, w0 & 1); ++w0; pend0 = 0; } }
            else          { if (pend1) { MBARRIER_WAIT_PARITY(sbase + KV_MB1, w1 & 1); ++w1; pend1 = 0; } }
            // stage B tile (16KB hi + 16KB lo)
            {
                float4* dh = reinterpret_cast<float4*>(smA + (buf ? KV_B1H : KV_B0H));
                float4* dl = reinterpret_cast<float4*>(smA + (buf ? KV_B1L : KV_B0L));
                if (isK) {
                    const float4* s4 = reinterpret_cast<const float4*>(
                        g_wkt + (size_t)(((m * 2 + nch) * 4 + kch)) * 16384);
#pragma unroll
                    for (int i = 0; i < 4; ++i) {
                        dh[tid + i * 256] = s4[tid + i * 256];
                        dl[tid + i * 256] = s4[1024 + tid + i * 256];
                    }
                } else {
                    const float4* s4 = reinterpret_cast<const float4*>(
                        g_wqt + (size_t)(m * 4 + kch) * 32768);
#pragma unroll
                    for (int i = 0; i < 4; ++i) {
                        dh[tid + i * 256] = s4[nch * 1024 + tid + i * 256];
                        dl[tid + i * 256] = s4[2048 + nch * 1024 + tid + i * 256];
                    }
                }
            }
            __syncthreads();
            if (wid == 0) {
                asm volatile("fence.proxy.async.shared::cta;" ::: "memory");
                TCGEN05_FENCE_AFTER();
                if (elect_one_pred()) {
                    const u64 bH = buf ? b1H : b0H, bL = buf ? b1L : b0L;
                    const uint32_t dcol = tmem + isK * 256 + nch * 128;
#pragma unroll
                    for (int j = 0; j < 4; ++j) {
                        const u64 ao = (u64)(kch * 1024 + j * 2), bo = (u64)(j * 2);
                        mma_f16_ss(dcol, aH + ao, bH + bo, IDESC_BF16_M128_N128,
                                   (kch == 0 && j == 0) ? 0u : 1u);
                        mma_f16_ss(dcol, aH + ao, bL + bo, IDESC_BF16_M128_N128, 1u);
                        mma_f16_ss(dcol, aL + ao, bH + bo, IDESC_BF16_M128_N128, 1u);
                    }
                    TCGEN05_COMMIT(sbase + (buf ? KV_MB1 : KV_MB0));
                }
            }
            if (buf == 0) pend0 = 1; else pend1 = 1;
        }
        if (pend0) { MBARRIER_WAIT_PARITY(sbase + KV_MB0, w0 & 1); ++w0; pend0 = 0; }
        if (pend1) { MBARRIER_WAIT_PARITY(sbase + KV_MB1, w1 & 1); ++w1; pend1 = 0; }
        TCGEN05_FENCE_AFTER();

        // ======== epi1: scores + softmax -> p[4] ========
        float p[4];
        const int qlane = (lane & ~3) + m;   // quad lane holding row (b*4+m)
        for (int cc = 0; cc < 4; ++cc) {
            const int dof = cb + cc * 32;
            uint32_t qr[32];
            TCGEN05_LD_32X32B_X32(qr, tmem + dof);
            TCGEN05_WAIT_LD();
            uint32_t kr[32];
            TCGEN05_LD_32X32B_X32(kr, tmem + 256 + dof);
            TCGEN05_WAIT_LD();
            const float* bqp = bq + m * 256 + dof;
            const float* bkp = bk + m * 256 + dof;
            float s = 0.f;
#pragma unroll
            for (int j = 0; j < 32; ++j) {
                const float qv = __shfl_sync(0xffffffffu, __uint_as_float(qr[j]), qlane)
                               + bqp[j] * 0.17677669529663687f;
                s = fmaf(qv, __uint_as_float(kr[j]) + bkp[j], s);
            }
            float mx = s;
            mx = fmaxf(mx, __shfl_xor_sync(0xffffffffu, mx, 1));
            mx = fmaxf(mx, __shfl_xor_sync(0xffffffffu, mx, 2));
            float e = expf(s - mx);
            float se = e;
            se += __shfl_xor_sync(0xffffffffu, se, 1);
            se += __shfl_xor_sync(0xffffffffu, se, 2);
            p[cc] = e / se;
        }
        TCGEN05_FENCE_BEFORE();
        __syncthreads();   // all Q reads done before V overwrites cols 0-255

        // ======== phase 2: V (cols 0-255), 8 chunks ========
        for (int t = 0; t < 8; ++t) {
            const int nch = t >> 2, kch = t & 3;
            const int buf = t & 1;
            if (buf == 0) { if (pend0) { MBARRIER_WAIT_PARITY(sbase + KV_MB0, w0 & 1); ++w0; pend0 = 0; } }
            else          { if (pend1) { MBARRIER_WAIT_PARITY(sbase + KV_MB1, w1 & 1); ++w1; pend1 = 0; } }
            {
                const float4* s4 = reinterpret_cast<const float4*>(
                    g_wvt + (size_t)(((m * 2 + nch) * 4 + kch)) * 16384);
                float4* dh = reinterpret_cast<float4*>(smA + (buf ? KV_B1H : KV_B0H));
                float4* dl = reinterpret_cast<float4*>(smA + (buf ? KV_B1L : KV_B0L));
#pragma unroll
                for (int i = 0; i < 4; ++i) {
                    dh[tid + i * 256] = s4[tid + i * 256];
                    dl[tid + i * 256] = s4[1024 + tid + i * 256];
                }
            }
            __syncthreads();
            if (wid == 0) {
                asm volatile("fence.proxy.async.shared::cta;" ::: "memory");
                TCGEN05_FENCE_AFTER();
                if (elect_one_pred()) {
                    const u64 bH = buf ? b1H : b0H, bL = buf ? b1L : b0L;
                    const uint32_t dcol = tmem + nch * 128;
#pragma unroll
                    for (int j = 0; j < 4; ++j) {
                        const u64 ao = (u64)(kch * 1024 + j * 2), bo = (u64)(j * 2);
                        mma_f16_ss(dcol, aH + ao, bH + bo, IDESC_BF16_M128_N128,
                                   (kch == 0 && j == 0) ? 0u : 1u);
                        mma_f16_ss(dcol, aH + ao, bL + bo, IDESC_BF16_M128_N128, 1u);
                        mma_f16_ss(dcol, aL + ao, bH + bo, IDESC_BF16_M128_N128, 1u);
                    }
                    TCGEN05_COMMIT(sbase + (buf ? KV_MB1 : KV_MB0));
                }
            }
            if (buf == 0) pend0 = 1; else pend1 = 1;
        }
        if (pend0) { MBARRIER_WAIT_PARITY(sbase + KV_MB0, w0 & 1); ++w0; pend0 = 0; }
        if (pend1) { MBARRIER_WAIT_PARITY(sbase + KV_MB1, w1 & 1); ++w1; pend1 = 0; }
        TCGEN05_FENCE_AFTER();

        // ======== epi2: Oh = sum p_n * v_n ========
        for (int cc = 0; cc < 4; ++cc) {
            const int dof = cb + cc * 32;
            uint32_t vr[32];
            TCGEN05_LD_32X32B_X32(vr, tmem + dof);
            TCGEN05_WAIT_LD();
            const float* bvp = bv + m * 256 + dof;
            float t32[32];
#pragma unroll
            for (int j = 0; j < 32; ++j)
                t32[j] = p[cc] * (__uint_as_float(vr[j]) + bvp[j]);
#pragma unroll
            for (int j = 0; j < 32; ++j) {
                t32[j] += __shfl_xor_sync(0xffffffffu, t32[j], 1);
                t32[j] += __shfl_xor_sync(0xffffffffu, t32[j], 2);
            }
            const int qi = lane & 3;
            float* op = g_oh + ((size_t)m * 32768 + b) * 256 + dof + qi * 8;
            *reinterpret_cast<float4*>(op) =
                make_float4(t32[qi * 8 + 0], t32[qi * 8 + 1], t32[qi * 8 + 2], t32[qi * 8 + 3]);
            *reinterpret_cast<float4*>(op + 4) =
                make_float4(t32[qi * 8 + 4], t32[qi * 8 + 5], t32[qi * 8 + 6], t32[qi * 8 + 7]);
        }
        TCGEN05_FENCE_BEFORE();
        __syncthreads();   // all V reads done before next m overwrites
    }

    if (tid == 0) {
        asm volatile("mbarrier.inval.shared.b64 [%0];" :: "r"(sbase + KV_MB0) : "memory");
        asm volatile("mbarrier.inval.shared.b64 [%0];" :: "r"(sbase + KV_MB1) : "memory");
    }
    __syncthreads();
    if (wid == 0) TCGEN05_DEALLOC(tmem, 512);

#else  // fp32 fallback (slow; never runs on sm_103a)
    const int b = blockIdx.x * 32 + (tid >> 3);
    const int h = tid & 7;
    for (int m = 0; m < 4; ++m) {
        float q[32];
        for (int d = 0; d < 32; ++d) {
            float qd = bq[m * 256 + h * 32 + d] * 0.17677669529663687f;
            for (int k = 0; k < 256; ++k)
                qd = fmaf(x[(size_t)(b * 4 + m) * 256 + k], wrec256(g_wqt, m, h * 32 + d, k), qd);
            q[d] = qd;
        }
        float sc[4];
        for (int n = 0; n < 4; ++n) {
            float s = 0.f;
            for (int d = 0; d < 32; ++d) {
                float kd = bk[m * 256 + h * 32 + d];
                for (int k = 0; k < 256; ++k)
                    kd = fmaf(x[(size_t)(b * 4 + n) * 256 + k], wrec128(g_wkt, m, h * 32 + d, k), kd);
                s = fmaf(q[d], kd, s);
            }
            sc[n] = s;
        }
        const float mx = fmaxf(fmaxf(sc[0], sc[1]), fmaxf(sc[2], sc[3]));
        float e[4], se = 0.f;
        for (int n = 0; n < 4; ++n) { e[n] = expf(sc[n] - mx); se += e[n]; }
        for (int d = 0; d < 32; ++d) {
            float o = 0.f;
            for (int n = 0; n < 4; ++n) {
                float vd = bv[m * 256 + h * 32 + d];
                for (int k = 0; k < 256; ++k)
                    vd = fmaf(x[(size_t)(b * 4 + n) * 256 + k], wrec128(g_wvt, m, h * 32 + d, k), vd);
                o = fmaf(e[n] / se, vd, o);
            }
            g_oh[((size_t)m * 32768 + b) * 256 + h * 32 + d] = o;
        }
    }
#endif
}

// =====================================================================
// Kernel D: Wo projection (tcgen05, 8 double-buffered N=128 chunks)
// =====================================================================
__global__ __launch_bounds__(256, 1)
void gcma_qo(const float* __restrict__ bo)
{
    extern __shared__ char smQ[];
    const int tid = threadIdx.x;
    const int m   = blockIdx.y;
    const int b0  = blockIdx.x * 128;

    const __nv_bfloat16* wt = g_wot;
    const float* bias = bo + m * 256;
    float* dst = g_ao + ((size_t)m * 32768 + b0) * 256;

#if GB_TC
    const uint32_t sbase = smem_to_u32(smQ);
    const int wid = tid >> 5, lane = tid & 31;
    char* sAhi = smQ + KV_AHI;
    char* sAlo = smQ + KV_ALO;

    if (wid == 0) TCGEN05_ALLOC(sbase + 0, 512);
    if (tid == 0) { MBARRIER_INIT(sbase + KV_MB0, 1); MBARRIER_INIT(sbase + KV_MB1, 1); }
    __syncthreads();
    uint32_t tmem;
    asm volatile("ld.shared.b32 %0, [%1];" : "=r"(tmem) : "r"(sbase + 0));

    for (int idx = tid; idx < 8192; idx += 256) {
        const int r = idx >> 6, k = (idx & 63) << 2;
        const float4 v = *reinterpret_cast<const float4*>(
            g_oh + ((size_t)m * 32768 + b0 + r) * 256 + k);
        __nv_bfloat16 h0, h1, h2, h3, l0, l1, l2, l3;
        bsplit(v.x, h0, l0); bsplit(v.y, h1, l1);
        bsplit(v.z, h2, l2); bsplit(v.w, h3, l3);
        const uint32_t sw = swz128((uint32_t)((r >> 3) + (k >> 6) * 16) * 1024 + (r & 7) * 128 + (k & 63) * 2);
        *reinterpret_cast<uint2*>(sAhi + sw) = make_uint2(pk2(h0, h1), pk2(h2, h3));
        *reinterpret_cast<uint2*>(sAlo + sw) = make_uint2(pk2(l0, l1), pk2(l2, l3));
    }

    const u64 aH = MAKE_SMEM_DESC(sbase + KV_AHI), aL = MAKE_SMEM_DESC(sbase + KV_ALO);
    const u64 b0H = MAKE_SMEM_DESC(sbase + KV_B0H), b0L = MAKE_SMEM_DESC(sbase + KV_B0L);
    const u64 b1H = MAKE_SMEM_DESC(sbase + KV_B1H), b1L = MAKE_SMEM_DESC(sbase + KV_B1L);

    int w0 = 0, w1 = 0, pend0 = 0, pend1 = 0;
    for (int c = 0; c < 8; ++c) {
        const int nch = c >> 2, kch = c & 3;
        const int buf = c & 1;
        if (buf == 0) { if (pend0) { MBARRIER_WAIT_PARITY(sbase + KV_MB0, w0 & 1); ++w0; pend0 = 0; } }
        else          { if (pend1) { MBARRIER_WAIT_PARITY(sbase + KV_MB1, w1 & 1); ++w1; pend1 = 0; } }
        {
            const float4* s4 = reinterpret_cast<const float4*>(wt + (size_t)(m * 4 + kch) * 32768);
            float4* dh = reinterpret_cast<float4*>(smQ + (buf ? KV_B1H : KV_B0H));
            float4* dl = reinterpret_cast<float4*>(smQ + (buf ? KV_B1L : KV_B0L));
#pragma unroll
            for (int i = 0; i < 4; ++i) {
                dh[tid + i * 256] = s4[nch * 1024 + tid + i * 256];
                dl[tid + i * 256] = s4[2048 + nch * 1024 + tid + i * 256];
            }
        }
        __syncthreads();
        if (wid == 0) {
            asm volatile("fence.proxy.async.shared::cta;" ::: "memory");
            TCGEN05_FENCE_AFTER();
            if (elect_one_pred()) {
                const u64 bH = buf ? b1H : b0H, bL = buf ? b1L : b0L;
                const uint32_t dcol = tmem + nch * 128;
#pragma unroll
                for (int j = 0; j < 4; ++j) {
                    const u64 ao = (u64)(kch * 1024 + j * 2), bo2 = (u64)(j * 2);
                    mma_f16_ss(dcol, aH + ao, bH + bo2, IDESC_BF16_M128_N128,
                               (kch == 0 && j == 0) ? 0u : 1u);
                    mma_f16_ss(dcol, aH + ao, bL + bo2, IDESC_BF16_M128_N128, 1u);
                    mma_f16_ss(dcol, aL + ao, bH + bo2, IDESC_BF16_M128_N128, 1u);
                }
                TCGEN05_COMMIT(sbase + (buf ? KV_MB1 : KV_MB0));
            }
        }
        if (buf == 0) pend0 = 1; else pend1 = 1;
    }
    if (pend0) { MBARRIER_WAIT_PARITY(sbase + KV_MB0, w0 & 1); ++w0; pend0 = 0; }
    if (pend1) { MBARRIER_WAIT_PARITY(sbase + KV_MB1, w1 & 1); ++w1; pend1 = 0; }
    TCGEN05_FENCE_AFTER();

    {
        const int rr = (wid & 3) * 32 + lane;
        const int cb = (wid >> 2) * 128;
        for (int cc = 0; cc < 4; ++cc) {
            uint32_t dr[32];
            TCGEN05_LD_32X32B_X32(dr, tmem + cb + cc * 32);
            TCGEN05_WAIT_LD();
            TCGEN05_FENCE_BEFORE();
            const int c0 = cb + cc * 32;
            float* drow = dst + (size_t)rr * 256 + c0;
#pragma unroll
            for (int q = 0; q < 8; ++q) {
                *reinterpret_cast<float4*>(drow + q * 4) =
                    make_float4(__uint_as_float(dr[q * 4 + 0]) + bias[c0 + q * 4 + 0],
                                __uint_as_float(dr[q * 4 + 1]) + bias[c0 + q * 4 + 1],
                                __uint_as_float(dr[q * 4 + 2]) + bias[c0 + q * 4 + 2],
                                __uint_as_float(dr[q * 4 + 3]) + bias[c0 + q * 4 + 3]);
            }
        }
    }

    __syncthreads();
    if (tid == 0) {
        asm volatile("mbarrier.inval.shared.b64 [%0];" :: "r"(sbase + KV_MB0) : "memory");
        asm volatile("mbarrier.inval.shared.b64 [%0];" :: "r"(sbase + KV_MB1) : "memory");
    }
    __syncthreads();
    if (wid == 0) TCGEN05_DEALLOC(tmem, 512);

#else
    for (int e = tid; e < 128 * 256; e += 256) {
        const int r = e >> 8, n = e & 255;
        float dot = 0.f;
        for (int k = 0; k < 256; ++k)
            dot = fmaf(g_oh[((size_t)m * 32768 + b0 + r) * 256 + k], wrec256(wt, m, n, k), dot);
        dst[(size_t)r * 256 + n] = dot + bias[n];
    }
#endif
}

// =====================================================================
// Kernel E: gate MLP + LayerNorm, grid (2048,4)
// =====================================================================
#define TL_XM   0
#define TL_AO   4096
#define TL_WT   8192
#define TL_GH   16512
#define TL_GATE 17536
#define TL_FLOATS 17552
#define TL_BYTES  (TL_FLOATS * 4)

__global__ __launch_bounds__(256, 1)
void gcma_tail(const float* __restrict__ x,
               const float* __restrict__ g1w, const float* __restrict__ g1b,
               const float* __restrict__ g2w, const float* __restrict__ g2b,
               const float* __restrict__ lng, const float* __restrict__ lnb,
               float* __restrict__ out)
{
    extern __shared__ float smL[];
    float* sXm   = smL + TL_XM;
    float* sAO   = smL + TL_AO;
    float* sWT   = smL + TL_WT;
    float* sGH   = smL + TL_GH;
    float* sGate = smL + TL_GATE;

    const int tid = threadIdx.x;
    const int m   = blockIdx.y;
    const int b0  = blockIdx.x * 16;
    const long g0 = (long)b0 * 4;

    const int warp = tid >> 5;
    const int colg = tid & 31;

    for (int idx = tid; idx < 1024; idx += 256) {
        const int r = idx >> 6, q = idx & 63;
        *reinterpret_cast<float4*>(sXm + r * 256 + q * 4) =
            *reinterpret_cast<const float4*>(x + ((size_t)(b0 + r) * 4 + m) * 256 + q * 4);
        *reinterpret_cast<float4*>(sAO + r * 256 + q * 4) =
            *reinterpret_cast<const float4*>(g_ao + ((size_t)m * 32768 + b0 + r) * 256 + q * 4);
    }

    {
        const float* W = g1w + (size_t)m * 32768;
        Wreg<2> wr;
        ldgW<2>(W, 512, 0, wr, tid);
        u64 gacc[2] = {0ULL, 0ULL};
        for (int dt = 0; dt < 16; ++dt) {
            __syncthreads();
            stsW<2>(sWT, wr, tid);
            if (dt < 15) ldgW<2>(W, 512, (dt + 1) * 32, wr, tid);
            __syncthreads();
            if (dt < 8)
                mmagb(sXm + warp * 2 * 256 + dt * 32, 256, sWT, gacc, colg);
            else
                mmagb(sAO + warp * 2 * 256 + (dt - 8) * 32, 256, sWT, gacc, colg);
        }
        const float gb0 = g1b[m * 64 + colg * 2];
        const float gb1 = g1b[m * 64 + colg * 2 + 1];
#pragma unroll
        for (int i = 0; i < 2; ++i) {
            const float2 p = unpk(gacc[i]);
            sGH[(warp * 2 + i) * 64 + colg * 2]     = tanhf(p.x + gb0);
            sGH[(warp * 2 + i) * 64 + colg * 2 + 1] = tanhf(p.y + gb1);
        }
    }
    __syncthreads();

    if (tid < 16) {
        const float* g2 = g2w + m * 64;
        float dot = g2b[m];
#pragma unroll 8
        for (int j = 0; j < 64; ++j) dot = fmaf(sGH[tid * 64 + j], g2[j], dot);
        const float gate = 1.f / (1.f + expf(-dot));
        sGate[tid] = gate;
        out[OUT_GATE_BASE + (size_t)(b0 + tid) * 4 + m] = gate;
    }
    __syncthreads();

    {
        const int lane = tid & 31;
        for (int bl = warp; bl < 16; bl += 8) {
            const float* xr  = sXm + bl * 256;
            const float* aor = sAO + bl * 256;
            const float gate = sGate[bl];
            float r[8];
            float sum = 0.f;
#pragma unroll
            for (int k = 0; k < 8; ++k) {
                const int d = k * 32 + lane;
                r[k] = xr[d] + gate * aor[d];
                sum += r[k];
            }
#pragma unroll
            for (int o = 16; o; o >>= 1) sum += __shfl_xor_sync(0xffffffffu, sum, o);
            const float mu = sum * (1.f / 256.f);
            float var = 0.f;
#pragma unroll
            for (int k = 0; k < 8; ++k) { const float t = r[k] - mu; var = fmaf(t, t, var); }
#pragma unroll
            for (int o = 16; o; o >>= 1) var += __shfl_xor_sync(0xffffffffu, var, o);
            const float rs = rsqrtf(var * (1.f / 256.f) + 1e-5f);
            float* yr = g_y + (size_t)(g0 + bl * 4 + m) * 256;
#pragma unroll
            for (int k = 0; k < 8; ++k) {
                const int d = k * 32 + lane;
                yr[d] = (r[k] - mu) * rs * lng[m * 256 + d] + lnb[m * 256 + d];
            }
        }
    }
}

// =====================================================================
// Kernel F: FF (tcgen05)
// =====================================================================
#define P2_SMEM 197632
#define P2_TM    0
#define P2_MB    8
#define P2_AHI   1024
#define P2_ALO   66560
#define P2_BHI   132096
#define P2_BLO   164864

static __device__ __forceinline__ void loadB(const __nv_bfloat16* base, int m, int c1, int c2,
                                             float4 pf[16], int tid) {
    const float4* src = reinterpret_cast<const float4*>(base + (size_t)((m * 4 + c1) * 4 + c2) * 32768);
#pragma unroll
    for (int i = 0; i < 8; ++i) {
        pf[i]     = src[tid + i * 256];
        pf[8 + i] = src[2048 + tid + i * 256];
    }
}
static __device__ __forceinline__ void stsB(char* sBhi, char* sBlo, const float4 pf[16], int tid) {
#pragma unroll
    for (int i = 0; i < 8; ++i) {
        reinterpret_cast<float4*>(sBhi)[tid + i * 256] = pf[i];
        reinterpret_cast<float4*>(sBlo)[tid + i * 256] = pf[8 + i];
    }
}

__global__ __launch_bounds__(256, 1)
void gcma_part2tc(const float* __restrict__ f1w, const float* __restrict__ f1b,
                  const float* __restrict__ f2w, const float* __restrict__ f2b,
                  float* __restrict__ out)
{
    extern __shared__ char sm2[];
    const int tid  = threadIdx.x;
    const int m    = blockIdx.y;
    const int b0   = blockIdx.x * 128;

#if GB_TC
    const uint32_t sbase = smem_to_u32(sm2);
    const uint32_t TMP  = sbase + P2_TM;
    const uint32_t MBAR = sbase + P2_MB;
    char* sAhi = sm2 + P2_AHI;
    char* sAlo = sm2 + P2_ALO;
    char* sBhi = sm2 + P2_BHI;
    char* sBlo = sm2 + P2_BLO;
    const uint32_t aHiA = sbase + P2_AHI, aLoA = sbase + P2_ALO;
    const uint32_t bHiA = sbase + P2_BHI, bLoA = sbase + P2_BLO;

    const int wid  = tid >> 5, lane = tid & 31;
    unsigned* hfbase = g_hfscr + (size_t)(blockIdx.y * 256 + blockIdx.x) * 131072u;

    if (wid == 0) TCGEN05_ALLOC(TMP, 512);
    if (tid == 0) MBARRIER_INIT(MBAR, 1);
    __syncthreads();
    uint32_t tmem;
    asm volatile("ld.shared.b32 %0, [%1];" : "=r"(tmem) : "r"(TMP));

    for (int idx = tid; idx < 8192; idx += 256) {
        const int r = idx >> 6, k = (idx & 63) << 2;
        const float4 v = *reinterpret_cast<const float4*>(
            g_y + ((size_t)(b0 + r) * 4 + m) * 256 + k);
        __nv_bfloat16 h0, h1, h2, h3, l0, l1, l2, l3;
        bsplit(v.x, h0, l0); bsplit(v.y, h1, l1);
        bsplit(v.z, h2, l2); bsplit(v.w, h3, l3);
        const uint32_t sw = swz128((uint32_t)((r >> 3) + (k >> 6) * 16) * 1024 + (r & 7) * 128 + (k & 63) * 2);
        *reinterpret_cast<uint2*>(sAhi + sw) = make_uint2(pk2(h0, h1), pk2(h2, h3));
        *reinterpret_cast<uint2*>(sAlo + sw) = make_uint2(pk2(l0, l1), pk2(l2, l3));
    }

    float4 pf[16];
    loadB(g_w1t, m, 0, 0, pf, tid);
    int ph = 0;
    const u64 aH = MAKE_SMEM_DESC(aHiA), aL = MAKE_SMEM_DESC(aLoA);
    const u64 bH = MAKE_SMEM_DESC(bHiA), bL = MAKE_SMEM_DESC(bLoA);

    for (int nch = 0; nch < 4; ++nch) {
        for (int kch = 0; kch < 4; ++kch) {
            stsB(sBhi, sBlo, pf, tid);
            __syncthreads();
            if (wid == 0) {
                asm volatile("fence.proxy.async.shared::cta;" ::: "memory");
                TCGEN05_FENCE_AFTER();
                if (elect_one_pred()) {
#pragma unroll
                    for (int j = 0; j < 4; ++j) {
                        const u64 ao = (u64)(kch * 1024 + j * 2), bo = (u64)(j * 2);
                        mma_f16_ss(tmem, aH + ao, bH + bo, IDESC_BF16_M128_N256,
                                   (kch == 0 && j == 0) ? 0u : 1u);
                        mma_f16_ss(tmem, aH + ao, bL + bo, IDESC_BF16_M128_N256, 1u);
                        mma_f16_ss(tmem, aL + ao, bH + bo, IDESC_BF16_M128_N256, 1u);
                    }
                    TCGEN05_COMMIT(MBAR);
                }
            }
            const int nb = nch * 4 + kch + 1;
            if (nb < 16) loadB(g_w1t, m, nb >> 2, nb & 3, pf, tid);
            else         loadB(g_w2t, m, 0, 0, pf, tid);
            MBARRIER_WAIT_PARITY(MBAR, ph & 1);
            ++ph;
            TCGEN05_FENCE_AFTER();
        }
        {
            const int r  = (wid & 3) * 32 + lane;
            const int cb = (wid >> 2) * 128;
            for (int cc = 0; cc < 4; ++cc) {
                uint32_t dr[32];
                TCGEN05_LD_32X32B_X32(dr, tmem + cb + cc * 32);
                TCGEN05_WAIT_LD();
                TCGEN05_FENCE_BEFORE();
                const int c0 = nch * 256 + cb + cc * 32;
                unsigned* dst = hfbase + (size_t)r * 1024 + c0;
#pragma unroll
                for (int j = 0; j < 32; ++j) {
                    float v = __uint_as_float(dr[j]) + f1b[m * 1024 + c0 + j];
                    v = 0.5f * v * (1.f + erff(v * 0.7071067811865476f));
                    __nv_bfloat16 h, l;
                    bsplit(v, h, l);
                    dst[j] = pk2(h, l);
                }
            }
        }
        __syncthreads();
    }

    for (int ch = 0; ch < 4; ++ch) {
        for (int idx = tid; idx < 8192; idx += 256) {
            const int r = idx >> 6, k = (idx & 63) << 2;
            const uint4 u = *reinterpret_cast<const uint4*>(
                hfbase + (size_t)r * 1024 + ch * 256 + k);
            const unsigned uu[4] = {u.x, u.y, u.z, u.w};
            __nv_bfloat16 h[4], l[4];
#pragma unroll
            for (int j = 0; j < 4; ++j) {
                h[j] = __ushort_as_bfloat16((unsigned short)(uu[j] & 0xFFFFu));
                l[j] = __ushort_as_bfloat16((unsigned short)(uu[j] >> 16));
            }
            const uint32_t sw = swz128((uint32_t)((r >> 3) + (k >> 6) * 16) * 1024 + (r & 7) * 128 + (k & 63) * 2);
            *reinterpret_cast<uint2*>(sAhi + sw) = make_uint2(pk2(h[0], h[1]), pk2(h[2], h[3]));
            *reinterpret_cast<uint2*>(sAlo + sw) = make_uint2(pk2(l[0], l[1]), pk2(l[2], l[3]));
        }
        for (int kc = 0; kc < 4; ++kc) {
            stsB(sBhi, sBlo, pf, tid);
            __syncthreads();
            if (wid == 0) {
                asm volatile("fence.proxy.async.shared::cta;" ::: "memory");
                TCGEN05_FENCE_AFTER();
                if (elect_one_pred()) {
#pragma unroll
                    for (int j = 0; j < 4; ++j) {
                        const u64 ao = (u64)(kc * 1024 + j * 2), bo = (u64)(j * 2);
                        mma_f16_ss(tmem + 256, aH + ao, bH + bo, IDESC_BF16_M128_N256,
                                   (ch == 0 && kc == 0 && j == 0) ? 0u : 1u);
                        mma_f16_ss(tmem + 256, aH + ao, bL + bo, IDESC_BF16_M128_N256, 1u);
                        mma_f16_ss(tmem + 256, aL + ao, bH + bo, IDESC_BF16_M128_N256, 1u);
                    }
                    TCGEN05_COMMIT(MBAR);
                }
            }
            const int nb = ch * 4 + kc + 1;
            if (nb < 16) loadB(g_w2t, m, nb >> 2, nb & 3, pf, tid);
            MBARRIER_WAIT_PARITY(MBAR, ph & 1);
            ++ph;
            TCGEN05_FENCE_AFTER();
        }
    }

    {
        const int r  = (wid & 3) * 32 + lane;
        const int cb = (wid >> 2) * 128;
        for (int cc = 0; cc < 4; ++cc) {
            uint32_t dr[32];
            TCGEN05_LD_32X32B_X32(dr, tmem + 256 + cb + cc * 32);
            TCGEN05_WAIT_LD();
            TCGEN05_FENCE_BEFORE();
            const int c0 = cb + cc * 32;
            const float* yrow = g_y + ((size_t)(b0 + r) * 4 + m) * 256 + c0;
            float* orow = out + ((size_t)(b0 + r) * 4 + m) * 256 + c0;
#pragma unroll
            for (int j = 0; j < 32; ++j)
                orow[j] = yrow[j] + __uint_as_float(dr[j]) + f2b[m * 256 + c0 + j];
        }
    }

    __syncthreads();
    if (tid == 0)
        asm volatile("mbarrier.inval.shared.b64 [%0];" :: "r"(MBAR) : "memory");
    __syncthreads();
    if (wid == 0) TCGEN05_DEALLOC(tmem, 512);

#else
    float* smf = reinterpret_cast<float*>(sm2);
    float* sY  = smf;
    float* sHF = smf + 16384;
    float* sWT = smf + 32768;
    const int warp = tid >> 5;
    const int colg = tid & 31;

    for (int half = 0; half < 2; ++half) {
        const int hb0 = b0 + half * 64;
        __syncthreads();
        for (int idx = tid; idx < 4096; idx += TPB) {
            const int r = idx >> 6, q = idx & 63;
            *reinterpret_cast<float4*>(sY + r * 256 + q * 4) =
                *reinterpret_cast<const float4*>(g_y + ((size_t)(hb0 + r) * 4 + m) * 256 + q * 4);
        }
        u64 facc[8][4];
#pragma unroll
        for (int i = 0; i < 8; ++i)
#pragma unroll
            for (int j = 0; j < 4; ++j) facc[i][j] = 0ULL;
        const float* aY  = sY  + warp * 8 * 256;
        const float* aHF = sHF + warp * 8 * 256;

        for (int ch = 0; ch < 4; ++ch) {
            u64 hacc[8][4];
#pragma unroll
            for (int i = 0; i < 8; ++i)
#pragma unroll
                for (int j = 0; j < 4; ++j) hacc[i][j] = 0ULL;
            {
                const float* W1 = f1w + (size_t)m * 262144 + (size_t)ch * 65536;
                Wreg<8> wr;
                ldgW<8>(W1, 256, 0, wr, tid);
                for (int dt = 0; dt < 8; ++dt) {
                    __syncthreads();
                    stsW<8>(sWT, wr, tid);
                    if (dt < 7) ldgW<8>(W1, 256, (dt + 1) * 32, wr, tid);
                    __syncthreads();
                    mma64b(aY + dt * 32, 256, sWT, hacc, colg);
                }
            }
            __syncthreads();
            {
                const float* b1 = f1b + m * 1024 + ch * 256;
                float bl0[4], bl1[4];
#pragma unroll
                for (int j = 0; j < 4; ++j) { bl0[j] = b1[colg * 4 + j]; bl1[j] = b1[128 + colg * 4 + j]; }
#pragma unroll
                for (int i = 0; i < 8; ++i) {
                    const int r = warp * 8 + i;
                    const float2 pa = unpk(hacc[i][0]), pb = unpk(hacc[i][1]);
                    const float2 pc = unpk(hacc[i][2]), pd = unpk(hacc[i][3]);
                    float v0[4] = {pa.x + bl0[0], pa.y + bl0[1], pb.x + bl0[2], pb.y + bl0[3]};
                    float v1[4] = {pc.x + bl1[0], pc.y + bl1[1], pd.x + bl1[2], pd.y + bl1[3]};
#pragma unroll
                    for (int j = 0; j < 4; ++j) {
                        v0[j] = 0.5f * v0[j] * (1.f + erff(v0[j] * 0.7071067811865476f));
                        v1[j] = 0.5f * v1[j] * (1.f + erff(v1[j] * 0.7071067811865476f));
                    }
                    *reinterpret_cast<float4*>(sHF + r * 256 + colg * 4) =
                        make_float4(v0[0], v0[1], v0[2], v0[3]);
                    *reinterpret_cast<float4*>(sHF + r * 256 + 128 + colg * 4) =
                        make_float4(v1[0], v1[1], v1[2], v1[3]);
                }
            }
            {
                const float* W2 = f2w + (size_t)m * 262144;
                Wreg<8> wr;
                ldgW<8>(W2, 1024, ch * 256, wr, tid);
                for (int dt = 0; dt < 8; ++dt) {
                    __syncthreads();
                    stsW<8>(sWT, wr, tid);
                    if (dt < 7) ldgW<8>(W2, 1024, ch * 256 + (dt + 1) * 32, wr, tid);
                    __syncthreads();
                    mma64b(aHF + dt * 32, 256, sWT, facc, colg);
                }
            }
            __syncthreads();
        }
        {
            const float* b2 = f2b + m * 256;
            float bl0[4], bl1[4];
#pragma unroll
            for (int j = 0; j < 4; ++j) { bl0[j] = b2[colg * 4 + j]; bl1[j] = b2[128 + colg * 4 + j]; }
#pragma unroll
            for (int i = 0; i < 8; ++i) {
                const int r = warp * 8 + i;
                const float4 y0 = *reinterpret_cast<const float4*>(sY + r * 256 + colg * 4);
                const float4 y1 = *reinterpret_cast<const float4*>(sY + r * 256 + 128 + colg * 4);
                const float2 pa = unpk(facc[i][0]), pb = unpk(facc[i][1]);
                const float2 pc = unpk(facc[i][2]), pd = unpk(facc[i][3]);
                float* op = out + ((size_t)(hb0 + r) * 4 + m) * 256;
                *reinterpret_cast<float4*>(op + colg * 4) =
                    make_float4(y0.x + pa.x + bl0[0], y0.y + pa.y + bl0[1],
                                y0.z + pb.x + bl0[2], y0.w + pb.y + bl0[3]);
                *reinterpret_cast<float4*>(op + 128 + colg * 4) =
                    make_float4(y1.x + pc.x + bl1[0], y1.y + pc.y + bl1[1],
                                y1.z + pd.x + bl1[2], y1.w + pd.y + bl1[3]);
            }
        }
    }
#endif
}

extern "C" void kernel_launch(void* const* d_in, const int* in_sizes, int n_in,
                              void* d_out, int out_size) {
    const float* x   = (const float*)d_in[0];
    const float* Wq  = (const float*)d_in[1];
    const float* bq  = (const float*)d_in[2];
    const float* Wk  = (const float*)d_in[3];
    const float* bk  = (const float*)d_in[4];
    const float* Wv  = (const float*)d_in[5];
    const float* bv  = (const float*)d_in[6];
    const float* Wo  = (const float*)d_in[7];
    const float* bo  = (const float*)d_in[8];
    const float* g1w = (const float*)d_in[9];
    const float* g1b = (const float*)d_in[10];
    const float* g2w = (const float*)d_in[11];
    const float* g2b = (const float*)d_in[12];
    const float* lng = (const float*)d_in[13];
    const float* lnb = (const float*)d_in[14];
    const float* f1w = (const float*)d_in[15];
    const float* f1b = (const float*)d_in[16];
    const float* f2w = (const float*)d_in[17];
    const float* f2b = (const float*)d_in[18];
    float* out = (float*)d_out;

    cudaFuncSetAttribute(gcma_kvattn, cudaFuncAttributeMaxDynamicSharedMemorySize, KV_SMEM);
    cudaFuncSetAttribute(gcma_qo, cudaFuncAttributeMaxDynamicSharedMemorySize, KV_SMEM);
    cudaFuncSetAttribute(gcma_tail, cudaFuncAttributeMaxDynamicSharedMemorySize, TL_BYTES);
    cudaFuncSetAttribute(gcma_part2tc, cudaFuncAttributeMaxDynamicSharedMemorySize, P2_SMEM);

    conv_w_kernel<<<12288, 256>>>(f1w, f2w, Wk, Wv, Wq, Wo);
    gcma_kvattn<<<1024, 256, KV_SMEM>>>(x, bq, bk, bv);
    gcma_qo<<<dim3(256, 4), 256, KV_SMEM>>>(bo);
    gcma_tail<<<dim3(2048, 4), 256, TL_BYTES>>>(x, g1w, g1b, g2w, g2b, lng, lnb, out);
    gcma_part2tc<<<dim3(256, 4), 256, P2_SMEM>>>(f1w, f1b, f2w, f2b, out);
}

// round 15
// speedup vs baseline: 3.0982x; 1.0304x over previous
#include <cuda_runtime.h>
#include <cuda_bf16.h>
#include <math.h>
#include <stdint.h>

typedef unsigned long long u64;

#define TPB 256
#define PW 260

#define OUT_GATE_BASE 33554432UL   // B*M*D

#if defined(__CUDA_ARCH_FEAT_SM103_ALL) || \
    (defined(__CUDA_ARCH_SPECIFIC__) && (__CUDA_ARCH_SPECIFIC__ == 1030)) || \
    (defined(__CUDA_ARCH_FAMILY_SPECIFIC__) && (__CUDA_ARCH_FAMILY_SPECIFIC__ == 1030))
#define GB_TC 1
#else
#define GB_TC 0
#endif

// scratch
__device__ float g_y [32768u * 4u * 256u];                // 128MB
__device__ float g_oh[4u * 32768u * 256u];                // 128MB  Oh[m][b][256]
__device__ float g_ao[4u * 32768u * 256u];                // 128MB  attn_out[m][b][256]
__device__ __nv_bfloat16 g_w1t[64u * 32768u];             // FF1 tiles (hi|lo)
__device__ __nv_bfloat16 g_w2t[64u * 32768u];             // FF2 tiles
__device__ __nv_bfloat16 g_wkt[32u * 16384u];             // Wk tiles 128n x 64k (hi|lo)
__device__ __nv_bfloat16 g_wvt[32u * 16384u];             // Wv tiles
__device__ __nv_bfloat16 g_wqt[16u * 32768u];             // Wq tiles 256n x 64k (scaled)
__device__ __nv_bfloat16 g_wot[16u * 32768u];             // Wo tiles 256n x 64k
__device__ unsigned g_hfscr[1024u * 131072u];             // hf scratch

// ---------- helpers ----------
static __device__ __forceinline__ u64 ffma2(u64 a, u64 b, u64 c) {
    u64 d;
    asm("fma.rn.f32x2 %0, %1, %2, %3;" : "=l"(d) : "l"(a), "l"(b), "l"(c));
    return d;
}
static __device__ __forceinline__ u64 dup2(float a) {
    u64 d;
    asm("mov.b64 %0, {%1, %1};" : "=l"(d) : "f"(a));
    return d;
}
static __device__ __forceinline__ float2 unpk(u64 p) {
    float2 r;
    asm("mov.b64 {%0, %1}, %2;" : "=f"(r.x), "=f"(r.y) : "l"(p));
    return r;
}
static __device__ __forceinline__ float comp4(const float4& v, int dd) {
    return dd == 0 ? v.x : dd == 1 ? v.y : dd == 2 ? v.z : v.w;
}
static __device__ __forceinline__ unsigned pk2(__nv_bfloat16 a, __nv_bfloat16 b) {
    return (unsigned)__bfloat16_as_ushort(a) | ((unsigned)__bfloat16_as_ushort(b) << 16);
}
static __device__ __forceinline__ void bsplit(float v, __nv_bfloat16& h, __nv_bfloat16& l) {
    h = __float2bfloat16(v);
    l = __float2bfloat16(v - __bfloat162float(h));
}
static __device__ __forceinline__ uint32_t swz128(uint32_t b) { return b ^ ((b >> 3) & 0x70); }
static __device__ __forceinline__ uint32_t smem_to_u32(const void* p) {
    uint32_t a;
    asm("{ .reg .u64 t; cvta.to.shared.u64 t, %1; cvt.u32.u64 %0, t; }" : "=r"(a) : "l"(p));
    return a;
}

// ---------- fp32 W staging (tail + fallbacks) ----------
template<int NIT>
struct Wreg { float f[NIT][4]; };

template<int NIT>
static __device__ __forceinline__ void ldgW(const float* __restrict__ W, int ldw, int k0,
                                            Wreg<NIT>& r, int tid) {
#pragma unroll
    for (int k = 0; k < NIT; ++k) {
        const int idx = tid + k * TPB;
        const int d = idx & 31, c4 = idx >> 5;
#pragma unroll
        for (int i = 0; i < 4; ++i)
            r.f[k][i] = W[(size_t)(c4 * 4 + i) * ldw + k0 + d];
    }
}
template<int NIT>
static __device__ __forceinline__ void stsW(float* sWT, const Wreg<NIT>& r, int tid) {
#pragma unroll
    for (int k = 0; k < NIT; ++k) {
        const int idx = tid + k * TPB;
        const int d = idx & 31, c4 = idx >> 5;
        *reinterpret_cast<float4*>(sWT + d * PW + c4 * 4) =
            make_float4(r.f[k][0], r.f[k][1], r.f[k][2], r.f[k][3]);
    }
}
static __device__ __forceinline__ void mma64b(const float* __restrict__ aRow, int lda,
                                              const float* __restrict__ sWT,
                                              u64 acc[8][4], int colg) {
#pragma unroll
    for (int d4 = 0; d4 < 8; ++d4) {
        float4 a4[8];
#pragma unroll
        for (int i = 0; i < 8; ++i)
            a4[i] = *reinterpret_cast<const float4*>(aRow + i * lda + (d4 << 2));
#pragma unroll
        for (int dd = 0; dd < 4; ++dd) {
            const int d = (d4 << 2) + dd;
            const ulonglong2 w0 = *reinterpret_cast<const ulonglong2*>(sWT + d * PW + (colg << 2));
            const ulonglong2 w1 = *reinterpret_cast<const ulonglong2*>(sWT + d * PW + 128 + (colg << 2));
#pragma unroll
            for (int i = 0; i < 8; ++i) {
                const u64 ad = dup2(comp4(a4[i], dd));
                acc[i][0] = ffma2(ad, w0.x, acc[i][0]);
                acc[i][1] = ffma2(ad, w0.y, acc[i][1]);
                acc[i][2] = ffma2(ad, w1.x, acc[i][2]);
                acc[i][3] = ffma2(ad, w1.y, acc[i][3]);
            }
        }
    }
}
// gate1 mma: 8 rows per warp, 2 cols per lane (packed u64)
static __device__ __forceinline__ void mmagb8(const float* __restrict__ aRow, int lda,
                                              const float* __restrict__ sWT,
                                              u64 gacc[8], int colg) {
#pragma unroll
    for (int d4 = 0; d4 < 8; ++d4) {
        float4 a4[8];
#pragma unroll
        for (int i = 0; i < 8; ++i)
            a4[i] = *reinterpret_cast<const float4*>(aRow + i * lda + (d4 << 2));
#pragma unroll
        for (int dd = 0; dd < 4; ++dd) {
            const u64 w = *reinterpret_cast<const u64*>(sWT + ((d4 << 2) + dd) * PW + colg * 2);
#pragma unroll
            for (int i = 0; i < 8; ++i)
                gacc[i] = ffma2(dup2(comp4(a4[i], dd)), w, gacc[i]);
        }
    }
}

// reconstruct a weight element from 128n x 64k split tiles (fallback only)
static __device__ __forceinline__ float wrec128(const __nv_bfloat16* wt, int m, int n, int k) {
    const int nch = n >> 7, nn = n & 127, kch = k >> 6, kk = k & 63;
    const __nv_bfloat16* tb = wt + (size_t)(((m * 2 + nch) * 4 + kch)) * 16384;
    const uint32_t sw = swz128((uint32_t)(nn >> 3) * 1024 + (nn & 7) * 128 + kk * 2);
    return __bfloat162float(tb[sw >> 1]) + __bfloat162float(tb[8192 + (sw >> 1)]);
}
// reconstruct from 256n x 64k split tiles (fallback only)
static __device__ __forceinline__ float wrec256(const __nv_bfloat16* wt, int m, int n, int k) {
    const int kch = k >> 6, kk = k & 63;
    const __nv_bfloat16* tb = wt + (size_t)(m * 4 + kch) * 32768;
    const uint32_t sw = swz128((uint32_t)(n >> 3) * 1024 + (n & 7) * 128 + kk * 2);
    return __bfloat162float(tb[sw >> 1]) + __bfloat162float(tb[16384 + (sw >> 1)]);
}

#if GB_TC
// ---------- tcgen05 ----------
static __device__ __forceinline__ uint32_t elect_one_pred() {
    uint32_t pred;
    asm volatile(
        "{\n\t.reg .pred p;\n\telect.sync _|p, 0xFFFFFFFF;\n\tselp.b32 %0, 1, 0, p;\n\t}"
        : "=r"(pred));
    return pred;
}
#define TCGEN05_ALLOC(sa, n) \
    asm volatile("tcgen05.alloc.cta_group::1.sync.aligned.shared::cta.b32 [%0], %1;" \
                 :: "r"((uint32_t)(sa)), "r"((uint32_t)(n)) : "memory")
#define TCGEN05_DEALLOC(ta, n) \
    asm volatile("tcgen05.dealloc.cta_group::1.sync.aligned.b32 %0, %1;" :: "r"(ta), "r"((uint32_t)(n)))
#define TCGEN05_COMMIT(mb) \
    asm volatile("tcgen05.commit.cta_group::1.mbarrier::arrive::one.shared::cluster.b64 [%0];" \
                 :: "r"((uint32_t)(mb)) : "memory")
#define TCGEN05_WAIT_LD()  asm volatile("tcgen05.wait::ld.sync.aligned;" ::: "memory")
#define TCGEN05_FENCE_AFTER()  asm volatile("tcgen05.fence::after_thread_sync;" ::: "memory")
#define TCGEN05_FENCE_BEFORE() asm volatile("tcgen05.fence::before_thread_sync;" ::: "memory")
#define MBARRIER_INIT(mb, c) \
    asm volatile("mbarrier.init.shared.b64 [%0], %1;" :: "r"((uint32_t)(mb)), "r"((uint32_t)(c)) : "memory")
#define MBARRIER_WAIT_PARITY(mb, par) do { \
    uint32_t _mb = (uint32_t)(mb), _pa = (uint32_t)(par), _dn; \
    asm volatile("{\n\t.reg .pred p;\n\t" \
        "mbarrier.try_wait.parity.acquire.cta.shared::cta.b64 p, [%1], %2;\n\t" \
        "selp.b32 %0, 1, 0, p;\n\t}" : "=r"(_dn) : "r"(_mb), "r"(_pa) : "memory"); \
    if (!_dn) { \
        asm volatile("{\n\t.reg .pred P1;\n\t" \
            "WL_%=:\n\tmbarrier.try_wait.parity.acquire.cta.shared::cta.b64 P1, [%0], %1, 0x989680;\n\t" \
            "@P1 bra.uni WD_%=;\n\tbra.uni WL_%=;\n\tWD_%=:\n\t}" \
            :: "r"(_mb), "r"(_pa) : "memory"); \
    } \
} while (0)
#define TCGEN05_LD_32X32B_X32(r, ta) \
    asm volatile("tcgen05.ld.sync.aligned.32x32b.x32.b32 " \
        "{%0, %1, %2, %3, %4, %5, %6, %7, %8, %9, %10, %11, %12, %13, %14, %15, " \
        "%16, %17, %18, %19, %20, %21, %22, %23, %24, %25, %26, %27, %28, %29, %30, %31}, [%32];" \
        : "=r"((r)[0]),  "=r"((r)[1]),  "=r"((r)[2]),  "=r"((r)[3]), \
          "=r"((r)[4]),  "=r"((r)[5]),  "=r"((r)[6]),  "=r"((r)[7]), \
          "=r"((r)[8]),  "=r"((r)[9]),  "=r"((r)[10]), "=r"((r)[11]), \
          "=r"((r)[12]), "=r"((r)[13]), "=r"((r)[14]), "=r"((r)[15]), \
          "=r"((r)[16]), "=r"((r)[17]), "=r"((r)[18]), "=r"((r)[19]), \
          "=r"((r)[20]), "=r"((r)[21]), "=r"((r)[22]), "=r"((r)[23]), \
          "=r"((r)[24]), "=r"((r)[25]), "=r"((r)[26]), "=r"((r)[27]), \
          "=r"((r)[28]), "=r"((r)[29]), "=r"((r)[30]), "=r"((r)[31]) \
        : "r"(ta))

static constexpr u64 SMEM_DESC_BASE_SW128 =
    (u64(2) << 61) | (u64(1) << 46) | (u64(64) << 32) | (u64(1) << 16);
#define MAKE_SMEM_DESC(a) (SMEM_DESC_BASE_SW128 | ((u64)((a) >> 4) & 0x3FFF))

static __device__ __forceinline__ void mma_f16_ss(uint32_t d, u64 ad, u64 bd,
                                                  uint32_t idesc, uint32_t en) {
    asm volatile(
        "{\n\t.reg .pred p;\n\tsetp.ne.u32 p, %4, 0;\n\t"
        "tcgen05.mma.cta_group::1.kind::f16 [%0], %1, %2, %3, {%5, %5, %5, %5}, p;\n\t}"
        :: "r"(d), "l"(ad), "l"(bd), "r"(idesc), "r"(en), "r"(0u)
        : "memory");
}
#endif  // GB_TC

#define IDESC_BF16_M128_N128 0x8200490u
#define IDESC_BF16_M128_N256 0x8400490u

// =====================================================================
// Kernel 0: pre-split + pre-swizzle weights (f1,f2,Wk,Wv,Wq,Wo)
// =====================================================================
__global__ __launch_bounds__(256, 4)
void conv_w_kernel(const float* __restrict__ f1w, const float* __restrict__ f2w,
                   const float* __restrict__ Wk, const float* __restrict__ Wv,
                   const float* __restrict__ Wq, const float* __restrict__ Wo)
{
    const unsigned gidx = blockIdx.x * 256 + threadIdx.x;
    if (gidx < 2097152u) {
        const int arr = gidx >> 20;
        const unsigned rem = gidx & 0xFFFFFu;
        const int t = rem >> 14;
        const int e = rem & 16383;
        const int n = e >> 6, k = e & 63;
        const int m = t >> 4, c1 = (t >> 2) & 3, c2 = t & 3;
        float w;
        if (arr == 0)
            w = f1w[(size_t)m * 262144 + (size_t)(c1 * 256 + n) * 256 + c2 * 64 + k];
        else
            w = f2w[(size_t)m * 262144 + (size_t)n * 1024 + c1 * 256 + c2 * 64 + k];
        __nv_bfloat16 h, l;
        bsplit(w, h, l);
        const uint32_t sw = swz128((uint32_t)(n >> 3) * 1024 + (n & 7) * 128 + k * 2);
        __nv_bfloat16* dst = (arr == 0 ? g_w1t : g_w2t) + (size_t)t * 32768;
        dst[sw >> 1]           = h;
        dst[16384 + (sw >> 1)] = l;
    } else if (gidx < 2621440u) {
        const unsigned idx2 = gidx - 2097152u;
        const int arr2 = idx2 >> 18;
        const unsigned rem = idx2 & 0x3FFFFu;
        const int t = rem >> 13;
        const int e = rem & 8191;
        const int n = e >> 6, k = e & 63;
        const int m = t >> 3, nch = (t >> 2) & 1, kch = t & 3;
        const float* W = (arr2 == 0 ? Wk : Wv);
        const float w = W[(size_t)m * 65536 + (size_t)(nch * 128 + n) * 256 + kch * 64 + k];
        __nv_bfloat16 h, l;
        bsplit(w, h, l);
        const uint32_t sw = swz128((uint32_t)(n >> 3) * 1024 + (n & 7) * 128 + k * 2);
        __nv_bfloat16* dst = (arr2 == 0 ? g_wkt : g_wvt) + (size_t)t * 16384;
        dst[sw >> 1]          = h;
        dst[8192 + (sw >> 1)] = l;
    } else {
        const unsigned idx3 = gidx - 2621440u;
        const int arr3 = idx3 >> 18;
        const unsigned rem = idx3 & 0x3FFFFu;
        const int t = rem >> 14;
        const int e = rem & 16383;
        const int n = e >> 6, k = e & 63;
        const int m = t >> 2, kch = t & 3;
        const float* W = (arr3 == 0 ? Wq : Wo);
        float w = W[(size_t)m * 65536 + (size_t)n * 256 + kch * 64 + k];
        if (arr3 == 0) w *= 0.17677669529663687f;
        __nv_bfloat16 h, l;
        bsplit(w, h, l);
        const uint32_t sw = swz128((uint32_t)(n >> 3) * 1024 + (n & 7) * 128 + k * 2);
        __nv_bfloat16* dst = (arr3 == 0 ? g_wqt : g_wot) + (size_t)t * 32768;
        dst[sw >> 1]           = h;
        dst[16384 + (sw >> 1)] = l;
    }
}

// =====================================================================
// shared smem layout: A 128KB + 2 x (16KB hi + 16KB lo) B
// =====================================================================
#define KV_SMEM 197632
#define KV_MB0  16
#define KV_MB1  24
#define KV_AHI  1024
#define KV_ALO  66560
#define KV_B0H  132096
#define KV_B0L  148480
#define KV_B1H  164864
#define KV_B1L  181248

// =====================================================================
// Kernel A: fused Q,K,V projection + attention. grid 1024, 256 threads.
// =====================================================================
__global__ __launch_bounds__(256, 1)
void gcma_kvattn(const float* __restrict__ x,
                 const float* __restrict__ bq,
                 const float* __restrict__ bk, const float* __restrict__ bv)
{
    extern __shared__ char smA[];
    const int tid = threadIdx.x;
    const int r0  = blockIdx.x * 128;

#if GB_TC
    const uint32_t sbase = smem_to_u32(smA);
    const int wid = tid >> 5, lane = tid & 31;
    char* sAhi = smA + KV_AHI;
    char* sAlo = smA + KV_ALO;

    if (wid == 0) TCGEN05_ALLOC(sbase + 0, 512);
    if (tid == 0) { MBARRIER_INIT(sbase + KV_MB0, 1); MBARRIER_INIT(sbase + KV_MB1, 1); }
    __syncthreads();
    uint32_t tmem;
    asm volatile("ld.shared.b32 %0, [%1];" : "=r"(tmem) : "r"(sbase + 0));

    for (int idx = tid; idx < 8192; idx += 256) {
        const int r = idx >> 6, k = (idx & 63) << 2;
        const float4 v = *reinterpret_cast<const float4*>(x + (size_t)(r0 + r) * 256 + k);
        __nv_bfloat16 h0, h1, h2, h3, l0, l1, l2, l3;
        bsplit(v.x, h0, l0); bsplit(v.y, h1, l1);
        bsplit(v.z, h2, l2); bsplit(v.w, h3, l3);
        const uint32_t sw = swz128((uint32_t)((r >> 3) + (k >> 6) * 16) * 1024 + (r & 7) * 128 + (k & 63) * 2);
        *reinterpret_cast<uint2*>(sAhi + sw) = make_uint2(pk2(h0, h1), pk2(h2, h3));
        *reinterpret_cast<uint2*>(sAlo + sw) = make_uint2(pk2(l0, l1), pk2(l2, l3));
    }

    const u64 aH = MAKE_SMEM_DESC(sbase + KV_AHI), aL = MAKE_SMEM_DESC(sbase + KV_ALO);
    const u64 b0H = MAKE_SMEM_DESC(sbase + KV_B0H), b0L = MAKE_SMEM_DESC(sbase + KV_B0L);
    const u64 b1H = MAKE_SMEM_DESC(sbase + KV_B1H), b1L = MAKE_SMEM_DESC(sbase + KV_B1L);

    const int rr = (wid & 3) * 32 + lane;
    const int cb = (wid >> 2) * 128;
    const int b  = blockIdx.x * 32 + (rr >> 2);

    int w0 = 0, w1 = 0, pend0 = 0, pend1 = 0;

    for (int m = 0; m < 4; ++m) {
        // phase 1: Q (cols 0-255) + K (cols 256-511)
        for (int t = 0; t < 16; ++t) {
            const int isK = t >> 3, nch = (t >> 2) & 1, kch = t & 3;
            const int buf = t & 1;
            if (buf == 0) { if (pend0) { MBARRIER_WAIT_PARITY(sbase + KV_MB0, w0 & 1); ++w0; pend0 = 0; } }
            else          { if (pend1) { MBARRIER_WAIT_PARITY(sbase + KV_MB1, w1 & 1); ++w1; pend1 = 0; } }
            {
                float4* dh = reinterpret_cast<float4*>(smA + (buf ? KV_B1H : KV_B0H));
                float4* dl = reinterpret_cast<float4*>(smA + (buf ? KV_B1L : KV_B0L));
                if (isK) {
                    const float4* s4 = reinterpret_cast<const float4*>(
                        g_wkt + (size_t)(((m * 2 + nch) * 4 + kch)) * 16384);
#pragma unroll
                    for (int i = 0; i < 4; ++i) {
                        dh[tid + i * 256] = s4[tid + i * 256];
                        dl[tid + i * 256] = s4[1024 + tid + i * 256];
                    }
                } else {
                    const float4* s4 = reinterpret_cast<const float4*>(
                        g_wqt + (size_t)(m * 4 + kch) * 32768);
#pragma unroll
                    for (int i = 0; i < 4; ++i) {
                        dh[tid + i * 256] = s4[nch * 1024 + tid + i * 256];
                        dl[tid + i * 256] = s4[2048 + nch * 1024 + tid + i * 256];
                    }
                }
            }
            __syncthreads();
            if (wid == 0) {
                asm volatile("fence.proxy.async.shared::cta;" ::: "memory");
                TCGEN05_FENCE_AFTER();
                if (elect_one_pred()) {
                    const u64 bH = buf ? b1H : b0H, bL = buf ? b1L : b0L;
                    const uint32_t dcol = tmem + isK * 256 + nch * 128;
#pragma unroll
                    for (int j = 0; j < 4; ++j) {
                        const u64 ao = (u64)(kch * 1024 + j * 2), bo = (u64)(j * 2);
                        mma_f16_ss(dcol, aH + ao, bH + bo, IDESC_BF16_M128_N128,
                                   (kch == 0 && j == 0) ? 0u : 1u);
                        mma_f16_ss(dcol, aH + ao, bL + bo, IDESC_BF16_M128_N128, 1u);
                        mma_f16_ss(dcol, aL + ao, bH + bo, IDESC_BF16_M128_N128, 1u);
                    }
                    TCGEN05_COMMIT(sbase + (buf ? KV_MB1 : KV_MB0));
                }
            }
            if (buf == 0) pend0 = 1; else pend1 = 1;
        }
        if (pend0) { MBARRIER_WAIT_PARITY(sbase + KV_MB0, w0 & 1); ++w0; pend0 = 0; }
        if (pend1) { MBARRIER_WAIT_PARITY(sbase + KV_MB1, w1 & 1); ++w1; pend1 = 0; }
        TCGEN05_FENCE_AFTER();

        // epi1: scores + softmax -> p[4]
        float p[4];
        const int qlane = (lane & ~3) + m;
        for (int cc = 0; cc < 4; ++cc) {
            const int dof = cb + cc * 32;
            uint32_t qr[32];
            TCGEN05_LD_32X32B_X32(qr, tmem + dof);
            TCGEN05_WAIT_LD();
            uint32_t kr[32];
            TCGEN05_LD_32X32B_X32(kr, tmem + 256 + dof);
            TCGEN05_WAIT_LD();
            const float* bqp = bq + m * 256 + dof;
            const float* bkp = bk + m * 256 + dof;
            float s = 0.f;
#pragma unroll
            for (int j = 0; j < 32; ++j) {
                const float qv = __shfl_sync(0xffffffffu, __uint_as_float(qr[j]), qlane)
                               + bqp[j] * 0.17677669529663687f;
                s = fmaf(qv, __uint_as_float(kr[j]) + bkp[j], s);
            }
            float mx = s;
            mx = fmaxf(mx, __shfl_xor_sync(0xffffffffu, mx, 1));
            mx = fmaxf(mx, __shfl_xor_sync(0xffffffffu, mx, 2));
            float e = expf(s - mx);
            float se = e;
            se += __shfl_xor_sync(0xffffffffu, se, 1);
            se += __shfl_xor_sync(0xffffffffu, se, 2);
            p[cc] = e / se;
        }
        TCGEN05_FENCE_BEFORE();
        __syncthreads();

        // phase 2: V (cols 0-255)
        for (int t = 0; t < 8; ++t) {
            const int nch = t >> 2, kch = t & 3;
            const int buf = t & 1;
            if (buf == 0) { if (pend0) { MBARRIER_WAIT_PARITY(sbase + KV_MB0, w0 & 1); ++w0; pend0 = 0; } }
            else          { if (pend1) { MBARRIER_WAIT_PARITY(sbase + KV_MB1, w1 & 1); ++w1; pend1 = 0; } }
            {
                const float4* s4 = reinterpret_cast<const float4*>(
                    g_wvt + (size_t)(((m * 2 + nch) * 4 + kch)) * 16384);
                float4* dh = reinterpret_cast<float4*>(smA + (buf ? KV_B1H : KV_B0H));
                float4* dl = reinterpret_cast<float4*>(smA + (buf ? KV_B1L : KV_B0L));
#pragma unroll
                for (int i = 0; i < 4; ++i) {
                    dh[tid + i * 256] = s4[tid + i * 256];
                    dl[tid + i * 256] = s4[1024 + tid + i * 256];
                }
            }
            __syncthreads();
            if (wid == 0) {
                asm volatile("fence.proxy.async.shared::cta;" ::: "memory");
                TCGEN05_FENCE_AFTER();
                if (elect_one_pred()) {
                    const u64 bH = buf ? b1H : b0H, bL = buf ? b1L : b0L;
                    const uint32_t dcol = tmem + nch * 128;
#pragma unroll
                    for (int j = 0; j < 4; ++j) {
                        const u64 ao = (u64)(kch * 1024 + j * 2), bo = (u64)(j * 2);
                        mma_f16_ss(dcol, aH + ao, bH + bo, IDESC_BF16_M128_N128,
                                   (kch == 0 && j == 0) ? 0u : 1u);
                        mma_f16_ss(dcol, aH + ao, bL + bo, IDESC_BF16_M128_N128, 1u);
                        mma_f16_ss(dcol, aL + ao, bH + bo, IDESC_BF16_M128_N128, 1u);
                    }
                    TCGEN05_COMMIT(sbase + (buf ? KV_MB1 : KV_MB0));
                }
            }
            if (buf == 0) pend0 = 1; else pend1 = 1;
        }
        if (pend0) { MBARRIER_WAIT_PARITY(sbase + KV_MB0, w0 & 1); ++w0; pend0 = 0; }
        if (pend1) { MBARRIER_WAIT_PARITY(sbase + KV_MB1, w1 & 1); ++w1; pend1 = 0; }
        TCGEN05_FENCE_AFTER();

        // epi2: Oh = sum p_n * v_n
        for (int cc = 0; cc < 4; ++cc) {
            const int dof = cb + cc * 32;
            uint32_t vr[32];
            TCGEN05_LD_32X32B_X32(vr, tmem + dof);
            TCGEN05_WAIT_LD();
            const float* bvp = bv + m * 256 + dof;
            float t32[32];
#pragma unroll
            for (int j = 0; j < 32; ++j)
                t32[j] = p[cc] * (__uint_as_float(vr[j]) + bvp[j]);
#pragma unroll
            for (int j = 0; j < 32; ++j) {
                t32[j] += __shfl_xor_sync(0xffffffffu, t32[j], 1);
                t32[j] += __shfl_xor_sync(0xffffffffu, t32[j], 2);
            }
            const int qi = lane & 3;
            float* op = g_oh + ((size_t)m * 32768 + b) * 256 + dof + qi * 8;
            *reinterpret_cast<float4*>(op) =
                make_float4(t32[qi * 8 + 0], t32[qi * 8 + 1], t32[qi * 8 + 2], t32[qi * 8 + 3]);
            *reinterpret_cast<float4*>(op + 4) =
                make_float4(t32[qi * 8 + 4], t32[qi * 8 + 5], t32[qi * 8 + 6], t32[qi * 8 + 7]);
        }
        TCGEN05_FENCE_BEFORE();
        __syncthreads();
    }

    if (tid == 0) {
        asm volatile("mbarrier.inval.shared.b64 [%0];" :: "r"(sbase + KV_MB0) : "memory");
        asm volatile("mbarrier.inval.shared.b64 [%0];" :: "r"(sbase + KV_MB1) : "memory");
    }
    __syncthreads();
    if (wid == 0) TCGEN05_DEALLOC(tmem, 512);

#else  // fp32 fallback (slow; never runs on sm_103a)
    const int b = blockIdx.x * 32 + (tid >> 3);
    const int h = tid & 7;
    for (int m = 0; m < 4; ++m) {
        float q[32];
        for (int d = 0; d < 32; ++d) {
            float qd = bq[m * 256 + h * 32 + d] * 0.17677669529663687f;
            for (int k = 0; k < 256; ++k)
                qd = fmaf(x[(size_t)(b * 4 + m) * 256 + k], wrec256(g_wqt, m, h * 32 + d, k), qd);
            q[d] = qd;
        }
        float sc[4];
        for (int n = 0; n < 4; ++n) {
            float s = 0.f;
            for (int d = 0; d < 32; ++d) {
                float kd = bk[m * 256 + h * 32 + d];
                for (int k = 0; k < 256; ++k)
                    kd = fmaf(x[(size_t)(b * 4 + n) * 256 + k], wrec128(g_wkt, m, h * 32 + d, k), kd);
                s = fmaf(q[d], kd, s);
            }
            sc[n] = s;
        }
        const float mx = fmaxf(fmaxf(sc[0], sc[1]), fmaxf(sc[2], sc[3]));
        float e[4], se = 0.f;
        for (int n = 0; n < 4; ++n) { e[n] = expf(sc[n] - mx); se += e[n]; }
        for (int d = 0; d < 32; ++d) {
            float o = 0.f;
            for (int n = 0; n < 4; ++n) {
                float vd = bv[m * 256 + h * 32 + d];
                for (int k = 0; k < 256; ++k)
                    vd = fmaf(x[(size_t)(b * 4 + n) * 256 + k], wrec128(g_wvt, m, h * 32 + d, k), vd);
                o = fmaf(e[n] / se, vd, o);
            }
            g_oh[((size_t)m * 32768 + b) * 256 + h * 32 + d] = o;
        }
    }
#endif
}

// =====================================================================
// Kernel D: Wo projection (tcgen05, 8 double-buffered N=128 chunks)
// =====================================================================
__global__ __launch_bounds__(256, 1)
void gcma_qo(const float* __restrict__ bo)
{
    extern __shared__ char smQ[];
    const int tid = threadIdx.x;
    const int m   = blockIdx.y;
    const int b0  = blockIdx.x * 128;

    const __nv_bfloat16* wt = g_wot;
    const float* bias = bo + m * 256;
    float* dst = g_ao + ((size_t)m * 32768 + b0) * 256;

#if GB_TC
    const uint32_t sbase = smem_to_u32(smQ);
    const int wid = tid >> 5, lane = tid & 31;
    char* sAhi = smQ + KV_AHI;
    char* sAlo = smQ + KV_ALO;

    if (wid == 0) TCGEN05_ALLOC(sbase + 0, 512);
    if (tid == 0) { MBARRIER_INIT(sbase + KV_MB0, 1); MBARRIER_INIT(sbase + KV_MB1, 1); }
    __syncthreads();
    uint32_t tmem;
    asm volatile("ld.shared.b32 %0, [%1];" : "=r"(tmem) : "r"(sbase + 0));

    for (int idx = tid; idx < 8192; idx += 256) {
        const int r = idx >> 6, k = (idx & 63) << 2;
        const float4 v = *reinterpret_cast<const float4*>(
            g_oh + ((size_t)m * 32768 + b0 + r) * 256 + k);
        __nv_bfloat16 h0, h1, h2, h3, l0, l1, l2, l3;
        bsplit(v.x, h0, l0); bsplit(v.y, h1, l1);
        bsplit(v.z, h2, l2); bsplit(v.w, h3, l3);
        const uint32_t sw = swz128((uint32_t)((r >> 3) + (k >> 6) * 16) * 1024 + (r & 7) * 128 + (k & 63) * 2);
        *reinterpret_cast<uint2*>(sAhi + sw) = make_uint2(pk2(h0, h1), pk2(h2, h3));
        *reinterpret_cast<uint2*>(sAlo + sw) = make_uint2(pk2(l0, l1), pk2(l2, l3));
    }

    const u64 aH = MAKE_SMEM_DESC(sbase + KV_AHI), aL = MAKE_SMEM_DESC(sbase + KV_ALO);
    const u64 b0H = MAKE_SMEM_DESC(sbase + KV_B0H), b0L = MAKE_SMEM_DESC(sbase + KV_B0L);
    const u64 b1H = MAKE_SMEM_DESC(sbase + KV_B1H), b1L = MAKE_SMEM_DESC(sbase + KV_B1L);

    int w0 = 0, w1 = 0, pend0 = 0, pend1 = 0;
    for (int c = 0; c < 8; ++c) {
        const int nch = c >> 2, kch = c & 3;
        const int buf = c & 1;
        if (buf == 0) { if (pend0) { MBARRIER_WAIT_PARITY(sbase + KV_MB0, w0 & 1); ++w0; pend0 = 0; } }
        else          { if (pend1) { MBARRIER_WAIT_PARITY(sbase + KV_MB1, w1 & 1); ++w1; pend1 = 0; } }
        {
            const float4* s4 = reinterpret_cast<const float4*>(wt + (size_t)(m * 4 + kch) * 32768);
            float4* dh = reinterpret_cast<float4*>(smQ + (buf ? KV_B1H : KV_B0H));
            float4* dl = reinterpret_cast<float4*>(smQ + (buf ? KV_B1L : KV_B0L));
#pragma unroll
            for (int i = 0; i < 4; ++i) {
                dh[tid + i * 256] = s4[nch * 1024 + tid + i * 256];
                dl[tid + i * 256] = s4[2048 + nch * 1024 + tid + i * 256];
            }
        }
        __syncthreads();
        if (wid == 0) {
            asm volatile("fence.proxy.async.shared::cta;" ::: "memory");
            TCGEN05_FENCE_AFTER();
            if (elect_one_pred()) {
                const u64 bH = buf ? b1H : b0H, bL = buf ? b1L : b0L;
                const uint32_t dcol = tmem + nch * 128;
#pragma unroll
                for (int j = 0; j < 4; ++j) {
                    const u64 ao = (u64)(kch * 1024 + j * 2), bo2 = (u64)(j * 2);
                    mma_f16_ss(dcol, aH + ao, bH + bo2, IDESC_BF16_M128_N128,
                               (kch == 0 && j == 0) ? 0u : 1u);
                    mma_f16_ss(dcol, aH + ao, bL + bo2, IDESC_BF16_M128_N128, 1u);
                    mma_f16_ss(dcol, aL + ao, bH + bo2, IDESC_BF16_M128_N128, 1u);
                }
                TCGEN05_COMMIT(sbase + (buf ? KV_MB1 : KV_MB0));
            }
        }
        if (buf == 0) pend0 = 1; else pend1 = 1;
    }
    if (pend0) { MBARRIER_WAIT_PARITY(sbase + KV_MB0, w0 & 1); ++w0; pend0 = 0; }
    if (pend1) { MBARRIER_WAIT_PARITY(sbase + KV_MB1, w1 & 1); ++w1; pend1 = 0; }
    TCGEN05_FENCE_AFTER();

    {
        const int rr = (wid & 3) * 32 + lane;
        const int cb = (wid >> 2) * 128;
        for (int cc = 0; cc < 4; ++cc) {
            uint32_t dr[32];
            TCGEN05_LD_32X32B_X32(dr, tmem + cb + cc * 32);
            TCGEN05_WAIT_LD();
            TCGEN05_FENCE_BEFORE();
            const int c0 = cb + cc * 32;
            float* drow = dst + (size_t)rr * 256 + c0;
#pragma unroll
            for (int q = 0; q < 8; ++q) {
                *reinterpret_cast<float4*>(drow + q * 4) =
                    make_float4(__uint_as_float(dr[q * 4 + 0]) + bias[c0 + q * 4 + 0],
                                __uint_as_float(dr[q * 4 + 1]) + bias[c0 + q * 4 + 1],
                                __uint_as_float(dr[q * 4 + 2]) + bias[c0 + q * 4 + 2],
                                __uint_as_float(dr[q * 4 + 3]) + bias[c0 + q * 4 + 3]);
            }
        }
    }

    __syncthreads();
    if (tid == 0) {
        asm volatile("mbarrier.inval.shared.b64 [%0];" :: "r"(sbase + KV_MB0) : "memory");
        asm volatile("mbarrier.inval.shared.b64 [%0];" :: "r"(sbase + KV_MB1) : "memory");
    }
    __syncthreads();
    if (wid == 0) TCGEN05_DEALLOC(tmem, 512);

#else
    for (int e = tid; e < 128 * 256; e += 256) {
        const int r = e >> 8, n = e & 255;
        float dot = 0.f;
        for (int k = 0; k < 256; ++k)
            dot = fmaf(g_oh[((size_t)m * 32768 + b0 + r) * 256 + k], wrec256(wt, m, n, k), dot);
        dst[(size_t)r * 256 + n] = dot + bias[n];
    }
#endif
}

// =====================================================================
// Kernel E: gate MLP + LayerNorm, 64 batch rows per block, grid (512,4)
// =====================================================================
#define TL_XM   0        // 64*256 = 16384
#define TL_AO   16384    // 16384
#define TL_WT   32768    // 8320
#define TL_GH   41088    // 64*64 = 4096
#define TL_GATE 45184    // 64
#define TL_FLOATS 45248
#define TL_BYTES  (TL_FLOATS * 4)

__global__ __launch_bounds__(256, 1)
void gcma_tail(const float* __restrict__ x,
               const float* __restrict__ g1w, const float* __restrict__ g1b,
               const float* __restrict__ g2w, const float* __restrict__ g2b,
               const float* __restrict__ lng, const float* __restrict__ lnb,
               float* __restrict__ out)
{
    extern __shared__ float smL[];
    float* sXm   = smL + TL_XM;
    float* sAO   = smL + TL_AO;
    float* sWT   = smL + TL_WT;
    float* sGH   = smL + TL_GH;
    float* sGate = smL + TL_GATE;

    const int tid = threadIdx.x;
    const int m   = blockIdx.y;
    const int b0  = blockIdx.x * 64;
    const long g0 = (long)b0 * 4;

    const int warp = tid >> 5;
    const int colg = tid & 31;

    for (int idx = tid; idx < 4096; idx += 256) {
        const int r = idx >> 6, q = idx & 63;
        *reinterpret_cast<float4*>(sXm + r * 256 + q * 4) =
            *reinterpret_cast<const float4*>(x + ((size_t)(b0 + r) * 4 + m) * 256 + q * 4);
        *reinterpret_cast<float4*>(sAO + r * 256 + q * 4) =
            *reinterpret_cast<const float4*>(g_ao + ((size_t)m * 32768 + b0 + r) * 256 + q * 4);
    }

    // gate layer 1: tanh([x;AO] @ g1w^T + g1b), 8 rows/warp, 2 cols/lane
    {
        const float* W = g1w + (size_t)m * 32768;
        Wreg<2> wr;
        ldgW<2>(W, 512, 0, wr, tid);
        u64 gacc[8];
#pragma unroll
        for (int i = 0; i < 8; ++i) gacc[i] = 0ULL;
        for (int dt = 0; dt < 16; ++dt) {
            __syncthreads();
            stsW<2>(sWT, wr, tid);
            if (dt < 15) ldgW<2>(W, 512, (dt + 1) * 32, wr, tid);
            __syncthreads();
            if (dt < 8)
                mmagb8(sXm + warp * 8 * 256 + dt * 32, 256, sWT, gacc, colg);
            else
                mmagb8(sAO + warp * 8 * 256 + (dt - 8) * 32, 256, sWT, gacc, colg);
        }
        const float gb0 = g1b[m * 64 + colg * 2];
        const float gb1 = g1b[m * 64 + colg * 2 + 1];
#pragma unroll
        for (int i = 0; i < 8; ++i) {
            const float2 p = unpk(gacc[i]);
            sGH[(warp * 8 + i) * 64 + colg * 2]     = tanhf(p.x + gb0);
            sGH[(warp * 8 + i) * 64 + colg * 2 + 1] = tanhf(p.y + gb1);
        }
    }
    __syncthreads();

    // gate layer 2 + sigmoid
    if (tid < 64) {
        const float* g2 = g2w + m * 64;
        float dot = g2b[m];
#pragma unroll 8
        for (int j = 0; j < 64; ++j) dot = fmaf(sGH[tid * 64 + j], g2[j], dot);
        const float gate = 1.f / (1.f + expf(-dot));
        sGate[tid] = gate;
        out[OUT_GATE_BASE + (size_t)(b0 + tid) * 4 + m] = gate;
    }
    __syncthreads();

    // residual + LayerNorm -> g_y (8 rows per warp)
    {
        const int lane = tid & 31;
#pragma unroll
        for (int i = 0; i < 8; ++i) {
            const int bl = warp * 8 + i;
            const float* xr  = sXm + bl * 256;
            const float* aor = sAO + bl * 256;
            const float gate = sGate[bl];
            float r[8];
            float sum = 0.f;
#pragma unroll
            for (int k = 0; k < 8; ++k) {
                const int d = k * 32 + lane;
                r[k] = xr[d] + gate * aor[d];
                sum += r[k];
            }
#pragma unroll
            for (int o = 16; o; o >>= 1) sum += __shfl_xor_sync(0xffffffffu, sum, o);
            const float mu = sum * (1.f / 256.f);
            float var = 0.f;
#pragma unroll
            for (int k = 0; k < 8; ++k) { const float t = r[k] - mu; var = fmaf(t, t, var); }
#pragma unroll
            for (int o = 16; o; o >>= 1) var += __shfl_xor_sync(0xffffffffu, var, o);
            const float rs = rsqrtf(var * (1.f / 256.f) + 1e-5f);
            float* yr = g_y + (size_t)(g0 + bl * 4 + m) * 256;
#pragma unroll
            for (int k = 0; k < 8; ++k) {
                const int d = k * 32 + lane;
                yr[d] = (r[k] - mu) * rs * lng[m * 256 + d] + lnb[m * 256 + d];
            }
        }
    }
}

// =====================================================================
// Kernel F: FF (tcgen05)
// =====================================================================
#define P2_SMEM 197632
#define P2_TM    0
#define P2_MB    8
#define P2_AHI   1024
#define P2_ALO   66560
#define P2_BHI   132096
#define P2_BLO   164864

static __device__ __forceinline__ void loadB(const __nv_bfloat16* base, int m, int c1, int c2,
                                             float4 pf[16], int tid) {
    const float4* src = reinterpret_cast<const float4*>(base + (size_t)((m * 4 + c1) * 4 + c2) * 32768);
#pragma unroll
    for (int i = 0; i < 8; ++i) {
        pf[i]     = src[tid + i * 256];
        pf[8 + i] = src[2048 + tid + i * 256];
    }
}
static __device__ __forceinline__ void stsB(char* sBhi, char* sBlo, const float4 pf[16], int tid) {
#pragma unroll
    for (int i = 0; i < 8; ++i) {
        reinterpret_cast<float4*>(sBhi)[tid + i * 256] = pf[i];
        reinterpret_cast<float4*>(sBlo)[tid + i * 256] = pf[8 + i];
    }
}

__global__ __launch_bounds__(256, 1)
void gcma_part2tc(const float* __restrict__ f1w, const float* __restrict__ f1b,
                  const float* __restrict__ f2w, const float* __restrict__ f2b,
                  float* __restrict__ out)
{
    extern __shared__ char sm2[];
    const int tid  = threadIdx.x;
    const int m    = blockIdx.y;
    const int b0   = blockIdx.x * 128;

#if GB_TC
    const uint32_t sbase = smem_to_u32(sm2);
    const uint32_t TMP  = sbase + P2_TM;
    const uint32_t MBAR = sbase + P2_MB;
    char* sAhi = sm2 + P2_AHI;
    char* sAlo = sm2 + P2_ALO;
    char* sBhi = sm2 + P2_BHI;
    char* sBlo = sm2 + P2_BLO;
    const uint32_t aHiA = sbase + P2_AHI, aLoA = sbase + P2_ALO;
    const uint32_t bHiA = sbase + P2_BHI, bLoA = sbase + P2_BLO;

    const int wid  = tid >> 5, lane = tid & 31;
    unsigned* hfbase = g_hfscr + (size_t)(blockIdx.y * 256 + blockIdx.x) * 131072u;

    if (wid == 0) TCGEN05_ALLOC(TMP, 512);
    if (tid == 0) MBARRIER_INIT(MBAR, 1);
    __syncthreads();
    uint32_t tmem;
    asm volatile("ld.shared.b32 %0, [%1];" : "=r"(tmem) : "r"(TMP));

    for (int idx = tid; idx < 8192; idx += 256) {
        const int r = idx >> 6, k = (idx & 63) << 2;
        const float4 v = *reinterpret_cast<const float4*>(
            g_y + ((size_t)(b0 + r) * 4 + m) * 256 + k);
        __nv_bfloat16 h0, h1, h2, h3, l0, l1, l2, l3;
        bsplit(v.x, h0, l0); bsplit(v.y, h1, l1);
        bsplit(v.z, h2, l2); bsplit(v.w, h3, l3);
        const uint32_t sw = swz128((uint32_t)((r >> 3) + (k >> 6) * 16) * 1024 + (r & 7) * 128 + (k & 63) * 2);
        *reinterpret_cast<uint2*>(sAhi + sw) = make_uint2(pk2(h0, h1), pk2(h2, h3));
        *reinterpret_cast<uint2*>(sAlo + sw) = make_uint2(pk2(l0, l1), pk2(l2, l3));
    }

    float4 pf[16];
    loadB(g_w1t, m, 0, 0, pf, tid);
    int ph = 0;
    const u64 aH = MAKE_SMEM_DESC(aHiA), aL = MAKE_SMEM_DESC(aLoA);
    const u64 bH = MAKE_SMEM_DESC(bHiA), bL = MAKE_SMEM_DESC(bLoA);

    for (int nch = 0; nch < 4; ++nch) {
        for (int kch = 0; kch < 4; ++kch) {
            stsB(sBhi, sBlo, pf, tid);
            __syncthreads();
            if (wid == 0) {
                asm volatile("fence.proxy.async.shared::cta;" ::: "memory");
                TCGEN05_FENCE_AFTER();
                if (elect_one_pred()) {
#pragma unroll
                    for (int j = 0; j < 4; ++j) {
                        const u64 ao = (u64)(kch * 1024 + j * 2), bo = (u64)(j * 2);
                        mma_f16_ss(tmem, aH + ao, bH + bo, IDESC_BF16_M128_N256,
                                   (kch == 0 && j == 0) ? 0u : 1u);
                        mma_f16_ss(tmem, aH + ao, bL + bo, IDESC_BF16_M128_N256, 1u);
                        mma_f16_ss(tmem, aL + ao, bH + bo, IDESC_BF16_M128_N256, 1u);
                    }
                    TCGEN05_COMMIT(MBAR);
                }
            }
            const int nb = nch * 4 + kch + 1;
            if (nb < 16) loadB(g_w1t, m, nb >> 2, nb & 3, pf, tid);
            else         loadB(g_w2t, m, 0, 0, pf, tid);
            MBARRIER_WAIT_PARITY(MBAR, ph & 1);
            ++ph;
            TCGEN05_FENCE_AFTER();
        }
        {
            const int r  = (wid & 3) * 32 + lane;
            const int cb = (wid >> 2) * 128;
            for (int cc = 0; cc < 4; ++cc) {
                uint32_t dr[32];
                TCGEN05_LD_32X32B_X32(dr, tmem + cb + cc * 32);
                TCGEN05_WAIT_LD();
                TCGEN05_FENCE_BEFORE();
                const int c0 = nch * 256 + cb + cc * 32;
                unsigned* dst = hfbase + (size_t)r * 1024 + c0;
#pragma unroll
                for (int j = 0; j < 32; ++j) {
                    float v = __uint_as_float(dr[j]) + f1b[m * 1024 + c0 + j];
                    v = 0.5f * v * (1.f + erff(v * 0.7071067811865476f));
                    __nv_bfloat16 h, l;
                    bsplit(v, h, l);
                    dst[j] = pk2(h, l);
                }
            }
        }
        __syncthreads();
    }

    for (int ch = 0; ch < 4; ++ch) {
        for (int idx = tid; idx < 8192; idx += 256) {
            const int r = idx >> 6, k = (idx & 63) << 2;
            const uint4 u = *reinterpret_cast<const uint4*>(
                hfbase + (size_t)r * 1024 + ch * 256 + k);
            const unsigned uu[4] = {u.x, u.y, u.z, u.w};
            __nv_bfloat16 h[4], l[4];
#pragma unroll
            for (int j = 0; j < 4; ++j) {
                h[j] = __ushort_as_bfloat16((unsigned short)(uu[j] & 0xFFFFu));
                l[j] = __ushort_as_bfloat16((unsigned short)(uu[j] >> 16));
            }
            const uint32_t sw = swz128((uint32_t)((r >> 3) + (k >> 6) * 16) * 1024 + (r & 7) * 128 + (k & 63) * 2);
            *reinterpret_cast<uint2*>(sAhi + sw) = make_uint2(pk2(h[0], h[1]), pk2(h[2], h[3]));
            *reinterpret_cast<uint2*>(sAlo + sw) = make_uint2(pk2(l[0], l[1]), pk2(l[2], l[3]));
        }
        for (int kc = 0; kc < 4; ++kc) {
            stsB(sBhi, sBlo, pf, tid);
            __syncthreads();
            if (wid == 0) {
                asm volatile("fence.proxy.async.shared::cta;" ::: "memory");
                TCGEN05_FENCE_AFTER();
                if (elect_one_pred()) {
#pragma unroll
                    for (int j = 0; j < 4; ++j) {
                        const u64 ao = (u64)(kc * 1024 + j * 2), bo = (u64)(j * 2);
                        mma_f16_ss(tmem + 256, aH + ao, bH + bo, IDESC_BF16_M128_N256,
                                   (ch == 0 && kc == 0 && j == 0) ? 0u : 1u);
                        mma_f16_ss(tmem + 256, aH + ao, bL + bo, IDESC_BF16_M128_N256, 1u);
                        mma_f16_ss(tmem + 256, aL + ao, bH + bo, IDESC_BF16_M128_N256, 1u);
                    }
                    TCGEN05_COMMIT(MBAR);
                }
            }
            const int nb = ch * 4 + kc + 1;
            if (nb < 16) loadB(g_w2t, m, nb >> 2, nb & 3, pf, tid);
            MBARRIER_WAIT_PARITY(MBAR, ph & 1);
            ++ph;
            TCGEN05_FENCE_AFTER();
        }
    }

    {
        const int r  = (wid & 3) * 32 + lane;
        const int cb = (wid >> 2) * 128;
        for (int cc = 0; cc < 4; ++cc) {
            uint32_t dr[32];
            TCGEN05_LD_32X32B_X32(dr, tmem + 256 + cb + cc * 32);
            TCGEN05_WAIT_LD();
            TCGEN05_FENCE_BEFORE();
            const int c0 = cb + cc * 32;
            const float* yrow = g_y + ((size_t)(b0 + r) * 4 + m) * 256 + c0;
            float* orow = out + ((size_t)(b0 + r) * 4 + m) * 256 + c0;
#pragma unroll
            for (int j = 0; j < 32; ++j)
                orow[j] = yrow[j] + __uint_as_float(dr[j]) + f2b[m * 256 + c0 + j];
        }
    }

    __syncthreads();
    if (tid == 0)
        asm volatile("mbarrier.inval.shared.b64 [%0];" :: "r"(MBAR) : "memory");
    __syncthreads();
    if (wid == 0) TCGEN05_DEALLOC(tmem, 512);

#else
    float* smf = reinterpret_cast<float*>(sm2);
    float* sY  = smf;
    float* sHF = smf + 16384;
    float* sWT = smf + 32768;
    const int warp = tid >> 5;
    const int colg = tid & 31;

    for (int half = 0; half < 2; ++half) {
        const int hb0 = b0 + half * 64;
        __syncthreads();
        for (int idx = tid; idx < 4096; idx += TPB) {
            const int r = idx >> 6, q = idx & 63;
            *reinterpret_cast<float4*>(sY + r * 256 + q * 4) =
                *reinterpret_cast<const float4*>(g_y + ((size_t)(hb0 + r) * 4 + m) * 256 + q * 4);
        }
        u64 facc[8][4];
#pragma unroll
        for (int i = 0; i < 8; ++i)
#pragma unroll
            for (int j = 0; j < 4; ++j) facc[i][j] = 0ULL;
        const float* aY  = sY  + warp * 8 * 256;
        const float* aHF = sHF + warp * 8 * 256;

        for (int ch = 0; ch < 4; ++ch) {
            u64 hacc[8][4];
#pragma unroll
            for (int i = 0; i < 8; ++i)
#pragma unroll
                for (int j = 0; j < 4; ++j) hacc[i][j] = 0ULL;
            {
                const float* W1 = f1w + (size_t)m * 262144 + (size_t)ch * 65536;
                Wreg<8> wr;
                ldgW<8>(W1, 256, 0, wr, tid);
                for (int dt = 0; dt < 8; ++dt) {
                    __syncthreads();
                    stsW<8>(sWT, wr, tid);
                    if (dt < 7) ldgW<8>(W1, 256, (dt + 1) * 32, wr, tid);
                    __syncthreads();
                    mma64b(aY + dt * 32, 256, sWT, hacc, colg);
                }
            }
            __syncthreads();
            {
                const float* b1 = f1b + m * 1024 + ch * 256;
                float bl0[4], bl1[4];
#pragma unroll
                for (int j = 0; j < 4; ++j) { bl0[j] = b1[colg * 4 + j]; bl1[j] = b1[128 + colg * 4 + j]; }
#pragma unroll
                for (int i = 0; i < 8; ++i) {
                    const int r = warp * 8 + i;
                    const float2 pa = unpk(hacc[i][0]), pb = unpk(hacc[i][1]);
                    const float2 pc = unpk(hacc[i][2]), pd = unpk(hacc[i][3]);
                    float v0[4] = {pa.x + bl0[0], pa.y + bl0[1], pb.x + bl0[2], pb.y + bl0[3]};
                    float v1[4] = {pc.x + bl1[0], pc.y + bl1[1], pd.x + bl1[2], pd.y + bl1[3]};
#pragma unroll
                    for (int j = 0; j < 4; ++j) {
                        v0[j] = 0.5f * v0[j] * (1.f + erff(v0[j] * 0.7071067811865476f));
                        v1[j] = 0.5f * v1[j] * (1.f + erff(v1[j] * 0.7071067811865476f));
                    }
                    *reinterpret_cast<float4*>(sHF + r * 256 + colg * 4) =
                        make_float4(v0[0], v0[1], v0[2], v0[3]);
                    *reinterpret_cast<float4*>(sHF + r * 256 + 128 + colg * 4) =
                        make_float4(v1[0], v1[1], v1[2], v1[3]);
                }
            }
            {
                const float* W2 = f2w + (size_t)m * 262144;
                Wreg<8> wr;
                ldgW<8>(W2, 1024, ch * 256, wr, tid);
                for (int dt = 0; dt < 8; ++dt) {
                    __syncthreads();
                    stsW<8>(sWT, wr, tid);
                    if (dt < 7) ldgW<8>(W2, 1024, ch * 256 + (dt + 1) * 32, wr, tid);
                    __syncthreads();
                    mma64b(aHF + dt * 32, 256, sWT, facc, colg);
                }
            }
            __syncthreads();
        }
        {
            const float* b2 = f2b + m * 256;
            float bl0[4], bl1[4];
#pragma unroll
            for (int j = 0; j < 4; ++j) { bl0[j] = b2[colg * 4 + j]; bl1[j] = b2[128 + colg * 4 + j]; }
#pragma unroll
            for (int i = 0; i < 8; ++i) {
                const int r = warp * 8 + i;
                const float4 y0 = *reinterpret_cast<const float4*>(sY + r * 256 + colg * 4);
                const float4 y1 = *reinterpret_cast<const float4*>(sY + r * 256 + 128 + colg * 4);
                const float2 pa = unpk(facc[i][0]), pb = unpk(facc[i][1]);
                const float2 pc = unpk(facc[i][2]), pd = unpk(facc[i][3]);
                float* op = out + ((size_t)(hb0 + r) * 4 + m) * 256;
                *reinterpret_cast<float4*>(op + colg * 4) =
                    make_float4(y0.x + pa.x + bl0[0], y0.y + pa.y + bl0[1],
                                y0.z + pb.x + bl0[2], y0.w + pb.y + bl0[3]);
                *reinterpret_cast<float4*>(op + 128 + colg * 4) =
                    make_float4(y1.x + pc.x + bl1[0], y1.y + pc.y + bl1[1],
                                y1.z + pd.x + bl1[2], y1.w + pd.y + bl1[3]);
            }
        }
    }
#endif
}

extern "C" void kernel_launch(void* const* d_in, const int* in_sizes, int n_in,
                              void* d_out, int out_size) {
    const float* x   = (const float*)d_in[0];
    const float* Wq  = (const float*)d_in[1];
    const float* bq  = (const float*)d_in[2];
    const float* Wk  = (const float*)d_in[3];
    const float* bk  = (const float*)d_in[4];
    const float* Wv  = (const float*)d_in[5];
    const float* bv  = (const float*)d_in[6];
    const float* Wo  = (const float*)d_in[7];
    const float* bo  = (const float*)d_in[8];
    const float* g1w = (const float*)d_in[9];
    const float* g1b = (const float*)d_in[10];
    const float* g2w = (const float*)d_in[11];
    const float* g2b = (const float*)d_in[12];
    const float* lng = (const float*)d_in[13];
    const float* lnb = (const float*)d_in[14];
    const float* f1w = (const float*)d_in[15];
    const float* f1b = (const float*)d_in[16];
    const float* f2w = (const float*)d_in[17];
    const float* f2b = (const float*)d_in[18];
    float* out = (float*)d_out;

    cudaFuncSetAttribute(gcma_kvattn, cudaFuncAttributeMaxDynamicSharedMemorySize, KV_SMEM);
    cudaFuncSetAttribute(gcma_qo, cudaFuncAttributeMaxDynamicSharedMemorySize, KV_SMEM);
    cudaFuncSetAttribute(gcma_tail, cudaFuncAttributeMaxDynamicSharedMemorySize, TL_BYTES);
    cudaFuncSetAttribute(gcma_part2tc, cudaFuncAttributeMaxDynamicSharedMemorySize, P2_SMEM);

    conv_w_kernel<<<12288, 256>>>(f1w, f2w, Wk, Wv, Wq, Wo);
    gcma_kvattn<<<1024, 256, KV_SMEM>>>(x, bq, bk, bv);
    gcma_qo<<<dim3(256, 4), 256, KV_SMEM>>>(bo);
    gcma_tail<<<dim3(512, 4), 256, TL_BYTES>>>(x, g1w, g1b, g2w, g2b, lng, lnb, out);
    gcma_part2tc<<<dim3(256, 4), 256, P2_SMEM>>>(f1w, f1b, f2w, f2b, out);
}

// round 16
// speedup vs baseline: 3.1222x; 1.0077x over previous
#include <cuda_runtime.h>
#include <cuda_bf16.h>
#include <math.h>
#include <stdint.h>

typedef unsigned long long u64;

#define TPB 256
#define PW 260

#define OUT_GATE_BASE 33554432UL   // B*M*D

#if defined(__CUDA_ARCH_FEAT_SM103_ALL) || \
    (defined(__CUDA_ARCH_SPECIFIC__) && (__CUDA_ARCH_SPECIFIC__ == 1030)) || \
    (defined(__CUDA_ARCH_FAMILY_SPECIFIC__) && (__CUDA_ARCH_FAMILY_SPECIFIC__ == 1030))
#define GB_TC 1
#else
#define GB_TC 0
#endif

// scratch
__device__ float g_y [32768u * 4u * 256u];                // 128MB
__device__ float g_oh[4u * 32768u * 256u];                // 128MB  Oh[m][b][256]
__device__ float g_ao[4u * 32768u * 256u];                // 128MB  attn_out[m][b][256]
__device__ __nv_bfloat16 g_w1t[64u * 32768u];             // FF1 tiles (hi|lo)
__device__ __nv_bfloat16 g_w2t[64u * 32768u];             // FF2 tiles
__device__ __nv_bfloat16 g_wkt[32u * 16384u];             // Wk tiles 128n x 64k (hi|lo)
__device__ __nv_bfloat16 g_wvt[32u * 16384u];             // Wv tiles
__device__ __nv_bfloat16 g_wqt[16u * 32768u];             // Wq tiles 256n x 64k (scaled)
__device__ __nv_bfloat16 g_wot[16u * 32768u];             // Wo tiles 256n x 64k
__device__ unsigned g_hfscr[1024u * 131072u];             // hf scratch

// ---------- helpers ----------
static __device__ __forceinline__ u64 ffma2(u64 a, u64 b, u64 c) {
    u64 d;
    asm("fma.rn.f32x2 %0, %1, %2, %3;" : "=l"(d) : "l"(a), "l"(b), "l"(c));
    return d;
}
static __device__ __forceinline__ u64 dup2(float a) {
    u64 d;
    asm("mov.b64 %0, {%1, %1};" : "=l"(d) : "f"(a));
    return d;
}
static __device__ __forceinline__ float2 unpk(u64 p) {
    float2 r;
    asm("mov.b64 {%0, %1}, %2;" : "=f"(r.x), "=f"(r.y) : "l"(p));
    return r;
}
static __device__ __forceinline__ float comp4(const float4& v, int dd) {
    return dd == 0 ? v.x : dd == 1 ? v.y : dd == 2 ? v.z : v.w;
}
static __device__ __forceinline__ unsigned pk2(__nv_bfloat16 a, __nv_bfloat16 b) {
    return (unsigned)__bfloat16_as_ushort(a) | ((unsigned)__bfloat16_as_ushort(b) << 16);
}
static __device__ __forceinline__ void bsplit(float v, __nv_bfloat16& h, __nv_bfloat16& l) {
    h = __float2bfloat16(v);
    l = __float2bfloat16(v - __bfloat162float(h));
}
static __device__ __forceinline__ uint32_t swz128(uint32_t b) { return b ^ ((b >> 3) & 0x70); }
static __device__ __forceinline__ uint32_t smem_to_u32(const void* p) {
    uint32_t a;
    asm("{ .reg .u64 t; cvta.to.shared.u64 t, %1; cvt.u32.u64 %0, t; }" : "=r"(a) : "l"(p));
    return a;
}

// ---------- fp32 W staging (tail + fallbacks) ----------
template<int NIT>
struct Wreg { float f[NIT][4]; };

template<int NIT>
static __device__ __forceinline__ void ldgW(const float* __restrict__ W, int ldw, int k0,
                                            Wreg<NIT>& r, int tid) {
#pragma unroll
    for (int k = 0; k < NIT; ++k) {
        const int idx = tid + k * TPB;
        const int d = idx & 31, c4 = idx >> 5;
#pragma unroll
        for (int i = 0; i < 4; ++i)
            r.f[k][i] = W[(size_t)(c4 * 4 + i) * ldw + k0 + d];
    }
}
template<int NIT>
static __device__ __forceinline__ void stsW(float* sWT, const Wreg<NIT>& r, int tid) {
#pragma unroll
    for (int k = 0; k < NIT; ++k) {
        const int idx = tid + k * TPB;
        const int d = idx & 31, c4 = idx >> 5;
        *reinterpret_cast<float4*>(sWT + d * PW + c4 * 4) =
            make_float4(r.f[k][0], r.f[k][1], r.f[k][2], r.f[k][3]);
    }
}
static __device__ __forceinline__ void mma64b(const float* __restrict__ aRow, int lda,
                                              const float* __restrict__ sWT,
                                              u64 acc[8][4], int colg) {
#pragma unroll
    for (int d4 = 0; d4 < 8; ++d4) {
        float4 a4[8];
#pragma unroll
        for (int i = 0; i < 8; ++i)
            a4[i] = *reinterpret_cast<const float4*>(aRow + i * lda + (d4 << 2));
#pragma unroll
        for (int dd = 0; dd < 4; ++dd) {
            const int d = (d4 << 2) + dd;
            const ulonglong2 w0 = *reinterpret_cast<const ulonglong2*>(sWT + d * PW + (colg << 2));
            const ulonglong2 w1 = *reinterpret_cast<const ulonglong2*>(sWT + d * PW + 128 + (colg << 2));
#pragma unroll
            for (int i = 0; i < 8; ++i) {
                const u64 ad = dup2(comp4(a4[i], dd));
                acc[i][0] = ffma2(ad, w0.x, acc[i][0]);
                acc[i][1] = ffma2(ad, w0.y, acc[i][1]);
                acc[i][2] = ffma2(ad, w1.x, acc[i][2]);
                acc[i][3] = ffma2(ad, w1.y, acc[i][3]);
            }
        }
    }
}
// gate1 mma: 8 rows per warp, 2 cols per lane (A read directly, may be gmem)
static __device__ __forceinline__ void mmagb8(const float* __restrict__ aRow, int lda,
                                              const float* __restrict__ sWT,
                                              u64 gacc[8], int colg) {
#pragma unroll
    for (int d4 = 0; d4 < 8; ++d4) {
        float4 a4[8];
#pragma unroll
        for (int i = 0; i < 8; ++i)
            a4[i] = *reinterpret_cast<const float4*>(aRow + i * lda + (d4 << 2));
#pragma unroll
        for (int dd = 0; dd < 4; ++dd) {
            const u64 w = *reinterpret_cast<const u64*>(sWT + ((d4 << 2) + dd) * PW + colg * 2);
#pragma unroll
            for (int i = 0; i < 8; ++i)
                gacc[i] = ffma2(dup2(comp4(a4[i], dd)), w, gacc[i]);
        }
    }
}

// reconstruct a weight element from 128n x 64k split tiles (fallback only)
static __device__ __forceinline__ float wrec128(const __nv_bfloat16* wt, int m, int n, int k) {
    const int nch = n >> 7, nn = n & 127, kch = k >> 6, kk = k & 63;
    const __nv_bfloat16* tb = wt + (size_t)(((m * 2 + nch) * 4 + kch)) * 16384;
    const uint32_t sw = swz128((uint32_t)(nn >> 3) * 1024 + (nn & 7) * 128 + kk * 2);
    return __bfloat162float(tb[sw >> 1]) + __bfloat162float(tb[8192 + (sw >> 1)]);
}
// reconstruct from 256n x 64k split tiles (fallback only)
static __device__ __forceinline__ float wrec256(const __nv_bfloat16* wt, int m, int n, int k) {
    const int kch = k >> 6, kk = k & 63;
    const __nv_bfloat16* tb = wt + (size_t)(m * 4 + kch) * 32768;
    const uint32_t sw = swz128((uint32_t)(n >> 3) * 1024 + (n & 7) * 128 + kk * 2);
    return __bfloat162float(tb[sw >> 1]) + __bfloat162float(tb[16384 + (sw >> 1)]);
}

#if GB_TC
// ---------- tcgen05 ----------
static __device__ __forceinline__ uint32_t elect_one_pred() {
    uint32_t pred;
    asm volatile(
        "{\n\t.reg .pred p;\n\telect.sync _|p, 0xFFFFFFFF;\n\tselp.b32 %0, 1, 0, p;\n\t}"
        : "=r"(pred));
    return pred;
}
#define TCGEN05_ALLOC(sa, n) \
    asm volatile("tcgen05.alloc.cta_group::1.sync.aligned.shared::cta.b32 [%0], %1;" \
                 :: "r"((uint32_t)(sa)), "r"((uint32_t)(n)) : "memory")
#define TCGEN05_DEALLOC(ta, n) \
    asm volatile("tcgen05.dealloc.cta_group::1.sync.aligned.b32 %0, %1;" :: "r"(ta), "r"((uint32_t)(n)))
#define TCGEN05_COMMIT(mb) \
    asm volatile("tcgen05.commit.cta_group::1.mbarrier::arrive::one.shared::cluster.b64 [%0];" \
                 :: "r"((uint32_t)(mb)) : "memory")
#define TCGEN05_WAIT_LD()  asm volatile("tcgen05.wait::ld.sync.aligned;" ::: "memory")
#define TCGEN05_FENCE_AFTER()  asm volatile("tcgen05.fence::after_thread_sync;" ::: "memory")
#define TCGEN05_FENCE_BEFORE() asm volatile("tcgen05.fence::before_thread_sync;" ::: "memory")
#define MBARRIER_INIT(mb, c) \
    asm volatile("mbarrier.init.shared.b64 [%0], %1;" :: "r"((uint32_t)(mb)), "r"((uint32_t)(c)) : "memory")
#define MBARRIER_WAIT_PARITY(mb, par) do { \
    uint32_t _mb = (uint32_t)(mb), _pa = (uint32_t)(par), _dn; \
    asm volatile("{\n\t.reg .pred p;\n\t" \
        "mbarrier.try_wait.parity.acquire.cta.shared::cta.b64 p, [%1], %2;\n\t" \
        "selp.b32 %0, 1, 0, p;\n\t}" : "=r"(_dn) : "r"(_mb), "r"(_pa) : "memory"); \
    if (!_dn) { \
        asm volatile("{\n\t.reg .pred P1;\n\t" \
            "WL_%=:\n\tmbarrier.try_wait.parity.acquire.cta.shared::cta.b64 P1, [%0], %1, 0x989680;\n\t" \
            "@P1 bra.uni WD_%=;\n\tbra.uni WL_%=;\n\tWD_%=:\n\t}" \
            :: "r"(_mb), "r"(_pa) : "memory"); \
    } \
} while (0)
#define TCGEN05_LD_32X32B_X32(r, ta) \
    asm volatile("tcgen05.ld.sync.aligned.32x32b.x32.b32 " \
        "{%0, %1, %2, %3, %4, %5, %6, %7, %8, %9, %10, %11, %12, %13, %14, %15, " \
        "%16, %17, %18, %19, %20, %21, %22, %23, %24, %25, %26, %27, %28, %29, %30, %31}, [%32];" \
        : "=r"((r)[0]),  "=r"((r)[1]),  "=r"((r)[2]),  "=r"((r)[3]), \
          "=r"((r)[4]),  "=r"((r)[5]),  "=r"((r)[6]),  "=r"((r)[7]), \
          "=r"((r)[8]),  "=r"((r)[9]),  "=r"((r)[10]), "=r"((r)[11]), \
          "=r"((r)[12]), "=r"((r)[13]), "=r"((r)[14]), "=r"((r)[15]), \
          "=r"((r)[16]), "=r"((r)[17]), "=r"((r)[18]), "=r"((r)[19]), \
          "=r"((r)[20]), "=r"((r)[21]), "=r"((r)[22]), "=r"((r)[23]), \
          "=r"((r)[24]), "=r"((r)[25]), "=r"((r)[26]), "=r"((r)[27]), \
          "=r"((r)[28]), "=r"((r)[29]), "=r"((r)[30]), "=r"((r)[31]) \
        : "r"(ta))

static constexpr u64 SMEM_DESC_BASE_SW128 =
    (u64(2) << 61) | (u64(1) << 46) | (u64(64) << 32) | (u64(1) << 16);
#define MAKE_SMEM_DESC(a) (SMEM_DESC_BASE_SW128 | ((u64)((a) >> 4) & 0x3FFF))

static __device__ __forceinline__ void mma_f16_ss(uint32_t d, u64 ad, u64 bd,
                                                  uint32_t idesc, uint32_t en) {
    asm volatile(
        "{\n\t.reg .pred p;\n\tsetp.ne.u32 p, %4, 0;\n\t"
        "tcgen05.mma.cta_group::1.kind::f16 [%0], %1, %2, %3, {%5, %5, %5, %5}, p;\n\t}"
        :: "r"(d), "l"(ad), "l"(bd), "r"(idesc), "r"(en), "r"(0u)
        : "memory");
}
#endif  // GB_TC

#define IDESC_BF16_M128_N128 0x8200490u
#define IDESC_BF16_M128_N256 0x8400490u

// =====================================================================
// Kernel 0: pre-split + pre-swizzle weights (f1,f2,Wk,Wv,Wq,Wo)
// =====================================================================
__global__ __launch_bounds__(256, 4)
void conv_w_kernel(const float* __restrict__ f1w, const float* __restrict__ f2w,
                   const float* __restrict__ Wk, const float* __restrict__ Wv,
                   const float* __restrict__ Wq, const float* __restrict__ Wo)
{
    const unsigned gidx = blockIdx.x * 256 + threadIdx.x;
    if (gidx < 2097152u) {
        const int arr = gidx >> 20;
        const unsigned rem = gidx & 0xFFFFFu;
        const int t = rem >> 14;
        const int e = rem & 16383;
        const int n = e >> 6, k = e & 63;
        const int m = t >> 4, c1 = (t >> 2) & 3, c2 = t & 3;
        float w;
        if (arr == 0)
            w = f1w[(size_t)m * 262144 + (size_t)(c1 * 256 + n) * 256 + c2 * 64 + k];
        else
            w = f2w[(size_t)m * 262144 + (size_t)n * 1024 + c1 * 256 + c2 * 64 + k];
        __nv_bfloat16 h, l;
        bsplit(w, h, l);
        const uint32_t sw = swz128((uint32_t)(n >> 3) * 1024 + (n & 7) * 128 + k * 2);
        __nv_bfloat16* dst = (arr == 0 ? g_w1t : g_w2t) + (size_t)t * 32768;
        dst[sw >> 1]           = h;
        dst[16384 + (sw >> 1)] = l;
    } else if (gidx < 2621440u) {
        const unsigned idx2 = gidx - 2097152u;
        const int arr2 = idx2 >> 18;
        const unsigned rem = idx2 & 0x3FFFFu;
        const int t = rem >> 13;
        const int e = rem & 8191;
        const int n = e >> 6, k = e & 63;
        const int m = t >> 3, nch = (t >> 2) & 1, kch = t & 3;
        const float* W = (arr2 == 0 ? Wk : Wv);
        const float w = W[(size_t)m * 65536 + (size_t)(nch * 128 + n) * 256 + kch * 64 + k];
        __nv_bfloat16 h, l;
        bsplit(w, h, l);
        const uint32_t sw = swz128((uint32_t)(n >> 3) * 1024 + (n & 7) * 128 + k * 2);
        __nv_bfloat16* dst = (arr2 == 0 ? g_wkt : g_wvt) + (size_t)t * 16384;
        dst[sw >> 1]          = h;
        dst[8192 + (sw >> 1)] = l;
    } else {
        const unsigned idx3 = gidx - 2621440u;
        const int arr3 = idx3 >> 18;
        const unsigned rem = idx3 & 0x3FFFFu;
        const int t = rem >> 14;
        const int e = rem & 16383;
        const int n = e >> 6, k = e & 63;
        const int m = t >> 2, kch = t & 3;
        const float* W = (arr3 == 0 ? Wq : Wo);
        float w = W[(size_t)m * 65536 + (size_t)n * 256 + kch * 64 + k];
        if (arr3 == 0) w *= 0.17677669529663687f;
        __nv_bfloat16 h, l;
        bsplit(w, h, l);
        const uint32_t sw = swz128((uint32_t)(n >> 3) * 1024 + (n & 7) * 128 + k * 2);
        __nv_bfloat16* dst = (arr3 == 0 ? g_wqt : g_wot) + (size_t)t * 32768;
        dst[sw >> 1]           = h;
        dst[16384 + (sw >> 1)] = l;
    }
}

// =====================================================================
// shared smem layout: A 128KB + 2 x (16KB hi + 16KB lo) B
// =====================================================================
#define KV_SMEM 197632
#define KV_MB0  16
#define KV_MB1  24
#define KV_AHI  1024
#define KV_ALO  66560
#define KV_B0H  132096
#define KV_B0L  148480
#define KV_B1H  164864
#define KV_B1L  181248

// =====================================================================
// Kernel A: fused Q,K,V projection + attention. grid 1024, 256 threads.
// =====================================================================
__global__ __launch_bounds__(256, 1)
void gcma_kvattn(const float* __restrict__ x,
                 const float* __restrict__ bq,
                 const float* __restrict__ bk, const float* __restrict__ bv)
{
    extern __shared__ char smA[];
    const int tid = threadIdx.x;
    const int r0  = blockIdx.x * 128;

#if GB_TC
    const uint32_t sbase = smem_to_u32(smA);
    const int wid = tid >> 5, lane = tid & 31;
    char* sAhi = smA + KV_AHI;
    char* sAlo = smA + KV_ALO;

    if (wid == 0) TCGEN05_ALLOC(sbase + 0, 512);
    if (tid == 0) { MBARRIER_INIT(sbase + KV_MB0, 1); MBARRIER_INIT(sbase + KV_MB1, 1); }
    __syncthreads();
    uint32_t tmem;
    asm volatile("ld.shared.b32 %0, [%1];" : "=r"(tmem) : "r"(sbase + 0));

    for (int idx = tid; idx < 8192; idx += 256) {
        const int r = idx >> 6, k = (idx & 63) << 2;
        const float4 v = *reinterpret_cast<const float4*>(x + (size_t)(r0 + r) * 256 + k);
        __nv_bfloat16 h0, h1, h2, h3, l0, l1, l2, l3;
        bsplit(v.x, h0, l0); bsplit(v.y, h1, l1);
        bsplit(v.z, h2, l2); bsplit(v.w, h3, l3);
        const uint32_t sw = swz128((uint32_t)((r >> 3) + (k >> 6) * 16) * 1024 + (r & 7) * 128 + (k & 63) * 2);
        *reinterpret_cast<uint2*>(sAhi + sw) = make_uint2(pk2(h0, h1), pk2(h2, h3));
        *reinterpret_cast<uint2*>(sAlo + sw) = make_uint2(pk2(l0, l1), pk2(l2, l3));
    }

    const u64 aH = MAKE_SMEM_DESC(sbase + KV_AHI), aL = MAKE_SMEM_DESC(sbase + KV_ALO);
    const u64 b0H = MAKE_SMEM_DESC(sbase + KV_B0H), b0L = MAKE_SMEM_DESC(sbase + KV_B0L);
    const u64 b1H = MAKE_SMEM_DESC(sbase + KV_B1H), b1L = MAKE_SMEM_DESC(sbase + KV_B1L);

    const int rr = (wid & 3) * 32 + lane;
    const int cb = (wid >> 2) * 128;
    const int b  = blockIdx.x * 32 + (rr >> 2);

    int w0 = 0, w1 = 0, pend0 = 0, pend1 = 0;

    for (int m = 0; m < 4; ++m) {
        // phase 1: Q (cols 0-255) + K (cols 256-511)
        for (int t = 0; t < 16; ++t) {
            const int isK = t >> 3, nch = (t >> 2) & 1, kch = t & 3;
            const int buf = t & 1;
            if (buf == 0) { if (pend0) { MBARRIER_WAIT_PARITY(sbase + KV_MB0, w0 & 1); ++w0; pend0 = 0; } }
            else          { if (pend1) { MBARRIER_WAIT_PARITY(sbase + KV_MB1, w1 & 1); ++w1; pend1 = 0; } }
            {
                float4* dh = reinterpret_cast<float4*>(smA + (buf ? KV_B1H : KV_B0H));
                float4* dl = reinterpret_cast<float4*>(smA + (buf ? KV_B1L : KV_B0L));
                if (isK) {
                    const float4* s4 = reinterpret_cast<const float4*>(
                        g_wkt + (size_t)(((m * 2 + nch) * 4 + kch)) * 16384);
#pragma unroll
                    for (int i = 0; i < 4; ++i) {
                        dh[tid + i * 256] = s4[tid + i * 256];
                        dl[tid + i * 256] = s4[1024 + tid + i * 256];
                    }
                } else {
                    const float4* s4 = reinterpret_cast<const float4*>(
                        g_wqt + (size_t)(m * 4 + kch) * 32768);
#pragma unroll
                    for (int i = 0; i < 4; ++i) {
                        dh[tid + i * 256] = s4[nch * 1024 + tid + i * 256];
                        dl[tid + i * 256] = s4[2048 + nch * 1024 + tid + i * 256];
                    }
                }
            }
            __syncthreads();
            if (wid == 0) {
                asm volatile("fence.proxy.async.shared::cta;" ::: "memory");
                TCGEN05_FENCE_AFTER();
                if (elect_one_pred()) {
                    const u64 bH = buf ? b1H : b0H, bL = buf ? b1L : b0L;
                    const uint32_t dcol = tmem + isK * 256 + nch * 128;
#pragma unroll
                    for (int j = 0; j < 4; ++j) {
                        const u64 ao = (u64)(kch * 1024 + j * 2), bo = (u64)(j * 2);
                        mma_f16_ss(dcol, aH + ao, bH + bo, IDESC_BF16_M128_N128,
                                   (kch == 0 && j == 0) ? 0u : 1u);
                        mma_f16_ss(dcol, aH + ao, bL + bo, IDESC_BF16_M128_N128, 1u);
                        mma_f16_ss(dcol, aL + ao, bH + bo, IDESC_BF16_M128_N128, 1u);
                    }
                    TCGEN05_COMMIT(sbase + (buf ? KV_MB1 : KV_MB0));
                }
            }
            if (buf == 0) pend0 = 1; else pend1 = 1;
        }
        if (pend0) { MBARRIER_WAIT_PARITY(sbase + KV_MB0, w0 & 1); ++w0; pend0 = 0; }
        if (pend1) { MBARRIER_WAIT_PARITY(sbase + KV_MB1, w1 & 1); ++w1; pend1 = 0; }
        TCGEN05_FENCE_AFTER();

        // epi1: scores + softmax -> p[4]
        float p[4];
        const int qlane = (lane & ~3) + m;
        for (int cc = 0; cc < 4; ++cc) {
            const int dof = cb + cc * 32;
            uint32_t qr[32];
            TCGEN05_LD_32X32B_X32(qr, tmem + dof);
            TCGEN05_WAIT_LD();
            uint32_t kr[32];
            TCGEN05_LD_32X32B_X32(kr, tmem + 256 + dof);
            TCGEN05_WAIT_LD();
            const float* bqp = bq + m * 256 + dof;
            const float* bkp = bk + m * 256 + dof;
            float s = 0.f;
#pragma unroll
            for (int j = 0; j < 32; ++j) {
                const float qv = __shfl_sync(0xffffffffu, __uint_as_float(qr[j]), qlane)
                               + bqp[j] * 0.17677669529663687f;
                s = fmaf(qv, __uint_as_float(kr[j]) + bkp[j], s);
            }
            float mx = s;
            mx = fmaxf(mx, __shfl_xor_sync(0xffffffffu, mx, 1));
            mx = fmaxf(mx, __shfl_xor_sync(0xffffffffu, mx, 2));
            float e = expf(s - mx);
            float se = e;
            se += __shfl_xor_sync(0xffffffffu, se, 1);
            se += __shfl_xor_sync(0xffffffffu, se, 2);
            p[cc] = e / se;
        }
        TCGEN05_FENCE_BEFORE();
        __syncthreads();

        // phase 2: V (cols 0-255)
        for (int t = 0; t < 8; ++t) {
            const int nch = t >> 2, kch = t & 3;
            const int buf = t & 1;
            if (buf == 0) { if (pend0) { MBARRIER_WAIT_PARITY(sbase + KV_MB0, w0 & 1); ++w0; pend0 = 0; } }
            else          { if (pend1) { MBARRIER_WAIT_PARITY(sbase + KV_MB1, w1 & 1); ++w1; pend1 = 0; } }
            {
                const float4* s4 = reinterpret_cast<const float4*>(
                    g_wvt + (size_t)(((m * 2 + nch) * 4 + kch)) * 16384);
                float4* dh = reinterpret_cast<float4*>(smA + (buf ? KV_B1H : KV_B0H));
                float4* dl = reinterpret_cast<float4*>(smA + (buf ? KV_B1L : KV_B0L));
#pragma unroll
                for (int i = 0; i < 4; ++i) {
                    dh[tid + i * 256] = s4[tid + i * 256];
                    dl[tid + i * 256] = s4[1024 + tid + i * 256];
                }
            }
            __syncthreads();
            if (wid == 0) {
                asm volatile("fence.proxy.async.shared::cta;" ::: "memory");
                TCGEN05_FENCE_AFTER();
                if (elect_one_pred()) {
                    const u64 bH = buf ? b1H : b0H, bL = buf ? b1L : b0L;
                    const uint32_t dcol = tmem + nch * 128;
#pragma unroll
                    for (int j = 0; j < 4; ++j) {
                        const u64 ao = (u64)(kch * 1024 + j * 2), bo = (u64)(j * 2);
                        mma_f16_ss(dcol, aH + ao, bH + bo, IDESC_BF16_M128_N128,
                                   (kch == 0 && j == 0) ? 0u : 1u);
                        mma_f16_ss(dcol, aH + ao, bL + bo, IDESC_BF16_M128_N128, 1u);
                        mma_f16_ss(dcol, aL + ao, bH + bo, IDESC_BF16_M128_N128, 1u);
                    }
                    TCGEN05_COMMIT(sbase + (buf ? KV_MB1 : KV_MB0));
                }
            }
            if (buf == 0) pend0 = 1; else pend1 = 1;
        }
        if (pend0) { MBARRIER_WAIT_PARITY(sbase + KV_MB0, w0 & 1); ++w0; pend0 = 0; }
        if (pend1) { MBARRIER_WAIT_PARITY(sbase + KV_MB1, w1 & 1); ++w1; pend1 = 0; }
        TCGEN05_FENCE_AFTER();

        // epi2: Oh = sum p_n * v_n
        for (int cc = 0; cc < 4; ++cc) {
            const int dof = cb + cc * 32;
            uint32_t vr[32];
            TCGEN05_LD_32X32B_X32(vr, tmem + dof);
            TCGEN05_WAIT_LD();
            const float* bvp = bv + m * 256 + dof;
            float t32[32];
#pragma unroll
            for (int j = 0; j < 32; ++j)
                t32[j] = p[cc] * (__uint_as_float(vr[j]) + bvp[j]);
#pragma unroll
            for (int j = 0; j < 32; ++j) {
                t32[j] += __shfl_xor_sync(0xffffffffu, t32[j], 1);
                t32[j] += __shfl_xor_sync(0xffffffffu, t32[j], 2);
            }
            const int qi = lane & 3;
            float* op = g_oh + ((size_t)m * 32768 + b) * 256 + dof + qi * 8;
            *reinterpret_cast<float4*>(op) =
                make_float4(t32[qi * 8 + 0], t32[qi * 8 + 1], t32[qi * 8 + 2], t32[qi * 8 + 3]);
            *reinterpret_cast<float4*>(op + 4) =
                make_float4(t32[qi * 8 + 4], t32[qi * 8 + 5], t32[qi * 8 + 6], t32[qi * 8 + 7]);
        }
        TCGEN05_FENCE_BEFORE();
        __syncthreads();
    }

    if (tid == 0) {
        asm volatile("mbarrier.inval.shared.b64 [%0];" :: "r"(sbase + KV_MB0) : "memory");
        asm volatile("mbarrier.inval.shared.b64 [%0];" :: "r"(sbase + KV_MB1) : "memory");
    }
    __syncthreads();
    if (wid == 0) TCGEN05_DEALLOC(tmem, 512);

#else  // fp32 fallback (slow; never runs on sm_103a)
    const int b = blockIdx.x * 32 + (tid >> 3);
    const int h = tid & 7;
    for (int m = 0; m < 4; ++m) {
        float q[32];
        for (int d = 0; d < 32; ++d) {
            float qd = bq[m * 256 + h * 32 + d] * 0.17677669529663687f;
            for (int k = 0; k < 256; ++k)
                qd = fmaf(x[(size_t)(b * 4 + m) * 256 + k], wrec256(g_wqt, m, h * 32 + d, k), qd);
            q[d] = qd;
        }
        float sc[4];
        for (int n = 0; n < 4; ++n) {
            float s = 0.f;
            for (int d = 0; d < 32; ++d) {
                float kd = bk[m * 256 + h * 32 + d];
                for (int k = 0; k < 256; ++k)
                    kd = fmaf(x[(size_t)(b * 4 + n) * 256 + k], wrec128(g_wkt, m, h * 32 + d, k), kd);
                s = fmaf(q[d], kd, s);
            }
            sc[n] = s;
        }
        const float mx = fmaxf(fmaxf(sc[0], sc[1]), fmaxf(sc[2], sc[3]));
        float e[4], se = 0.f;
        for (int n = 0; n < 4; ++n) { e[n] = expf(sc[n] - mx); se += e[n]; }
        for (int d = 0; d < 32; ++d) {
            float o = 0.f;
            for (int n = 0; n < 4; ++n) {
                float vd = bv[m * 256 + h * 32 + d];
                for (int k = 0; k < 256; ++k)
                    vd = fmaf(x[(size_t)(b * 4 + n) * 256 + k], wrec128(g_wvt, m, h * 32 + d, k), vd);
                o = fmaf(e[n] / se, vd, o);
            }
            g_oh[((size_t)m * 32768 + b) * 256 + h * 32 + d] = o;
        }
    }
#endif
}

// =====================================================================
// Kernel D: Wo projection (tcgen05, 8 double-buffered N=128 chunks)
// =====================================================================
__global__ __launch_bounds__(256, 1)
void gcma_qo(const float* __restrict__ bo)
{
    extern __shared__ char smQ[];
    const int tid = threadIdx.x;
    const int m   = blockIdx.y;
    const int b0  = blockIdx.x * 128;

    const __nv_bfloat16* wt = g_wot;
    const float* bias = bo + m * 256;
    float* dst = g_ao + ((size_t)m * 32768 + b0) * 256;

#if GB_TC
    const uint32_t sbase = smem_to_u32(smQ);
    const int wid = tid >> 5, lane = tid & 31;
    char* sAhi = smQ + KV_AHI;
    char* sAlo = smQ + KV_ALO;

    if (wid == 0) TCGEN05_ALLOC(sbase + 0, 512);
    if (tid == 0) { MBARRIER_INIT(sbase + KV_MB0, 1); MBARRIER_INIT(sbase + KV_MB1, 1); }
    __syncthreads();
    uint32_t tmem;
    asm volatile("ld.shared.b32 %0, [%1];" : "=r"(tmem) : "r"(sbase + 0));

    for (int idx = tid; idx < 8192; idx += 256) {
        const int r = idx >> 6, k = (idx & 63) << 2;
        const float4 v = *reinterpret_cast<const float4*>(
            g_oh + ((size_t)m * 32768 + b0 + r) * 256 + k);
        __nv_bfloat16 h0, h1, h2, h3, l0, l1, l2, l3;
        bsplit(v.x, h0, l0); bsplit(v.y, h1, l1);
        bsplit(v.z, h2, l2); bsplit(v.w, h3, l3);
        const uint32_t sw = swz128((uint32_t)((r >> 3) + (k >> 6) * 16) * 1024 + (r & 7) * 128 + (k & 63) * 2);
        *reinterpret_cast<uint2*>(sAhi + sw) = make_uint2(pk2(h0, h1), pk2(h2, h3));
        *reinterpret_cast<uint2*>(sAlo + sw) = make_uint2(pk2(l0, l1), pk2(l2, l3));
    }

    const u64 aH = MAKE_SMEM_DESC(sbase + KV_AHI), aL = MAKE_SMEM_DESC(sbase + KV_ALO);
    const u64 b0H = MAKE_SMEM_DESC(sbase + KV_B0H), b0L = MAKE_SMEM_DESC(sbase + KV_B0L);
    const u64 b1H = MAKE_SMEM_DESC(sbase + KV_B1H), b1L = MAKE_SMEM_DESC(sbase + KV_B1L);

    int w0 = 0, w1 = 0, pend0 = 0, pend1 = 0;
    for (int c = 0; c < 8; ++c) {
        const int nch = c >> 2, kch = c & 3;
        const int buf = c & 1;
        if (buf == 0) { if (pend0) { MBARRIER_WAIT_PARITY(sbase + KV_MB0, w0 & 1); ++w0; pend0 = 0; } }
        else          { if (pend1) { MBARRIER_WAIT_PARITY(sbase + KV_MB1, w1 & 1); ++w1; pend1 = 0; } }
        {
            const float4* s4 = reinterpret_cast<const float4*>(wt + (size_t)(m * 4 + kch) * 32768);
            float4* dh = reinterpret_cast<float4*>(smQ + (buf ? KV_B1H : KV_B0H));
            float4* dl = reinterpret_cast<float4*>(smQ + (buf ? KV_B1L : KV_B0L));
#pragma unroll
            for (int i = 0; i < 4; ++i) {
                dh[tid + i * 256] = s4[nch * 1024 + tid + i * 256];
                dl[tid + i * 256] = s4[2048 + nch * 1024 + tid + i * 256];
            }
        }
        __syncthreads();
        if (wid == 0) {
            asm volatile("fence.proxy.async.shared::cta;" ::: "memory");
            TCGEN05_FENCE_AFTER();
            if (elect_one_pred()) {
                const u64 bH = buf ? b1H : b0H, bL = buf ? b1L : b0L;
                const uint32_t dcol = tmem + nch * 128;
#pragma unroll
                for (int j = 0; j < 4; ++j) {
                    const u64 ao = (u64)(kch * 1024 + j * 2), bo2 = (u64)(j * 2);
                    mma_f16_ss(dcol, aH + ao, bH + bo2, IDESC_BF16_M128_N128,
                               (kch == 0 && j == 0) ? 0u : 1u);
                    mma_f16_ss(dcol, aH + ao, bL + bo2, IDESC_BF16_M128_N128, 1u);
                    mma_f16_ss(dcol, aL + ao, bH + bo2, IDESC_BF16_M128_N128, 1u);
                }
                TCGEN05_COMMIT(sbase + (buf ? KV_MB1 : KV_MB0));
            }
        }
        if (buf == 0) pend0 = 1; else pend1 = 1;
    }
    if (pend0) { MBARRIER_WAIT_PARITY(sbase + KV_MB0, w0 & 1); ++w0; pend0 = 0; }
    if (pend1) { MBARRIER_WAIT_PARITY(sbase + KV_MB1, w1 & 1); ++w1; pend1 = 0; }
    TCGEN05_FENCE_AFTER();

    {
        const int rr = (wid & 3) * 32 + lane;
        const int cb = (wid >> 2) * 128;
        for (int cc = 0; cc < 4; ++cc) {
            uint32_t dr[32];
            TCGEN05_LD_32X32B_X32(dr, tmem + cb + cc * 32);
            TCGEN05_WAIT_LD();
            TCGEN05_FENCE_BEFORE();
            const int c0 = cb + cc * 32;
            float* drow = dst + (size_t)rr * 256 + c0;
#pragma unroll
            for (int q = 0; q < 8; ++q) {
                *reinterpret_cast<float4*>(drow + q * 4) =
                    make_float4(__uint_as_float(dr[q * 4 + 0]) + bias[c0 + q * 4 + 0],
                                __uint_as_float(dr[q * 4 + 1]) + bias[c0 + q * 4 + 1],
                                __uint_as_float(dr[q * 4 + 2]) + bias[c0 + q * 4 + 2],
                                __uint_as_float(dr[q * 4 + 3]) + bias[c0 + q * 4 + 3]);
            }
        }
    }

    __syncthreads();
    if (tid == 0) {
        asm volatile("mbarrier.inval.shared.b64 [%0];" :: "r"(sbase + KV_MB0) : "memory");
        asm volatile("mbarrier.inval.shared.b64 [%0];" :: "r"(sbase + KV_MB1) : "memory");
    }
    __syncthreads();
    if (wid == 0) TCGEN05_DEALLOC(tmem, 512);

#else
    for (int e = tid; e < 128 * 256; e += 256) {
        const int r = e >> 8, n = e & 255;
        float dot = 0.f;
        for (int k = 0; k < 256; ++k)
            dot = fmaf(g_oh[((size_t)m * 32768 + b0 + r) * 256 + k], wrec256(wt, m, n, k), dot);
        dst[(size_t)r * 256 + n] = dot + bias[n];
    }
#endif
}

// =====================================================================
// Kernel E: gate MLP + LayerNorm, 64 rows/block, grid (512,4)
// A read directly from gmem (each element exactly once); small smem ->
// multiple blocks/SM for latency hiding.
// =====================================================================
#define TL_WT   0        // 8320 floats
#define TL_GH   8320     // 64*64 = 4096
#define TL_GATE 12416    // 64
#define TL_FLOATS 12480
#define TL_BYTES  (TL_FLOATS * 4)

__global__ __launch_bounds__(256, 2)
void gcma_tail(const float* __restrict__ x,
               const float* __restrict__ g1w, const float* __restrict__ g1b,
               const float* __restrict__ g2w, const float* __restrict__ g2b,
               const float* __restrict__ lng, const float* __restrict__ lnb,
               float* __restrict__ out)
{
    extern __shared__ float smL[];
    float* sWT   = smL + TL_WT;
    float* sGH   = smL + TL_GH;
    float* sGate = smL + TL_GATE;

    const int tid = threadIdx.x;
    const int m   = blockIdx.y;
    const int b0  = blockIdx.x * 64;
    const long g0 = (long)b0 * 4;

    const int warp = tid >> 5;
    const int colg = tid & 31;

    const float* xBase  = x    + ((size_t)b0 * 4 + m) * 256;        // row stride 1024
    const float* aoBase = g_ao + ((size_t)m * 32768 + b0) * 256;    // row stride 256

    // gate layer 1: tanh([x;AO] @ g1w^T + g1b), 8 rows/warp, 2 cols/lane
    // A read directly from gmem (broadcast LDG within warp)
    {
        const float* W = g1w + (size_t)m * 32768;
        Wreg<2> wr;
        ldgW<2>(W, 512, 0, wr, tid);
        u64 gacc[8];
#pragma unroll
        for (int i = 0; i < 8; ++i) gacc[i] = 0ULL;
        const float* aX  = xBase  + (size_t)(warp * 8) * 1024;
        const float* aAO = aoBase + (size_t)(warp * 8) * 256;
        for (int dt = 0; dt < 16; ++dt) {
            __syncthreads();
            stsW<2>(sWT, wr, tid);
            if (dt < 15) ldgW<2>(W, 512, (dt + 1) * 32, wr, tid);
            __syncthreads();
            if (dt < 8)
                mmagb8(aX + dt * 32, 1024, sWT, gacc, colg);
            else
                mmagb8(aAO + (dt - 8) * 32, 256, sWT, gacc, colg);
        }
        const float gb0 = g1b[m * 64 + colg * 2];
        const float gb1 = g1b[m * 64 + colg * 2 + 1];
#pragma unroll
        for (int i = 0; i < 8; ++i) {
            const float2 p = unpk(gacc[i]);
            sGH[(warp * 8 + i) * 64 + colg * 2]     = tanhf(p.x + gb0);
            sGH[(warp * 8 + i) * 64 + colg * 2 + 1] = tanhf(p.y + gb1);
        }
    }
    __syncthreads();

    // gate layer 2 + sigmoid
    if (tid < 64) {
        const float* g2 = g2w + m * 64;
        float dot = g2b[m];
#pragma unroll 8
        for (int j = 0; j < 64; ++j) dot = fmaf(sGH[tid * 64 + j], g2[j], dot);
        const float gate = 1.f / (1.f + expf(-dot));
        sGate[tid] = gate;
        out[OUT_GATE_BASE + (size_t)(b0 + tid) * 4 + m] = gate;
    }
    __syncthreads();

    // residual + LayerNorm -> g_y (8 rows per warp; x/ao re-read from L2)
    {
        const int lane = tid & 31;
#pragma unroll
        for (int i = 0; i < 8; ++i) {
            const int bl = warp * 8 + i;
            const float* xr  = xBase  + (size_t)bl * 1024;
            const float* aor = aoBase + (size_t)bl * 256;
            const float gate = sGate[bl];
            float r[8];
            float sum = 0.f;
#pragma unroll
            for (int k = 0; k < 8; ++k) {
                const int d = k * 32 + lane;
                r[k] = xr[d] + gate * aor[d];
                sum += r[k];
            }
#pragma unroll
            for (int o = 16; o; o >>= 1) sum += __shfl_xor_sync(0xffffffffu, sum, o);
            const float mu = sum * (1.f / 256.f);
            float var = 0.f;
#pragma unroll
            for (int k = 0; k < 8; ++k) { const float t = r[k] - mu; var = fmaf(t, t, var); }
#pragma unroll
            for (int o = 16; o; o >>= 1) var += __shfl_xor_sync(0xffffffffu, var, o);
            const float rs = rsqrtf(var * (1.f / 256.f) + 1e-5f);
            float* yr = g_y + (size_t)(g0 + bl * 4 + m) * 256;
#pragma unroll
            for (int k = 0; k < 8; ++k) {
                const int d = k * 32 + lane;
                yr[d] = (r[k] - mu) * rs * lng[m * 256 + d] + lnb[m * 256 + d];
            }
        }
    }
}

// =====================================================================
// Kernel F: FF (tcgen05)
// =====================================================================
#define P2_SMEM 197632
#define P2_TM    0
#define P2_MB    8
#define P2_AHI   1024
#define P2_ALO   66560
#define P2_BHI   132096
#define P2_BLO   164864

static __device__ __forceinline__ void loadB(const __nv_bfloat16* base, int m, int c1, int c2,
                                             float4 pf[16], int tid) {
    const float4* src = reinterpret_cast<const float4*>(base + (size_t)((m * 4 + c1) * 4 + c2) * 32768);
#pragma unroll
    for (int i = 0; i < 8; ++i) {
        pf[i]     = src[tid + i * 256];
        pf[8 + i] = src[2048 + tid + i * 256];
    }
}
static __device__ __forceinline__ void stsB(char* sBhi, char* sBlo, const float4 pf[16], int tid) {
#pragma unroll
    for (int i = 0; i < 8; ++i) {
        reinterpret_cast<float4*>(sBhi)[tid + i * 256] = pf[i];
        reinterpret_cast<float4*>(sBlo)[tid + i * 256] = pf[8 + i];
    }
}

__global__ __launch_bounds__(256, 1)
void gcma_part2tc(const float* __restrict__ f1w, const float* __restrict__ f1b,
                  const float* __restrict__ f2w, const float* __restrict__ f2b,
                  float* __restrict__ out)
{
    extern __shared__ char sm2[];
    const int tid  = threadIdx.x;
    const int m    = blockIdx.y;
    const int b0   = blockIdx.x * 128;

#if GB_TC
    const uint32_t sbase = smem_to_u32(sm2);
    const uint32_t TMP  = sbase + P2_TM;
    const uint32_t MBAR = sbase + P2_MB;
    char* sAhi = sm2 + P2_AHI;
    char* sAlo = sm2 + P2_ALO;
    char* sBhi = sm2 + P2_BHI;
    char* sBlo = sm2 + P2_BLO;
    const uint32_t aHiA = sbase + P2_AHI, aLoA = sbase + P2_ALO;
    const uint32_t bHiA = sbase + P2_BHI, bLoA = sbase + P2_BLO;

    const int wid  = tid >> 5, lane = tid & 31;
    unsigned* hfbase = g_hfscr + (size_t)(blockIdx.y * 256 + blockIdx.x) * 131072u;

    if (wid == 0) TCGEN05_ALLOC(TMP, 512);
    if (tid == 0) MBARRIER_INIT(MBAR, 1);
    __syncthreads();
    uint32_t tmem;
    asm volatile("ld.shared.b32 %0, [%1];" : "=r"(tmem) : "r"(TMP));

    for (int idx = tid; idx < 8192; idx += 256) {
        const int r = idx >> 6, k = (idx & 63) << 2;
        const float4 v = *reinterpret_cast<const float4*>(
            g_y + ((size_t)(b0 + r) * 4 + m) * 256 + k);
        __nv_bfloat16 h0, h1, h2, h3, l0, l1, l2, l3;
        bsplit(v.x, h0, l0); bsplit(v.y, h1, l1);
        bsplit(v.z, h2, l2); bsplit(v.w, h3, l3);
        const uint32_t sw = swz128((uint32_t)((r >> 3) + (k >> 6) * 16) * 1024 + (r & 7) * 128 + (k & 63) * 2);
        *reinterpret_cast<uint2*>(sAhi + sw) = make_uint2(pk2(h0, h1), pk2(h2, h3));
        *reinterpret_cast<uint2*>(sAlo + sw) = make_uint2(pk2(l0, l1), pk2(l2, l3));
    }

    float4 pf[16];
    loadB(g_w1t, m, 0, 0, pf, tid);
    int ph = 0;
    const u64 aH = MAKE_SMEM_DESC(aHiA), aL = MAKE_SMEM_DESC(aLoA);
    const u64 bH = MAKE_SMEM_DESC(bHiA), bL = MAKE_SMEM_DESC(bLoA);

    for (int nch = 0; nch < 4; ++nch) {
        for (int kch = 0; kch < 4; ++kch) {
            stsB(sBhi, sBlo, pf, tid);
            __syncthreads();
            if (wid == 0) {
                asm volatile("fence.proxy.async.shared::cta;" ::: "memory");
                TCGEN05_FENCE_AFTER();
                if (elect_one_pred()) {
#pragma unroll
                    for (int j = 0; j < 4; ++j) {
                        const u64 ao = (u64)(kch * 1024 + j * 2), bo = (u64)(j * 2);
                        mma_f16_ss(tmem, aH + ao, bH + bo, IDESC_BF16_M128_N256,
                                   (kch == 0 && j == 0) ? 0u : 1u);
                        mma_f16_ss(tmem, aH + ao, bL + bo, IDESC_BF16_M128_N256, 1u);
                        mma_f16_ss(tmem, aL + ao, bH + bo, IDESC_BF16_M128_N256, 1u);
                    }
                    TCGEN05_COMMIT(MBAR);
                }
            }
            const int nb = nch * 4 + kch + 1;
            if (nb < 16) loadB(g_w1t, m, nb >> 2, nb & 3, pf, tid);
            else         loadB(g_w2t, m, 0, 0, pf, tid);
            MBARRIER_WAIT_PARITY(MBAR, ph & 1);
            ++ph;
            TCGEN05_FENCE_AFTER();
        }
        {
            const int r  = (wid & 3) * 32 + lane;
            const int cb = (wid >> 2) * 128;
            for (int cc = 0; cc < 4; ++cc) {
                uint32_t dr[32];
                TCGEN05_LD_32X32B_X32(dr, tmem + cb + cc * 32);
                TCGEN05_WAIT_LD();
                TCGEN05_FENCE_BEFORE();
                const int c0 = nch * 256 + cb + cc * 32;
                unsigned* dst = hfbase + (size_t)r * 1024 + c0;
#pragma unroll
                for (int j = 0; j < 32; ++j) {
                    float v = __uint_as_float(dr[j]) + f1b[m * 1024 + c0 + j];
                    v = 0.5f * v * (1.f + erff(v * 0.7071067811865476f));
                    __nv_bfloat16 h, l;
                    bsplit(v, h, l);
                    dst[j] = pk2(h, l);
                }
            }
        }
        __syncthreads();
    }

    for (int ch = 0; ch < 4; ++ch) {
        for (int idx = tid; idx < 8192; idx += 256) {
            const int r = idx >> 6, k = (idx & 63) << 2;
            const uint4 u = *reinterpret_cast<const uint4*>(
                hfbase + (size_t)r * 1024 + ch * 256 + k);
            const unsigned uu[4] = {u.x, u.y, u.z, u.w};
            __nv_bfloat16 h[4], l[4];
#pragma unroll
            for (int j = 0; j < 4; ++j) {
                h[j] = __ushort_as_bfloat16((unsigned short)(uu[j] & 0xFFFFu));
                l[j] = __ushort_as_bfloat16((unsigned short)(uu[j] >> 16));
            }
            const uint32_t sw = swz128((uint32_t)((r >> 3) + (k >> 6) * 16) * 1024 + (r & 7) * 128 + (k & 63) * 2);
            *reinterpret_cast<uint2*>(sAhi + sw) = make_uint2(pk2(h[0], h[1]), pk2(h[2], h[3]));
            *reinterpret_cast<uint2*>(sAlo + sw) = make_uint2(pk2(l[0], l[1]), pk2(l[2], l[3]));
        }
        for (int kc = 0; kc < 4; ++kc) {
            stsB(sBhi, sBlo, pf, tid);
            __syncthreads();
            if (wid == 0) {
                asm volatile("fence.proxy.async.shared::cta;" ::: "memory");
                TCGEN05_FENCE_AFTER();
                if (elect_one_pred()) {
#pragma unroll
                    for (int j = 0; j < 4; ++j) {
                        const u64 ao = (u64)(kc * 1024 + j * 2), bo = (u64)(j * 2);
                        mma_f16_ss(tmem + 256, aH + ao, bH + bo, IDESC_BF16_M128_N256,
                                   (ch == 0 && kc == 0 && j == 0) ? 0u : 1u);
                        mma_f16_ss(tmem + 256, aH + ao, bL + bo, IDESC_BF16_M128_N256, 1u);
                        mma_f16_ss(tmem + 256, aL + ao, bH + bo, IDESC_BF16_M128_N256, 1u);
                    }
                    TCGEN05_COMMIT(MBAR);
                }
            }
            const int nb = ch * 4 + kc + 1;
            if (nb < 16) loadB(g_w2t, m, nb >> 2, nb & 3, pf, tid);
            MBARRIER_WAIT_PARITY(MBAR, ph & 1);
            ++ph;
            TCGEN05_FENCE_AFTER();
        }
    }

    {
        const int r  = (wid & 3) * 32 + lane;
        const int cb = (wid >> 2) * 128;
        for (int cc = 0; cc < 4; ++cc) {
            uint32_t dr[32];
            TCGEN05_LD_32X32B_X32(dr, tmem + 256 + cb + cc * 32);
            TCGEN05_WAIT_LD();
            TCGEN05_FENCE_BEFORE();
            const int c0 = cb + cc * 32;
            const float* yrow = g_y + ((size_t)(b0 + r) * 4 + m) * 256 + c0;
            float* orow = out + ((size_t)(b0 + r) * 4 + m) * 256 + c0;
#pragma unroll
            for (int j = 0; j < 32; ++j)
                orow[j] = yrow[j] + __uint_as_float(dr[j]) + f2b[m * 256 + c0 + j];
        }
    }

    __syncthreads();
    if (tid == 0)
        asm volatile("mbarrier.inval.shared.b64 [%0];" :: "r"(MBAR) : "memory");
    __syncthreads();
    if (wid == 0) TCGEN05_DEALLOC(tmem, 512);

#else
    float* smf = reinterpret_cast<float*>(sm2);
    float* sY  = smf;
    float* sHF = smf + 16384;
    float* sWT = smf + 32768;
    const int warp = tid >> 5;
    const int colg = tid & 31;

    for (int half = 0; half < 2; ++half) {
        const int hb0 = b0 + half * 64;
        __syncthreads();
        for (int idx = tid; idx < 4096; idx += TPB) {
            const int r = idx >> 6, q = idx & 63;
            *reinterpret_cast<float4*>(sY + r * 256 + q * 4) =
                *reinterpret_cast<const float4*>(g_y + ((size_t)(hb0 + r) * 4 + m) * 256 + q * 4);
        }
        u64 facc[8][4];
#pragma unroll
        for (int i = 0; i < 8; ++i)
#pragma unroll
            for (int j = 0; j < 4; ++j) facc[i][j] = 0ULL;
        const float* aY  = sY  + warp * 8 * 256;
        const float* aHF = sHF + warp * 8 * 256;

        for (int ch = 0; ch < 4; ++ch) {
            u64 hacc[8][4];
#pragma unroll
            for (int i = 0; i < 8; ++i)
#pragma unroll
                for (int j = 0; j < 4; ++j) hacc[i][j] = 0ULL;
            {
                const float* W1 = f1w + (size_t)m * 262144 + (size_t)ch * 65536;
                Wreg<8> wr;
                ldgW<8>(W1, 256, 0, wr, tid);
                for (int dt = 0; dt < 8; ++dt) {
                    __syncthreads();
                    stsW<8>(sWT, wr, tid);
                    if (dt < 7) ldgW<8>(W1, 256, (dt + 1) * 32, wr, tid);
                    __syncthreads();
                    mma64b(aY + dt * 32, 256, sWT, hacc, colg);
                }
            }
            __syncthreads();
            {
                const float* b1 = f1b + m * 1024 + ch * 256;
                float bl0[4], bl1[4];
#pragma unroll
                for (int j = 0; j < 4; ++j) { bl0[j] = b1[colg * 4 + j]; bl1[j] = b1[128 + colg * 4 + j]; }
#pragma unroll
                for (int i = 0; i < 8; ++i) {
                    const int r = warp * 8 + i;
                    const float2 pa = unpk(hacc[i][0]), pb = unpk(hacc[i][1]);
                    const float2 pc = unpk(hacc[i][2]), pd = unpk(hacc[i][3]);
                    float v0[4] = {pa.x + bl0[0], pa.y + bl0[1], pb.x + bl0[2], pb.y + bl0[3]};
                    float v1[4] = {pc.x + bl1[0], pc.y + bl1[1], pd.x + bl1[2], pd.y + bl1[3]};
#pragma unroll
                    for (int j = 0; j < 4; ++j) {
                        v0[j] = 0.5f * v0[j] * (1.f + erff(v0[j] * 0.7071067811865476f));
                        v1[j] = 0.5f * v1[j] * (1.f + erff(v1[j] * 0.7071067811865476f));
                    }
                    *reinterpret_cast<float4*>(sHF + r * 256 + colg * 4) =
                        make_float4(v0[0], v0[1], v0[2], v0[3]);
                    *reinterpret_cast<float4*>(sHF + r * 256 + 128 + colg * 4) =
                        make_float4(v1[0], v1[1], v1[2], v1[3]);
                }
            }
            {
                const float* W2 = f2w + (size_t)m * 262144;
                Wreg<8> wr;
                ldgW<8>(W2, 1024, ch * 256, wr, tid);
                for (int dt = 0; dt < 8; ++dt) {
                    __syncthreads();
                    stsW<8>(sWT, wr, tid);
                    if (dt < 7) ldgW<8>(W2, 1024, ch * 256 + (dt + 1) * 32, wr, tid);
                    __syncthreads();
                    mma64b(aHF + dt * 32, 256, sWT, facc, colg);
                }
            }
            __syncthreads();
        }
        {
            const float* b2 = f2b + m * 256;
            float bl0[4], bl1[4];
#pragma unroll
            for (int j = 0; j < 4; ++j) { bl0[j] = b2[colg * 4 + j]; bl1[j] = b2[128 + colg * 4 + j]; }
#pragma unroll
            for (int i = 0; i < 8; ++i) {
                const int r = warp * 8 + i;
                const float4 y0 = *reinterpret_cast<const float4*>(sY + r * 256 + colg * 4);
                const float4 y1 = *reinterpret_cast<const float4*>(sY + r * 256 + 128 + colg * 4);
                const float2 pa = unpk(facc[i][0]), pb = unpk(facc[i][1]);
                const float2 pc = unpk(facc[i][2]), pd = unpk(facc[i][3]);
                float* op = out + ((size_t)(hb0 + r) * 4 + m) * 256;
                *reinterpret_cast<float4*>(op + colg * 4) =
                    make_float4(y0.x + pa.x + bl0[0], y0.y + pa.y + bl0[1],
                                y0.z + pb.x + bl0[2], y0.w + pb.y + bl0[3]);
                *reinterpret_cast<float4*>(op + 128 + colg * 4) =
                    make_float4(y1.x + pc.x + bl1[0], y1.y + pc.y + bl1[1],
                                y1.z + pd.x + bl1[2], y1.w + pd.y + bl1[3]);
            }
        }
    }
#endif
}

extern "C" void kernel_launch(void* const* d_in, const int* in_sizes, int n_in,
                              void* d_out, int out_size) {
    const float* x   = (const float*)d_in[0];
    const float* Wq  = (const float*)d_in[1];
    const float* bq  = (const float*)d_in[2];
    const float* Wk  = (const float*)d_in[3];
    const float* bk  = (const float*)d_in[4];
    const float* Wv  = (const float*)d_in[5];
    const float* bv  = (const float*)d_in[6];
    const float* Wo  = (const float*)d_in[7];
    const float* bo  = (const float*)d_in[8];
    const float* g1w = (const float*)d_in[9];
    const float* g1b = (const float*)d_in[10];
    const float* g2w = (const float*)d_in[11];
    const float* g2b = (const float*)d_in[12];
    const float* lng = (const float*)d_in[13];
    const float* lnb = (const float*)d_in[14];
    const float* f1w = (const float*)d_in[15];
    const float* f1b = (const float*)d_in[16];
    const float* f2w = (const float*)d_in[17];
    const float* f2b = (const float*)d_in[18];
    float* out = (float*)d_out;

    cudaFuncSetAttribute(gcma_kvattn, cudaFuncAttributeMaxDynamicSharedMemorySize, KV_SMEM);
    cudaFuncSetAttribute(gcma_qo, cudaFuncAttributeMaxDynamicSharedMemorySize, KV_SMEM);
    cudaFuncSetAttribute(gcma_tail, cudaFuncAttributeMaxDynamicSharedMemorySize, TL_BYTES);
    cudaFuncSetAttribute(gcma_part2tc, cudaFuncAttributeMaxDynamicSharedMemorySize, P2_SMEM);

    conv_w_kernel<<<12288, 256>>>(f1w, f2w, Wk, Wv, Wq, Wo);
    gcma_kvattn<<<1024, 256, KV_SMEM>>>(x, bq, bk, bv);
    gcma_qo<<<dim3(256, 4), 256, KV_SMEM>>>(bo);
    gcma_tail<<<dim3(512, 4), 256, TL_BYTES>>>(x, g1w, g1b, g2w, g2b, lng, lnb, out);
    gcma_part2tc<<<dim3(256, 4), 256, P2_SMEM>>>(f1w, f1b, f2w, f2b, out);
}